// round 1
// baseline (speedup 1.0000x reference)
#include <cuda_runtime.h>
#include <cuda_bf16.h>
#include <math.h>

#define Bq   4
#define Sq   1024
#define Dq   1024
#define Hh   16
#define HD   64
#define Ll   2
#define Ee   8
#define DFFq 4096
#define TOK  (Bq*Sq)   // 4096

// ---------------- static scratch (allocation-free rule: __device__ globals) ---
__device__ float g_X[TOK*Dq];        // residual stream
__device__ float g_H[TOK*Dq];        // LN output
__device__ float g_Q[TOK*Dq];
__device__ float g_K[TOK*Dq];
__device__ float g_V[TOK*Dq];
__device__ float g_Y[TOK*Dq];        // attention output
__device__ float g_hidden[(size_t)Ee*TOK*DFFq]; // 512MB expert hidden
__device__ int   g_counts[Ee];
__device__ int   g_tok[Ee*TOK];
__device__ float g_wt[Ee*TOK];
__device__ int   g_te[TOK*2];        // per-token top2 expert ids
__device__ float g_tw[TOK*2];        // per-token top2 weights
__device__ int   g_bsel[Bq*2];       // per-sample (seq moe)
__device__ float g_bw[Bq*2];
__device__ float g_xmean[Bq*Dq];

// ---------------- helpers ----------------------------------------------------
__device__ __forceinline__ void top2_of8(const float* lg, int& i1, int& i2,
                                         float& w1, float& w2) {
    i1 = 0; float v1 = lg[0];
#pragma unroll
    for (int e = 1; e < Ee; e++) if (lg[e] > v1) { v1 = lg[e]; i1 = e; }
    i2 = -1; float v2 = -3.0e38f;
#pragma unroll
    for (int e = 0; e < Ee; e++) if (e != i1 && lg[e] > v2) { v2 = lg[e]; i2 = e; }
    float ex = expf(v2 - v1);                 // softmax over [v1, v2], v1 >= v2
    w1 = 1.0f / (1.0f + ex);
    w2 = ex / (1.0f + ex);
}

__device__ __forceinline__ float gelu_exact(float x) {
    return 0.5f * x * (1.0f + erff(x * 0.7071067811865476f));
}

// ---------------- simple kernels ---------------------------------------------
__global__ void copy_in_kernel(const float* __restrict__ src) {
    int i = blockIdx.x * 256 + threadIdx.x;
    g_X[i] = src[i];
}
__global__ void copy_out_kernel(float* __restrict__ dst) {
    int i = blockIdx.x * 256 + threadIdx.x;
    dst[i] = g_X[i];
}

// LayerNorm: g_H = LN(g_X) * w + b    (one block per token)
__global__ void ln_kernel(const float* __restrict__ w, const float* __restrict__ b) {
    int t = blockIdx.x, tid = threadIdx.x;
    const float* xr = g_X + (size_t)t * Dq;
    float s = 0.f, s2 = 0.f;
    for (int d = tid; d < Dq; d += 256) { float v = xr[d]; s += v; s2 += v * v; }
    __shared__ float r1[256], r2[256];
    r1[tid] = s; r2[tid] = s2; __syncthreads();
    for (int off = 128; off; off >>= 1) {
        if (tid < off) { r1[tid] += r1[tid + off]; r2[tid] += r2[tid + off]; }
        __syncthreads();
    }
    float mean = r1[0] * (1.0f / Dq);
    float var  = r2[0] * (1.0f / Dq) - mean * mean;
    float rstd = rsqrtf(var + 1e-5f);
    float* hr = g_H + (size_t)t * Dq;
    for (int d = tid; d < Dq; d += 256)
        hr[d] = (xr[d] - mean) * rstd * w[d] + b[d];
}

// ---------------- dense GEMM: C[M=4096, N] = A @ W + bias (+Res) -------------
// 64x64 tile, BK=16, 256 threads, 4x4 per thread, fp32
template<int RESADD>
__global__ void gemm_dense(const float* __restrict__ A, const float* __restrict__ W,
                           const float* __restrict__ bias, float* __restrict__ C,
                           const float* __restrict__ Res, int Kd, int N) {
    __shared__ float As[16][65];
    __shared__ float Bs[16][64];
    int tid = threadIdx.x;
    int rowBase = blockIdx.y * 64, colBase = blockIdx.x * 64;
    int tx = tid & 15, ty = tid >> 4;
    int lmA = tid >> 2, lkA = (tid & 3) << 2;
    int lkB = tid >> 4, lnB = (tid & 15) << 2;
    const float* Ap = A + (size_t)(rowBase + lmA) * Kd + lkA;
    const float* Wp = W + (size_t)lkB * N + colBase + lnB;
    float acc[4][4] = {};
    for (int k0 = 0; k0 < Kd; k0 += 16) {
        float4 av = *(const float4*)(Ap + k0);
        float4 bv = *(const float4*)(Wp + (size_t)k0 * N);
        As[lkA + 0][lmA] = av.x; As[lkA + 1][lmA] = av.y;
        As[lkA + 2][lmA] = av.z; As[lkA + 3][lmA] = av.w;
        *(float4*)&Bs[lkB][lnB] = bv;
        __syncthreads();
#pragma unroll
        for (int kk = 0; kk < 16; kk++) {
            float a0 = As[kk][ty * 4 + 0], a1 = As[kk][ty * 4 + 1];
            float a2 = As[kk][ty * 4 + 2], a3 = As[kk][ty * 4 + 3];
            float4 bb = *(const float4*)&Bs[kk][tx * 4];
            acc[0][0] += a0 * bb.x; acc[0][1] += a0 * bb.y; acc[0][2] += a0 * bb.z; acc[0][3] += a0 * bb.w;
            acc[1][0] += a1 * bb.x; acc[1][1] += a1 * bb.y; acc[1][2] += a1 * bb.z; acc[1][3] += a1 * bb.w;
            acc[2][0] += a2 * bb.x; acc[2][1] += a2 * bb.y; acc[2][2] += a2 * bb.z; acc[2][3] += a2 * bb.w;
            acc[3][0] += a3 * bb.x; acc[3][1] += a3 * bb.y; acc[3][2] += a3 * bb.z; acc[3][3] += a3 * bb.w;
        }
        __syncthreads();
    }
#pragma unroll
    for (int i = 0; i < 4; i++) {
        int r = rowBase + ty * 4 + i;
#pragma unroll
        for (int j = 0; j < 4; j++) {
            int c = colBase + tx * 4 + j;
            float v = acc[i][j] + bias[c];
            if (RESADD) v += Res[(size_t)r * N + c];
            C[(size_t)r * N + c] = v;
        }
    }
}

// ---------------- MoE GEMMs --------------------------------------------------
// MODE 1: hidden[e][r] = GELU(g_H[tok] @ w1[l,e] + b1[l,e])     (gathered rows)
// MODE 2: g_X[tok]    += (hidden[e][r] @ w2[l,e] + b2[l,e]) * wt (atomic scatter)
template<int MODE>
__global__ void gemm_moe(const float* __restrict__ Wall, const float* __restrict__ ball,
                         int Kd, int N, int layer) {
    int e = blockIdx.z;
    int cnt = g_counts[e];
    int rowBase = blockIdx.y * 64;
    if (rowBase >= cnt) return;
    int colBase = blockIdx.x * 64;
    const float* W    = Wall + ((size_t)(layer * Ee + e)) * Kd * N;
    const float* bias = ball + (size_t)(layer * Ee + e) * N;

    __shared__ float As[16][65];
    __shared__ float Bs[16][64];
    int tid = threadIdx.x;
    int tx = tid & 15, ty = tid >> 4;
    int lmA = tid >> 2, lkA = (tid & 3) << 2;
    int lkB = tid >> 4, lnB = (tid & 15) << 2;

    int mg = rowBase + lmA;
    const float* Ap;
    if (MODE == 1) {
        int mgc = mg < cnt ? mg : cnt - 1;
        Ap = g_H + (size_t)g_tok[e * TOK + mgc] * Kd + lkA;
    } else {
        Ap = g_hidden + ((size_t)e * TOK + mg) * Kd + lkA;  // mg < TOK always
    }
    const float* Wp = W + (size_t)lkB * N + colBase + lnB;
    float acc[4][4] = {};
    for (int k0 = 0; k0 < Kd; k0 += 16) {
        float4 av = *(const float4*)(Ap + k0);
        float4 bv = *(const float4*)(Wp + (size_t)k0 * N);
        As[lkA + 0][lmA] = av.x; As[lkA + 1][lmA] = av.y;
        As[lkA + 2][lmA] = av.z; As[lkA + 3][lmA] = av.w;
        *(float4*)&Bs[lkB][lnB] = bv;
        __syncthreads();
#pragma unroll
        for (int kk = 0; kk < 16; kk++) {
            float a0 = As[kk][ty * 4 + 0], a1 = As[kk][ty * 4 + 1];
            float a2 = As[kk][ty * 4 + 2], a3 = As[kk][ty * 4 + 3];
            float4 bb = *(const float4*)&Bs[kk][tx * 4];
            acc[0][0] += a0 * bb.x; acc[0][1] += a0 * bb.y; acc[0][2] += a0 * bb.z; acc[0][3] += a0 * bb.w;
            acc[1][0] += a1 * bb.x; acc[1][1] += a1 * bb.y; acc[1][2] += a1 * bb.z; acc[1][3] += a1 * bb.w;
            acc[2][0] += a2 * bb.x; acc[2][1] += a2 * bb.y; acc[2][2] += a2 * bb.z; acc[2][3] += a2 * bb.w;
            acc[3][0] += a3 * bb.x; acc[3][1] += a3 * bb.y; acc[3][2] += a3 * bb.z; acc[3][3] += a3 * bb.w;
        }
        __syncthreads();
    }
#pragma unroll
    for (int i = 0; i < 4; i++) {
        int r = rowBase + ty * 4 + i;
        if (r >= cnt) continue;
        if (MODE == 1) {
#pragma unroll
            for (int j = 0; j < 4; j++) {
                int c = colBase + tx * 4 + j;
                g_hidden[((size_t)e * TOK + r) * N + c] = gelu_exact(acc[i][j] + bias[c]);
            }
        } else {
            int tokid = g_tok[e * TOK + r];
            float wt  = g_wt[e * TOK + r];
#pragma unroll
            for (int j = 0; j < 4; j++) {
                int c = colBase + tx * 4 + j;
                atomicAdd(&g_X[(size_t)tokid * N + c], (acc[i][j] + bias[c]) * wt);
            }
        }
    }
}

// ---------------- attention (one block per (b,h,q)) --------------------------
__global__ void attn_kernel() {
    int q = blockIdx.x, h = blockIdx.y, b = blockIdx.z;
    int tid = threadIdx.x;                 // 128 threads
    __shared__ float qv[HD];
    __shared__ float sc[Sq];
    __shared__ float sred[128];
    __shared__ float oacc[128];

    const float* qp = g_Q + ((size_t)(b * Sq + q)) * Dq + h * HD;
    if (tid < HD) qv[tid] = qp[tid];
    __syncthreads();

    int kn = q + 1;
    float lm = -3.0e38f;
    for (int k = tid; k < kn; k += 128) {
        const float* kp = g_K + ((size_t)(b * Sq + k)) * Dq + h * HD;
        float s = 0.f;
#pragma unroll
        for (int j = 0; j < HD; j++) s += qv[j] * kp[j];
        s *= 0.125f;                       // hd^-0.5
        sc[k] = s;
        lm = fmaxf(lm, s);
    }
    sred[tid] = lm; __syncthreads();
    for (int off = 64; off; off >>= 1) {
        if (tid < off) sred[tid] = fmaxf(sred[tid], sred[tid + off]);
        __syncthreads();
    }
    float m = sred[0]; __syncthreads();

    float ls = 0.f;
    for (int k = tid; k < kn; k += 128) {
        float ev = expf(sc[k] - m);
        sc[k] = ev; ls += ev;
    }
    sred[tid] = ls; __syncthreads();
    for (int off = 64; off; off >>= 1) {
        if (tid < off) sred[tid] += sred[tid + off];
        __syncthreads();
    }
    float inv = 1.0f / sred[0];

    int d = tid & 63, half = tid >> 6;
    float acc = 0.f;
    for (int k = half; k < kn; k += 2)
        acc += sc[k] * g_V[((size_t)(b * Sq + k)) * Dq + h * HD + d];
    oacc[tid] = acc; __syncthreads();
    if (half == 0)
        g_Y[((size_t)(b * Sq + q)) * Dq + h * HD + d] = (oacc[d] + oacc[64 + d]) * inv;
}

// ---------------- gating -----------------------------------------------------
// token gating: one warp per token computes 8 logits from g_H, writes top-2
__global__ void gate_token_kernel(const float* __restrict__ gw,
                                  const float* __restrict__ gb, int layer) {
    int t = blockIdx.x * 4 + (threadIdx.x >> 5);
    int lane = threadIdx.x & 31;
    if (t >= TOK) return;
    const float* hrow = g_H + (size_t)t * Dq;
    const float* gwl = gw + (size_t)layer * Dq * Ee;
    float acc[Ee] = {};
    for (int d = lane; d < Dq; d += 32) {
        float hv = hrow[d];
        const float* g = gwl + (size_t)d * Ee;
#pragma unroll
        for (int e = 0; e < Ee; e++) acc[e] += hv * g[e];
    }
#pragma unroll
    for (int e = 0; e < Ee; e++)
        for (int off = 16; off; off >>= 1)
            acc[e] += __shfl_xor_sync(0xffffffffu, acc[e], off);
    if (lane == 0) {
        float lg[Ee];
#pragma unroll
        for (int e = 0; e < Ee; e++) lg[e] = acc[e] + gb[layer * Ee + e];
        int i1, i2; float w1, w2;
        top2_of8(lg, i1, i2, w1, w2);
        g_te[t * 2] = i1; g_te[t * 2 + 1] = i2;
        g_tw[t * 2] = w1; g_tw[t * 2 + 1] = w2;
    }
}

// seq gating step 1: per-sample mean over S of g_H
__global__ void xmean_kernel() {
    int b = blockIdx.y;
    int d = blockIdx.x * 256 + threadIdx.x;
    float s = 0.f;
    for (int ss = 0; ss < Sq; ss++)
        s += g_H[((size_t)(b * Sq + ss)) * Dq + d];
    g_xmean[b * Dq + d] = s * (1.0f / Sq);
}

// seq gating step 2: per-sample logits + top2 (one block per sample, 8 warps)
__global__ void gate_seq_kernel(const float* __restrict__ gw,
                                const float* __restrict__ gb, int layer) {
    int b = blockIdx.x;
    int tid = threadIdx.x, e = tid >> 5, lane = tid & 31;
    const float* gwl = gw + (size_t)layer * Dq * Ee;
    float acc = 0.f;
    for (int d = lane; d < Dq; d += 32)
        acc += g_xmean[b * Dq + d] * gwl[(size_t)d * Ee + e];
    for (int off = 16; off; off >>= 1)
        acc += __shfl_xor_sync(0xffffffffu, acc, off);
    __shared__ float lg[Ee];
    if (lane == 0) lg[e] = acc + gb[layer * Ee + e];
    __syncthreads();
    if (tid == 0) {
        int i1, i2; float w1, w2;
        top2_of8(lg, i1, i2, w1, w2);
        g_bsel[b * 2] = i1; g_bsel[b * 2 + 1] = i2;
        g_bw[b * 2] = w1;  g_bw[b * 2 + 1] = w2;
    }
}

__global__ void zero_counts_kernel() {
    if (threadIdx.x < Ee) g_counts[threadIdx.x] = 0;
}

// build per-expert token lists (atomic; order-free)
__global__ void assign_kernel(int seq_mode) {
    int t = blockIdx.x * 256 + threadIdx.x;
    if (t >= TOK) return;
    int e1, e2; float w1, w2;
    if (seq_mode) {
        int b = t / Sq;
        e1 = g_bsel[b * 2]; e2 = g_bsel[b * 2 + 1];
        w1 = g_bw[b * 2];   w2 = g_bw[b * 2 + 1];
    } else {
        e1 = g_te[t * 2]; e2 = g_te[t * 2 + 1];
        w1 = g_tw[t * 2]; w2 = g_tw[t * 2 + 1];
    }
    int s1 = atomicAdd(&g_counts[e1], 1);
    g_tok[e1 * TOK + s1] = t; g_wt[e1 * TOK + s1] = w1;
    int s2 = atomicAdd(&g_counts[e2], 1);
    g_tok[e2 * TOK + s2] = t; g_wt[e2 * TOK + s2] = w2;
}

// ---------------- host side --------------------------------------------------
extern "C" void kernel_launch(void* const* d_in, const int* in_sizes, int n_in,
                              void* d_out, int out_size) {
    const float* x      = (const float*)d_in[0];
    const float* ln1_w  = (const float*)d_in[1];
    const float* ln1_b  = (const float*)d_in[2];
    const float* ln2_w  = (const float*)d_in[3];
    const float* ln2_b  = (const float*)d_in[4];
    const float* wq     = (const float*)d_in[5];
    const float* wk     = (const float*)d_in[6];
    const float* wv     = (const float*)d_in[7];
    const float* wo     = (const float*)d_in[8];
    const float* bq     = (const float*)d_in[9];
    const float* bk     = (const float*)d_in[10];
    const float* bv     = (const float*)d_in[11];
    const float* bo     = (const float*)d_in[12];
    const float* gate_w = (const float*)d_in[13];
    const float* gate_b = (const float*)d_in[14];
    const float* e_w1   = (const float*)d_in[15];
    const float* e_b1   = (const float*)d_in[16];
    const float* e_w2   = (const float*)d_in[17];
    const float* e_b2   = (const float*)d_in[18];

    float *Xp, *Hp, *Qp, *Kp, *Vp, *Yp;
    cudaGetSymbolAddress((void**)&Xp, g_X);
    cudaGetSymbolAddress((void**)&Hp, g_H);
    cudaGetSymbolAddress((void**)&Qp, g_Q);
    cudaGetSymbolAddress((void**)&Kp, g_K);
    cudaGetSymbolAddress((void**)&Vp, g_V);
    cudaGetSymbolAddress((void**)&Yp, g_Y);

    const size_t DD = (size_t)Dq * Dq;
    const int nelem = TOK * Dq;

    copy_in_kernel<<<nelem / 256, 256>>>(x);

    for (int l = 0; l < Ll; l++) {
        // --- attention block ---
        ln_kernel<<<TOK, 256>>>(ln1_w + (size_t)l * Dq, ln1_b + (size_t)l * Dq);
        dim3 gproj(Dq / 64, TOK / 64);
        gemm_dense<0><<<gproj, 256>>>(Hp, wq + l * DD, bq + (size_t)l * Dq, Qp, nullptr, Dq, Dq);
        gemm_dense<0><<<gproj, 256>>>(Hp, wk + l * DD, bk + (size_t)l * Dq, Kp, nullptr, Dq, Dq);
        gemm_dense<0><<<gproj, 256>>>(Hp, wv + l * DD, bv + (size_t)l * Dq, Vp, nullptr, Dq, Dq);
        attn_kernel<<<dim3(Sq, Hh, Bq), 128>>>();
        gemm_dense<1><<<gproj, 256>>>(Yp, wo + l * DD, bo + (size_t)l * Dq, Xp, Xp, Dq, Dq);

        // --- MoE block ---
        ln_kernel<<<TOK, 256>>>(ln2_w + (size_t)l * Dq, ln2_b + (size_t)l * Dq);
        if (l % 2 == 0) {
            gate_token_kernel<<<TOK / 4, 128>>>(gate_w, gate_b, l);
        } else {
            xmean_kernel<<<dim3(Dq / 256, Bq), 256>>>();
            gate_seq_kernel<<<Bq, 256>>>(gate_w, gate_b, l);
        }
        zero_counts_kernel<<<1, 32>>>();
        assign_kernel<<<TOK / 256, 256>>>(l % 2);
        gemm_moe<1><<<dim3(DFFq / 64, TOK / 64, Ee), 256>>>(e_w1, e_b1, Dq, DFFq, l);
        gemm_moe<2><<<dim3(Dq / 64, TOK / 64, Ee), 256>>>(e_w2, e_b2, DFFq, Dq, l);
    }

    copy_out_kernel<<<nelem / 256, 256>>>((float*)d_out);
    (void)in_sizes; (void)n_in; (void)out_size;
}

// round 2
// speedup vs baseline: 4.4330x; 4.4330x over previous
#include <cuda_runtime.h>
#include <cuda_bf16.h>
#include <math.h>
#include <stdint.h>

#define Bq   4
#define Sq   1024
#define Dq   1024
#define Hh   16
#define HD   64
#define Ll   2
#define Ee   8
#define DFFq 4096
#define TOK  (Bq*Sq)   // 4096

// ---------------- static scratch ---------------------------------------------
__device__ float g_X[TOK*Dq];
__device__ float g_H[TOK*Dq];
__device__ float g_Q[TOK*Dq];
__device__ float g_K[TOK*Dq];
__device__ float g_V[TOK*Dq];
__device__ float g_Y[TOK*Dq];
__device__ float g_hidden[(size_t)Ee*TOK*DFFq];
__device__ int   g_counts[Ee];
__device__ int   g_tok[Ee*TOK];
__device__ float g_wt[Ee*TOK];
__device__ int   g_te[TOK*2];
__device__ float g_tw[TOK*2];
__device__ int   g_bsel[Bq*2];
__device__ float g_bw[Bq*2];
__device__ float g_xmean[Bq*Dq];

// ---------------- helpers ----------------------------------------------------
__device__ __forceinline__ void top2_of8(const float* lg, int& i1, int& i2,
                                         float& w1, float& w2) {
    i1 = 0; float v1 = lg[0];
#pragma unroll
    for (int e = 1; e < Ee; e++) if (lg[e] > v1) { v1 = lg[e]; i1 = e; }
    i2 = -1; float v2 = -3.0e38f;
#pragma unroll
    for (int e = 0; e < Ee; e++) if (e != i1 && lg[e] > v2) { v2 = lg[e]; i2 = e; }
    float ex = expf(v2 - v1);
    w1 = 1.0f / (1.0f + ex);
    w2 = ex / (1.0f + ex);
}

__device__ __forceinline__ float gelu_exact(float x) {
    return 0.5f * x * (1.0f + erff(x * 0.7071067811865476f));
}

__device__ __forceinline__ float tf32r(float x) {
    uint32_t u; asm("cvt.rna.tf32.f32 %0, %1;" : "=r"(u) : "f"(x));
    return __uint_as_float(u);
}

__device__ __forceinline__ void mma_tf32(float c[4], const uint32_t a[4],
                                         const uint32_t b[2]) {
    asm volatile(
        "mma.sync.aligned.m16n8k8.row.col.f32.tf32.tf32.f32 "
        "{%0,%1,%2,%3},{%4,%5,%6,%7},{%8,%9},{%0,%1,%2,%3};"
        : "+f"(c[0]), "+f"(c[1]), "+f"(c[2]), "+f"(c[3])
        : "r"(a[0]), "r"(a[1]), "r"(a[2]), "r"(a[3]), "r"(b[0]), "r"(b[1]));
}

// ---------------- simple kernels ---------------------------------------------
__global__ void copy_in_kernel(const float* __restrict__ src) {
    int i = blockIdx.x * 256 + threadIdx.x;
    g_X[i] = src[i];
}
__global__ void copy_out_kernel(float* __restrict__ dst) {
    int i = blockIdx.x * 256 + threadIdx.x;
    dst[i] = g_X[i];
}

__global__ void ln_kernel(const float* __restrict__ w, const float* __restrict__ b) {
    int t = blockIdx.x, tid = threadIdx.x;
    const float* xr = g_X + (size_t)t * Dq;
    float s = 0.f, s2 = 0.f;
    for (int d = tid; d < Dq; d += 256) { float v = xr[d]; s += v; s2 += v * v; }
    __shared__ float r1[256], r2[256];
    r1[tid] = s; r2[tid] = s2; __syncthreads();
    for (int off = 128; off; off >>= 1) {
        if (tid < off) { r1[tid] += r1[tid + off]; r2[tid] += r2[tid + off]; }
        __syncthreads();
    }
    float mean = r1[0] * (1.0f / Dq);
    float var  = r2[0] * (1.0f / Dq) - mean * mean;
    float rstd = rsqrtf(var + 1e-5f);
    float* hr = g_H + (size_t)t * Dq;
    for (int d = tid; d < Dq; d += 256)
        hr[d] = (xr[d] - mean) * rstd * w[d] + b[d];
}

// ---------------- fp32 GEMM (layer-0 attention path only) --------------------
template<int RESADD>
__global__ void gemm_dense(const float* __restrict__ A, const float* __restrict__ W,
                           const float* __restrict__ bias, float* __restrict__ C,
                           const float* __restrict__ Res, int Kd, int N) {
    __shared__ float As[16][65];
    __shared__ float Bs[16][64];
    int tid = threadIdx.x;
    int rowBase = blockIdx.y * 64, colBase = blockIdx.x * 64;
    int tx = tid & 15, ty = tid >> 4;
    int lmA = tid >> 2, lkA = (tid & 3) << 2;
    int lkB = tid >> 4, lnB = (tid & 15) << 2;
    const float* Ap = A + (size_t)(rowBase + lmA) * Kd + lkA;
    const float* Wp = W + (size_t)lkB * N + colBase + lnB;
    float acc[4][4] = {};
    for (int k0 = 0; k0 < Kd; k0 += 16) {
        float4 av = *(const float4*)(Ap + k0);
        float4 bv = *(const float4*)(Wp + (size_t)k0 * N);
        As[lkA + 0][lmA] = av.x; As[lkA + 1][lmA] = av.y;
        As[lkA + 2][lmA] = av.z; As[lkA + 3][lmA] = av.w;
        *(float4*)&Bs[lkB][lnB] = bv;
        __syncthreads();
#pragma unroll
        for (int kk = 0; kk < 16; kk++) {
            float a0 = As[kk][ty * 4 + 0], a1 = As[kk][ty * 4 + 1];
            float a2 = As[kk][ty * 4 + 2], a3 = As[kk][ty * 4 + 3];
            float4 bb = *(const float4*)&Bs[kk][tx * 4];
            acc[0][0] += a0 * bb.x; acc[0][1] += a0 * bb.y; acc[0][2] += a0 * bb.z; acc[0][3] += a0 * bb.w;
            acc[1][0] += a1 * bb.x; acc[1][1] += a1 * bb.y; acc[1][2] += a1 * bb.z; acc[1][3] += a1 * bb.w;
            acc[2][0] += a2 * bb.x; acc[2][1] += a2 * bb.y; acc[2][2] += a2 * bb.z; acc[2][3] += a2 * bb.w;
            acc[3][0] += a3 * bb.x; acc[3][1] += a3 * bb.y; acc[3][2] += a3 * bb.z; acc[3][3] += a3 * bb.w;
        }
        __syncthreads();
    }
#pragma unroll
    for (int i = 0; i < 4; i++) {
        int r = rowBase + ty * 4 + i;
#pragma unroll
        for (int j = 0; j < 4; j++) {
            int c = colBase + tx * 4 + j;
            float v = acc[i][j] + bias[c];
            if (RESADD) v += Res[(size_t)r * N + c];
            C[(size_t)r * N + c] = v;
        }
    }
}

// ---------------- TF32 tensor-core GEMM --------------------------------------
// MODE 0: C = A@W + bias
// MODE 1: C = A@W + bias + Res
// MODE 2: g_hidden[e] = GELU(gather(g_H)@W + bias)
// MODE 3: g_X[tok]   += (g_hidden[e]@W + bias) * wt   (atomic)
#define BMt 128
#define BNt 128
#define BKt 16

template<int MODE>
__global__ __launch_bounds__(256)
void gemm_tc(const float* __restrict__ A, const float* __restrict__ Wall,
             const float* __restrict__ ball, float* __restrict__ Cp,
             const float* __restrict__ Res, int Kd, int N, int layer) {
    __shared__ float As[2][BKt][BMt + 4];
    __shared__ float Bs[2][BKt][BNt + 4];
    __shared__ int   s_tok[BMt];
    __shared__ float s_wt[BMt];

    int tid = threadIdx.x;
    int rowBase = blockIdx.y * BMt, colBase = blockIdx.x * BNt;

    int e = 0, cnt = 0;
    const float* W = Wall;
    const float* bias = ball;
    if (MODE >= 2) {
        e = blockIdx.z;
        cnt = g_counts[e];
        if (rowBase >= cnt) return;
        W    = Wall + (size_t)(layer * Ee + e) * Kd * N;
        bias = ball + (size_t)(layer * Ee + e) * N;
        if (tid < BMt) {
            int r = rowBase + tid;
            int rc = r < cnt ? r : cnt - 1;
            s_tok[tid] = g_tok[e * TOK + rc];
            s_wt[tid]  = g_wt [e * TOK + rc];
        }
        __syncthreads();
    }

    int lrA = tid >> 1;
    int kcA = (tid & 1) << 3;
    const float* Aptr;
    if (MODE == 2)      Aptr = g_H + (size_t)s_tok[lrA] * Kd + kcA;
    else if (MODE == 3) Aptr = g_hidden + ((size_t)e * TOK + rowBase + lrA) * Kd + kcA;
    else                Aptr = A + (size_t)(rowBase + lrA) * Kd + kcA;

    int krB = tid >> 5;
    int ncB = (tid & 31) << 2;
    const float* Wptr = W + (size_t)krB * N + colBase + ncB;

    int lane = tid & 31, warp = tid >> 5;
    int wm = (warp & 1) * 64, wn = (warp >> 1) * 32;
    int gid = lane >> 2, tig = lane & 3;

    float acc[4][4][4];
#pragma unroll
    for (int a = 0; a < 4; a++)
#pragma unroll
        for (int b2 = 0; b2 < 4; b2++)
#pragma unroll
            for (int c = 0; c < 4; c++) acc[a][b2][c] = 0.f;

    int nk = Kd / BKt;

    float4 av0 = *(const float4*)(Aptr);
    float4 av1 = *(const float4*)(Aptr + 4);
    float4 bv0 = *(const float4*)(Wptr);
    float4 bv1 = *(const float4*)(Wptr + (size_t)8 * N);

    As[0][kcA + 0][lrA] = tf32r(av0.x); As[0][kcA + 1][lrA] = tf32r(av0.y);
    As[0][kcA + 2][lrA] = tf32r(av0.z); As[0][kcA + 3][lrA] = tf32r(av0.w);
    As[0][kcA + 4][lrA] = tf32r(av1.x); As[0][kcA + 5][lrA] = tf32r(av1.y);
    As[0][kcA + 6][lrA] = tf32r(av1.z); As[0][kcA + 7][lrA] = tf32r(av1.w);
    Bs[0][krB][ncB + 0] = tf32r(bv0.x); Bs[0][krB][ncB + 1] = tf32r(bv0.y);
    Bs[0][krB][ncB + 2] = tf32r(bv0.z); Bs[0][krB][ncB + 3] = tf32r(bv0.w);
    Bs[0][krB + 8][ncB + 0] = tf32r(bv1.x); Bs[0][krB + 8][ncB + 1] = tf32r(bv1.y);
    Bs[0][krB + 8][ncB + 2] = tf32r(bv1.z); Bs[0][krB + 8][ncB + 3] = tf32r(bv1.w);
    __syncthreads();

    for (int t = 0; t < nk; t++) {
        if (t + 1 < nk) {
            const float* Ap2 = Aptr + (t + 1) * BKt;
            av0 = *(const float4*)(Ap2);
            av1 = *(const float4*)(Ap2 + 4);
            const float* Wp2 = Wptr + (size_t)(t + 1) * BKt * N;
            bv0 = *(const float4*)(Wp2);
            bv1 = *(const float4*)(Wp2 + (size_t)8 * N);
        }
        int s = t & 1;
#pragma unroll
        for (int kk = 0; kk < BKt; kk += 8) {
            uint32_t af[4][4], bf[4][2];
#pragma unroll
            for (int mt = 0; mt < 4; mt++) {
                int m0 = wm + mt * 16 + gid;
                af[mt][0] = __float_as_uint(As[s][kk + tig    ][m0]);
                af[mt][1] = __float_as_uint(As[s][kk + tig    ][m0 + 8]);
                af[mt][2] = __float_as_uint(As[s][kk + tig + 4][m0]);
                af[mt][3] = __float_as_uint(As[s][kk + tig + 4][m0 + 8]);
            }
#pragma unroll
            for (int nt = 0; nt < 4; nt++) {
                int n0 = wn + nt * 8 + gid;
                bf[nt][0] = __float_as_uint(Bs[s][kk + tig    ][n0]);
                bf[nt][1] = __float_as_uint(Bs[s][kk + tig + 4][n0]);
            }
#pragma unroll
            for (int mt = 0; mt < 4; mt++)
#pragma unroll
                for (int nt = 0; nt < 4; nt++)
                    mma_tf32(acc[mt][nt], af[mt], bf[nt]);
        }
        if (t + 1 < nk) {
            int s2 = s ^ 1;
            As[s2][kcA + 0][lrA] = tf32r(av0.x); As[s2][kcA + 1][lrA] = tf32r(av0.y);
            As[s2][kcA + 2][lrA] = tf32r(av0.z); As[s2][kcA + 3][lrA] = tf32r(av0.w);
            As[s2][kcA + 4][lrA] = tf32r(av1.x); As[s2][kcA + 5][lrA] = tf32r(av1.y);
            As[s2][kcA + 6][lrA] = tf32r(av1.z); As[s2][kcA + 7][lrA] = tf32r(av1.w);
            Bs[s2][krB][ncB + 0] = tf32r(bv0.x); Bs[s2][krB][ncB + 1] = tf32r(bv0.y);
            Bs[s2][krB][ncB + 2] = tf32r(bv0.z); Bs[s2][krB][ncB + 3] = tf32r(bv0.w);
            Bs[s2][krB + 8][ncB + 0] = tf32r(bv1.x); Bs[s2][krB + 8][ncB + 1] = tf32r(bv1.y);
            Bs[s2][krB + 8][ncB + 2] = tf32r(bv1.z); Bs[s2][krB + 8][ncB + 3] = tf32r(bv1.w);
        }
        __syncthreads();
    }

#pragma unroll
    for (int mt = 0; mt < 4; mt++) {
#pragma unroll
        for (int c = 0; c < 4; c++) {
            int rl = wm + mt * 16 + gid + ((c & 2) ? 8 : 0);
            int r  = rowBase + rl;
#pragma unroll
            for (int nt = 0; nt < 4; nt++) {
                int cg = colBase + wn + nt * 8 + tig * 2 + (c & 1);
                float v = acc[mt][nt][c] + bias[cg];
                if (MODE == 0) {
                    Cp[(size_t)r * N + cg] = v;
                } else if (MODE == 1) {
                    Cp[(size_t)r * N + cg] = v + Res[(size_t)r * N + cg];
                } else if (MODE == 2) {
                    if (r < cnt)
                        g_hidden[((size_t)e * TOK + r) * N + cg] = gelu_exact(v);
                } else {
                    if (r < cnt)
                        atomicAdd(&g_X[(size_t)s_tok[rl] * N + cg], v * s_wt[rl]);
                }
            }
        }
    }
}

// ---------------- flash attention (fp32, 64-q block, 32-k tiles) -------------
__global__ __launch_bounds__(256) void flash_attn() {
    __shared__ float Qs[64][65];
    __shared__ float Ks[32][65];
    __shared__ float Vs[32][65];
    __shared__ float Ps[64][33];

    int qb = blockIdx.x, h = blockIdx.y, b = blockIdx.z;
    int tid = threadIdx.x;
    int ty = tid >> 4, tx = tid & 15;

    for (int i = tid; i < 64 * 16; i += 256) {
        int r = i >> 4, c4 = (i & 15) << 2;
        float4 v = *(const float4*)&g_Q[((size_t)(b * Sq + qb * 64 + r)) * Dq + h * HD + c4];
        Qs[r][c4] = v.x; Qs[r][c4 + 1] = v.y; Qs[r][c4 + 2] = v.z; Qs[r][c4 + 3] = v.w;
    }

    float m[4], l[4], o[4][4];
#pragma unroll
    for (int i = 0; i < 4; i++) {
        m[i] = -3.0e38f; l[i] = 0.f;
#pragma unroll
        for (int j = 0; j < 4; j++) o[i][j] = 0.f;
    }

    int nkt = (qb + 1) * 2;   // 32-wide k tiles
    for (int kt = 0; kt < nkt; kt++) {
        __syncthreads();
        for (int i = tid; i < 32 * 16; i += 256) {
            int r = i >> 4, c4 = (i & 15) << 2;
            size_t base = ((size_t)(b * Sq + kt * 32 + r)) * Dq + h * HD + c4;
            float4 kv = *(const float4*)&g_K[base];
            Ks[r][c4] = kv.x; Ks[r][c4 + 1] = kv.y; Ks[r][c4 + 2] = kv.z; Ks[r][c4 + 3] = kv.w;
            float4 vv = *(const float4*)&g_V[base];
            Vs[r][c4] = vv.x; Vs[r][c4 + 1] = vv.y; Vs[r][c4 + 2] = vv.z; Vs[r][c4 + 3] = vv.w;
        }
        __syncthreads();

        float s4[4][2];
#pragma unroll
        for (int i = 0; i < 4; i++) { s4[i][0] = 0.f; s4[i][1] = 0.f; }
        for (int d = 0; d < 64; d++) {
            float k0 = Ks[tx * 2][d], k1 = Ks[tx * 2 + 1][d];
#pragma unroll
            for (int i = 0; i < 4; i++) {
                float qv = Qs[ty * 4 + i][d];
                s4[i][0] += qv * k0;
                s4[i][1] += qv * k1;
            }
        }
        bool edge = (kt == nkt - 1) || (kt == nkt - 2);
#pragma unroll
        for (int i = 0; i < 4; i++)
#pragma unroll
            for (int j = 0; j < 2; j++) {
                float sv = s4[i][j] * 0.125f;
                if (edge && (kt * 32 + tx * 2 + j > qb * 64 + ty * 4 + i)) sv = -3.0e38f;
                s4[i][j] = sv;
            }
#pragma unroll
        for (int i = 0; i < 4; i++) {
            float rm = fmaxf(s4[i][0], s4[i][1]);
#pragma unroll
            for (int off = 1; off < 16; off <<= 1)
                rm = fmaxf(rm, __shfl_xor_sync(0xffffffffu, rm, off));
            float mn = fmaxf(m[i], rm);
            float alpha = expf(m[i] - mn);
            float p0 = expf(s4[i][0] - mn);
            float p1 = expf(s4[i][1] - mn);
            float rs = p0 + p1;
#pragma unroll
            for (int off = 1; off < 16; off <<= 1)
                rs += __shfl_xor_sync(0xffffffffu, rs, off);
            l[i] = l[i] * alpha + rs;
            m[i] = mn;
#pragma unroll
            for (int j = 0; j < 4; j++) o[i][j] *= alpha;
            Ps[ty * 4 + i][tx * 2]     = p0;
            Ps[ty * 4 + i][tx * 2 + 1] = p1;
        }
        __syncthreads();
        for (int kk = 0; kk < 32; kk++) {
            float a4[4], v4[4];
#pragma unroll
            for (int i = 0; i < 4; i++) a4[i] = Ps[ty * 4 + i][kk];
#pragma unroll
            for (int j = 0; j < 4; j++) v4[j] = Vs[kk][tx * 4 + j];
#pragma unroll
            for (int i = 0; i < 4; i++)
#pragma unroll
                for (int j = 0; j < 4; j++) o[i][j] += a4[i] * v4[j];
        }
    }

#pragma unroll
    for (int i = 0; i < 4; i++) {
        float inv = 1.0f / l[i];
#pragma unroll
        for (int j = 0; j < 4; j++)
            g_Y[((size_t)(b * Sq + qb * 64 + ty * 4 + i)) * Dq + h * HD + tx * 4 + j] = o[i][j] * inv;
    }
}

// ---------------- gating -----------------------------------------------------
__global__ void gate_token_kernel(const float* __restrict__ gw,
                                  const float* __restrict__ gb, int layer) {
    int t = blockIdx.x * 4 + (threadIdx.x >> 5);
    int lane = threadIdx.x & 31;
    if (t >= TOK) return;
    const float* hrow = g_H + (size_t)t * Dq;
    const float* gwl = gw + (size_t)layer * Dq * Ee;
    float acc[Ee] = {};
    for (int d = lane; d < Dq; d += 32) {
        float hv = hrow[d];
        const float* g = gwl + (size_t)d * Ee;
#pragma unroll
        for (int e = 0; e < Ee; e++) acc[e] += hv * g[e];
    }
#pragma unroll
    for (int e = 0; e < Ee; e++)
        for (int off = 16; off; off >>= 1)
            acc[e] += __shfl_xor_sync(0xffffffffu, acc[e], off);
    if (lane == 0) {
        float lg[Ee];
#pragma unroll
        for (int e = 0; e < Ee; e++) lg[e] = acc[e] + gb[layer * Ee + e];
        int i1, i2; float w1, w2;
        top2_of8(lg, i1, i2, w1, w2);
        g_te[t * 2] = i1; g_te[t * 2 + 1] = i2;
        g_tw[t * 2] = w1; g_tw[t * 2 + 1] = w2;
    }
}

__global__ void xmean_kernel() {
    int b = blockIdx.y;
    int d = blockIdx.x * 256 + threadIdx.x;
    float s = 0.f;
    for (int ss = 0; ss < Sq; ss++)
        s += g_H[((size_t)(b * Sq + ss)) * Dq + d];
    g_xmean[b * Dq + d] = s * (1.0f / Sq);
}

__global__ void gate_seq_kernel(const float* __restrict__ gw,
                                const float* __restrict__ gb, int layer) {
    int b = blockIdx.x;
    int tid = threadIdx.x, e = tid >> 5, lane = tid & 31;
    const float* gwl = gw + (size_t)layer * Dq * Ee;
    float acc = 0.f;
    for (int d = lane; d < Dq; d += 32)
        acc += g_xmean[b * Dq + d] * gwl[(size_t)d * Ee + e];
    for (int off = 16; off; off >>= 1)
        acc += __shfl_xor_sync(0xffffffffu, acc, off);
    __shared__ float lg[Ee];
    if (lane == 0) lg[e] = acc + gb[layer * Ee + e];
    __syncthreads();
    if (tid == 0) {
        int i1, i2; float w1, w2;
        top2_of8(lg, i1, i2, w1, w2);
        g_bsel[b * 2] = i1; g_bsel[b * 2 + 1] = i2;
        g_bw[b * 2] = w1;  g_bw[b * 2 + 1] = w2;
    }
}

__global__ void zero_counts_kernel() {
    if (threadIdx.x < Ee) g_counts[threadIdx.x] = 0;
}

__global__ void assign_kernel(int seq_mode) {
    int t = blockIdx.x * 256 + threadIdx.x;
    if (t >= TOK) return;
    int e1, e2; float w1, w2;
    if (seq_mode) {
        int b = t / Sq;
        e1 = g_bsel[b * 2]; e2 = g_bsel[b * 2 + 1];
        w1 = g_bw[b * 2];   w2 = g_bw[b * 2 + 1];
    } else {
        e1 = g_te[t * 2]; e2 = g_te[t * 2 + 1];
        w1 = g_tw[t * 2]; w2 = g_tw[t * 2 + 1];
    }
    int s1 = atomicAdd(&g_counts[e1], 1);
    g_tok[e1 * TOK + s1] = t; g_wt[e1 * TOK + s1] = w1;
    int s2 = atomicAdd(&g_counts[e2], 1);
    g_tok[e2 * TOK + s2] = t; g_wt[e2 * TOK + s2] = w2;
}

// ---------------- host side --------------------------------------------------
extern "C" void kernel_launch(void* const* d_in, const int* in_sizes, int n_in,
                              void* d_out, int out_size) {
    const float* x      = (const float*)d_in[0];
    const float* ln1_w  = (const float*)d_in[1];
    const float* ln1_b  = (const float*)d_in[2];
    const float* ln2_w  = (const float*)d_in[3];
    const float* ln2_b  = (const float*)d_in[4];
    const float* wq     = (const float*)d_in[5];
    const float* wk     = (const float*)d_in[6];
    const float* wv     = (const float*)d_in[7];
    const float* wo     = (const float*)d_in[8];
    const float* bq     = (const float*)d_in[9];
    const float* bk     = (const float*)d_in[10];
    const float* bv     = (const float*)d_in[11];
    const float* bo     = (const float*)d_in[12];
    const float* gate_w = (const float*)d_in[13];
    const float* gate_b = (const float*)d_in[14];
    const float* e_w1   = (const float*)d_in[15];
    const float* e_b1   = (const float*)d_in[16];
    const float* e_w2   = (const float*)d_in[17];
    const float* e_b2   = (const float*)d_in[18];

    float *Xp, *Hp, *Qp, *Kp, *Vp, *Yp;
    cudaGetSymbolAddress((void**)&Xp, g_X);
    cudaGetSymbolAddress((void**)&Hp, g_H);
    cudaGetSymbolAddress((void**)&Qp, g_Q);
    cudaGetSymbolAddress((void**)&Kp, g_K);
    cudaGetSymbolAddress((void**)&Vp, g_V);
    cudaGetSymbolAddress((void**)&Yp, g_Y);

    const size_t DD = (size_t)Dq * Dq;
    const int nelem = TOK * Dq;

    copy_in_kernel<<<nelem / 256, 256>>>(x);

    for (int l = 0; l < Ll; l++) {
        // --- attention block ---
        ln_kernel<<<TOK, 256>>>(ln1_w + (size_t)l * Dq, ln1_b + (size_t)l * Dq);
        if (l == 0) {
            // fp32 path: layer-0 attention feeds the brittle token-gating decisions
            dim3 gproj(Dq / 64, TOK / 64);
            gemm_dense<0><<<gproj, 256>>>(Hp, wq + l * DD, bq + (size_t)l * Dq, Qp, nullptr, Dq, Dq);
            gemm_dense<0><<<gproj, 256>>>(Hp, wk + l * DD, bk + (size_t)l * Dq, Kp, nullptr, Dq, Dq);
            gemm_dense<0><<<gproj, 256>>>(Hp, wv + l * DD, bv + (size_t)l * Dq, Vp, nullptr, Dq, Dq);
        } else {
            dim3 gtc(Dq / BNt, TOK / BMt);
            gemm_tc<0><<<gtc, 256>>>(Hp, wq + l * DD, bq + (size_t)l * Dq, Qp, nullptr, Dq, Dq, l);
            gemm_tc<0><<<gtc, 256>>>(Hp, wk + l * DD, bk + (size_t)l * Dq, Kp, nullptr, Dq, Dq, l);
            gemm_tc<0><<<gtc, 256>>>(Hp, wv + l * DD, bv + (size_t)l * Dq, Vp, nullptr, Dq, Dq, l);
        }
        flash_attn<<<dim3(Sq / 64, Hh, Bq), 256>>>();
        if (l == 0) {
            dim3 gproj(Dq / 64, TOK / 64);
            gemm_dense<1><<<gproj, 256>>>(Yp, wo + l * DD, bo + (size_t)l * Dq, Xp, Xp, Dq, Dq);
        } else {
            dim3 gtc(Dq / BNt, TOK / BMt);
            gemm_tc<1><<<gtc, 256>>>(Yp, wo + l * DD, bo + (size_t)l * Dq, Xp, Xp, Dq, Dq, l);
        }

        // --- MoE block ---
        ln_kernel<<<TOK, 256>>>(ln2_w + (size_t)l * Dq, ln2_b + (size_t)l * Dq);
        if (l % 2 == 0) {
            gate_token_kernel<<<TOK / 4, 128>>>(gate_w, gate_b, l);
        } else {
            xmean_kernel<<<dim3(Dq / 256, Bq), 256>>>();
            gate_seq_kernel<<<Bq, 256>>>(gate_w, gate_b, l);
        }
        zero_counts_kernel<<<1, 32>>>();
        assign_kernel<<<TOK / 256, 256>>>(l % 2);
        gemm_tc<2><<<dim3(DFFq / BNt, TOK / BMt, Ee), 256>>>(nullptr, e_w1, e_b1, nullptr, nullptr, Dq, DFFq, l);
        gemm_tc<3><<<dim3(Dq / BNt, TOK / BMt, Ee), 256>>>(nullptr, e_w2, e_b2, nullptr, nullptr, DFFq, Dq, l);
    }

    copy_out_kernel<<<nelem / 256, 256>>>((float*)d_out);
    (void)in_sizes; (void)n_in; (void)out_size;
}

// round 4
// speedup vs baseline: 5.8284x; 1.3148x over previous
#include <cuda_runtime.h>
#include <math.h>
#include <stdint.h>

#define Bq   4
#define Sq   1024
#define Dq   1024
#define Hh   16
#define HD   64
#define Ll   2
#define Ee   8
#define DFFq 4096
#define TOK  (Bq*Sq)   // 4096

// ---------------- static scratch ---------------------------------------------
__device__ float g_X[TOK*Dq];
__device__ float g_H[TOK*Dq];
__device__ float g_Q[TOK*Dq];
__device__ float g_K[TOK*Dq];
__device__ float g_V[TOK*Dq];
__device__ float g_Y[TOK*Dq];
__device__ float g_hidden[(size_t)Ee*TOK*DFFq];
__device__ int   g_counts[Ee];
__device__ int   g_tok[Ee*TOK];
__device__ float g_wt[Ee*TOK];
__device__ int   g_te[TOK*2];
__device__ float g_tw[TOK*2];
__device__ int   g_bsel[Bq*2];
__device__ float g_bw[Bq*2];
__device__ float g_xmean[Bq*Dq];

// ---------------- helpers ----------------------------------------------------
__device__ __forceinline__ void top2_of8(const float* lg, int& i1, int& i2,
                                         float& w1, float& w2) {
    i1 = 0; float v1 = lg[0];
#pragma unroll
    for (int e = 1; e < Ee; e++) if (lg[e] > v1) { v1 = lg[e]; i1 = e; }
    i2 = -1; float v2 = -3.0e38f;
#pragma unroll
    for (int e = 0; e < Ee; e++) if (e != i1 && lg[e] > v2) { v2 = lg[e]; i2 = e; }
    float ex = expf(v2 - v1);
    w1 = 1.0f / (1.0f + ex);
    w2 = ex / (1.0f + ex);
}
__device__ __forceinline__ float gelu_exact(float x) {
    return 0.5f * x * (1.0f + erff(x * 0.7071067811865476f));
}
__device__ __forceinline__ float tf32r(float x) {
    uint32_t u; asm("cvt.rna.tf32.f32 %0, %1;" : "=r"(u) : "f"(x));
    return __uint_as_float(u);
}
__device__ __forceinline__ void mma_tf32(float c[4], const uint32_t a[4],
                                         const uint32_t b[2]) {
    asm volatile(
        "mma.sync.aligned.m16n8k8.row.col.f32.tf32.tf32.f32 "
        "{%0,%1,%2,%3},{%4,%5,%6,%7},{%8,%9},{%0,%1,%2,%3};"
        : "+f"(c[0]), "+f"(c[1]), "+f"(c[2]), "+f"(c[3])
        : "r"(a[0]), "r"(a[1]), "r"(a[2]), "r"(a[3]), "r"(b[0]), "r"(b[1]));
}

// ---------------- simple kernels ---------------------------------------------
__global__ void copy_in_kernel(const float* __restrict__ src) {
    int i = blockIdx.x * 256 + threadIdx.x;
    g_X[i] = src[i];
}
__global__ void copy_out_kernel(float* __restrict__ dst) {
    int i = blockIdx.x * 256 + threadIdx.x;
    dst[i] = g_X[i];
}

__global__ void ln_kernel(const float* __restrict__ w, const float* __restrict__ b) {
    int t = blockIdx.x, tid = threadIdx.x;
    const float* xr = g_X + (size_t)t * Dq;
    float s = 0.f, s2 = 0.f;
    for (int d = tid; d < Dq; d += 256) { float v = xr[d]; s += v; s2 += v * v; }
    __shared__ float r1[256], r2[256];
    r1[tid] = s; r2[tid] = s2; __syncthreads();
    for (int off = 128; off; off >>= 1) {
        if (tid < off) { r1[tid] += r1[tid + off]; r2[tid] += r2[tid + off]; }
        __syncthreads();
    }
    float mean = r1[0] * (1.0f / Dq);
    float var  = r2[0] * (1.0f / Dq) - mean * mean;
    float rstd = rsqrtf(var + 1e-5f);
    float* hr = g_H + (size_t)t * Dq;
    for (int d = tid; d < Dq; d += 256)
        hr[d] = (xr[d] - mean) * rstd * w[d] + b[d];
}

// ---------------- TF32 tensor-core GEMM --------------------------------------
// MODE 0: C = A@W + bias      MODE 1: C = A@W + bias + Res(=C)
// MODE 2: g_hidden[e] = GELU(gather(g_H)@W + bias)
// MODE 3: g_X[tok] += (g_hidden[e]@W + bias) * wt   (atomic)
// SPLIT=1: 3-pass tf32 Dekker split (~fp32 precision)
#define BMt 128
#define BNt 128
#define BKt 16
#define TWg 136                 // 128 + 8 pad -> conflict-free fragment loads
#define TILE_F (BKt*TWg)        // 2176 floats per tile

template<int MODE, int SPLIT>
__global__ void __launch_bounds__(256)
gemm_tc(const float* __restrict__ A, const float* __restrict__ Wall,
        const float* __restrict__ ball, float* __restrict__ Cp,
        int Kd, int N, int layer) {
    extern __shared__ float smf[];
    int*   s_tok = (int*)smf;
    float* s_wt  = smf + 128;
    float* tiles = smf + 256;
    const int NT = SPLIT ? 4 : 2;       // tiles per buffer (Ah[,Al],Bh[,Bl])

    int tid = threadIdx.x;
    int rowBase = blockIdx.y * BMt, colBase = blockIdx.x * BNt;

    int e = 0, cnt = 0;
    const float* W = Wall;
    const float* bias = ball;
    if (MODE >= 2) {
        e = blockIdx.z;
        cnt = g_counts[e];
        if (rowBase >= cnt) return;
        W    = Wall + (size_t)(layer * Ee + e) * Kd * N;
        bias = ball + (size_t)(layer * Ee + e) * N;
        if (tid < 128) {
            int r = rowBase + tid;
            int rc = r < cnt ? r : cnt - 1;
            s_tok[tid] = g_tok[e * TOK + rc];
            s_wt[tid]  = g_wt [e * TOK + rc];
        }
        __syncthreads();
    }

    int lrA = tid >> 1, kcA = (tid & 1) << 3;
    const float* Ap;
    if (MODE == 2)      Ap = g_H + (size_t)s_tok[lrA] * Kd + kcA;
    else if (MODE == 3) Ap = g_hidden + ((size_t)e * TOK + rowBase + lrA) * Kd + kcA;
    else                Ap = A + (size_t)(rowBase + lrA) * Kd + kcA;

    int krB = tid >> 5, ncB = (tid & 31) << 2;
    const float* Wp = W + (size_t)krB * N + colBase + ncB;

    int lane = tid & 31, warp = tid >> 5;
    int wm = (warp & 1) * 64, wn = (warp >> 1) * 32;
    int gid = lane >> 2, tig = lane & 3;

    float acc[4][4][4];
#pragma unroll
    for (int a = 0; a < 4; a++)
#pragma unroll
        for (int b2 = 0; b2 < 4; b2++)
#pragma unroll
            for (int c = 0; c < 4; c++) acc[a][b2][c] = 0.f;

    int nk = Kd / BKt;
    float4 av0, av1, bv0, bv1;

    av0 = *(const float4*)(Ap);
    av1 = *(const float4*)(Ap + 4);
    bv0 = *(const float4*)(Wp);
    bv1 = *(const float4*)(Wp + (size_t)8 * N);

    // store chunk 0
    {
        float* Ah = tiles;
        float* Bh = tiles + (SPLIT ? 2 : 1) * TILE_F;
        float va[8] = {av0.x, av0.y, av0.z, av0.w, av1.x, av1.y, av1.z, av1.w};
#pragma unroll
        for (int g = 0; g < 8; g++) {
            float v = va[g];
            float hi = tf32r(v);
            Ah[(kcA + g) * TWg + lrA] = hi;
            if (SPLIT) Ah[TILE_F + (kcA + g) * TWg + lrA] = v - hi;
        }
        float vb[8] = {bv0.x, bv0.y, bv0.z, bv0.w, bv1.x, bv1.y, bv1.z, bv1.w};
#pragma unroll
        for (int g = 0; g < 8; g++) {
            int rr = krB + (g >> 2) * 8, cc = ncB + (g & 3);
            float v = vb[g];
            float hi = tf32r(v);
            Bh[rr * TWg + cc] = hi;
            if (SPLIT) Bh[TILE_F + rr * TWg + cc] = v - hi;
        }
    }
    __syncthreads();

    for (int t = 0; t < nk; t++) {
        if (t + 1 < nk) {
            const float* a2 = Ap + (size_t)(t + 1) * BKt;
            av0 = *(const float4*)(a2);
            av1 = *(const float4*)(a2 + 4);
            const float* w2 = Wp + (size_t)(t + 1) * BKt * N;
            bv0 = *(const float4*)(w2);
            bv1 = *(const float4*)(w2 + (size_t)8 * N);
        }
        int s = t & 1;
        float* Ah = tiles + s * NT * TILE_F;
        float* Al = Ah + TILE_F;
        float* Bh = Ah + (SPLIT ? 2 : 1) * TILE_F;
        float* Bl = Ah + 3 * TILE_F;

#pragma unroll
        for (int kk = 0; kk < BKt; kk += 8) {
            uint32_t afh[4][4], afl[4][4], bfh[4][2], bfl[4][2];
#pragma unroll
            for (int mt = 0; mt < 4; mt++) {
                int m0 = wm + mt * 16 + gid;
                afh[mt][0] = __float_as_uint(Ah[(kk + tig) * TWg + m0]);
                afh[mt][1] = __float_as_uint(Ah[(kk + tig) * TWg + m0 + 8]);
                afh[mt][2] = __float_as_uint(Ah[(kk + tig + 4) * TWg + m0]);
                afh[mt][3] = __float_as_uint(Ah[(kk + tig + 4) * TWg + m0 + 8]);
                if (SPLIT) {
                    afl[mt][0] = __float_as_uint(Al[(kk + tig) * TWg + m0]);
                    afl[mt][1] = __float_as_uint(Al[(kk + tig) * TWg + m0 + 8]);
                    afl[mt][2] = __float_as_uint(Al[(kk + tig + 4) * TWg + m0]);
                    afl[mt][3] = __float_as_uint(Al[(kk + tig + 4) * TWg + m0 + 8]);
                }
            }
#pragma unroll
            for (int nt = 0; nt < 4; nt++) {
                int n0 = wn + nt * 8 + gid;
                bfh[nt][0] = __float_as_uint(Bh[(kk + tig) * TWg + n0]);
                bfh[nt][1] = __float_as_uint(Bh[(kk + tig + 4) * TWg + n0]);
                if (SPLIT) {
                    bfl[nt][0] = __float_as_uint(Bl[(kk + tig) * TWg + n0]);
                    bfl[nt][1] = __float_as_uint(Bl[(kk + tig + 4) * TWg + n0]);
                }
            }
#pragma unroll
            for (int mt = 0; mt < 4; mt++)
#pragma unroll
                for (int nt = 0; nt < 4; nt++) {
                    mma_tf32(acc[mt][nt], afh[mt], bfh[nt]);
                    if (SPLIT) {
                        mma_tf32(acc[mt][nt], afh[mt], bfl[nt]);
                        mma_tf32(acc[mt][nt], afl[mt], bfh[nt]);
                    }
                }
        }

        if (t + 1 < nk) {
            int s2 = s ^ 1;
            float* Ah2 = tiles + s2 * NT * TILE_F;
            float* Bh2 = Ah2 + (SPLIT ? 2 : 1) * TILE_F;
            float va[8] = {av0.x, av0.y, av0.z, av0.w, av1.x, av1.y, av1.z, av1.w};
#pragma unroll
            for (int g = 0; g < 8; g++) {
                float v = va[g];
                float hi = tf32r(v);
                Ah2[(kcA + g) * TWg + lrA] = hi;
                if (SPLIT) Ah2[TILE_F + (kcA + g) * TWg + lrA] = v - hi;
            }
            float vb[8] = {bv0.x, bv0.y, bv0.z, bv0.w, bv1.x, bv1.y, bv1.z, bv1.w};
#pragma unroll
            for (int g = 0; g < 8; g++) {
                int rr = krB + (g >> 2) * 8, cc = ncB + (g & 3);
                float v = vb[g];
                float hi = tf32r(v);
                Bh2[rr * TWg + cc] = hi;
                if (SPLIT) Bh2[TILE_F + rr * TWg + cc] = v - hi;
            }
        }
        __syncthreads();
    }

#pragma unroll
    for (int mt = 0; mt < 4; mt++) {
#pragma unroll
        for (int c = 0; c < 4; c++) {
            int rl = wm + mt * 16 + gid + ((c & 2) ? 8 : 0);
            int r  = rowBase + rl;
#pragma unroll
            for (int nt = 0; nt < 4; nt++) {
                int cg = colBase + wn + nt * 8 + tig * 2 + (c & 1);
                float v = acc[mt][nt][c] + bias[cg];
                if (MODE == 0) {
                    Cp[(size_t)r * N + cg] = v;
                } else if (MODE == 1) {
                    Cp[(size_t)r * N + cg] = v + Cp[(size_t)r * N + cg];
                } else if (MODE == 2) {
                    if (r < cnt)
                        g_hidden[((size_t)e * TOK + r) * N + cg] = gelu_exact(v);
                } else {
                    if (r < cnt)
                        atomicAdd(&g_X[(size_t)s_tok[rl] * N + cg], v * s_wt[rl]);
                }
            }
        }
    }
}

// ---------------- flash attention v2 (fp32, 64q x 64k, float4 LDS) -----------
// smem: Qt[d][q] Kt[d][k] Vs[k][d] Ps[q][k], all [64][68]
#define FA_STR 68
#define FA_T   (64*FA_STR)
#define FA_SMEM (4*FA_T*4)     // bytes

__global__ __launch_bounds__(256) void flash_attn() {
    extern __shared__ float fs[];
    float* Qt = fs;
    float* Kt = fs + FA_T;
    float* Vs = fs + 2 * FA_T;
    float* Ps = fs + 3 * FA_T;

    int qb = blockIdx.x, h = blockIdx.y, b = blockIdx.z;
    int tid = threadIdx.x;
    int ty = tid >> 4, tx = tid & 15;

    for (int i = tid; i < 1024; i += 256) {
        int r = i >> 4, d4 = (i & 15) << 2;
        float4 v = *(const float4*)&g_Q[((size_t)(b * Sq + qb * 64 + r)) * Dq + h * HD + d4];
        Qt[(d4 + 0) * FA_STR + r] = v.x;
        Qt[(d4 + 1) * FA_STR + r] = v.y;
        Qt[(d4 + 2) * FA_STR + r] = v.z;
        Qt[(d4 + 3) * FA_STR + r] = v.w;
    }

    float m[4], l[4], o[4][4];
#pragma unroll
    for (int i = 0; i < 4; i++) {
        m[i] = -3.0e38f; l[i] = 0.f;
#pragma unroll
        for (int j = 0; j < 4; j++) o[i][j] = 0.f;
    }

    for (int kt = 0; kt <= qb; kt++) {
        __syncthreads();
        for (int i = tid; i < 1024; i += 256) {
            int r = i >> 4, d4 = (i & 15) << 2;
            size_t base = ((size_t)(b * Sq + kt * 64 + r)) * Dq + h * HD + d4;
            float4 kv = *(const float4*)&g_K[base];
            Kt[(d4 + 0) * FA_STR + r] = kv.x;
            Kt[(d4 + 1) * FA_STR + r] = kv.y;
            Kt[(d4 + 2) * FA_STR + r] = kv.z;
            Kt[(d4 + 3) * FA_STR + r] = kv.w;
            float4 vv = *(const float4*)&g_V[base];
            *(float4*)&Vs[r * FA_STR + d4] = vv;
        }
        __syncthreads();

        float s[4][4];
#pragma unroll
        for (int i = 0; i < 4; i++)
#pragma unroll
            for (int j = 0; j < 4; j++) s[i][j] = 0.f;

        for (int d = 0; d < 64; d++) {
            float4 qf = *(const float4*)&Qt[d * FA_STR + ty * 4];
            float4 kf = *(const float4*)&Kt[d * FA_STR + tx * 4];
            float qa[4] = {qf.x, qf.y, qf.z, qf.w};
            float ka[4] = {kf.x, kf.y, kf.z, kf.w};
#pragma unroll
            for (int i = 0; i < 4; i++)
#pragma unroll
                for (int j = 0; j < 4; j++) s[i][j] += qa[i] * ka[j];
        }

        bool edge = (kt == qb);
#pragma unroll
        for (int i = 0; i < 4; i++) {
            float p[4];
#pragma unroll
            for (int j = 0; j < 4; j++) {
                float sv = s[i][j] * 0.125f;
                if (edge && (tx * 4 + j > ty * 4 + i)) sv = -3.0e38f;
                p[j] = sv;
            }
            float rm = fmaxf(fmaxf(p[0], p[1]), fmaxf(p[2], p[3]));
#pragma unroll
            for (int off = 1; off < 16; off <<= 1)
                rm = fmaxf(rm, __shfl_xor_sync(0xffffffffu, rm, off));
            float mn = fmaxf(m[i], rm);
            float alpha = __expf(m[i] - mn);
            float rs = 0.f;
#pragma unroll
            for (int j = 0; j < 4; j++) { p[j] = __expf(p[j] - mn); rs += p[j]; }
#pragma unroll
            for (int off = 1; off < 16; off <<= 1)
                rs += __shfl_xor_sync(0xffffffffu, rs, off);
            l[i] = l[i] * alpha + rs;
            m[i] = mn;
#pragma unroll
            for (int j = 0; j < 4; j++) o[i][j] *= alpha;
            *(float4*)&Ps[(ty * 4 + i) * FA_STR + tx * 4] =
                make_float4(p[0], p[1], p[2], p[3]);
        }
        __syncthreads();

        for (int k4 = 0; k4 < 16; k4++) {
            float4 pf[4], vf[4];
#pragma unroll
            for (int i = 0; i < 4; i++)
                pf[i] = *(const float4*)&Ps[(ty * 4 + i) * FA_STR + k4 * 4];
#pragma unroll
            for (int kk = 0; kk < 4; kk++)
                vf[kk] = *(const float4*)&Vs[(k4 * 4 + kk) * FA_STR + tx * 4];
#pragma unroll
            for (int i = 0; i < 4; i++) {
                float pa[4] = {pf[i].x, pf[i].y, pf[i].z, pf[i].w};
#pragma unroll
                for (int kk = 0; kk < 4; kk++) {
                    o[i][0] += pa[kk] * vf[kk].x;
                    o[i][1] += pa[kk] * vf[kk].y;
                    o[i][2] += pa[kk] * vf[kk].z;
                    o[i][3] += pa[kk] * vf[kk].w;
                }
            }
        }
    }

#pragma unroll
    for (int i = 0; i < 4; i++) {
        float inv = 1.0f / l[i];
#pragma unroll
        for (int j = 0; j < 4; j++)
            g_Y[((size_t)(b * Sq + qb * 64 + ty * 4 + i)) * Dq + h * HD + tx * 4 + j] = o[i][j] * inv;
    }
}

// ---------------- gating -----------------------------------------------------
__global__ void gate_token_kernel(const float* __restrict__ gw,
                                  const float* __restrict__ gb, int layer) {
    int t = blockIdx.x * 4 + (threadIdx.x >> 5);
    int lane = threadIdx.x & 31;
    if (t >= TOK) return;
    const float* hrow = g_H + (size_t)t * Dq;
    const float* gwl = gw + (size_t)layer * Dq * Ee;
    float acc[Ee] = {};
    for (int d = lane; d < Dq; d += 32) {
        float hv = hrow[d];
        const float* g = gwl + (size_t)d * Ee;
#pragma unroll
        for (int e = 0; e < Ee; e++) acc[e] += hv * g[e];
    }
#pragma unroll
    for (int e = 0; e < Ee; e++)
        for (int off = 16; off; off >>= 1)
            acc[e] += __shfl_xor_sync(0xffffffffu, acc[e], off);
    if (lane == 0) {
        float lg[Ee];
#pragma unroll
        for (int e = 0; e < Ee; e++) lg[e] = acc[e] + gb[layer * Ee + e];
        int i1, i2; float w1, w2;
        top2_of8(lg, i1, i2, w1, w2);
        g_te[t * 2] = i1; g_te[t * 2 + 1] = i2;
        g_tw[t * 2] = w1; g_tw[t * 2 + 1] = w2;
    }
}

__global__ void xmean_kernel() {
    int b = blockIdx.y;
    int d = blockIdx.x * 256 + threadIdx.x;
    float s = 0.f;
    for (int ss = 0; ss < Sq; ss++)
        s += g_H[((size_t)(b * Sq + ss)) * Dq + d];
    g_xmean[b * Dq + d] = s * (1.0f / Sq);
}

__global__ void gate_seq_kernel(const float* __restrict__ gw,
                                const float* __restrict__ gb, int layer) {
    int b = blockIdx.x;
    int tid = threadIdx.x, e = tid >> 5, lane = tid & 31;
    const float* gwl = gw + (size_t)layer * Dq * Ee;
    float acc = 0.f;
    for (int d = lane; d < Dq; d += 32)
        acc += g_xmean[b * Dq + d] * gwl[(size_t)d * Ee + e];
    for (int off = 16; off; off >>= 1)
        acc += __shfl_xor_sync(0xffffffffu, acc, off);
    __shared__ float lg[Ee];
    if (lane == 0) lg[e] = acc + gb[layer * Ee + e];
    __syncthreads();
    if (tid == 0) {
        int i1, i2; float w1, w2;
        top2_of8(lg, i1, i2, w1, w2);
        g_bsel[b * 2] = i1; g_bsel[b * 2 + 1] = i2;
        g_bw[b * 2] = w1;  g_bw[b * 2 + 1] = w2;
    }
}

__global__ void zero_counts_kernel() {
    if (threadIdx.x < Ee) g_counts[threadIdx.x] = 0;
}

__global__ void assign_kernel(int seq_mode) {
    int t = blockIdx.x * 256 + threadIdx.x;
    if (t >= TOK) return;
    int e1, e2; float w1, w2;
    if (seq_mode) {
        int b = t / Sq;
        e1 = g_bsel[b * 2]; e2 = g_bsel[b * 2 + 1];
        w1 = g_bw[b * 2];   w2 = g_bw[b * 2 + 1];
    } else {
        e1 = g_te[t * 2]; e2 = g_te[t * 2 + 1];
        w1 = g_tw[t * 2]; w2 = g_tw[t * 2 + 1];
    }
    int s1 = atomicAdd(&g_counts[e1], 1);
    g_tok[e1 * TOK + s1] = t; g_wt[e1 * TOK + s1] = w1;
    int s2 = atomicAdd(&g_counts[e2], 1);
    g_tok[e2 * TOK + s2] = t; g_wt[e2 * TOK + s2] = w2;
}

// ---------------- host side --------------------------------------------------
#define SMEM_G0 ((256 + 2*2*TILE_F) * 4)   // 35840
#define SMEM_G1 ((256 + 2*4*TILE_F) * 4)   // 70656

extern "C" void kernel_launch(void* const* d_in, const int* in_sizes, int n_in,
                              void* d_out, int out_size) {
    const float* x      = (const float*)d_in[0];
    const float* ln1_w  = (const float*)d_in[1];
    const float* ln1_b  = (const float*)d_in[2];
    const float* ln2_w  = (const float*)d_in[3];
    const float* ln2_b  = (const float*)d_in[4];
    const float* wq     = (const float*)d_in[5];
    const float* wk     = (const float*)d_in[6];
    const float* wv     = (const float*)d_in[7];
    const float* wo     = (const float*)d_in[8];
    const float* bq     = (const float*)d_in[9];
    const float* bk     = (const float*)d_in[10];
    const float* bv     = (const float*)d_in[11];
    const float* bo     = (const float*)d_in[12];
    const float* gate_w = (const float*)d_in[13];
    const float* gate_b = (const float*)d_in[14];
    const float* e_w1   = (const float*)d_in[15];
    const float* e_b1   = (const float*)d_in[16];
    const float* e_w2   = (const float*)d_in[17];
    const float* e_b2   = (const float*)d_in[18];

    float *Xp, *Hp, *Qp, *Kp, *Vp, *Yp;
    cudaGetSymbolAddress((void**)&Xp, g_X);
    cudaGetSymbolAddress((void**)&Hp, g_H);
    cudaGetSymbolAddress((void**)&Qp, g_Q);
    cudaGetSymbolAddress((void**)&Kp, g_K);
    cudaGetSymbolAddress((void**)&Vp, g_V);
    cudaGetSymbolAddress((void**)&Yp, g_Y);

    static int attr_set = 0;
    if (!attr_set) {
        cudaFuncSetAttribute(gemm_tc<0,0>, cudaFuncAttributeMaxDynamicSharedMemorySize, SMEM_G0);
        cudaFuncSetAttribute(gemm_tc<1,0>, cudaFuncAttributeMaxDynamicSharedMemorySize, SMEM_G0);
        cudaFuncSetAttribute(gemm_tc<2,0>, cudaFuncAttributeMaxDynamicSharedMemorySize, SMEM_G0);
        cudaFuncSetAttribute(gemm_tc<3,0>, cudaFuncAttributeMaxDynamicSharedMemorySize, SMEM_G0);
        cudaFuncSetAttribute(gemm_tc<0,1>, cudaFuncAttributeMaxDynamicSharedMemorySize, SMEM_G1);
        cudaFuncSetAttribute(gemm_tc<1,1>, cudaFuncAttributeMaxDynamicSharedMemorySize, SMEM_G1);
        cudaFuncSetAttribute(flash_attn,   cudaFuncAttributeMaxDynamicSharedMemorySize, FA_SMEM);
        attr_set = 1;
    }

    const size_t DD = (size_t)Dq * Dq;
    const int nelem = TOK * Dq;

    copy_in_kernel<<<nelem / 256, 256>>>(x);

    dim3 gproj(Dq / BNt, TOK / BMt);
    for (int l = 0; l < Ll; l++) {
        // --- attention block ---
        ln_kernel<<<TOK, 256>>>(ln1_w + (size_t)l * Dq, ln1_b + (size_t)l * Dq);
        if (l == 0) {
            // split path: ~fp32 precision feeding layer-0 token gating
            gemm_tc<0,1><<<gproj, 256, SMEM_G1>>>(Hp, wq + l * DD, bq + (size_t)l * Dq, Qp, Dq, Dq, l);
            gemm_tc<0,1><<<gproj, 256, SMEM_G1>>>(Hp, wk + l * DD, bk + (size_t)l * Dq, Kp, Dq, Dq, l);
            gemm_tc<0,1><<<gproj, 256, SMEM_G1>>>(Hp, wv + l * DD, bv + (size_t)l * Dq, Vp, Dq, Dq, l);
        } else {
            gemm_tc<0,0><<<gproj, 256, SMEM_G0>>>(Hp, wq + l * DD, bq + (size_t)l * Dq, Qp, Dq, Dq, l);
            gemm_tc<0,0><<<gproj, 256, SMEM_G0>>>(Hp, wk + l * DD, bk + (size_t)l * Dq, Kp, Dq, Dq, l);
            gemm_tc<0,0><<<gproj, 256, SMEM_G0>>>(Hp, wv + l * DD, bv + (size_t)l * Dq, Vp, Dq, Dq, l);
        }
        flash_attn<<<dim3(Sq / 64, Hh, Bq), 256, FA_SMEM>>>();
        if (l == 0) {
            gemm_tc<1,1><<<gproj, 256, SMEM_G1>>>(Yp, wo + l * DD, bo + (size_t)l * Dq, Xp, Dq, Dq, l);
        } else {
            gemm_tc<1,0><<<gproj, 256, SMEM_G0>>>(Yp, wo + l * DD, bo + (size_t)l * Dq, Xp, Dq, Dq, l);
        }

        // --- MoE block ---
        ln_kernel<<<TOK, 256>>>(ln2_w + (size_t)l * Dq, ln2_b + (size_t)l * Dq);
        if (l % 2 == 0) {
            gate_token_kernel<<<TOK / 4, 128>>>(gate_w, gate_b, l);
        } else {
            xmean_kernel<<<dim3(Dq / 256, Bq), 256>>>();
            gate_seq_kernel<<<Bq, 256>>>(gate_w, gate_b, l);
        }
        zero_counts_kernel<<<1, 32>>>();
        assign_kernel<<<TOK / 256, 256>>>(l % 2);
        gemm_tc<2,0><<<dim3(DFFq / BNt, TOK / BMt, Ee), 256, SMEM_G0>>>(nullptr, e_w1, e_b1, nullptr, Dq, DFFq, l);
        gemm_tc<3,0><<<dim3(Dq / BNt, TOK / BMt, Ee), 256, SMEM_G0>>>(nullptr, e_w2, e_b2, nullptr, DFFq, Dq, l);
    }

    copy_out_kernel<<<nelem / 256, 256>>>((float*)d_out);
    (void)in_sizes; (void)n_in; (void)out_size;
}

// round 5
// speedup vs baseline: 6.0003x; 1.0295x over previous
#include <cuda_runtime.h>
#include <math.h>
#include <stdint.h>

#define Bq   4
#define Sq   1024
#define Dq   1024
#define Hh   16
#define HD   64
#define Ll   2
#define Ee   8
#define DFFq 4096
#define TOK  (Bq*Sq)   // 4096

// ---------------- static scratch ---------------------------------------------
__device__ float g_X[TOK*Dq];
__device__ float g_H[TOK*Dq];
__device__ float g_Q[TOK*Dq];
__device__ float g_K[TOK*Dq];
__device__ float g_V[TOK*Dq];
__device__ float g_Y[TOK*Dq];
__device__ float g_hidden[(size_t)Ee*TOK*DFFq];
__device__ int   g_counts[Ee];
__device__ int   g_tok[Ee*TOK];
__device__ float g_wt[Ee*TOK];
__device__ int   g_te[TOK*2];
__device__ float g_tw[TOK*2];
__device__ int   g_bsel[Bq*2];
__device__ float g_bw[Bq*2];
__device__ float g_xmean[Bq*Dq];

// ---------------- helpers ----------------------------------------------------
__device__ __forceinline__ void top2_of8(const float* lg, int& i1, int& i2,
                                         float& w1, float& w2) {
    i1 = 0; float v1 = lg[0];
#pragma unroll
    for (int e = 1; e < Ee; e++) if (lg[e] > v1) { v1 = lg[e]; i1 = e; }
    i2 = -1; float v2 = -3.0e38f;
#pragma unroll
    for (int e = 0; e < Ee; e++) if (e != i1 && lg[e] > v2) { v2 = lg[e]; i2 = e; }
    float ex = expf(v2 - v1);
    w1 = 1.0f / (1.0f + ex);
    w2 = ex / (1.0f + ex);
}
__device__ __forceinline__ float gelu_exact(float x) {
    return 0.5f * x * (1.0f + erff(x * 0.7071067811865476f));
}
__device__ __forceinline__ float tf32r(float x) {
    uint32_t u; asm("cvt.rna.tf32.f32 %0, %1;" : "=r"(u) : "f"(x));
    return __uint_as_float(u);
}
__device__ __forceinline__ void mma_tf32(float c[4], const uint32_t a[4],
                                         const uint32_t b[2]) {
    asm volatile(
        "mma.sync.aligned.m16n8k8.row.col.f32.tf32.tf32.f32 "
        "{%0,%1,%2,%3},{%4,%5,%6,%7},{%8,%9},{%0,%1,%2,%3};"
        : "+f"(c[0]), "+f"(c[1]), "+f"(c[2]), "+f"(c[3])
        : "r"(a[0]), "r"(a[1]), "r"(a[2]), "r"(a[3]), "r"(b[0]), "r"(b[1]));
}

// ---------------- simple kernels ---------------------------------------------
__global__ void copy_in_kernel(const float* __restrict__ src) {
    int i = blockIdx.x * 256 + threadIdx.x;
    g_X[i] = src[i];
}
__global__ void copy_out_kernel(float* __restrict__ dst) {
    int i = blockIdx.x * 256 + threadIdx.x;
    dst[i] = g_X[i];
}

__global__ void ln_kernel(const float* __restrict__ w, const float* __restrict__ b) {
    int t = blockIdx.x, tid = threadIdx.x;
    const float* xr = g_X + (size_t)t * Dq;
    float s = 0.f, s2 = 0.f;
    for (int d = tid; d < Dq; d += 256) { float v = xr[d]; s += v; s2 += v * v; }
    __shared__ float r1[256], r2[256];
    r1[tid] = s; r2[tid] = s2; __syncthreads();
    for (int off = 128; off; off >>= 1) {
        if (tid < off) { r1[tid] += r1[tid + off]; r2[tid] += r2[tid + off]; }
        __syncthreads();
    }
    float mean = r1[0] * (1.0f / Dq);
    float var  = r2[0] * (1.0f / Dq) - mean * mean;
    float rstd = rsqrtf(var + 1e-5f);
    float* hr = g_H + (size_t)t * Dq;
    for (int d = tid; d < Dq; d += 256)
        hr[d] = (xr[d] - mean) * rstd * w[d] + b[d];
}

// ---------------- split TF32 GEMM (layer-0 path, 128x128) --------------------
#define BMt 128
#define BNt 128
#define BKt 16
#define TWg 136
#define TILE_F (BKt*TWg)

template<int MODE>
__global__ void __launch_bounds__(256)
gemm_tc(const float* __restrict__ A, const float* __restrict__ Wall,
        const float* __restrict__ ball, float* __restrict__ Cp,
        int Kd, int N, int layer) {
    extern __shared__ float smf[];
    float* tiles = smf + 256;

    int tid = threadIdx.x;
    int rowBase = blockIdx.y * BMt, colBase = blockIdx.x * BNt;
    const float* bias = ball;

    int lrA = tid >> 1, kcA = (tid & 1) << 3;
    const float* Ap = A + (size_t)(rowBase + lrA) * Kd + kcA;
    int krB = tid >> 5, ncB = (tid & 31) << 2;
    const float* Wp = Wall + (size_t)krB * N + colBase + ncB;

    int lane = tid & 31, warp = tid >> 5;
    int wm = (warp & 1) * 64, wn = (warp >> 1) * 32;
    int gid = lane >> 2, tig = lane & 3;

    float acc[4][4][4];
#pragma unroll
    for (int a = 0; a < 4; a++)
#pragma unroll
        for (int b2 = 0; b2 < 4; b2++)
#pragma unroll
            for (int c = 0; c < 4; c++) acc[a][b2][c] = 0.f;

    int nk = Kd / BKt;
    float4 av0, av1, bv0, bv1;
    av0 = *(const float4*)(Ap);
    av1 = *(const float4*)(Ap + 4);
    bv0 = *(const float4*)(Wp);
    bv1 = *(const float4*)(Wp + (size_t)8 * N);
    {
        float* Ah = tiles;
        float* Bh = tiles + 2 * TILE_F;
        float va[8] = {av0.x, av0.y, av0.z, av0.w, av1.x, av1.y, av1.z, av1.w};
#pragma unroll
        for (int g = 0; g < 8; g++) {
            float v = va[g], hi = tf32r(v);
            Ah[(kcA + g) * TWg + lrA] = hi;
            Ah[TILE_F + (kcA + g) * TWg + lrA] = v - hi;
        }
        float vb[8] = {bv0.x, bv0.y, bv0.z, bv0.w, bv1.x, bv1.y, bv1.z, bv1.w};
#pragma unroll
        for (int g = 0; g < 8; g++) {
            int rr = krB + (g >> 2) * 8, cc = ncB + (g & 3);
            float v = vb[g], hi = tf32r(v);
            Bh[rr * TWg + cc] = hi;
            Bh[TILE_F + rr * TWg + cc] = v - hi;
        }
    }
    __syncthreads();

    for (int t = 0; t < nk; t++) {
        if (t + 1 < nk) {
            const float* a2 = Ap + (size_t)(t + 1) * BKt;
            av0 = *(const float4*)(a2);
            av1 = *(const float4*)(a2 + 4);
            const float* w2 = Wp + (size_t)(t + 1) * BKt * N;
            bv0 = *(const float4*)(w2);
            bv1 = *(const float4*)(w2 + (size_t)8 * N);
        }
        int s = t & 1;
        float* Ah = tiles + s * 4 * TILE_F;
        float* Al = Ah + TILE_F;
        float* Bh = Ah + 2 * TILE_F;
        float* Bl = Ah + 3 * TILE_F;

#pragma unroll
        for (int kk = 0; kk < BKt; kk += 8) {
            uint32_t afh[4][4], afl[4][4], bfh[4][2], bfl[4][2];
#pragma unroll
            for (int mt = 0; mt < 4; mt++) {
                int m0 = wm + mt * 16 + gid;
                afh[mt][0] = __float_as_uint(Ah[(kk + tig) * TWg + m0]);
                afh[mt][1] = __float_as_uint(Ah[(kk + tig) * TWg + m0 + 8]);
                afh[mt][2] = __float_as_uint(Ah[(kk + tig + 4) * TWg + m0]);
                afh[mt][3] = __float_as_uint(Ah[(kk + tig + 4) * TWg + m0 + 8]);
                afl[mt][0] = __float_as_uint(Al[(kk + tig) * TWg + m0]);
                afl[mt][1] = __float_as_uint(Al[(kk + tig) * TWg + m0 + 8]);
                afl[mt][2] = __float_as_uint(Al[(kk + tig + 4) * TWg + m0]);
                afl[mt][3] = __float_as_uint(Al[(kk + tig + 4) * TWg + m0 + 8]);
            }
#pragma unroll
            for (int nt = 0; nt < 4; nt++) {
                int n0 = wn + nt * 8 + gid;
                bfh[nt][0] = __float_as_uint(Bh[(kk + tig) * TWg + n0]);
                bfh[nt][1] = __float_as_uint(Bh[(kk + tig + 4) * TWg + n0]);
                bfl[nt][0] = __float_as_uint(Bl[(kk + tig) * TWg + n0]);
                bfl[nt][1] = __float_as_uint(Bl[(kk + tig + 4) * TWg + n0]);
            }
#pragma unroll
            for (int mt = 0; mt < 4; mt++)
#pragma unroll
                for (int nt = 0; nt < 4; nt++) {
                    mma_tf32(acc[mt][nt], afh[mt], bfh[nt]);
                    mma_tf32(acc[mt][nt], afh[mt], bfl[nt]);
                    mma_tf32(acc[mt][nt], afl[mt], bfh[nt]);
                }
        }

        if (t + 1 < nk) {
            int s2 = s ^ 1;
            float* Ah2 = tiles + s2 * 4 * TILE_F;
            float* Bh2 = Ah2 + 2 * TILE_F;
            float va[8] = {av0.x, av0.y, av0.z, av0.w, av1.x, av1.y, av1.z, av1.w};
#pragma unroll
            for (int g = 0; g < 8; g++) {
                float v = va[g], hi = tf32r(v);
                Ah2[(kcA + g) * TWg + lrA] = hi;
                Ah2[TILE_F + (kcA + g) * TWg + lrA] = v - hi;
            }
            float vb[8] = {bv0.x, bv0.y, bv0.z, bv0.w, bv1.x, bv1.y, bv1.z, bv1.w};
#pragma unroll
            for (int g = 0; g < 8; g++) {
                int rr = krB + (g >> 2) * 8, cc = ncB + (g & 3);
                float v = vb[g], hi = tf32r(v);
                Bh2[rr * TWg + cc] = hi;
                Bh2[TILE_F + rr * TWg + cc] = v - hi;
            }
        }
        __syncthreads();
    }

#pragma unroll
    for (int mt = 0; mt < 4; mt++) {
#pragma unroll
        for (int c = 0; c < 4; c++) {
            int r = rowBase + wm + mt * 16 + gid + ((c & 2) ? 8 : 0);
#pragma unroll
            for (int nt = 0; nt < 4; nt++) {
                int cg = colBase + wn + nt * 8 + tig * 2 + (c & 1);
                float v = acc[mt][nt][c] + bias[cg];
                if (MODE == 1) v += Cp[(size_t)r * N + cg];
                Cp[(size_t)r * N + cg] = v;
            }
        }
    }
}

// ---------------- big-tile single-pass TF32 GEMM (128x256) -------------------
// MODE 0: C = A@W + bias    MODE 1: C += (in place via read)   MODE 2: MoE GEMM1
// MODE 3: MoE GEMM2 (atomic scatter)
#define BMb 128
#define BNb 256
#define BKb 16
#define AWb 136
#define BWb 264
#define ATb (BKb*AWb)   // 2176
#define BTb (BKb*BWb)   // 4224
#define SMEM_BIG ((256 + 2*(ATb+BTb)) * 4)   // 52224

template<int MODE>
__global__ void __launch_bounds__(256, 1)
gemm_big(const float* __restrict__ A, const float* __restrict__ Wall,
         const float* __restrict__ ball, float* __restrict__ Cp,
         int Kd, int N, int layer) {
    extern __shared__ float smf[];
    int*   s_tok = (int*)smf;
    float* s_wt  = smf + 128;
    float* tiles = smf + 256;

    int tid = threadIdx.x;
    int rowBase = blockIdx.y * BMb, colBase = blockIdx.x * BNb;

    int e = 0, cnt = 0;
    const float* W = Wall;
    const float* bias = ball;
    if (MODE >= 2) {
        e = blockIdx.z;
        cnt = g_counts[e];
        if (rowBase >= cnt) return;
        W    = Wall + (size_t)(layer * Ee + e) * Kd * N;
        bias = ball + (size_t)(layer * Ee + e) * N;
        if (tid < 128) {
            int r = rowBase + tid;
            int rc = r < cnt ? r : cnt - 1;
            s_tok[tid] = g_tok[e * TOK + rc];
            s_wt[tid]  = g_wt [e * TOK + rc];
        }
        __syncthreads();
    }

    int lrA = tid >> 1, kcA = (tid & 1) << 3;
    const float* Ap;
    if (MODE == 2)      Ap = g_H + (size_t)s_tok[lrA] * Kd + kcA;
    else if (MODE == 3) Ap = g_hidden + ((size_t)e * TOK + rowBase + lrA) * Kd + kcA;
    else                Ap = A + (size_t)(rowBase + lrA) * Kd + kcA;

    int krB = tid >> 5, ncB = (tid & 31) << 3;
    const float* Wp = W + (size_t)krB * N + colBase + ncB;

    int lane = tid & 31, warp = tid >> 5;
    int wm = (warp & 1) * 64, wn = (warp >> 1) * 64;
    int gid = lane >> 2, tig = lane & 3;

    float acc[4][8][4];
#pragma unroll
    for (int a = 0; a < 4; a++)
#pragma unroll
        for (int b2 = 0; b2 < 8; b2++)
#pragma unroll
            for (int c = 0; c < 4; c++) acc[a][b2][c] = 0.f;

    int nk = Kd / BKb;
    float4 av0, av1, bv0, bv1, bv2, bv3;
    av0 = *(const float4*)(Ap);
    av1 = *(const float4*)(Ap + 4);
    bv0 = *(const float4*)(Wp);
    bv1 = *(const float4*)(Wp + 4);
    bv2 = *(const float4*)(Wp + (size_t)8 * N);
    bv3 = *(const float4*)(Wp + (size_t)8 * N + 4);
    {
        float* As = tiles;
        float* Bs = tiles + ATb;
        float va[8] = {av0.x, av0.y, av0.z, av0.w, av1.x, av1.y, av1.z, av1.w};
#pragma unroll
        for (int g = 0; g < 8; g++)
            As[(kcA + g) * AWb + lrA] = tf32r(va[g]);
        *(float4*)&Bs[krB * BWb + ncB] =
            make_float4(tf32r(bv0.x), tf32r(bv0.y), tf32r(bv0.z), tf32r(bv0.w));
        *(float4*)&Bs[krB * BWb + ncB + 4] =
            make_float4(tf32r(bv1.x), tf32r(bv1.y), tf32r(bv1.z), tf32r(bv1.w));
        *(float4*)&Bs[(krB + 8) * BWb + ncB] =
            make_float4(tf32r(bv2.x), tf32r(bv2.y), tf32r(bv2.z), tf32r(bv2.w));
        *(float4*)&Bs[(krB + 8) * BWb + ncB + 4] =
            make_float4(tf32r(bv3.x), tf32r(bv3.y), tf32r(bv3.z), tf32r(bv3.w));
    }
    __syncthreads();

    for (int t = 0; t < nk; t++) {
        if (t + 1 < nk) {
            const float* a2 = Ap + (size_t)(t + 1) * BKb;
            av0 = *(const float4*)(a2);
            av1 = *(const float4*)(a2 + 4);
            const float* w2 = Wp + (size_t)(t + 1) * BKb * N;
            bv0 = *(const float4*)(w2);
            bv1 = *(const float4*)(w2 + 4);
            bv2 = *(const float4*)(w2 + (size_t)8 * N);
            bv3 = *(const float4*)(w2 + (size_t)8 * N + 4);
        }
        int s = t & 1;
        float* As = tiles + s * (ATb + BTb);
        float* Bs = As + ATb;

#pragma unroll
        for (int kk = 0; kk < BKb; kk += 8) {
            uint32_t af[4][4], bf[8][2];
#pragma unroll
            for (int mt = 0; mt < 4; mt++) {
                int m0 = wm + mt * 16 + gid;
                af[mt][0] = __float_as_uint(As[(kk + tig) * AWb + m0]);
                af[mt][1] = __float_as_uint(As[(kk + tig) * AWb + m0 + 8]);
                af[mt][2] = __float_as_uint(As[(kk + tig + 4) * AWb + m0]);
                af[mt][3] = __float_as_uint(As[(kk + tig + 4) * AWb + m0 + 8]);
            }
#pragma unroll
            for (int nt = 0; nt < 8; nt++) {
                int n0 = wn + nt * 8 + gid;
                bf[nt][0] = __float_as_uint(Bs[(kk + tig) * BWb + n0]);
                bf[nt][1] = __float_as_uint(Bs[(kk + tig + 4) * BWb + n0]);
            }
#pragma unroll
            for (int mt = 0; mt < 4; mt++)
#pragma unroll
                for (int nt = 0; nt < 8; nt++)
                    mma_tf32(acc[mt][nt], af[mt], bf[nt]);
        }

        if (t + 1 < nk) {
            int s2 = s ^ 1;
            float* As2 = tiles + s2 * (ATb + BTb);
            float* Bs2 = As2 + ATb;
            float va[8] = {av0.x, av0.y, av0.z, av0.w, av1.x, av1.y, av1.z, av1.w};
#pragma unroll
            for (int g = 0; g < 8; g++)
                As2[(kcA + g) * AWb + lrA] = tf32r(va[g]);
            *(float4*)&Bs2[krB * BWb + ncB] =
                make_float4(tf32r(bv0.x), tf32r(bv0.y), tf32r(bv0.z), tf32r(bv0.w));
            *(float4*)&Bs2[krB * BWb + ncB + 4] =
                make_float4(tf32r(bv1.x), tf32r(bv1.y), tf32r(bv1.z), tf32r(bv1.w));
            *(float4*)&Bs2[(krB + 8) * BWb + ncB] =
                make_float4(tf32r(bv2.x), tf32r(bv2.y), tf32r(bv2.z), tf32r(bv2.w));
            *(float4*)&Bs2[(krB + 8) * BWb + ncB + 4] =
                make_float4(tf32r(bv3.x), tf32r(bv3.y), tf32r(bv3.z), tf32r(bv3.w));
        }
        __syncthreads();
    }

#pragma unroll
    for (int mt = 0; mt < 4; mt++) {
#pragma unroll
        for (int c = 0; c < 4; c++) {
            int rl = wm + mt * 16 + gid + ((c & 2) ? 8 : 0);
            int r  = rowBase + rl;
#pragma unroll
            for (int nt = 0; nt < 8; nt++) {
                int cg = colBase + wn + nt * 8 + tig * 2 + (c & 1);
                float v = acc[mt][nt][c] + bias[cg];
                if (MODE == 0) {
                    Cp[(size_t)r * N + cg] = v;
                } else if (MODE == 1) {
                    Cp[(size_t)r * N + cg] = v + Cp[(size_t)r * N + cg];
                } else if (MODE == 2) {
                    if (r < cnt)
                        g_hidden[((size_t)e * TOK + r) * N + cg] = gelu_exact(v);
                } else {
                    if (r < cnt)
                        atomicAdd(&g_X[(size_t)s_tok[rl] * N + cg], v * s_wt[rl]);
                }
            }
        }
    }
}

// ---------------- tensor-core flash attention --------------------------------
// 128-q block, 8 warps x m16; QK^T and P@V via mma.m16n8k8.tf32.
// SPLIT=1 (layer 0): 3-pass Dekker split everywhere (~fp32 precision).
#define FQSZ (64*136)
#define FKSZ (64*72)
#define FPSZ (64*136)
#define FL_SMEM0 ((FQSZ + 2*FKSZ + FPSZ) * 4)        // 106496
#define FL_SMEM1 ((FQSZ + 2*FKSZ + FPSZ) * 8)        // 212992

__device__ __forceinline__ int fsw(int d) { return ((d >> 2) & 7) << 3; }

template<int SPLIT>
__global__ void __launch_bounds__(256)
flash_tc() {
    extern __shared__ float fs[];
    float* Qh = fs;
    float* Ql = Qh + FQSZ;
    float* Kh = Qh + FQSZ * (SPLIT + 1);
    float* Kl = Kh + FKSZ;
    float* Vh = Kh + FKSZ * (SPLIT + 1);
    float* Vl = Vh + FKSZ;
    float* Ph = Vh + FKSZ * (SPLIT + 1);
    float* Pl = Ph + FPSZ;

    int qb = blockIdx.x, h = blockIdx.y, b = blockIdx.z;
    int tid = threadIdx.x, warp = tid >> 5, lane = tid & 31;
    int gid = lane >> 2, tig = lane & 3;
    int mrow = warp * 16 + gid;

    // load Q (128 x 64), transposed [d][m] with column swizzle
    for (int i = tid; i < 2048; i += 256) {
        int r = i >> 4, d4 = (i & 15) << 2;
        float4 v = *(const float4*)&g_Q[((size_t)(b * Sq + qb * 128 + r)) * Dq + h * HD + d4];
        float va[4] = {v.x, v.y, v.z, v.w};
#pragma unroll
        for (int j = 0; j < 4; j++) {
            int d = d4 + j;
            int cs = r ^ fsw(d);
            float hi = tf32r(va[j]);
            Qh[d * 136 + cs] = hi;
            if (SPLIT) Ql[d * 136 + cs] = tf32r(va[j] - hi);
        }
    }

    float mA = -1e30f, mB = -1e30f, lA = 0.f, lB = 0.f;
    float o[8][4];
#pragma unroll
    for (int nt = 0; nt < 8; nt++)
#pragma unroll
        for (int c = 0; c < 4; c++) o[nt][c] = 0.f;

    int nkt = 2 * qb + 2;
    for (int kt = 0; kt < nkt; kt++) {
        __syncthreads();
        // load K (transposed [d][k], swizzled) and V (natural [k][d])
        for (int i = tid; i < 1024; i += 256) {
            int r = i >> 4, d4 = (i & 15) << 2;
            size_t base = ((size_t)(b * Sq + kt * 64 + r)) * Dq + h * HD + d4;
            float4 kv = *(const float4*)&g_K[base];
            float ka[4] = {kv.x, kv.y, kv.z, kv.w};
#pragma unroll
            for (int j = 0; j < 4; j++) {
                int d = d4 + j;
                int cs = r ^ fsw(d);
                float hi = tf32r(ka[j]);
                Kh[d * 72 + cs] = hi;
                if (SPLIT) Kl[d * 72 + cs] = tf32r(ka[j] - hi);
            }
            float4 vv = *(const float4*)&g_V[base];
            float4 vh = make_float4(tf32r(vv.x), tf32r(vv.y), tf32r(vv.z), tf32r(vv.w));
            *(float4*)&Vh[r * 72 + d4] = vh;
            if (SPLIT)
                *(float4*)&Vl[r * 72 + d4] =
                    make_float4(tf32r(vv.x - vh.x), tf32r(vv.y - vh.y),
                                tf32r(vv.z - vh.z), tf32r(vv.w - vh.w));
        }
        __syncthreads();

        // S = Q @ K^T
        float s[8][4];
#pragma unroll
        for (int nt = 0; nt < 8; nt++)
#pragma unroll
            for (int c = 0; c < 4; c++) s[nt][c] = 0.f;

#pragma unroll
        for (int ks = 0; ks < 8; ks++) {
            int kb = ks * 8;
            int s0 = fsw(kb + tig), s1 = fsw(kb + tig + 4);
            uint32_t a[4], al[4];
            a[0] = __float_as_uint(Qh[(kb + tig) * 136 + (mrow ^ s0)]);
            a[1] = __float_as_uint(Qh[(kb + tig) * 136 + ((mrow + 8) ^ s0)]);
            a[2] = __float_as_uint(Qh[(kb + tig + 4) * 136 + (mrow ^ s1)]);
            a[3] = __float_as_uint(Qh[(kb + tig + 4) * 136 + ((mrow + 8) ^ s1)]);
            if (SPLIT) {
                al[0] = __float_as_uint(Ql[(kb + tig) * 136 + (mrow ^ s0)]);
                al[1] = __float_as_uint(Ql[(kb + tig) * 136 + ((mrow + 8) ^ s0)]);
                al[2] = __float_as_uint(Ql[(kb + tig + 4) * 136 + (mrow ^ s1)]);
                al[3] = __float_as_uint(Ql[(kb + tig + 4) * 136 + ((mrow + 8) ^ s1)]);
            }
#pragma unroll
            for (int nt = 0; nt < 8; nt++) {
                int n0 = nt * 8 + gid;
                uint32_t bb[2], bl[2];
                bb[0] = __float_as_uint(Kh[(kb + tig) * 72 + (n0 ^ s0)]);
                bb[1] = __float_as_uint(Kh[(kb + tig + 4) * 72 + (n0 ^ s1)]);
                mma_tf32(s[nt], a, bb);
                if (SPLIT) {
                    bl[0] = __float_as_uint(Kl[(kb + tig) * 72 + (n0 ^ s0)]);
                    bl[1] = __float_as_uint(Kl[(kb + tig + 4) * 72 + (n0 ^ s1)]);
                    mma_tf32(s[nt], a, bl);
                    mma_tf32(s[nt], al, bb);
                }
            }
        }

        // scale + causal mask
        int rowg = qb * 128 + warp * 16 + gid;
        if (kt * 64 + 63 > rowg) {
#pragma unroll
            for (int nt = 0; nt < 8; nt++)
#pragma unroll
                for (int c = 0; c < 4; c++) {
                    int col = kt * 64 + nt * 8 + 2 * tig + (c & 1);
                    int row = rowg + ((c & 2) ? 8 : 0);
                    float sv = s[nt][c] * 0.125f;
                    s[nt][c] = (col > row) ? -1e30f : sv;
                }
        } else {
#pragma unroll
            for (int nt = 0; nt < 8; nt++)
#pragma unroll
                for (int c = 0; c < 4; c++) s[nt][c] *= 0.125f;
        }

        // online softmax (rows gid / gid+8, quad reductions)
        float rmA = -1e30f, rmB = -1e30f;
#pragma unroll
        for (int nt = 0; nt < 8; nt++) {
            rmA = fmaxf(rmA, fmaxf(s[nt][0], s[nt][1]));
            rmB = fmaxf(rmB, fmaxf(s[nt][2], s[nt][3]));
        }
#pragma unroll
        for (int off = 1; off < 4; off <<= 1) {
            rmA = fmaxf(rmA, __shfl_xor_sync(0xffffffffu, rmA, off));
            rmB = fmaxf(rmB, __shfl_xor_sync(0xffffffffu, rmB, off));
        }
        float mnA = fmaxf(mA, rmA), mnB = fmaxf(mB, rmB);
        float alA = __expf(mA - mnA), alB = __expf(mB - mnB);
        float rsA = 0.f, rsB = 0.f;
#pragma unroll
        for (int nt = 0; nt < 8; nt++) {
            s[nt][0] = __expf(s[nt][0] - mnA); rsA += s[nt][0];
            s[nt][1] = __expf(s[nt][1] - mnA); rsA += s[nt][1];
            s[nt][2] = __expf(s[nt][2] - mnB); rsB += s[nt][2];
            s[nt][3] = __expf(s[nt][3] - mnB); rsB += s[nt][3];
        }
#pragma unroll
        for (int off = 1; off < 4; off <<= 1) {
            rsA += __shfl_xor_sync(0xffffffffu, rsA, off);
            rsB += __shfl_xor_sync(0xffffffffu, rsB, off);
        }
        lA = lA * alA + rsA; mA = mnA;
        lB = lB * alB + rsB; mB = mnB;
#pragma unroll
        for (int nt = 0; nt < 8; nt++) {
            o[nt][0] *= alA; o[nt][1] *= alA;
            o[nt][2] *= alB; o[nt][3] *= alB;
        }

        // stage P (warp-private columns of [k][m] layout)
        __syncwarp();
#pragma unroll
        for (int nt = 0; nt < 8; nt++)
#pragma unroll
            for (int c = 0; c < 4; c++) {
                int cl = nt * 8 + 2 * tig + (c & 1);
                int mr = warp * 16 + gid + ((c & 2) ? 8 : 0);
                float p = s[nt][c], ph = tf32r(p);
                Ph[cl * 136 + mr] = ph;
                if (SPLIT) Pl[cl * 136 + mr] = tf32r(p - ph);
            }
        __syncwarp();

        // O += P @ V
#pragma unroll
        for (int ks = 0; ks < 8; ks++) {
            int kb = ks * 8;
            uint32_t a[4], al[4];
            a[0] = __float_as_uint(Ph[(kb + tig) * 136 + mrow]);
            a[1] = __float_as_uint(Ph[(kb + tig) * 136 + mrow + 8]);
            a[2] = __float_as_uint(Ph[(kb + tig + 4) * 136 + mrow]);
            a[3] = __float_as_uint(Ph[(kb + tig + 4) * 136 + mrow + 8]);
            if (SPLIT) {
                al[0] = __float_as_uint(Pl[(kb + tig) * 136 + mrow]);
                al[1] = __float_as_uint(Pl[(kb + tig) * 136 + mrow + 8]);
                al[2] = __float_as_uint(Pl[(kb + tig + 4) * 136 + mrow]);
                al[3] = __float_as_uint(Pl[(kb + tig + 4) * 136 + mrow + 8]);
            }
#pragma unroll
            for (int nt = 0; nt < 8; nt++) {
                int n0 = nt * 8 + gid;
                uint32_t bb[2], bl[2];
                bb[0] = __float_as_uint(Vh[(kb + tig) * 72 + n0]);
                bb[1] = __float_as_uint(Vh[(kb + tig + 4) * 72 + n0]);
                mma_tf32(o[nt], a, bb);
                if (SPLIT) {
                    bl[0] = __float_as_uint(Vl[(kb + tig) * 72 + n0]);
                    bl[1] = __float_as_uint(Vl[(kb + tig + 4) * 72 + n0]);
                    mma_tf32(o[nt], a, bl);
                    mma_tf32(o[nt], al, bb);
                }
            }
        }
    }

    // write O
    float invA = 1.0f / lA, invB = 1.0f / lB;
    size_t rbase0 = ((size_t)(b * Sq + qb * 128 + warp * 16 + gid)) * Dq + h * HD;
    size_t rbase1 = rbase0 + (size_t)8 * Dq;
#pragma unroll
    for (int nt = 0; nt < 8; nt++) {
        int d0 = nt * 8 + 2 * tig;
        *(float2*)&g_Y[rbase0 + d0] = make_float2(o[nt][0] * invA, o[nt][1] * invA);
        *(float2*)&g_Y[rbase1 + d0] = make_float2(o[nt][2] * invB, o[nt][3] * invB);
    }
}

// ---------------- gating -----------------------------------------------------
__global__ void gate_token_kernel(const float* __restrict__ gw,
                                  const float* __restrict__ gb, int layer) {
    int t = blockIdx.x * 4 + (threadIdx.x >> 5);
    int lane = threadIdx.x & 31;
    if (t >= TOK) return;
    const float* hrow = g_H + (size_t)t * Dq;
    const float* gwl = gw + (size_t)layer * Dq * Ee;
    float acc[Ee] = {};
    for (int d = lane; d < Dq; d += 32) {
        float hv = hrow[d];
        const float* g = gwl + (size_t)d * Ee;
#pragma unroll
        for (int e = 0; e < Ee; e++) acc[e] += hv * g[e];
    }
#pragma unroll
    for (int e = 0; e < Ee; e++)
        for (int off = 16; off; off >>= 1)
            acc[e] += __shfl_xor_sync(0xffffffffu, acc[e], off);
    if (lane == 0) {
        float lg[Ee];
#pragma unroll
        for (int e = 0; e < Ee; e++) lg[e] = acc[e] + gb[layer * Ee + e];
        int i1, i2; float w1, w2;
        top2_of8(lg, i1, i2, w1, w2);
        g_te[t * 2] = i1; g_te[t * 2 + 1] = i2;
        g_tw[t * 2] = w1; g_tw[t * 2 + 1] = w2;
    }
}

__global__ void xmean_kernel() {
    int b = blockIdx.y;
    int d = blockIdx.x * 256 + threadIdx.x;
    float s = 0.f;
    for (int ss = 0; ss < Sq; ss++)
        s += g_H[((size_t)(b * Sq + ss)) * Dq + d];
    g_xmean[b * Dq + d] = s * (1.0f / Sq);
}

__global__ void gate_seq_kernel(const float* __restrict__ gw,
                                const float* __restrict__ gb, int layer) {
    int b = blockIdx.x;
    int tid = threadIdx.x, e = tid >> 5, lane = tid & 31;
    const float* gwl = gw + (size_t)layer * Dq * Ee;
    float acc = 0.f;
    for (int d = lane; d < Dq; d += 32)
        acc += g_xmean[b * Dq + d] * gwl[(size_t)d * Ee + e];
    for (int off = 16; off; off >>= 1)
        acc += __shfl_xor_sync(0xffffffffu, acc, off);
    __shared__ float lg[Ee];
    if (lane == 0) lg[e] = acc + gb[layer * Ee + e];
    __syncthreads();
    if (tid == 0) {
        int i1, i2; float w1, w2;
        top2_of8(lg, i1, i2, w1, w2);
        g_bsel[b * 2] = i1; g_bsel[b * 2 + 1] = i2;
        g_bw[b * 2] = w1;  g_bw[b * 2 + 1] = w2;
    }
}

__global__ void zero_counts_kernel() {
    if (threadIdx.x < Ee) g_counts[threadIdx.x] = 0;
}

__global__ void assign_kernel(int seq_mode) {
    int t = blockIdx.x * 256 + threadIdx.x;
    if (t >= TOK) return;
    int e1, e2; float w1, w2;
    if (seq_mode) {
        int b = t / Sq;
        e1 = g_bsel[b * 2]; e2 = g_bsel[b * 2 + 1];
        w1 = g_bw[b * 2];   w2 = g_bw[b * 2 + 1];
    } else {
        e1 = g_te[t * 2]; e2 = g_te[t * 2 + 1];
        w1 = g_tw[t * 2]; w2 = g_tw[t * 2 + 1];
    }
    int s1 = atomicAdd(&g_counts[e1], 1);
    g_tok[e1 * TOK + s1] = t; g_wt[e1 * TOK + s1] = w1;
    int s2 = atomicAdd(&g_counts[e2], 1);
    g_tok[e2 * TOK + s2] = t; g_wt[e2 * TOK + s2] = w2;
}

// ---------------- host side --------------------------------------------------
#define SMEM_G1 ((256 + 2*4*TILE_F) * 4)   // 70656

extern "C" void kernel_launch(void* const* d_in, const int* in_sizes, int n_in,
                              void* d_out, int out_size) {
    const float* x      = (const float*)d_in[0];
    const float* ln1_w  = (const float*)d_in[1];
    const float* ln1_b  = (const float*)d_in[2];
    const float* ln2_w  = (const float*)d_in[3];
    const float* ln2_b  = (const float*)d_in[4];
    const float* wq     = (const float*)d_in[5];
    const float* wk     = (const float*)d_in[6];
    const float* wv     = (const float*)d_in[7];
    const float* wo     = (const float*)d_in[8];
    const float* bq     = (const float*)d_in[9];
    const float* bk     = (const float*)d_in[10];
    const float* bv     = (const float*)d_in[11];
    const float* bo     = (const float*)d_in[12];
    const float* gate_w = (const float*)d_in[13];
    const float* gate_b = (const float*)d_in[14];
    const float* e_w1   = (const float*)d_in[15];
    const float* e_b1   = (const float*)d_in[16];
    const float* e_w2   = (const float*)d_in[17];
    const float* e_b2   = (const float*)d_in[18];

    float *Xp, *Hp, *Qp, *Kp, *Vp, *Yp;
    cudaGetSymbolAddress((void**)&Xp, g_X);
    cudaGetSymbolAddress((void**)&Hp, g_H);
    cudaGetSymbolAddress((void**)&Qp, g_Q);
    cudaGetSymbolAddress((void**)&Kp, g_K);
    cudaGetSymbolAddress((void**)&Vp, g_V);
    cudaGetSymbolAddress((void**)&Yp, g_Y);

    static int attr_set = 0;
    if (!attr_set) {
        cudaFuncSetAttribute(gemm_tc<0>, cudaFuncAttributeMaxDynamicSharedMemorySize, SMEM_G1);
        cudaFuncSetAttribute(gemm_tc<1>, cudaFuncAttributeMaxDynamicSharedMemorySize, SMEM_G1);
        cudaFuncSetAttribute(gemm_big<0>, cudaFuncAttributeMaxDynamicSharedMemorySize, SMEM_BIG);
        cudaFuncSetAttribute(gemm_big<1>, cudaFuncAttributeMaxDynamicSharedMemorySize, SMEM_BIG);
        cudaFuncSetAttribute(gemm_big<2>, cudaFuncAttributeMaxDynamicSharedMemorySize, SMEM_BIG);
        cudaFuncSetAttribute(gemm_big<3>, cudaFuncAttributeMaxDynamicSharedMemorySize, SMEM_BIG);
        cudaFuncSetAttribute(flash_tc<0>, cudaFuncAttributeMaxDynamicSharedMemorySize, FL_SMEM0);
        cudaFuncSetAttribute(flash_tc<1>, cudaFuncAttributeMaxDynamicSharedMemorySize, FL_SMEM1);
        attr_set = 1;
    }

    const size_t DD = (size_t)Dq * Dq;
    const int nelem = TOK * Dq;

    copy_in_kernel<<<nelem / 256, 256>>>(x);

    dim3 gsplit(Dq / BNt, TOK / BMt);          // 8 x 32
    dim3 gbig(Dq / BNb, TOK / BMb);            // 4 x 32
    for (int l = 0; l < Ll; l++) {
        // --- attention block ---
        ln_kernel<<<TOK, 256>>>(ln1_w + (size_t)l * Dq, ln1_b + (size_t)l * Dq);
        if (l == 0) {
            gemm_tc<0><<<gsplit, 256, SMEM_G1>>>(Hp, wq + l * DD, bq + (size_t)l * Dq, Qp, Dq, Dq, l);
            gemm_tc<0><<<gsplit, 256, SMEM_G1>>>(Hp, wk + l * DD, bk + (size_t)l * Dq, Kp, Dq, Dq, l);
            gemm_tc<0><<<gsplit, 256, SMEM_G1>>>(Hp, wv + l * DD, bv + (size_t)l * Dq, Vp, Dq, Dq, l);
            flash_tc<1><<<dim3(Sq / 128, Hh, Bq), 256, FL_SMEM1>>>();
            gemm_tc<1><<<gsplit, 256, SMEM_G1>>>(Yp, wo + l * DD, bo + (size_t)l * Dq, Xp, Dq, Dq, l);
        } else {
            gemm_big<0><<<gbig, 256, SMEM_BIG>>>(Hp, wq + l * DD, bq + (size_t)l * Dq, Qp, Dq, Dq, l);
            gemm_big<0><<<gbig, 256, SMEM_BIG>>>(Hp, wk + l * DD, bk + (size_t)l * Dq, Kp, Dq, Dq, l);
            gemm_big<0><<<gbig, 256, SMEM_BIG>>>(Hp, wv + l * DD, bv + (size_t)l * Dq, Vp, Dq, Dq, l);
            flash_tc<0><<<dim3(Sq / 128, Hh, Bq), 256, FL_SMEM0>>>();
            gemm_big<1><<<gbig, 256, SMEM_BIG>>>(Yp, wo + l * DD, bo + (size_t)l * Dq, Xp, Dq, Dq, l);
        }

        // --- MoE block ---
        ln_kernel<<<TOK, 256>>>(ln2_w + (size_t)l * Dq, ln2_b + (size_t)l * Dq);
        if (l % 2 == 0) {
            gate_token_kernel<<<TOK / 4, 128>>>(gate_w, gate_b, l);
        } else {
            xmean_kernel<<<dim3(Dq / 256, Bq), 256>>>();
            gate_seq_kernel<<<Bq, 256>>>(gate_w, gate_b, l);
        }
        zero_counts_kernel<<<1, 32>>>();
        assign_kernel<<<TOK / 256, 256>>>(l % 2);
        gemm_big<2><<<dim3(DFFq / BNb, TOK / BMb, Ee), 256, SMEM_BIG>>>(nullptr, e_w1, e_b1, nullptr, Dq, DFFq, l);
        gemm_big<3><<<dim3(Dq / BNb, TOK / BMb, Ee), 256, SMEM_BIG>>>(nullptr, e_w2, e_b2, nullptr, DFFq, Dq, l);
    }

    copy_out_kernel<<<nelem / 256, 256>>>((float*)d_out);
    (void)in_sizes; (void)n_in; (void)out_size;
}

// round 6
// speedup vs baseline: 6.1690x; 1.0281x over previous
#include <cuda_runtime.h>
#include <math.h>
#include <stdint.h>

#define Bq   4
#define Sq   1024
#define Dq   1024
#define Hh   16
#define HD   64
#define Ll   2
#define Ee   8
#define DFFq 4096
#define TOK  (Bq*Sq)   // 4096

// ---------------- static scratch ---------------------------------------------
__device__ float g_X[TOK*Dq];
__device__ float g_H[TOK*Dq];
__device__ float g_Q[TOK*Dq];
__device__ float g_K[TOK*Dq];
__device__ float g_V[TOK*Dq];
__device__ float g_Y[TOK*Dq];
__device__ float g_hidden[(size_t)Ee*TOK*DFFq];
__device__ int   g_counts[Ee];
__device__ int   g_tok[Ee*TOK];
__device__ float g_wt[Ee*TOK];
__device__ int   g_te[TOK*2];
__device__ float g_tw[TOK*2];
__device__ int   g_bsel[Bq*2];
__device__ float g_bw[Bq*2];
__device__ float g_xmean[Bq*Dq];

// ---------------- helpers ----------------------------------------------------
__device__ __forceinline__ void top2_of8(const float* lg, int& i1, int& i2,
                                         float& w1, float& w2) {
    i1 = 0; float v1 = lg[0];
#pragma unroll
    for (int e = 1; e < Ee; e++) if (lg[e] > v1) { v1 = lg[e]; i1 = e; }
    i2 = -1; float v2 = -3.0e38f;
#pragma unroll
    for (int e = 0; e < Ee; e++) if (e != i1 && lg[e] > v2) { v2 = lg[e]; i2 = e; }
    float ex = expf(v2 - v1);
    w1 = 1.0f / (1.0f + ex);
    w2 = ex / (1.0f + ex);
}
__device__ __forceinline__ float gelu_exact(float x) {
    return 0.5f * x * (1.0f + erff(x * 0.7071067811865476f));
}
__device__ __forceinline__ float tf32r(float x) {
    uint32_t u; asm("cvt.rna.tf32.f32 %0, %1;" : "=r"(u) : "f"(x));
    return __uint_as_float(u);
}
__device__ __forceinline__ void mma_tf32(float c[4], const uint32_t a[4],
                                         const uint32_t b[2]) {
    asm volatile(
        "mma.sync.aligned.m16n8k8.row.col.f32.tf32.tf32.f32 "
        "{%0,%1,%2,%3},{%4,%5,%6,%7},{%8,%9},{%0,%1,%2,%3};"
        : "+f"(c[0]), "+f"(c[1]), "+f"(c[2]), "+f"(c[3])
        : "r"(a[0]), "r"(a[1]), "r"(a[2]), "r"(a[3]), "r"(b[0]), "r"(b[1]));
}

// ---------------- simple kernels ---------------------------------------------
__global__ void copy_in_kernel(const float* __restrict__ src) {
    int i = blockIdx.x * 256 + threadIdx.x;
    g_X[i] = src[i];
}
__global__ void copy_out_kernel(float* __restrict__ dst) {
    int i = blockIdx.x * 256 + threadIdx.x;
    dst[i] = g_X[i];
}

__global__ void ln_kernel(const float* __restrict__ w, const float* __restrict__ b) {
    int t = blockIdx.x, tid = threadIdx.x;
    const float* xr = g_X + (size_t)t * Dq;
    float s = 0.f, s2 = 0.f;
    for (int d = tid; d < Dq; d += 256) { float v = xr[d]; s += v; s2 += v * v; }
    __shared__ float r1[256], r2[256];
    r1[tid] = s; r2[tid] = s2; __syncthreads();
    for (int off = 128; off; off >>= 1) {
        if (tid < off) { r1[tid] += r1[tid + off]; r2[tid] += r2[tid + off]; }
        __syncthreads();
    }
    float mean = r1[0] * (1.0f / Dq);
    float var  = r2[0] * (1.0f / Dq) - mean * mean;
    float rstd = rsqrtf(var + 1e-5f);
    float* hr = g_H + (size_t)t * Dq;
    for (int d = tid; d < Dq; d += 256)
        hr[d] = (xr[d] - mean) * rstd * w[d] + b[d];
}

// ---------------- split TF32 GEMM (layer-0 path, 128x128, 512 thr) -----------
#define BMt 128
#define BNt 128
#define BKt 16
#define TWg 136
#define TILE_F (BKt*TWg)
#define SMEM_G1 ((256 + 2*4*TILE_F) * 4)   // 70656

template<int MODE>
__global__ void __launch_bounds__(512, 1)
gemm_split(const float* __restrict__ A, const float* __restrict__ Wall,
           const float* __restrict__ ball, float* __restrict__ Cp,
           int Kd, int N, int layer) {
    extern __shared__ float smf[];
    float* tiles = smf + 256;

    int tid = threadIdx.x;
    int rowBase = blockIdx.y * BMt, colBase = blockIdx.x * BNt;
    const float* bias = ball;

    // A: 128 rows x 16k, 4 floats/thread.  B: 16k x 128, float4/thread.
    int lrA = tid >> 2, kcA = (tid & 3) << 2;
    const float* Ap = A + (size_t)(rowBase + lrA) * Kd + kcA;
    int krB = tid >> 5, ncB = (tid & 31) << 2;
    const float* Wp = Wall + (size_t)krB * N + colBase + ncB;

    int lane = tid & 31, warp = tid >> 5;
    int wm = (warp & 3) * 32, wn = (warp >> 2) * 32;
    int gid = lane >> 2, tig = lane & 3;

    float acc[2][4][4];
#pragma unroll
    for (int a = 0; a < 2; a++)
#pragma unroll
        for (int b2 = 0; b2 < 4; b2++)
#pragma unroll
            for (int c = 0; c < 4; c++) acc[a][b2][c] = 0.f;

    int nk = Kd / BKt;
    float4 av, bv;
    av = *(const float4*)(Ap);
    bv = *(const float4*)(Wp);
    {
        float* Ah = tiles;
        float* Bh = tiles + 2 * TILE_F;
        float va[4] = {av.x, av.y, av.z, av.w};
#pragma unroll
        for (int g = 0; g < 4; g++) {
            float v = va[g], hi = tf32r(v);
            Ah[(kcA + g) * TWg + lrA] = hi;
            Ah[TILE_F + (kcA + g) * TWg + lrA] = v - hi;
        }
        float vb[4] = {bv.x, bv.y, bv.z, bv.w};
#pragma unroll
        for (int g = 0; g < 4; g++) {
            float v = vb[g], hi = tf32r(v);
            Bh[krB * TWg + ncB + g] = hi;
            Bh[TILE_F + krB * TWg + ncB + g] = v - hi;
        }
    }
    __syncthreads();

    for (int t = 0; t < nk; t++) {
        if (t + 1 < nk) {
            av = *(const float4*)(Ap + (size_t)(t + 1) * BKt);
            bv = *(const float4*)(Wp + (size_t)(t + 1) * BKt * N);
        }
        int s = t & 1;
        float* Ah = tiles + s * 4 * TILE_F;
        float* Al = Ah + TILE_F;
        float* Bh = Ah + 2 * TILE_F;
        float* Bl = Ah + 3 * TILE_F;

#pragma unroll
        for (int kk = 0; kk < BKt; kk += 8) {
            uint32_t afh[2][4], afl[2][4], bfh[4][2], bfl[4][2];
#pragma unroll
            for (int mt = 0; mt < 2; mt++) {
                int m0 = wm + mt * 16 + gid;
                afh[mt][0] = __float_as_uint(Ah[(kk + tig) * TWg + m0]);
                afh[mt][1] = __float_as_uint(Ah[(kk + tig) * TWg + m0 + 8]);
                afh[mt][2] = __float_as_uint(Ah[(kk + tig + 4) * TWg + m0]);
                afh[mt][3] = __float_as_uint(Ah[(kk + tig + 4) * TWg + m0 + 8]);
                afl[mt][0] = __float_as_uint(Al[(kk + tig) * TWg + m0]);
                afl[mt][1] = __float_as_uint(Al[(kk + tig) * TWg + m0 + 8]);
                afl[mt][2] = __float_as_uint(Al[(kk + tig + 4) * TWg + m0]);
                afl[mt][3] = __float_as_uint(Al[(kk + tig + 4) * TWg + m0 + 8]);
            }
#pragma unroll
            for (int nt = 0; nt < 4; nt++) {
                int n0 = wn + nt * 8 + gid;
                bfh[nt][0] = __float_as_uint(Bh[(kk + tig) * TWg + n0]);
                bfh[nt][1] = __float_as_uint(Bh[(kk + tig + 4) * TWg + n0]);
                bfl[nt][0] = __float_as_uint(Bl[(kk + tig) * TWg + n0]);
                bfl[nt][1] = __float_as_uint(Bl[(kk + tig + 4) * TWg + n0]);
            }
#pragma unroll
            for (int mt = 0; mt < 2; mt++)
#pragma unroll
                for (int nt = 0; nt < 4; nt++) {
                    mma_tf32(acc[mt][nt], afh[mt], bfh[nt]);
                    mma_tf32(acc[mt][nt], afh[mt], bfl[nt]);
                    mma_tf32(acc[mt][nt], afl[mt], bfh[nt]);
                }
        }

        if (t + 1 < nk) {
            int s2 = s ^ 1;
            float* Ah2 = tiles + s2 * 4 * TILE_F;
            float* Bh2 = Ah2 + 2 * TILE_F;
            float va[4] = {av.x, av.y, av.z, av.w};
#pragma unroll
            for (int g = 0; g < 4; g++) {
                float v = va[g], hi = tf32r(v);
                Ah2[(kcA + g) * TWg + lrA] = hi;
                Ah2[TILE_F + (kcA + g) * TWg + lrA] = v - hi;
            }
            float vb[4] = {bv.x, bv.y, bv.z, bv.w};
#pragma unroll
            for (int g = 0; g < 4; g++) {
                float v = vb[g], hi = tf32r(v);
                Bh2[krB * TWg + ncB + g] = hi;
                Bh2[TILE_F + krB * TWg + ncB + g] = v - hi;
            }
        }
        __syncthreads();
    }

#pragma unroll
    for (int mt = 0; mt < 2; mt++) {
#pragma unroll
        for (int c = 0; c < 4; c++) {
            int r = rowBase + wm + mt * 16 + gid + ((c & 2) ? 8 : 0);
#pragma unroll
            for (int nt = 0; nt < 4; nt++) {
                int cg = colBase + wn + nt * 8 + tig * 2 + (c & 1);
                float v = acc[mt][nt][c] + bias[cg];
                if (MODE == 1) v += Cp[(size_t)r * N + cg];
                Cp[(size_t)r * N + cg] = v;
            }
        }
    }
}

// ---------------- big-tile single-pass TF32 GEMM (128x256, 512 thr) ----------
// MODE 0: C = A@W + bias    MODE 1: C += Res   MODE 2: MoE GEMM1 (GELU)
// MODE 3: MoE GEMM2 (atomic scatter)
#define BMb 128
#define BNb 256
#define BKb 16
#define AWb 136
#define BWb 264
#define ATb (BKb*AWb)   // 2176
#define BTb (BKb*BWb)   // 4224
#define SMEM_BIG ((256 + 2*(ATb+BTb)) * 4)   // 52224

template<int MODE>
__global__ void __launch_bounds__(512, 1)
gemm_big(const float* __restrict__ A, const float* __restrict__ Wall,
         const float* __restrict__ ball, float* __restrict__ Cp,
         int Kd, int N, int layer) {
    extern __shared__ float smf[];
    int*   s_tok = (int*)smf;
    float* s_wt  = smf + 128;
    float* tiles = smf + 256;

    int tid = threadIdx.x;
    int rowBase = blockIdx.y * BMb, colBase = blockIdx.x * BNb;

    int e = 0, cnt = 0;
    const float* W = Wall;
    const float* bias = ball;
    if (MODE >= 2) {
        e = blockIdx.z;
        cnt = g_counts[e];
        if (rowBase >= cnt) return;
        W    = Wall + (size_t)(layer * Ee + e) * Kd * N;
        bias = ball + (size_t)(layer * Ee + e) * N;
        if (tid < 128) {
            int r = rowBase + tid;
            int rc = r < cnt ? r : cnt - 1;
            s_tok[tid] = g_tok[e * TOK + rc];
            s_wt[tid]  = g_wt [e * TOK + rc];
        }
        __syncthreads();
    }

    // A: 128 x 16, 4 floats/thread.  B: 16 x 256, 2x float4/thread (rows krB, krB+8).
    int lrA = tid >> 2, kcA = (tid & 3) << 2;
    const float* Ap;
    if (MODE == 2)      Ap = g_H + (size_t)s_tok[lrA] * Kd + kcA;
    else if (MODE == 3) Ap = g_hidden + ((size_t)e * TOK + rowBase + lrA) * Kd + kcA;
    else                Ap = A + (size_t)(rowBase + lrA) * Kd + kcA;

    int krB = tid >> 6, ncB = (tid & 63) << 2;
    const float* Wp = W + (size_t)krB * N + colBase + ncB;

    int lane = tid & 31, warp = tid >> 5;
    int wm = (warp & 1) * 64, wn = (warp >> 1) * 32;
    int gid = lane >> 2, tig = lane & 3;

    float acc[4][4][4];
#pragma unroll
    for (int a = 0; a < 4; a++)
#pragma unroll
        for (int b2 = 0; b2 < 4; b2++)
#pragma unroll
            for (int c = 0; c < 4; c++) acc[a][b2][c] = 0.f;

    int nk = Kd / BKb;
    float4 av, bv0, bv1;
    av  = *(const float4*)(Ap);
    bv0 = *(const float4*)(Wp);
    bv1 = *(const float4*)(Wp + (size_t)8 * N);
    {
        float* As = tiles;
        float* Bs = tiles + ATb;
        float va[4] = {av.x, av.y, av.z, av.w};
#pragma unroll
        for (int g = 0; g < 4; g++)
            As[(kcA + g) * AWb + lrA] = tf32r(va[g]);
        *(float4*)&Bs[krB * BWb + ncB] =
            make_float4(tf32r(bv0.x), tf32r(bv0.y), tf32r(bv0.z), tf32r(bv0.w));
        *(float4*)&Bs[(krB + 8) * BWb + ncB] =
            make_float4(tf32r(bv1.x), tf32r(bv1.y), tf32r(bv1.z), tf32r(bv1.w));
    }
    __syncthreads();

    for (int t = 0; t < nk; t++) {
        if (t + 1 < nk) {
            av  = *(const float4*)(Ap + (size_t)(t + 1) * BKb);
            const float* w2 = Wp + (size_t)(t + 1) * BKb * N;
            bv0 = *(const float4*)(w2);
            bv1 = *(const float4*)(w2 + (size_t)8 * N);
        }
        int s = t & 1;
        float* As = tiles + s * (ATb + BTb);
        float* Bs = As + ATb;

#pragma unroll
        for (int kk = 0; kk < BKb; kk += 8) {
            uint32_t af[4][4], bf[4][2];
#pragma unroll
            for (int mt = 0; mt < 4; mt++) {
                int m0 = wm + mt * 16 + gid;
                af[mt][0] = __float_as_uint(As[(kk + tig) * AWb + m0]);
                af[mt][1] = __float_as_uint(As[(kk + tig) * AWb + m0 + 8]);
                af[mt][2] = __float_as_uint(As[(kk + tig + 4) * AWb + m0]);
                af[mt][3] = __float_as_uint(As[(kk + tig + 4) * AWb + m0 + 8]);
            }
#pragma unroll
            for (int nt = 0; nt < 4; nt++) {
                int n0 = wn + nt * 8 + gid;
                bf[nt][0] = __float_as_uint(Bs[(kk + tig) * BWb + n0]);
                bf[nt][1] = __float_as_uint(Bs[(kk + tig + 4) * BWb + n0]);
            }
#pragma unroll
            for (int mt = 0; mt < 4; mt++)
#pragma unroll
                for (int nt = 0; nt < 4; nt++)
                    mma_tf32(acc[mt][nt], af[mt], bf[nt]);
        }

        if (t + 1 < nk) {
            int s2 = s ^ 1;
            float* As2 = tiles + s2 * (ATb + BTb);
            float* Bs2 = As2 + ATb;
            float va[4] = {av.x, av.y, av.z, av.w};
#pragma unroll
            for (int g = 0; g < 4; g++)
                As2[(kcA + g) * AWb + lrA] = tf32r(va[g]);
            *(float4*)&Bs2[krB * BWb + ncB] =
                make_float4(tf32r(bv0.x), tf32r(bv0.y), tf32r(bv0.z), tf32r(bv0.w));
            *(float4*)&Bs2[(krB + 8) * BWb + ncB] =
                make_float4(tf32r(bv1.x), tf32r(bv1.y), tf32r(bv1.z), tf32r(bv1.w));
        }
        __syncthreads();
    }

#pragma unroll
    for (int mt = 0; mt < 4; mt++) {
#pragma unroll
        for (int c = 0; c < 4; c++) {
            int rl = wm + mt * 16 + gid + ((c & 2) ? 8 : 0);
            int r  = rowBase + rl;
#pragma unroll
            for (int nt = 0; nt < 4; nt++) {
                int cg = colBase + wn + nt * 8 + tig * 2 + (c & 1);
                float v = acc[mt][nt][c] + bias[cg];
                if (MODE == 0) {
                    Cp[(size_t)r * N + cg] = v;
                } else if (MODE == 1) {
                    Cp[(size_t)r * N + cg] = v + Cp[(size_t)r * N + cg];
                } else if (MODE == 2) {
                    if (r < cnt)
                        g_hidden[((size_t)e * TOK + r) * N + cg] = gelu_exact(v);
                } else {
                    if (r < cnt)
                        atomicAdd(&g_X[(size_t)s_tok[rl] * N + cg], v * s_wt[rl]);
                }
            }
        }
    }
}

// ---------------- tensor-core flash attention --------------------------------
// 128-q block, 8 warps x m16; QK^T and P@V via mma.m16n8k8.tf32.
// SPLIT=1 (layer 0): 3-pass Dekker split everywhere (~fp32 precision).
#define FQSZ (64*136)
#define FKSZ (64*72)
#define FPSZ (64*136)
#define FL_SMEM0 ((FQSZ + 2*FKSZ + FPSZ) * 4)        // 106496
#define FL_SMEM1 ((FQSZ + 2*FKSZ + FPSZ) * 8)        // 212992

__device__ __forceinline__ int fsw(int d) { return ((d >> 2) & 7) << 3; }

template<int SPLIT>
__global__ void __launch_bounds__(256)
flash_tc() {
    extern __shared__ float fs[];
    float* Qh = fs;
    float* Ql = Qh + FQSZ;
    float* Kh = Qh + FQSZ * (SPLIT + 1);
    float* Kl = Kh + FKSZ;
    float* Vh = Kh + FKSZ * (SPLIT + 1);
    float* Vl = Vh + FKSZ;
    float* Ph = Vh + FKSZ * (SPLIT + 1);
    float* Pl = Ph + FPSZ;

    int qb = blockIdx.x, h = blockIdx.y, b = blockIdx.z;
    int tid = threadIdx.x, warp = tid >> 5, lane = tid & 31;
    int gid = lane >> 2, tig = lane & 3;
    int mrow = warp * 16 + gid;

    for (int i = tid; i < 2048; i += 256) {
        int r = i >> 4, d4 = (i & 15) << 2;
        float4 v = *(const float4*)&g_Q[((size_t)(b * Sq + qb * 128 + r)) * Dq + h * HD + d4];
        float va[4] = {v.x, v.y, v.z, v.w};
#pragma unroll
        for (int j = 0; j < 4; j++) {
            int d = d4 + j;
            int cs = r ^ fsw(d);
            float hi = tf32r(va[j]);
            Qh[d * 136 + cs] = hi;
            if (SPLIT) Ql[d * 136 + cs] = tf32r(va[j] - hi);
        }
    }

    float mA = -1e30f, mB = -1e30f, lA = 0.f, lB = 0.f;
    float o[8][4];
#pragma unroll
    for (int nt = 0; nt < 8; nt++)
#pragma unroll
        for (int c = 0; c < 4; c++) o[nt][c] = 0.f;

    int nkt = 2 * qb + 2;
    for (int kt = 0; kt < nkt; kt++) {
        __syncthreads();
        for (int i = tid; i < 1024; i += 256) {
            int r = i >> 4, d4 = (i & 15) << 2;
            size_t base = ((size_t)(b * Sq + kt * 64 + r)) * Dq + h * HD + d4;
            float4 kv = *(const float4*)&g_K[base];
            float ka[4] = {kv.x, kv.y, kv.z, kv.w};
#pragma unroll
            for (int j = 0; j < 4; j++) {
                int d = d4 + j;
                int cs = r ^ fsw(d);
                float hi = tf32r(ka[j]);
                Kh[d * 72 + cs] = hi;
                if (SPLIT) Kl[d * 72 + cs] = tf32r(ka[j] - hi);
            }
            float4 vv = *(const float4*)&g_V[base];
            float4 vh = make_float4(tf32r(vv.x), tf32r(vv.y), tf32r(vv.z), tf32r(vv.w));
            *(float4*)&Vh[r * 72 + d4] = vh;
            if (SPLIT)
                *(float4*)&Vl[r * 72 + d4] =
                    make_float4(tf32r(vv.x - vh.x), tf32r(vv.y - vh.y),
                                tf32r(vv.z - vh.z), tf32r(vv.w - vh.w));
        }
        __syncthreads();

        float s[8][4];
#pragma unroll
        for (int nt = 0; nt < 8; nt++)
#pragma unroll
            for (int c = 0; c < 4; c++) s[nt][c] = 0.f;

#pragma unroll
        for (int ks = 0; ks < 8; ks++) {
            int kb = ks * 8;
            int s0 = fsw(kb + tig), s1 = fsw(kb + tig + 4);
            uint32_t a[4], al[4];
            a[0] = __float_as_uint(Qh[(kb + tig) * 136 + (mrow ^ s0)]);
            a[1] = __float_as_uint(Qh[(kb + tig) * 136 + ((mrow + 8) ^ s0)]);
            a[2] = __float_as_uint(Qh[(kb + tig + 4) * 136 + (mrow ^ s1)]);
            a[3] = __float_as_uint(Qh[(kb + tig + 4) * 136 + ((mrow + 8) ^ s1)]);
            if (SPLIT) {
                al[0] = __float_as_uint(Ql[(kb + tig) * 136 + (mrow ^ s0)]);
                al[1] = __float_as_uint(Ql[(kb + tig) * 136 + ((mrow + 8) ^ s0)]);
                al[2] = __float_as_uint(Ql[(kb + tig + 4) * 136 + (mrow ^ s1)]);
                al[3] = __float_as_uint(Ql[(kb + tig + 4) * 136 + ((mrow + 8) ^ s1)]);
            }
#pragma unroll
            for (int nt = 0; nt < 8; nt++) {
                int n0 = nt * 8 + gid;
                uint32_t bb[2], bl[2];
                bb[0] = __float_as_uint(Kh[(kb + tig) * 72 + (n0 ^ s0)]);
                bb[1] = __float_as_uint(Kh[(kb + tig + 4) * 72 + (n0 ^ s1)]);
                mma_tf32(s[nt], a, bb);
                if (SPLIT) {
                    bl[0] = __float_as_uint(Kl[(kb + tig) * 72 + (n0 ^ s0)]);
                    bl[1] = __float_as_uint(Kl[(kb + tig + 4) * 72 + (n0 ^ s1)]);
                    mma_tf32(s[nt], a, bl);
                    mma_tf32(s[nt], al, bb);
                }
            }
        }

        int rowg = qb * 128 + warp * 16 + gid;
        if (kt * 64 + 63 > rowg) {
#pragma unroll
            for (int nt = 0; nt < 8; nt++)
#pragma unroll
                for (int c = 0; c < 4; c++) {
                    int col = kt * 64 + nt * 8 + 2 * tig + (c & 1);
                    int row = rowg + ((c & 2) ? 8 : 0);
                    float sv = s[nt][c] * 0.125f;
                    s[nt][c] = (col > row) ? -1e30f : sv;
                }
        } else {
#pragma unroll
            for (int nt = 0; nt < 8; nt++)
#pragma unroll
                for (int c = 0; c < 4; c++) s[nt][c] *= 0.125f;
        }

        float rmA = -1e30f, rmB = -1e30f;
#pragma unroll
        for (int nt = 0; nt < 8; nt++) {
            rmA = fmaxf(rmA, fmaxf(s[nt][0], s[nt][1]));
            rmB = fmaxf(rmB, fmaxf(s[nt][2], s[nt][3]));
        }
#pragma unroll
        for (int off = 1; off < 4; off <<= 1) {
            rmA = fmaxf(rmA, __shfl_xor_sync(0xffffffffu, rmA, off));
            rmB = fmaxf(rmB, __shfl_xor_sync(0xffffffffu, rmB, off));
        }
        float mnA = fmaxf(mA, rmA), mnB = fmaxf(mB, rmB);
        float alA = __expf(mA - mnA), alB = __expf(mB - mnB);
        float rsA = 0.f, rsB = 0.f;
#pragma unroll
        for (int nt = 0; nt < 8; nt++) {
            s[nt][0] = __expf(s[nt][0] - mnA); rsA += s[nt][0];
            s[nt][1] = __expf(s[nt][1] - mnA); rsA += s[nt][1];
            s[nt][2] = __expf(s[nt][2] - mnB); rsB += s[nt][2];
            s[nt][3] = __expf(s[nt][3] - mnB); rsB += s[nt][3];
        }
#pragma unroll
        for (int off = 1; off < 4; off <<= 1) {
            rsA += __shfl_xor_sync(0xffffffffu, rsA, off);
            rsB += __shfl_xor_sync(0xffffffffu, rsB, off);
        }
        lA = lA * alA + rsA; mA = mnA;
        lB = lB * alB + rsB; mB = mnB;
#pragma unroll
        for (int nt = 0; nt < 8; nt++) {
            o[nt][0] *= alA; o[nt][1] *= alA;
            o[nt][2] *= alB; o[nt][3] *= alB;
        }

        __syncwarp();
#pragma unroll
        for (int nt = 0; nt < 8; nt++)
#pragma unroll
            for (int c = 0; c < 4; c++) {
                int cl = nt * 8 + 2 * tig + (c & 1);
                int mr = warp * 16 + gid + ((c & 2) ? 8 : 0);
                float p = s[nt][c], ph = tf32r(p);
                Ph[cl * 136 + mr] = ph;
                if (SPLIT) Pl[cl * 136 + mr] = tf32r(p - ph);
            }
        __syncwarp();

#pragma unroll
        for (int ks = 0; ks < 8; ks++) {
            int kb = ks * 8;
            uint32_t a[4], al[4];
            a[0] = __float_as_uint(Ph[(kb + tig) * 136 + mrow]);
            a[1] = __float_as_uint(Ph[(kb + tig) * 136 + mrow + 8]);
            a[2] = __float_as_uint(Ph[(kb + tig + 4) * 136 + mrow]);
            a[3] = __float_as_uint(Ph[(kb + tig + 4) * 136 + mrow + 8]);
            if (SPLIT) {
                al[0] = __float_as_uint(Pl[(kb + tig) * 136 + mrow]);
                al[1] = __float_as_uint(Pl[(kb + tig) * 136 + mrow + 8]);
                al[2] = __float_as_uint(Pl[(kb + tig + 4) * 136 + mrow]);
                al[3] = __float_as_uint(Pl[(kb + tig + 4) * 136 + mrow + 8]);
            }
#pragma unroll
            for (int nt = 0; nt < 8; nt++) {
                int n0 = nt * 8 + gid;
                uint32_t bb[2], bl[2];
                bb[0] = __float_as_uint(Vh[(kb + tig) * 72 + n0]);
                bb[1] = __float_as_uint(Vh[(kb + tig + 4) * 72 + n0]);
                mma_tf32(o[nt], a, bb);
                if (SPLIT) {
                    bl[0] = __float_as_uint(Vl[(kb + tig) * 72 + n0]);
                    bl[1] = __float_as_uint(Vl[(kb + tig + 4) * 72 + n0]);
                    mma_tf32(o[nt], a, bl);
                    mma_tf32(o[nt], al, bb);
                }
            }
        }
    }

    float invA = 1.0f / lA, invB = 1.0f / lB;
    size_t rbase0 = ((size_t)(b * Sq + qb * 128 + warp * 16 + gid)) * Dq + h * HD;
    size_t rbase1 = rbase0 + (size_t)8 * Dq;
#pragma unroll
    for (int nt = 0; nt < 8; nt++) {
        int d0 = nt * 8 + 2 * tig;
        *(float2*)&g_Y[rbase0 + d0] = make_float2(o[nt][0] * invA, o[nt][1] * invA);
        *(float2*)&g_Y[rbase1 + d0] = make_float2(o[nt][2] * invB, o[nt][3] * invB);
    }
}

// ---------------- gating -----------------------------------------------------
__global__ void gate_token_kernel(const float* __restrict__ gw,
                                  const float* __restrict__ gb, int layer) {
    int t = blockIdx.x * 4 + (threadIdx.x >> 5);
    int lane = threadIdx.x & 31;
    if (t >= TOK) return;
    const float* hrow = g_H + (size_t)t * Dq;
    const float* gwl = gw + (size_t)layer * Dq * Ee;
    float acc[Ee] = {};
    for (int d = lane; d < Dq; d += 32) {
        float hv = hrow[d];
        const float* g = gwl + (size_t)d * Ee;
#pragma unroll
        for (int e = 0; e < Ee; e++) acc[e] += hv * g[e];
    }
#pragma unroll
    for (int e = 0; e < Ee; e++)
        for (int off = 16; off; off >>= 1)
            acc[e] += __shfl_xor_sync(0xffffffffu, acc[e], off);
    if (lane == 0) {
        float lg[Ee];
#pragma unroll
        for (int e = 0; e < Ee; e++) lg[e] = acc[e] + gb[layer * Ee + e];
        int i1, i2; float w1, w2;
        top2_of8(lg, i1, i2, w1, w2);
        g_te[t * 2] = i1; g_te[t * 2 + 1] = i2;
        g_tw[t * 2] = w1; g_tw[t * 2 + 1] = w2;
    }
}

__global__ void xmean_kernel() {
    int b = blockIdx.y;
    int d = blockIdx.x * 256 + threadIdx.x;
    float s = 0.f;
    for (int ss = 0; ss < Sq; ss++)
        s += g_H[((size_t)(b * Sq + ss)) * Dq + d];
    g_xmean[b * Dq + d] = s * (1.0f / Sq);
}

__global__ void gate_seq_kernel(const float* __restrict__ gw,
                                const float* __restrict__ gb, int layer) {
    int b = blockIdx.x;
    int tid = threadIdx.x, e = tid >> 5, lane = tid & 31;
    const float* gwl = gw + (size_t)layer * Dq * Ee;
    float acc = 0.f;
    for (int d = lane; d < Dq; d += 32)
        acc += g_xmean[b * Dq + d] * gwl[(size_t)d * Ee + e];
    for (int off = 16; off; off >>= 1)
        acc += __shfl_xor_sync(0xffffffffu, acc, off);
    __shared__ float lg[Ee];
    if (lane == 0) lg[e] = acc + gb[layer * Ee + e];
    __syncthreads();
    if (tid == 0) {
        int i1, i2; float w1, w2;
        top2_of8(lg, i1, i2, w1, w2);
        g_bsel[b * 2] = i1; g_bsel[b * 2 + 1] = i2;
        g_bw[b * 2] = w1;  g_bw[b * 2 + 1] = w2;
    }
}

__global__ void zero_counts_kernel() {
    if (threadIdx.x < Ee) g_counts[threadIdx.x] = 0;
}

__global__ void assign_kernel(int seq_mode) {
    int t = blockIdx.x * 256 + threadIdx.x;
    if (t >= TOK) return;
    int e1, e2; float w1, w2;
    if (seq_mode) {
        int b = t / Sq;
        e1 = g_bsel[b * 2]; e2 = g_bsel[b * 2 + 1];
        w1 = g_bw[b * 2];   w2 = g_bw[b * 2 + 1];
    } else {
        e1 = g_te[t * 2]; e2 = g_te[t * 2 + 1];
        w1 = g_tw[t * 2]; w2 = g_tw[t * 2 + 1];
    }
    int s1 = atomicAdd(&g_counts[e1], 1);
    g_tok[e1 * TOK + s1] = t; g_wt[e1 * TOK + s1] = w1;
    int s2 = atomicAdd(&g_counts[e2], 1);
    g_tok[e2 * TOK + s2] = t; g_wt[e2 * TOK + s2] = w2;
}

// ---------------- host side --------------------------------------------------
extern "C" void kernel_launch(void* const* d_in, const int* in_sizes, int n_in,
                              void* d_out, int out_size) {
    const float* x      = (const float*)d_in[0];
    const float* ln1_w  = (const float*)d_in[1];
    const float* ln1_b  = (const float*)d_in[2];
    const float* ln2_w  = (const float*)d_in[3];
    const float* ln2_b  = (const float*)d_in[4];
    const float* wq     = (const float*)d_in[5];
    const float* wk     = (const float*)d_in[6];
    const float* wv     = (const float*)d_in[7];
    const float* wo     = (const float*)d_in[8];
    const float* bq     = (const float*)d_in[9];
    const float* bk     = (const float*)d_in[10];
    const float* bv     = (const float*)d_in[11];
    const float* bo     = (const float*)d_in[12];
    const float* gate_w = (const float*)d_in[13];
    const float* gate_b = (const float*)d_in[14];
    const float* e_w1   = (const float*)d_in[15];
    const float* e_b1   = (const float*)d_in[16];
    const float* e_w2   = (const float*)d_in[17];
    const float* e_b2   = (const float*)d_in[18];

    float *Xp, *Hp, *Qp, *Kp, *Vp, *Yp;
    cudaGetSymbolAddress((void**)&Xp, g_X);
    cudaGetSymbolAddress((void**)&Hp, g_H);
    cudaGetSymbolAddress((void**)&Qp, g_Q);
    cudaGetSymbolAddress((void**)&Kp, g_K);
    cudaGetSymbolAddress((void**)&Vp, g_V);
    cudaGetSymbolAddress((void**)&Yp, g_Y);

    static int attr_set = 0;
    if (!attr_set) {
        cudaFuncSetAttribute(gemm_split<0>, cudaFuncAttributeMaxDynamicSharedMemorySize, SMEM_G1);
        cudaFuncSetAttribute(gemm_split<1>, cudaFuncAttributeMaxDynamicSharedMemorySize, SMEM_G1);
        cudaFuncSetAttribute(gemm_big<0>, cudaFuncAttributeMaxDynamicSharedMemorySize, SMEM_BIG);
        cudaFuncSetAttribute(gemm_big<1>, cudaFuncAttributeMaxDynamicSharedMemorySize, SMEM_BIG);
        cudaFuncSetAttribute(gemm_big<2>, cudaFuncAttributeMaxDynamicSharedMemorySize, SMEM_BIG);
        cudaFuncSetAttribute(gemm_big<3>, cudaFuncAttributeMaxDynamicSharedMemorySize, SMEM_BIG);
        cudaFuncSetAttribute(flash_tc<0>, cudaFuncAttributeMaxDynamicSharedMemorySize, FL_SMEM0);
        cudaFuncSetAttribute(flash_tc<1>, cudaFuncAttributeMaxDynamicSharedMemorySize, FL_SMEM1);
        attr_set = 1;
    }

    const size_t DD = (size_t)Dq * Dq;
    const int nelem = TOK * Dq;

    copy_in_kernel<<<nelem / 256, 256>>>(x);

    dim3 gsplit(Dq / BNt, TOK / BMt);          // 8 x 32
    dim3 gbig(Dq / BNb, TOK / BMb);            // 4 x 32
    for (int l = 0; l < Ll; l++) {
        // --- attention block ---
        ln_kernel<<<TOK, 256>>>(ln1_w + (size_t)l * Dq, ln1_b + (size_t)l * Dq);
        if (l == 0) {
            gemm_split<0><<<gsplit, 512, SMEM_G1>>>(Hp, wq + l * DD, bq + (size_t)l * Dq, Qp, Dq, Dq, l);
            gemm_split<0><<<gsplit, 512, SMEM_G1>>>(Hp, wk + l * DD, bk + (size_t)l * Dq, Kp, Dq, Dq, l);
            gemm_split<0><<<gsplit, 512, SMEM_G1>>>(Hp, wv + l * DD, bv + (size_t)l * Dq, Vp, Dq, Dq, l);
            flash_tc<1><<<dim3(Sq / 128, Hh, Bq), 256, FL_SMEM1>>>();
            gemm_split<1><<<gsplit, 512, SMEM_G1>>>(Yp, wo + l * DD, bo + (size_t)l * Dq, Xp, Dq, Dq, l);
        } else {
            gemm_big<0><<<gbig, 512, SMEM_BIG>>>(Hp, wq + l * DD, bq + (size_t)l * Dq, Qp, Dq, Dq, l);
            gemm_big<0><<<gbig, 512, SMEM_BIG>>>(Hp, wk + l * DD, bk + (size_t)l * Dq, Kp, Dq, Dq, l);
            gemm_big<0><<<gbig, 512, SMEM_BIG>>>(Hp, wv + l * DD, bv + (size_t)l * Dq, Vp, Dq, Dq, l);
            flash_tc<0><<<dim3(Sq / 128, Hh, Bq), 256, FL_SMEM0>>>();
            gemm_big<1><<<gbig, 512, SMEM_BIG>>>(Yp, wo + l * DD, bo + (size_t)l * Dq, Xp, Dq, Dq, l);
        }

        // --- MoE block ---
        ln_kernel<<<TOK, 256>>>(ln2_w + (size_t)l * Dq, ln2_b + (size_t)l * Dq);
        if (l % 2 == 0) {
            gate_token_kernel<<<TOK / 4, 128>>>(gate_w, gate_b, l);
        } else {
            xmean_kernel<<<dim3(Dq / 256, Bq), 256>>>();
            gate_seq_kernel<<<Bq, 256>>>(gate_w, gate_b, l);
        }
        zero_counts_kernel<<<1, 32>>>();
        assign_kernel<<<TOK / 256, 256>>>(l % 2);
        gemm_big<2><<<dim3(DFFq / BNb, TOK / BMb, Ee), 512, SMEM_BIG>>>(nullptr, e_w1, e_b1, nullptr, Dq, DFFq, l);
        gemm_big<3><<<dim3(Dq / BNb, TOK / BMb, Ee), 512, SMEM_BIG>>>(nullptr, e_w2, e_b2, nullptr, DFFq, Dq, l);
    }

    copy_out_kernel<<<nelem / 256, 256>>>((float*)d_out);
    (void)in_sizes; (void)n_in; (void)out_size;
}

// round 7
// speedup vs baseline: 6.5707x; 1.0651x over previous
#include <cuda_runtime.h>
#include <cuda_fp16.h>
#include <math.h>
#include <stdint.h>

#define Bq   4
#define Sq   1024
#define Dq   1024
#define Hh   16
#define HD   64
#define Ll   2
#define Ee   8
#define DFFq 4096
#define TOK  (Bq*Sq)   // 4096

// ---------------- static scratch ---------------------------------------------
__device__ float g_X[TOK*Dq];
__device__ float g_H[TOK*Dq];
__device__ float g_Q[TOK*Dq];
__device__ float g_K[TOK*Dq];
__device__ float g_V[TOK*Dq];
__device__ float g_Y[TOK*Dq];
__device__ float g_hidden[(size_t)Ee*TOK*DFFq];
__device__ int   g_counts[Ee];
__device__ int   g_tok[Ee*TOK];
__device__ float g_wt[Ee*TOK];
__device__ int   g_te[TOK*2];
__device__ float g_tw[TOK*2];
__device__ int   g_bsel[Bq*2];
__device__ float g_bw[Bq*2];
__device__ float g_xmean[Bq*Dq];

// ---------------- helpers ----------------------------------------------------
__device__ __forceinline__ void top2_of8(const float* lg, int& i1, int& i2,
                                         float& w1, float& w2) {
    i1 = 0; float v1 = lg[0];
#pragma unroll
    for (int e = 1; e < Ee; e++) if (lg[e] > v1) { v1 = lg[e]; i1 = e; }
    i2 = -1; float v2 = -3.0e38f;
#pragma unroll
    for (int e = 0; e < Ee; e++) if (e != i1 && lg[e] > v2) { v2 = lg[e]; i2 = e; }
    float ex = expf(v2 - v1);
    w1 = 1.0f / (1.0f + ex);
    w2 = ex / (1.0f + ex);
}
__device__ __forceinline__ float gelu_exact(float x) {
    return 0.5f * x * (1.0f + erff(x * 0.7071067811865476f));
}
__device__ __forceinline__ float tf32r(float x) {
    uint32_t u; asm("cvt.rna.tf32.f32 %0, %1;" : "=r"(u) : "f"(x));
    return __uint_as_float(u);
}
__device__ __forceinline__ void mma_tf32(float c[4], const uint32_t a[4],
                                         const uint32_t b[2]) {
    asm volatile(
        "mma.sync.aligned.m16n8k8.row.col.f32.tf32.tf32.f32 "
        "{%0,%1,%2,%3},{%4,%5,%6,%7},{%8,%9},{%0,%1,%2,%3};"
        : "+f"(c[0]), "+f"(c[1]), "+f"(c[2]), "+f"(c[3])
        : "r"(a[0]), "r"(a[1]), "r"(a[2]), "r"(a[3]), "r"(b[0]), "r"(b[1]));
}
__device__ __forceinline__ void mma_f16(float c[4], const uint32_t a[4],
                                        const uint32_t b[2]) {
    asm volatile(
        "mma.sync.aligned.m16n8k16.row.col.f32.f16.f16.f32 "
        "{%0,%1,%2,%3},{%4,%5,%6,%7},{%8,%9},{%0,%1,%2,%3};"
        : "+f"(c[0]), "+f"(c[1]), "+f"(c[2]), "+f"(c[3])
        : "r"(a[0]), "r"(a[1]), "r"(a[2]), "r"(a[3]), "r"(b[0]), "r"(b[1]));
}
__device__ __forceinline__ uint32_t pack_h2(__half a, __half b) {
    __half2 h = __halves2half2(a, b);
    return *(uint32_t*)&h;
}

// ---------------- simple kernels ---------------------------------------------
__global__ void copy_in_kernel(const float* __restrict__ src) {
    int i = blockIdx.x * 256 + threadIdx.x;
    g_X[i] = src[i];
}
__global__ void copy_out_kernel(float* __restrict__ dst) {
    int i = blockIdx.x * 256 + threadIdx.x;
    dst[i] = g_X[i];
}

__global__ void ln_kernel(const float* __restrict__ w, const float* __restrict__ b) {
    int t = blockIdx.x, tid = threadIdx.x;
    const float* xr = g_X + (size_t)t * Dq;
    float s = 0.f, s2 = 0.f;
    for (int d = tid; d < Dq; d += 256) { float v = xr[d]; s += v; s2 += v * v; }
    __shared__ float r1[256], r2[256];
    r1[tid] = s; r2[tid] = s2; __syncthreads();
    for (int off = 128; off; off >>= 1) {
        if (tid < off) { r1[tid] += r1[tid + off]; r2[tid] += r2[tid + off]; }
        __syncthreads();
    }
    float mean = r1[0] * (1.0f / Dq);
    float var  = r2[0] * (1.0f / Dq) - mean * mean;
    float rstd = rsqrtf(var + 1e-5f);
    float* hr = g_H + (size_t)t * Dq;
    for (int d = tid; d < Dq; d += 256)
        hr[d] = (xr[d] - mean) * rstd * w[d] + b[d];
}

// ---------------- fp16 3-pass split GEMM (layer-0 path, 128x128, 512 thr) ----
// Dekker split: x = hi + lo (fp16 each); x@w = hh + hl + lh (+O(2^-22))
// smem: per buffer 4 tiles (Ahi, Alo, Bhi, Blo), each [8 kpair][136] u32(half2)
#define T2W 136
#define T2SZ (8*T2W)           // 1088 u32 per tile
#define H3BUF (4*T2SZ)         // 4352 u32 per buffer
#define SMEM_H3 ((256 + 2*H3BUF) * 4)   // 35840 B

template<int MODE>
__global__ void __launch_bounds__(512, 1)
gemm_h3(const float* __restrict__ A, const float* __restrict__ Wall,
        const float* __restrict__ ball, float* __restrict__ Cp,
        int Kd, int N, int layer) {
    extern __shared__ float smf[];
    uint32_t* tiles = (uint32_t*)(smf + 256);

    int tid = threadIdx.x;
    int rowBase = blockIdx.y * 128, colBase = blockIdx.x * 128;
    const float* bias = ball;

    // A loader: thread -> (row lrA, 4 k's at kcA4)
    int lrA = tid >> 2, kcA4 = (tid & 3) << 2, kpA = (tid & 3) << 1;
    const float* Ap = A + (size_t)(rowBase + lrA) * Kd + kcA4;
    // B loader: thread -> (kpair kpB, 2 n's at nB); loads rows 2kpB, 2kpB+1
    int kpB = tid >> 6, nB = (tid & 63) << 1;
    const float* Wp = Wall + (size_t)(2 * kpB) * N + colBase + nB;

    int lane = tid & 31, warp = tid >> 5;
    int wm = (warp & 3) * 32, wn = (warp >> 2) * 32;
    int gid = lane >> 2, tig = lane & 3;

    float acc[2][4][4];
#pragma unroll
    for (int a = 0; a < 2; a++)
#pragma unroll
        for (int b2 = 0; b2 < 4; b2++)
#pragma unroll
            for (int c = 0; c < 4; c++) acc[a][b2][c] = 0.f;

    int nk = Kd / 16;
    float4 av;
    float2 br0, br1;
    av  = *(const float4*)(Ap);
    br0 = *(const float2*)(Wp);
    br1 = *(const float2*)(Wp + N);

    // store chunk 0
    {
        uint32_t* Ahi = tiles;
        uint32_t* Alo = tiles + T2SZ;
        uint32_t* Bhi = tiles + 2 * T2SZ;
        uint32_t* Blo = tiles + 3 * T2SZ;
        __half h0 = __float2half_rn(av.x), h1 = __float2half_rn(av.y);
        __half h2 = __float2half_rn(av.z), h3 = __float2half_rn(av.w);
        __half l0 = __float2half_rn(av.x - __half2float(h0));
        __half l1 = __float2half_rn(av.y - __half2float(h1));
        __half l2 = __float2half_rn(av.z - __half2float(h2));
        __half l3 = __float2half_rn(av.w - __half2float(h3));
        Ahi[kpA * T2W + lrA]       = pack_h2(h0, h1);
        Ahi[(kpA + 1) * T2W + lrA] = pack_h2(h2, h3);
        Alo[kpA * T2W + lrA]       = pack_h2(l0, l1);
        Alo[(kpA + 1) * T2W + lrA] = pack_h2(l2, l3);
        __half w00 = __float2half_rn(br0.x), w10 = __float2half_rn(br1.x);
        __half w01 = __float2half_rn(br0.y), w11 = __float2half_rn(br1.y);
        Bhi[kpB * T2W + nB]     = pack_h2(w00, w10);
        Bhi[kpB * T2W + nB + 1] = pack_h2(w01, w11);
        Blo[kpB * T2W + nB]     = pack_h2(__float2half_rn(br0.x - __half2float(w00)),
                                          __float2half_rn(br1.x - __half2float(w10)));
        Blo[kpB * T2W + nB + 1] = pack_h2(__float2half_rn(br0.y - __half2float(w01)),
                                          __float2half_rn(br1.y - __half2float(w11)));
    }
    __syncthreads();

    for (int t = 0; t < nk; t++) {
        if (t + 1 < nk) {
            av  = *(const float4*)(Ap + (size_t)(t + 1) * 16);
            const float* w2 = Wp + (size_t)(t + 1) * 16 * N;
            br0 = *(const float2*)(w2);
            br1 = *(const float2*)(w2 + N);
        }
        int s = t & 1;
        const uint32_t* Ahi = tiles + s * H3BUF;
        const uint32_t* Alo = Ahi + T2SZ;
        const uint32_t* Bhi = Ahi + 2 * T2SZ;
        const uint32_t* Blo = Ahi + 3 * T2SZ;

        uint32_t ah[2][4], al[2][4], bh[4][2], bl[4][2];
#pragma unroll
        for (int mt = 0; mt < 2; mt++) {
            int m0 = wm + mt * 16 + gid;
            ah[mt][0] = Ahi[tig * T2W + m0];
            ah[mt][1] = Ahi[tig * T2W + m0 + 8];
            ah[mt][2] = Ahi[(tig + 4) * T2W + m0];
            ah[mt][3] = Ahi[(tig + 4) * T2W + m0 + 8];
            al[mt][0] = Alo[tig * T2W + m0];
            al[mt][1] = Alo[tig * T2W + m0 + 8];
            al[mt][2] = Alo[(tig + 4) * T2W + m0];
            al[mt][3] = Alo[(tig + 4) * T2W + m0 + 8];
        }
#pragma unroll
        for (int nt = 0; nt < 4; nt++) {
            int n0 = wn + nt * 8 + gid;
            bh[nt][0] = Bhi[tig * T2W + n0];
            bh[nt][1] = Bhi[(tig + 4) * T2W + n0];
            bl[nt][0] = Blo[tig * T2W + n0];
            bl[nt][1] = Blo[(tig + 4) * T2W + n0];
        }
        // pass-major: distinct accumulators between reuse
#pragma unroll
        for (int mt = 0; mt < 2; mt++)
#pragma unroll
            for (int nt = 0; nt < 4; nt++)
                mma_f16(acc[mt][nt], ah[mt], bh[nt]);
#pragma unroll
        for (int mt = 0; mt < 2; mt++)
#pragma unroll
            for (int nt = 0; nt < 4; nt++)
                mma_f16(acc[mt][nt], ah[mt], bl[nt]);
#pragma unroll
        for (int mt = 0; mt < 2; mt++)
#pragma unroll
            for (int nt = 0; nt < 4; nt++)
                mma_f16(acc[mt][nt], al[mt], bh[nt]);

        if (t + 1 < nk) {
            int s2 = s ^ 1;
            uint32_t* Ahi2 = tiles + s2 * H3BUF;
            uint32_t* Alo2 = Ahi2 + T2SZ;
            uint32_t* Bhi2 = Ahi2 + 2 * T2SZ;
            uint32_t* Blo2 = Ahi2 + 3 * T2SZ;
            __half h0 = __float2half_rn(av.x), h1 = __float2half_rn(av.y);
            __half h2 = __float2half_rn(av.z), h3 = __float2half_rn(av.w);
            __half l0 = __float2half_rn(av.x - __half2float(h0));
            __half l1 = __float2half_rn(av.y - __half2float(h1));
            __half l2 = __float2half_rn(av.z - __half2float(h2));
            __half l3 = __float2half_rn(av.w - __half2float(h3));
            Ahi2[kpA * T2W + lrA]       = pack_h2(h0, h1);
            Ahi2[(kpA + 1) * T2W + lrA] = pack_h2(h2, h3);
            Alo2[kpA * T2W + lrA]       = pack_h2(l0, l1);
            Alo2[(kpA + 1) * T2W + lrA] = pack_h2(l2, l3);
            __half w00 = __float2half_rn(br0.x), w10 = __float2half_rn(br1.x);
            __half w01 = __float2half_rn(br0.y), w11 = __float2half_rn(br1.y);
            Bhi2[kpB * T2W + nB]     = pack_h2(w00, w10);
            Bhi2[kpB * T2W + nB + 1] = pack_h2(w01, w11);
            Blo2[kpB * T2W + nB]     = pack_h2(__float2half_rn(br0.x - __half2float(w00)),
                                               __float2half_rn(br1.x - __half2float(w10)));
            Blo2[kpB * T2W + nB + 1] = pack_h2(__float2half_rn(br0.y - __half2float(w01)),
                                               __float2half_rn(br1.y - __half2float(w11)));
        }
        __syncthreads();
    }

#pragma unroll
    for (int mt = 0; mt < 2; mt++) {
#pragma unroll
        for (int c = 0; c < 4; c++) {
            int r = rowBase + wm + mt * 16 + gid + ((c & 2) ? 8 : 0);
#pragma unroll
            for (int nt = 0; nt < 4; nt++) {
                int cg = colBase + wn + nt * 8 + tig * 2 + (c & 1);
                float v = acc[mt][nt][c] + bias[cg];
                if (MODE == 1) v += Cp[(size_t)r * N + cg];
                Cp[(size_t)r * N + cg] = v;
            }
        }
    }
}

// ---------------- big-tile single-pass TF32 GEMM (128x256, 512 thr) ----------
#define BMb 128
#define BNb 256
#define BKb 16
#define AWb 136
#define BWb 264
#define ATb (BKb*AWb)
#define BTb (BKb*BWb)
#define SMEM_BIG ((256 + 2*(ATb+BTb)) * 4)

template<int MODE>
__global__ void __launch_bounds__(512, 1)
gemm_big(const float* __restrict__ A, const float* __restrict__ Wall,
         const float* __restrict__ ball, float* __restrict__ Cp,
         int Kd, int N, int layer) {
    extern __shared__ float smf[];
    int*   s_tok = (int*)smf;
    float* s_wt  = smf + 128;
    float* tiles = smf + 256;

    int tid = threadIdx.x;
    int rowBase = blockIdx.y * BMb, colBase = blockIdx.x * BNb;

    int e = 0, cnt = 0;
    const float* W = Wall;
    const float* bias = ball;
    if (MODE >= 2) {
        e = blockIdx.z;
        cnt = g_counts[e];
        if (rowBase >= cnt) return;
        W    = Wall + (size_t)(layer * Ee + e) * Kd * N;
        bias = ball + (size_t)(layer * Ee + e) * N;
        if (tid < 128) {
            int r = rowBase + tid;
            int rc = r < cnt ? r : cnt - 1;
            s_tok[tid] = g_tok[e * TOK + rc];
            s_wt[tid]  = g_wt [e * TOK + rc];
        }
        __syncthreads();
    }

    int lrA = tid >> 2, kcA = (tid & 3) << 2;
    const float* Ap;
    if (MODE == 2)      Ap = g_H + (size_t)s_tok[lrA] * Kd + kcA;
    else if (MODE == 3) Ap = g_hidden + ((size_t)e * TOK + rowBase + lrA) * Kd + kcA;
    else                Ap = A + (size_t)(rowBase + lrA) * Kd + kcA;

    int krB = tid >> 6, ncB = (tid & 63) << 2;
    const float* Wp = W + (size_t)krB * N + colBase + ncB;

    int lane = tid & 31, warp = tid >> 5;
    int wm = (warp & 1) * 64, wn = (warp >> 1) * 32;
    int gid = lane >> 2, tig = lane & 3;

    float acc[4][4][4];
#pragma unroll
    for (int a = 0; a < 4; a++)
#pragma unroll
        for (int b2 = 0; b2 < 4; b2++)
#pragma unroll
            for (int c = 0; c < 4; c++) acc[a][b2][c] = 0.f;

    int nk = Kd / BKb;
    float4 av, bv0, bv1;
    av  = *(const float4*)(Ap);
    bv0 = *(const float4*)(Wp);
    bv1 = *(const float4*)(Wp + (size_t)8 * N);
    {
        float* As = tiles;
        float* Bs = tiles + ATb;
        float va[4] = {av.x, av.y, av.z, av.w};
#pragma unroll
        for (int g = 0; g < 4; g++)
            As[(kcA + g) * AWb + lrA] = tf32r(va[g]);
        *(float4*)&Bs[krB * BWb + ncB] =
            make_float4(tf32r(bv0.x), tf32r(bv0.y), tf32r(bv0.z), tf32r(bv0.w));
        *(float4*)&Bs[(krB + 8) * BWb + ncB] =
            make_float4(tf32r(bv1.x), tf32r(bv1.y), tf32r(bv1.z), tf32r(bv1.w));
    }
    __syncthreads();

    for (int t = 0; t < nk; t++) {
        if (t + 1 < nk) {
            av  = *(const float4*)(Ap + (size_t)(t + 1) * BKb);
            const float* w2 = Wp + (size_t)(t + 1) * BKb * N;
            bv0 = *(const float4*)(w2);
            bv1 = *(const float4*)(w2 + (size_t)8 * N);
        }
        int s = t & 1;
        float* As = tiles + s * (ATb + BTb);
        float* Bs = As + ATb;

#pragma unroll
        for (int kk = 0; kk < BKb; kk += 8) {
            uint32_t af[4][4], bf[4][2];
#pragma unroll
            for (int mt = 0; mt < 4; mt++) {
                int m0 = wm + mt * 16 + gid;
                af[mt][0] = __float_as_uint(As[(kk + tig) * AWb + m0]);
                af[mt][1] = __float_as_uint(As[(kk + tig) * AWb + m0 + 8]);
                af[mt][2] = __float_as_uint(As[(kk + tig + 4) * AWb + m0]);
                af[mt][3] = __float_as_uint(As[(kk + tig + 4) * AWb + m0 + 8]);
            }
#pragma unroll
            for (int nt = 0; nt < 4; nt++) {
                int n0 = wn + nt * 8 + gid;
                bf[nt][0] = __float_as_uint(Bs[(kk + tig) * BWb + n0]);
                bf[nt][1] = __float_as_uint(Bs[(kk + tig + 4) * BWb + n0]);
            }
#pragma unroll
            for (int mt = 0; mt < 4; mt++)
#pragma unroll
                for (int nt = 0; nt < 4; nt++)
                    mma_tf32(acc[mt][nt], af[mt], bf[nt]);
        }

        if (t + 1 < nk) {
            int s2 = s ^ 1;
            float* As2 = tiles + s2 * (ATb + BTb);
            float* Bs2 = As2 + ATb;
            float va[4] = {av.x, av.y, av.z, av.w};
#pragma unroll
            for (int g = 0; g < 4; g++)
                As2[(kcA + g) * AWb + lrA] = tf32r(va[g]);
            *(float4*)&Bs2[krB * BWb + ncB] =
                make_float4(tf32r(bv0.x), tf32r(bv0.y), tf32r(bv0.z), tf32r(bv0.w));
            *(float4*)&Bs2[(krB + 8) * BWb + ncB] =
                make_float4(tf32r(bv1.x), tf32r(bv1.y), tf32r(bv1.z), tf32r(bv1.w));
        }
        __syncthreads();
    }

#pragma unroll
    for (int mt = 0; mt < 4; mt++) {
#pragma unroll
        for (int c = 0; c < 4; c++) {
            int rl = wm + mt * 16 + gid + ((c & 2) ? 8 : 0);
            int r  = rowBase + rl;
#pragma unroll
            for (int nt = 0; nt < 4; nt++) {
                int cg = colBase + wn + nt * 8 + tig * 2 + (c & 1);
                float v = acc[mt][nt][c] + bias[cg];
                if (MODE == 0) {
                    Cp[(size_t)r * N + cg] = v;
                } else if (MODE == 1) {
                    Cp[(size_t)r * N + cg] = v + Cp[(size_t)r * N + cg];
                } else if (MODE == 2) {
                    if (r < cnt)
                        g_hidden[((size_t)e * TOK + r) * N + cg] = gelu_exact(v);
                } else {
                    if (r < cnt)
                        atomicAdd(&g_X[(size_t)s_tok[rl] * N + cg], v * s_wt[rl]);
                }
            }
        }
    }
}

// ---------------- tensor-core flash attention --------------------------------
#define FQSZ (64*136)
#define FKSZ (64*72)
#define FPSZ (64*136)
#define FL_SMEM0 ((FQSZ + 2*FKSZ + FPSZ) * 4)
#define FL_SMEM1 ((FQSZ + 2*FKSZ + FPSZ) * 8)

__device__ __forceinline__ int fsw(int d) { return ((d >> 2) & 7) << 3; }

template<int SPLIT>
__global__ void __launch_bounds__(256)
flash_tc() {
    extern __shared__ float fs[];
    float* Qh = fs;
    float* Ql = Qh + FQSZ;
    float* Kh = Qh + FQSZ * (SPLIT + 1);
    float* Kl = Kh + FKSZ;
    float* Vh = Kh + FKSZ * (SPLIT + 1);
    float* Vl = Vh + FKSZ;
    float* Ph = Vh + FKSZ * (SPLIT + 1);
    float* Pl = Ph + FPSZ;

    int qb = blockIdx.x, h = blockIdx.y, b = blockIdx.z;
    int tid = threadIdx.x, warp = tid >> 5, lane = tid & 31;
    int gid = lane >> 2, tig = lane & 3;
    int mrow = warp * 16 + gid;

    for (int i = tid; i < 2048; i += 256) {
        int r = i >> 4, d4 = (i & 15) << 2;
        float4 v = *(const float4*)&g_Q[((size_t)(b * Sq + qb * 128 + r)) * Dq + h * HD + d4];
        float va[4] = {v.x, v.y, v.z, v.w};
#pragma unroll
        for (int j = 0; j < 4; j++) {
            int d = d4 + j;
            int cs = r ^ fsw(d);
            float hi = tf32r(va[j]);
            Qh[d * 136 + cs] = hi;
            if (SPLIT) Ql[d * 136 + cs] = tf32r(va[j] - hi);
        }
    }

    float mA = -1e30f, mB = -1e30f, lA = 0.f, lB = 0.f;
    float o[8][4];
#pragma unroll
    for (int nt = 0; nt < 8; nt++)
#pragma unroll
        for (int c = 0; c < 4; c++) o[nt][c] = 0.f;

    int nkt = 2 * qb + 2;
    for (int kt = 0; kt < nkt; kt++) {
        __syncthreads();
        for (int i = tid; i < 1024; i += 256) {
            int r = i >> 4, d4 = (i & 15) << 2;
            size_t base = ((size_t)(b * Sq + kt * 64 + r)) * Dq + h * HD + d4;
            float4 kv = *(const float4*)&g_K[base];
            float ka[4] = {kv.x, kv.y, kv.z, kv.w};
#pragma unroll
            for (int j = 0; j < 4; j++) {
                int d = d4 + j;
                int cs = r ^ fsw(d);
                float hi = tf32r(ka[j]);
                Kh[d * 72 + cs] = hi;
                if (SPLIT) Kl[d * 72 + cs] = tf32r(ka[j] - hi);
            }
            float4 vv = *(const float4*)&g_V[base];
            float4 vh = make_float4(tf32r(vv.x), tf32r(vv.y), tf32r(vv.z), tf32r(vv.w));
            *(float4*)&Vh[r * 72 + d4] = vh;
            if (SPLIT)
                *(float4*)&Vl[r * 72 + d4] =
                    make_float4(tf32r(vv.x - vh.x), tf32r(vv.y - vh.y),
                                tf32r(vv.z - vh.z), tf32r(vv.w - vh.w));
        }
        __syncthreads();

        float s[8][4];
#pragma unroll
        for (int nt = 0; nt < 8; nt++)
#pragma unroll
            for (int c = 0; c < 4; c++) s[nt][c] = 0.f;

#pragma unroll
        for (int ks = 0; ks < 8; ks++) {
            int kb = ks * 8;
            int s0 = fsw(kb + tig), s1 = fsw(kb + tig + 4);
            uint32_t a[4], al[4];
            a[0] = __float_as_uint(Qh[(kb + tig) * 136 + (mrow ^ s0)]);
            a[1] = __float_as_uint(Qh[(kb + tig) * 136 + ((mrow + 8) ^ s0)]);
            a[2] = __float_as_uint(Qh[(kb + tig + 4) * 136 + (mrow ^ s1)]);
            a[3] = __float_as_uint(Qh[(kb + tig + 4) * 136 + ((mrow + 8) ^ s1)]);
            if (SPLIT) {
                al[0] = __float_as_uint(Ql[(kb + tig) * 136 + (mrow ^ s0)]);
                al[1] = __float_as_uint(Ql[(kb + tig) * 136 + ((mrow + 8) ^ s0)]);
                al[2] = __float_as_uint(Ql[(kb + tig + 4) * 136 + (mrow ^ s1)]);
                al[3] = __float_as_uint(Ql[(kb + tig + 4) * 136 + ((mrow + 8) ^ s1)]);
            }
            // groups of 4 nt: pass-major within group (same-acc distance 4)
#pragma unroll
            for (int gq = 0; gq < 2; gq++) {
                uint32_t bb[4][2], bl[4][2];
#pragma unroll
                for (int j = 0; j < 4; j++) {
                    int n0 = (gq * 4 + j) * 8 + gid;
                    bb[j][0] = __float_as_uint(Kh[(kb + tig) * 72 + (n0 ^ s0)]);
                    bb[j][1] = __float_as_uint(Kh[(kb + tig + 4) * 72 + (n0 ^ s1)]);
                    if (SPLIT) {
                        bl[j][0] = __float_as_uint(Kl[(kb + tig) * 72 + (n0 ^ s0)]);
                        bl[j][1] = __float_as_uint(Kl[(kb + tig + 4) * 72 + (n0 ^ s1)]);
                    }
                }
#pragma unroll
                for (int j = 0; j < 4; j++) mma_tf32(s[gq * 4 + j], a, bb[j]);
                if (SPLIT) {
#pragma unroll
                    for (int j = 0; j < 4; j++) mma_tf32(s[gq * 4 + j], a, bl[j]);
#pragma unroll
                    for (int j = 0; j < 4; j++) mma_tf32(s[gq * 4 + j], al, bb[j]);
                }
            }
        }

        int rowg = qb * 128 + warp * 16 + gid;
        if (kt * 64 + 63 > rowg) {
#pragma unroll
            for (int nt = 0; nt < 8; nt++)
#pragma unroll
                for (int c = 0; c < 4; c++) {
                    int col = kt * 64 + nt * 8 + 2 * tig + (c & 1);
                    int row = rowg + ((c & 2) ? 8 : 0);
                    float sv = s[nt][c] * 0.125f;
                    s[nt][c] = (col > row) ? -1e30f : sv;
                }
        } else {
#pragma unroll
            for (int nt = 0; nt < 8; nt++)
#pragma unroll
                for (int c = 0; c < 4; c++) s[nt][c] *= 0.125f;
        }

        float rmA = -1e30f, rmB = -1e30f;
#pragma unroll
        for (int nt = 0; nt < 8; nt++) {
            rmA = fmaxf(rmA, fmaxf(s[nt][0], s[nt][1]));
            rmB = fmaxf(rmB, fmaxf(s[nt][2], s[nt][3]));
        }
#pragma unroll
        for (int off = 1; off < 4; off <<= 1) {
            rmA = fmaxf(rmA, __shfl_xor_sync(0xffffffffu, rmA, off));
            rmB = fmaxf(rmB, __shfl_xor_sync(0xffffffffu, rmB, off));
        }
        float mnA = fmaxf(mA, rmA), mnB = fmaxf(mB, rmB);
        float alA = __expf(mA - mnA), alB = __expf(mB - mnB);
        float rsA = 0.f, rsB = 0.f;
#pragma unroll
        for (int nt = 0; nt < 8; nt++) {
            s[nt][0] = __expf(s[nt][0] - mnA); rsA += s[nt][0];
            s[nt][1] = __expf(s[nt][1] - mnA); rsA += s[nt][1];
            s[nt][2] = __expf(s[nt][2] - mnB); rsB += s[nt][2];
            s[nt][3] = __expf(s[nt][3] - mnB); rsB += s[nt][3];
        }
#pragma unroll
        for (int off = 1; off < 4; off <<= 1) {
            rsA += __shfl_xor_sync(0xffffffffu, rsA, off);
            rsB += __shfl_xor_sync(0xffffffffu, rsB, off);
        }
        lA = lA * alA + rsA; mA = mnA;
        lB = lB * alB + rsB; mB = mnB;
#pragma unroll
        for (int nt = 0; nt < 8; nt++) {
            o[nt][0] *= alA; o[nt][1] *= alA;
            o[nt][2] *= alB; o[nt][3] *= alB;
        }

        __syncwarp();
#pragma unroll
        for (int nt = 0; nt < 8; nt++)
#pragma unroll
            for (int c = 0; c < 4; c++) {
                int cl = nt * 8 + 2 * tig + (c & 1);
                int mr = warp * 16 + gid + ((c & 2) ? 8 : 0);
                float p = s[nt][c], ph = tf32r(p);
                Ph[cl * 136 + mr] = ph;
                if (SPLIT) Pl[cl * 136 + mr] = tf32r(p - ph);
            }
        __syncwarp();

#pragma unroll
        for (int ks = 0; ks < 8; ks++) {
            int kb = ks * 8;
            uint32_t a[4], al[4];
            a[0] = __float_as_uint(Ph[(kb + tig) * 136 + mrow]);
            a[1] = __float_as_uint(Ph[(kb + tig) * 136 + mrow + 8]);
            a[2] = __float_as_uint(Ph[(kb + tig + 4) * 136 + mrow]);
            a[3] = __float_as_uint(Ph[(kb + tig + 4) * 136 + mrow + 8]);
            if (SPLIT) {
                al[0] = __float_as_uint(Pl[(kb + tig) * 136 + mrow]);
                al[1] = __float_as_uint(Pl[(kb + tig) * 136 + mrow + 8]);
                al[2] = __float_as_uint(Pl[(kb + tig + 4) * 136 + mrow]);
                al[3] = __float_as_uint(Pl[(kb + tig + 4) * 136 + mrow + 8]);
            }
#pragma unroll
            for (int gq = 0; gq < 2; gq++) {
                uint32_t bb[4][2], bl[4][2];
#pragma unroll
                for (int j = 0; j < 4; j++) {
                    int n0 = (gq * 4 + j) * 8 + gid;
                    bb[j][0] = __float_as_uint(Vh[(kb + tig) * 72 + n0]);
                    bb[j][1] = __float_as_uint(Vh[(kb + tig + 4) * 72 + n0]);
                    if (SPLIT) {
                        bl[j][0] = __float_as_uint(Vl[(kb + tig) * 72 + n0]);
                        bl[j][1] = __float_as_uint(Vl[(kb + tig + 4) * 72 + n0]);
                    }
                }
#pragma unroll
                for (int j = 0; j < 4; j++) mma_tf32(o[gq * 4 + j], a, bb[j]);
                if (SPLIT) {
#pragma unroll
                    for (int j = 0; j < 4; j++) mma_tf32(o[gq * 4 + j], a, bl[j]);
#pragma unroll
                    for (int j = 0; j < 4; j++) mma_tf32(o[gq * 4 + j], al, bb[j]);
                }
            }
        }
    }

    float invA = 1.0f / lA, invB = 1.0f / lB;
    size_t rbase0 = ((size_t)(b * Sq + qb * 128 + warp * 16 + gid)) * Dq + h * HD;
    size_t rbase1 = rbase0 + (size_t)8 * Dq;
#pragma unroll
    for (int nt = 0; nt < 8; nt++) {
        int d0 = nt * 8 + 2 * tig;
        *(float2*)&g_Y[rbase0 + d0] = make_float2(o[nt][0] * invA, o[nt][1] * invA);
        *(float2*)&g_Y[rbase1 + d0] = make_float2(o[nt][2] * invB, o[nt][3] * invB);
    }
}

// ---------------- gating -----------------------------------------------------
__global__ void gate_token_kernel(const float* __restrict__ gw,
                                  const float* __restrict__ gb, int layer) {
    int t = blockIdx.x * 4 + (threadIdx.x >> 5);
    int lane = threadIdx.x & 31;
    if (t >= TOK) return;
    const float* hrow = g_H + (size_t)t * Dq;
    const float* gwl = gw + (size_t)layer * Dq * Ee;
    float acc[Ee] = {};
    for (int d = lane; d < Dq; d += 32) {
        float hv = hrow[d];
        const float* g = gwl + (size_t)d * Ee;
#pragma unroll
        for (int e = 0; e < Ee; e++) acc[e] += hv * g[e];
    }
#pragma unroll
    for (int e = 0; e < Ee; e++)
        for (int off = 16; off; off >>= 1)
            acc[e] += __shfl_xor_sync(0xffffffffu, acc[e], off);
    if (lane == 0) {
        float lg[Ee];
#pragma unroll
        for (int e = 0; e < Ee; e++) lg[e] = acc[e] + gb[layer * Ee + e];
        int i1, i2; float w1, w2;
        top2_of8(lg, i1, i2, w1, w2);
        g_te[t * 2] = i1; g_te[t * 2 + 1] = i2;
        g_tw[t * 2] = w1; g_tw[t * 2 + 1] = w2;
    }
}

__global__ void xmean_kernel() {
    int b = blockIdx.y;
    int d = blockIdx.x * 256 + threadIdx.x;
    float s = 0.f;
    for (int ss = 0; ss < Sq; ss++)
        s += g_H[((size_t)(b * Sq + ss)) * Dq + d];
    g_xmean[b * Dq + d] = s * (1.0f / Sq);
}

__global__ void gate_seq_kernel(const float* __restrict__ gw,
                                const float* __restrict__ gb, int layer) {
    int b = blockIdx.x;
    int tid = threadIdx.x, e = tid >> 5, lane = tid & 31;
    const float* gwl = gw + (size_t)layer * Dq * Ee;
    float acc = 0.f;
    for (int d = lane; d < Dq; d += 32)
        acc += g_xmean[b * Dq + d] * gwl[(size_t)d * Ee + e];
    for (int off = 16; off; off >>= 1)
        acc += __shfl_xor_sync(0xffffffffu, acc, off);
    __shared__ float lg[Ee];
    if (lane == 0) lg[e] = acc + gb[layer * Ee + e];
    __syncthreads();
    if (tid == 0) {
        int i1, i2; float w1, w2;
        top2_of8(lg, i1, i2, w1, w2);
        g_bsel[b * 2] = i1; g_bsel[b * 2 + 1] = i2;
        g_bw[b * 2] = w1;  g_bw[b * 2 + 1] = w2;
    }
}

__global__ void zero_counts_kernel() {
    if (threadIdx.x < Ee) g_counts[threadIdx.x] = 0;
}

__global__ void assign_kernel(int seq_mode) {
    int t = blockIdx.x * 256 + threadIdx.x;
    if (t >= TOK) return;
    int e1, e2; float w1, w2;
    if (seq_mode) {
        int b = t / Sq;
        e1 = g_bsel[b * 2]; e2 = g_bsel[b * 2 + 1];
        w1 = g_bw[b * 2];   w2 = g_bw[b * 2 + 1];
    } else {
        e1 = g_te[t * 2]; e2 = g_te[t * 2 + 1];
        w1 = g_tw[t * 2]; w2 = g_tw[t * 2 + 1];
    }
    int s1 = atomicAdd(&g_counts[e1], 1);
    g_tok[e1 * TOK + s1] = t; g_wt[e1 * TOK + s1] = w1;
    int s2 = atomicAdd(&g_counts[e2], 1);
    g_tok[e2 * TOK + s2] = t; g_wt[e2 * TOK + s2] = w2;
}

// ---------------- host side --------------------------------------------------
extern "C" void kernel_launch(void* const* d_in, const int* in_sizes, int n_in,
                              void* d_out, int out_size) {
    const float* x      = (const float*)d_in[0];
    const float* ln1_w  = (const float*)d_in[1];
    const float* ln1_b  = (const float*)d_in[2];
    const float* ln2_w  = (const float*)d_in[3];
    const float* ln2_b  = (const float*)d_in[4];
    const float* wq     = (const float*)d_in[5];
    const float* wk     = (const float*)d_in[6];
    const float* wv     = (const float*)d_in[7];
    const float* wo     = (const float*)d_in[8];
    const float* bq     = (const float*)d_in[9];
    const float* bk     = (const float*)d_in[10];
    const float* bv     = (const float*)d_in[11];
    const float* bo     = (const float*)d_in[12];
    const float* gate_w = (const float*)d_in[13];
    const float* gate_b = (const float*)d_in[14];
    const float* e_w1   = (const float*)d_in[15];
    const float* e_b1   = (const float*)d_in[16];
    const float* e_w2   = (const float*)d_in[17];
    const float* e_b2   = (const float*)d_in[18];

    float *Xp, *Hp, *Qp, *Kp, *Vp, *Yp;
    cudaGetSymbolAddress((void**)&Xp, g_X);
    cudaGetSymbolAddress((void**)&Hp, g_H);
    cudaGetSymbolAddress((void**)&Qp, g_Q);
    cudaGetSymbolAddress((void**)&Kp, g_K);
    cudaGetSymbolAddress((void**)&Vp, g_V);
    cudaGetSymbolAddress((void**)&Yp, g_Y);

    static int attr_set = 0;
    if (!attr_set) {
        cudaFuncSetAttribute(gemm_h3<0>, cudaFuncAttributeMaxDynamicSharedMemorySize, SMEM_H3);
        cudaFuncSetAttribute(gemm_h3<1>, cudaFuncAttributeMaxDynamicSharedMemorySize, SMEM_H3);
        cudaFuncSetAttribute(gemm_big<0>, cudaFuncAttributeMaxDynamicSharedMemorySize, SMEM_BIG);
        cudaFuncSetAttribute(gemm_big<1>, cudaFuncAttributeMaxDynamicSharedMemorySize, SMEM_BIG);
        cudaFuncSetAttribute(gemm_big<2>, cudaFuncAttributeMaxDynamicSharedMemorySize, SMEM_BIG);
        cudaFuncSetAttribute(gemm_big<3>, cudaFuncAttributeMaxDynamicSharedMemorySize, SMEM_BIG);
        cudaFuncSetAttribute(flash_tc<0>, cudaFuncAttributeMaxDynamicSharedMemorySize, FL_SMEM0);
        cudaFuncSetAttribute(flash_tc<1>, cudaFuncAttributeMaxDynamicSharedMemorySize, FL_SMEM1);
        attr_set = 1;
    }

    const size_t DD = (size_t)Dq * Dq;
    const int nelem = TOK * Dq;

    copy_in_kernel<<<nelem / 256, 256>>>(x);

    dim3 gsplit(Dq / 128, TOK / 128);          // 8 x 32
    dim3 gbig(Dq / BNb, TOK / BMb);            // 4 x 32
    for (int l = 0; l < Ll; l++) {
        // --- attention block ---
        ln_kernel<<<TOK, 256>>>(ln1_w + (size_t)l * Dq, ln1_b + (size_t)l * Dq);
        if (l == 0) {
            gemm_h3<0><<<gsplit, 512, SMEM_H3>>>(Hp, wq + l * DD, bq + (size_t)l * Dq, Qp, Dq, Dq, l);
            gemm_h3<0><<<gsplit, 512, SMEM_H3>>>(Hp, wk + l * DD, bk + (size_t)l * Dq, Kp, Dq, Dq, l);
            gemm_h3<0><<<gsplit, 512, SMEM_H3>>>(Hp, wv + l * DD, bv + (size_t)l * Dq, Vp, Dq, Dq, l);
            flash_tc<1><<<dim3(Sq / 128, Hh, Bq), 256, FL_SMEM1>>>();
            gemm_h3<1><<<gsplit, 512, SMEM_H3>>>(Yp, wo + l * DD, bo + (size_t)l * Dq, Xp, Dq, Dq, l);
        } else {
            gemm_big<0><<<gbig, 512, SMEM_BIG>>>(Hp, wq + l * DD, bq + (size_t)l * Dq, Qp, Dq, Dq, l);
            gemm_big<0><<<gbig, 512, SMEM_BIG>>>(Hp, wk + l * DD, bk + (size_t)l * Dq, Kp, Dq, Dq, l);
            gemm_big<0><<<gbig, 512, SMEM_BIG>>>(Hp, wv + l * DD, bv + (size_t)l * Dq, Vp, Dq, Dq, l);
            flash_tc<0><<<dim3(Sq / 128, Hh, Bq), 256, FL_SMEM0>>>();
            gemm_big<1><<<gbig, 512, SMEM_BIG>>>(Yp, wo + l * DD, bo + (size_t)l * Dq, Xp, Dq, Dq, l);
        }

        // --- MoE block ---
        ln_kernel<<<TOK, 256>>>(ln2_w + (size_t)l * Dq, ln2_b + (size_t)l * Dq);
        if (l % 2 == 0) {
            gate_token_kernel<<<TOK / 4, 128>>>(gate_w, gate_b, l);
        } else {
            xmean_kernel<<<dim3(Dq / 256, Bq), 256>>>();
            gate_seq_kernel<<<Bq, 256>>>(gate_w, gate_b, l);
        }
        zero_counts_kernel<<<1, 32>>>();
        assign_kernel<<<TOK / 256, 256>>>(l % 2);
        gemm_big<2><<<dim3(DFFq / BNb, TOK / BMb, Ee), 512, SMEM_BIG>>>(nullptr, e_w1, e_b1, nullptr, Dq, DFFq, l);
        gemm_big<3><<<dim3(Dq / BNb, TOK / BMb, Ee), 512, SMEM_BIG>>>(nullptr, e_w2, e_b2, nullptr, DFFq, Dq, l);
    }

    copy_out_kernel<<<nelem / 256, 256>>>((float*)d_out);
    (void)in_sizes; (void)n_in; (void)out_size;
}

// round 8
// speedup vs baseline: 8.6158x; 1.3112x over previous
#include <cuda_runtime.h>
#include <cuda_fp16.h>
#include <math.h>
#include <stdint.h>

#define Bq   4
#define Sq   1024
#define Dq   1024
#define Hh   16
#define HD   64
#define Ll   2
#define Ee   8
#define DFFq 4096
#define TOK  (Bq*Sq)   // 4096

// ---------------- static scratch ---------------------------------------------
__device__ float g_X[TOK*Dq];
__device__ float g_H[TOK*Dq];
__device__ float g_Q[TOK*Dq];
__device__ float g_K[TOK*Dq];
__device__ float g_V[TOK*Dq];
__device__ float g_Y[TOK*Dq];
__device__ float g_hidden[(size_t)Ee*TOK*DFFq];
__device__ int   g_counts[Ee];
__device__ int   g_tok[Ee*TOK];
__device__ float g_wt[Ee*TOK];
__device__ int   g_te[TOK*2];
__device__ float g_tw[TOK*2];
__device__ int   g_bsel[Bq*2];
__device__ float g_bw[Bq*2];
__device__ float g_xmean[Bq*Dq];

// ---------------- helpers ----------------------------------------------------
__device__ __forceinline__ void top2_of8(const float* lg, int& i1, int& i2,
                                         float& w1, float& w2) {
    i1 = 0; float v1 = lg[0];
#pragma unroll
    for (int e = 1; e < Ee; e++) if (lg[e] > v1) { v1 = lg[e]; i1 = e; }
    i2 = -1; float v2 = -3.0e38f;
#pragma unroll
    for (int e = 0; e < Ee; e++) if (e != i1 && lg[e] > v2) { v2 = lg[e]; i2 = e; }
    float ex = expf(v2 - v1);
    w1 = 1.0f / (1.0f + ex);
    w2 = ex / (1.0f + ex);
}
__device__ __forceinline__ float gelu_exact(float x) {
    return 0.5f * x * (1.0f + erff(x * 0.7071067811865476f));
}
__device__ __forceinline__ float tf32r(float x) {
    uint32_t u; asm("cvt.rna.tf32.f32 %0, %1;" : "=r"(u) : "f"(x));
    return __uint_as_float(u);
}
__device__ __forceinline__ void mma_tf32(float c[4], const uint32_t a[4],
                                         const uint32_t b[2]) {
    asm volatile(
        "mma.sync.aligned.m16n8k8.row.col.f32.tf32.tf32.f32 "
        "{%0,%1,%2,%3},{%4,%5,%6,%7},{%8,%9},{%0,%1,%2,%3};"
        : "+f"(c[0]), "+f"(c[1]), "+f"(c[2]), "+f"(c[3])
        : "r"(a[0]), "r"(a[1]), "r"(a[2]), "r"(a[3]), "r"(b[0]), "r"(b[1]));
}
__device__ __forceinline__ void mma_f16(float c[4], const uint32_t a[4],
                                        const uint32_t b[2]) {
    asm volatile(
        "mma.sync.aligned.m16n8k16.row.col.f32.f16.f16.f32 "
        "{%0,%1,%2,%3},{%4,%5,%6,%7},{%8,%9},{%0,%1,%2,%3};"
        : "+f"(c[0]), "+f"(c[1]), "+f"(c[2]), "+f"(c[3])
        : "r"(a[0]), "r"(a[1]), "r"(a[2]), "r"(a[3]), "r"(b[0]), "r"(b[1]));
}
__device__ __forceinline__ uint32_t pack_h2(__half a, __half b) {
    __half2 h = __halves2half2(a, b);
    return *(uint32_t*)&h;
}
__device__ __forceinline__ uint32_t pack_f2h(float a, float b) {
    return pack_h2(__float2half_rn(a), __float2half_rn(b));
}

// ---------------- simple kernels ---------------------------------------------
__global__ void copy_in_kernel(const float* __restrict__ src) {
    int i = blockIdx.x * 256 + threadIdx.x;
    g_X[i] = src[i];
}
__global__ void copy_out_kernel(float* __restrict__ dst) {
    int i = blockIdx.x * 256 + threadIdx.x;
    dst[i] = g_X[i];
}

__global__ void ln_kernel(const float* __restrict__ w, const float* __restrict__ b) {
    int t = blockIdx.x, tid = threadIdx.x;
    const float* xr = g_X + (size_t)t * Dq;
    float s = 0.f, s2 = 0.f;
    for (int d = tid; d < Dq; d += 256) { float v = xr[d]; s += v; s2 += v * v; }
    __shared__ float r1[256], r2[256];
    r1[tid] = s; r2[tid] = s2; __syncthreads();
    for (int off = 128; off; off >>= 1) {
        if (tid < off) { r1[tid] += r1[tid + off]; r2[tid] += r2[tid + off]; }
        __syncthreads();
    }
    float mean = r1[0] * (1.0f / Dq);
    float var  = r2[0] * (1.0f / Dq) - mean * mean;
    float rstd = rsqrtf(var + 1e-5f);
    float* hr = g_H + (size_t)t * Dq;
    for (int d = tid; d < Dq; d += 256)
        hr[d] = (xr[d] - mean) * rstd * w[d] + b[d];
}

// ---------------- fp16 3-pass split GEMM (layer-0 path, 128x128, 512 thr) ----
#define T2W 136
#define T2SZ (8*T2W)
#define H3BUF (4*T2SZ)
#define SMEM_H3 ((256 + 2*H3BUF) * 4)   // 35840 B

template<int MODE>
__global__ void __launch_bounds__(512, 1)
gemm_h3(const float* __restrict__ A, const float* __restrict__ Wall,
        const float* __restrict__ ball, float* __restrict__ Cp,
        int Kd, int N, int layer) {
    extern __shared__ float smf[];
    uint32_t* tiles = (uint32_t*)(smf + 256);

    int tid = threadIdx.x;
    int rowBase = blockIdx.y * 128, colBase = blockIdx.x * 128;
    const float* bias = ball;

    int lrA = tid >> 2, kcA4 = (tid & 3) << 2, kpA = (tid & 3) << 1;
    const float* Ap = A + (size_t)(rowBase + lrA) * Kd + kcA4;
    int kpB = tid >> 6, nB = (tid & 63) << 1;
    const float* Wp = Wall + (size_t)(2 * kpB) * N + colBase + nB;

    int lane = tid & 31, warp = tid >> 5;
    int wm = (warp & 3) * 32, wn = (warp >> 2) * 32;
    int gid = lane >> 2, tig = lane & 3;

    float acc[2][4][4];
#pragma unroll
    for (int a = 0; a < 2; a++)
#pragma unroll
        for (int b2 = 0; b2 < 4; b2++)
#pragma unroll
            for (int c = 0; c < 4; c++) acc[a][b2][c] = 0.f;

    int nk = Kd / 16;
    float4 av;
    float2 br0, br1;
    av  = *(const float4*)(Ap);
    br0 = *(const float2*)(Wp);
    br1 = *(const float2*)(Wp + N);

    {
        uint32_t* Ahi = tiles;
        uint32_t* Alo = tiles + T2SZ;
        uint32_t* Bhi = tiles + 2 * T2SZ;
        uint32_t* Blo = tiles + 3 * T2SZ;
        __half h0 = __float2half_rn(av.x), h1 = __float2half_rn(av.y);
        __half h2 = __float2half_rn(av.z), h3 = __float2half_rn(av.w);
        Ahi[kpA * T2W + lrA]       = pack_h2(h0, h1);
        Ahi[(kpA + 1) * T2W + lrA] = pack_h2(h2, h3);
        Alo[kpA * T2W + lrA]       = pack_f2h(av.x - __half2float(h0), av.y - __half2float(h1));
        Alo[(kpA + 1) * T2W + lrA] = pack_f2h(av.z - __half2float(h2), av.w - __half2float(h3));
        __half w00 = __float2half_rn(br0.x), w10 = __float2half_rn(br1.x);
        __half w01 = __float2half_rn(br0.y), w11 = __float2half_rn(br1.y);
        Bhi[kpB * T2W + nB]     = pack_h2(w00, w10);
        Bhi[kpB * T2W + nB + 1] = pack_h2(w01, w11);
        Blo[kpB * T2W + nB]     = pack_f2h(br0.x - __half2float(w00), br1.x - __half2float(w10));
        Blo[kpB * T2W + nB + 1] = pack_f2h(br0.y - __half2float(w01), br1.y - __half2float(w11));
    }
    __syncthreads();

    for (int t = 0; t < nk; t++) {
        if (t + 1 < nk) {
            av  = *(const float4*)(Ap + (size_t)(t + 1) * 16);
            const float* w2 = Wp + (size_t)(t + 1) * 16 * N;
            br0 = *(const float2*)(w2);
            br1 = *(const float2*)(w2 + N);
        }
        int s = t & 1;
        const uint32_t* Ahi = tiles + s * H3BUF;
        const uint32_t* Alo = Ahi + T2SZ;
        const uint32_t* Bhi = Ahi + 2 * T2SZ;
        const uint32_t* Blo = Ahi + 3 * T2SZ;

        uint32_t ah[2][4], al[2][4], bh[4][2], bl[4][2];
#pragma unroll
        for (int mt = 0; mt < 2; mt++) {
            int m0 = wm + mt * 16 + gid;
            ah[mt][0] = Ahi[tig * T2W + m0];
            ah[mt][1] = Ahi[tig * T2W + m0 + 8];
            ah[mt][2] = Ahi[(tig + 4) * T2W + m0];
            ah[mt][3] = Ahi[(tig + 4) * T2W + m0 + 8];
            al[mt][0] = Alo[tig * T2W + m0];
            al[mt][1] = Alo[tig * T2W + m0 + 8];
            al[mt][2] = Alo[(tig + 4) * T2W + m0];
            al[mt][3] = Alo[(tig + 4) * T2W + m0 + 8];
        }
#pragma unroll
        for (int nt = 0; nt < 4; nt++) {
            int n0 = wn + nt * 8 + gid;
            bh[nt][0] = Bhi[tig * T2W + n0];
            bh[nt][1] = Bhi[(tig + 4) * T2W + n0];
            bl[nt][0] = Blo[tig * T2W + n0];
            bl[nt][1] = Blo[(tig + 4) * T2W + n0];
        }
#pragma unroll
        for (int mt = 0; mt < 2; mt++)
#pragma unroll
            for (int nt = 0; nt < 4; nt++)
                mma_f16(acc[mt][nt], ah[mt], bh[nt]);
#pragma unroll
        for (int mt = 0; mt < 2; mt++)
#pragma unroll
            for (int nt = 0; nt < 4; nt++)
                mma_f16(acc[mt][nt], ah[mt], bl[nt]);
#pragma unroll
        for (int mt = 0; mt < 2; mt++)
#pragma unroll
            for (int nt = 0; nt < 4; nt++)
                mma_f16(acc[mt][nt], al[mt], bh[nt]);

        if (t + 1 < nk) {
            int s2 = s ^ 1;
            uint32_t* Ahi2 = tiles + s2 * H3BUF;
            uint32_t* Alo2 = Ahi2 + T2SZ;
            uint32_t* Bhi2 = Ahi2 + 2 * T2SZ;
            uint32_t* Blo2 = Ahi2 + 3 * T2SZ;
            __half h0 = __float2half_rn(av.x), h1 = __float2half_rn(av.y);
            __half h2 = __float2half_rn(av.z), h3 = __float2half_rn(av.w);
            Ahi2[kpA * T2W + lrA]       = pack_h2(h0, h1);
            Ahi2[(kpA + 1) * T2W + lrA] = pack_h2(h2, h3);
            Alo2[kpA * T2W + lrA]       = pack_f2h(av.x - __half2float(h0), av.y - __half2float(h1));
            Alo2[(kpA + 1) * T2W + lrA] = pack_f2h(av.z - __half2float(h2), av.w - __half2float(h3));
            __half w00 = __float2half_rn(br0.x), w10 = __float2half_rn(br1.x);
            __half w01 = __float2half_rn(br0.y), w11 = __float2half_rn(br1.y);
            Bhi2[kpB * T2W + nB]     = pack_h2(w00, w10);
            Bhi2[kpB * T2W + nB + 1] = pack_h2(w01, w11);
            Blo2[kpB * T2W + nB]     = pack_f2h(br0.x - __half2float(w00), br1.x - __half2float(w10));
            Blo2[kpB * T2W + nB + 1] = pack_f2h(br0.y - __half2float(w01), br1.y - __half2float(w11));
        }
        __syncthreads();
    }

#pragma unroll
    for (int mt = 0; mt < 2; mt++) {
#pragma unroll
        for (int c = 0; c < 4; c++) {
            int r = rowBase + wm + mt * 16 + gid + ((c & 2) ? 8 : 0);
#pragma unroll
            for (int nt = 0; nt < 4; nt++) {
                int cg = colBase + wn + nt * 8 + tig * 2 + (c & 1);
                float v = acc[mt][nt][c] + bias[cg];
                if (MODE == 1) v += Cp[(size_t)r * N + cg];
                Cp[(size_t)r * N + cg] = v;
            }
        }
    }
}

// ---------------- fp16 1-pass big-tile GEMM (128x256, 512 thr) ---------------
// MODE 0: C = A@W + bias    MODE 1: C += Res   MODE 2: MoE GEMM1 (GELU)
// MODE 3: MoE GEMM2 (atomic scatter)
// smem/buffer: A [8 kpair][136] u32, B [8 kpair][264] u32
#define HB_AW 136
#define HB_BW 264
#define HB_AT (8*HB_AW)            // 1088
#define HB_BT (8*HB_BW)            // 2112
#define HB_BUF (HB_AT+HB_BT)       // 3200
#define SMEM_HB ((256 + 2*HB_BUF) * 4)   // 26624 B

template<int MODE>
__global__ void __launch_bounds__(512, 1)
gemm_hb(const float* __restrict__ A, const float* __restrict__ Wall,
        const float* __restrict__ ball, float* __restrict__ Cp,
        int Kd, int N, int layer) {
    extern __shared__ float smf[];
    int*   s_tok = (int*)smf;
    float* s_wt  = smf + 128;
    uint32_t* tiles = (uint32_t*)(smf + 256);

    int tid = threadIdx.x;
    int rowBase = blockIdx.y * 128, colBase = blockIdx.x * 256;

    int e = 0, cnt = 0;
    const float* W = Wall;
    const float* bias = ball;
    if (MODE >= 2) {
        e = blockIdx.z;
        cnt = g_counts[e];
        if (rowBase >= cnt) return;
        W    = Wall + (size_t)(layer * Ee + e) * Kd * N;
        bias = ball + (size_t)(layer * Ee + e) * N;
        if (tid < 128) {
            int r = rowBase + tid;
            int rc = r < cnt ? r : cnt - 1;
            s_tok[tid] = g_tok[e * TOK + rc];
            s_wt[tid]  = g_wt [e * TOK + rc];
        }
        __syncthreads();
    }

    // A loader: row lrA, k's kcA4..kcA4+3 (kpairs kpA, kpA+1)
    int lrA = tid >> 2, kcA4 = (tid & 3) << 2, kpA = (tid & 3) << 1;
    const float* Ap;
    if (MODE == 2)      Ap = g_H + (size_t)s_tok[lrA] * Kd + kcA4;
    else if (MODE == 3) Ap = g_hidden + ((size_t)e * TOK + rowBase + lrA) * Kd + kcA4;
    else                Ap = A + (size_t)(rowBase + lrA) * Kd + kcA4;

    // B loader: kpair kpB (rows 2kpB, 2kpB+1), 4 n's at nB4
    int kpB = tid >> 6, nB4 = (tid & 63) << 2;
    const float* Wp = W + (size_t)(2 * kpB) * N + colBase + nB4;

    int lane = tid & 31, warp = tid >> 5;
    int wm = (warp & 1) * 64, wn = (warp >> 1) * 32;
    int gid = lane >> 2, tig = lane & 3;

    float acc[4][4][4];
#pragma unroll
    for (int a = 0; a < 4; a++)
#pragma unroll
        for (int b2 = 0; b2 < 4; b2++)
#pragma unroll
            for (int c = 0; c < 4; c++) acc[a][b2][c] = 0.f;

    int nk = Kd / 16;
    float4 av, bv0, bv1;
    av  = *(const float4*)(Ap);
    bv0 = *(const float4*)(Wp);
    bv1 = *(const float4*)(Wp + N);
    {
        uint32_t* As = tiles;
        uint32_t* Bs = tiles + HB_AT;
        As[kpA * HB_AW + lrA]       = pack_f2h(av.x, av.y);
        As[(kpA + 1) * HB_AW + lrA] = pack_f2h(av.z, av.w);
        Bs[kpB * HB_BW + nB4 + 0] = pack_f2h(bv0.x, bv1.x);
        Bs[kpB * HB_BW + nB4 + 1] = pack_f2h(bv0.y, bv1.y);
        Bs[kpB * HB_BW + nB4 + 2] = pack_f2h(bv0.z, bv1.z);
        Bs[kpB * HB_BW + nB4 + 3] = pack_f2h(bv0.w, bv1.w);
    }
    __syncthreads();

    for (int t = 0; t < nk; t++) {
        if (t + 1 < nk) {
            av  = *(const float4*)(Ap + (size_t)(t + 1) * 16);
            const float* w2 = Wp + (size_t)(t + 1) * 16 * N;
            bv0 = *(const float4*)(w2);
            bv1 = *(const float4*)(w2 + N);
        }
        int s = t & 1;
        const uint32_t* As = tiles + s * HB_BUF;
        const uint32_t* Bs = As + HB_AT;

        uint32_t af[4][4], bf[4][2];
#pragma unroll
        for (int mt = 0; mt < 4; mt++) {
            int m0 = wm + mt * 16 + gid;
            af[mt][0] = As[tig * HB_AW + m0];
            af[mt][1] = As[tig * HB_AW + m0 + 8];
            af[mt][2] = As[(tig + 4) * HB_AW + m0];
            af[mt][3] = As[(tig + 4) * HB_AW + m0 + 8];
        }
#pragma unroll
        for (int nt = 0; nt < 4; nt++) {
            int n0 = wn + nt * 8 + gid;
            bf[nt][0] = Bs[tig * HB_BW + n0];
            bf[nt][1] = Bs[(tig + 4) * HB_BW + n0];
        }
#pragma unroll
        for (int mt = 0; mt < 4; mt++)
#pragma unroll
            for (int nt = 0; nt < 4; nt++)
                mma_f16(acc[mt][nt], af[mt], bf[nt]);

        if (t + 1 < nk) {
            int s2 = s ^ 1;
            uint32_t* As2 = tiles + s2 * HB_BUF;
            uint32_t* Bs2 = As2 + HB_AT;
            As2[kpA * HB_AW + lrA]       = pack_f2h(av.x, av.y);
            As2[(kpA + 1) * HB_AW + lrA] = pack_f2h(av.z, av.w);
            Bs2[kpB * HB_BW + nB4 + 0] = pack_f2h(bv0.x, bv1.x);
            Bs2[kpB * HB_BW + nB4 + 1] = pack_f2h(bv0.y, bv1.y);
            Bs2[kpB * HB_BW + nB4 + 2] = pack_f2h(bv0.z, bv1.z);
            Bs2[kpB * HB_BW + nB4 + 3] = pack_f2h(bv0.w, bv1.w);
        }
        __syncthreads();
    }

#pragma unroll
    for (int mt = 0; mt < 4; mt++) {
#pragma unroll
        for (int c = 0; c < 4; c++) {
            int rl = wm + mt * 16 + gid + ((c & 2) ? 8 : 0);
            int r  = rowBase + rl;
#pragma unroll
            for (int nt = 0; nt < 4; nt++) {
                int cg = colBase + wn + nt * 8 + tig * 2 + (c & 1);
                float v = acc[mt][nt][c] + bias[cg];
                if (MODE == 0) {
                    Cp[(size_t)r * N + cg] = v;
                } else if (MODE == 1) {
                    Cp[(size_t)r * N + cg] = v + Cp[(size_t)r * N + cg];
                } else if (MODE == 2) {
                    if (r < cnt)
                        g_hidden[((size_t)e * TOK + r) * N + cg] = gelu_exact(v);
                } else {
                    if (r < cnt)
                        atomicAdd(&g_X[(size_t)s_tok[rl] * N + cg], v * s_wt[rl]);
                }
            }
        }
    }
}

// ---------------- tensor-core flash attention --------------------------------
#define FQSZ (64*136)
#define FKSZ (64*72)
#define FPSZ (64*136)
#define FL_SMEM0 ((FQSZ + 2*FKSZ + FPSZ) * 4)
#define FL_SMEM1 ((FQSZ + 2*FKSZ + FPSZ) * 8)

__device__ __forceinline__ int fsw(int d) { return ((d >> 2) & 7) << 3; }

template<int SPLIT>
__global__ void __launch_bounds__(256)
flash_tc() {
    extern __shared__ float fs[];
    float* Qh = fs;
    float* Ql = Qh + FQSZ;
    float* Kh = Qh + FQSZ * (SPLIT + 1);
    float* Kl = Kh + FKSZ;
    float* Vh = Kh + FKSZ * (SPLIT + 1);
    float* Vl = Vh + FKSZ;
    float* Ph = Vh + FKSZ * (SPLIT + 1);
    float* Pl = Ph + FPSZ;

    int qb = blockIdx.x, h = blockIdx.y, b = blockIdx.z;
    int tid = threadIdx.x, warp = tid >> 5, lane = tid & 31;
    int gid = lane >> 2, tig = lane & 3;
    int mrow = warp * 16 + gid;

    for (int i = tid; i < 2048; i += 256) {
        int r = i >> 4, d4 = (i & 15) << 2;
        float4 v = *(const float4*)&g_Q[((size_t)(b * Sq + qb * 128 + r)) * Dq + h * HD + d4];
        float va[4] = {v.x, v.y, v.z, v.w};
#pragma unroll
        for (int j = 0; j < 4; j++) {
            int d = d4 + j;
            int cs = r ^ fsw(d);
            float hi = tf32r(va[j]);
            Qh[d * 136 + cs] = hi;
            if (SPLIT) Ql[d * 136 + cs] = tf32r(va[j] - hi);
        }
    }

    float mA = -1e30f, mB = -1e30f, lA = 0.f, lB = 0.f;
    float o[8][4];
#pragma unroll
    for (int nt = 0; nt < 8; nt++)
#pragma unroll
        for (int c = 0; c < 4; c++) o[nt][c] = 0.f;

    int nkt = 2 * qb + 2;
    for (int kt = 0; kt < nkt; kt++) {
        __syncthreads();
        for (int i = tid; i < 1024; i += 256) {
            int r = i >> 4, d4 = (i & 15) << 2;
            size_t base = ((size_t)(b * Sq + kt * 64 + r)) * Dq + h * HD + d4;
            float4 kv = *(const float4*)&g_K[base];
            float ka[4] = {kv.x, kv.y, kv.z, kv.w};
#pragma unroll
            for (int j = 0; j < 4; j++) {
                int d = d4 + j;
                int cs = r ^ fsw(d);
                float hi = tf32r(ka[j]);
                Kh[d * 72 + cs] = hi;
                if (SPLIT) Kl[d * 72 + cs] = tf32r(ka[j] - hi);
            }
            float4 vv = *(const float4*)&g_V[base];
            float4 vh = make_float4(tf32r(vv.x), tf32r(vv.y), tf32r(vv.z), tf32r(vv.w));
            *(float4*)&Vh[r * 72 + d4] = vh;
            if (SPLIT)
                *(float4*)&Vl[r * 72 + d4] =
                    make_float4(tf32r(vv.x - vh.x), tf32r(vv.y - vh.y),
                                tf32r(vv.z - vh.z), tf32r(vv.w - vh.w));
        }
        __syncthreads();

        float s[8][4];
#pragma unroll
        for (int nt = 0; nt < 8; nt++)
#pragma unroll
            for (int c = 0; c < 4; c++) s[nt][c] = 0.f;

#pragma unroll
        for (int ks = 0; ks < 8; ks++) {
            int kb = ks * 8;
            int s0 = fsw(kb + tig), s1 = fsw(kb + tig + 4);
            uint32_t a[4], al[4];
            a[0] = __float_as_uint(Qh[(kb + tig) * 136 + (mrow ^ s0)]);
            a[1] = __float_as_uint(Qh[(kb + tig) * 136 + ((mrow + 8) ^ s0)]);
            a[2] = __float_as_uint(Qh[(kb + tig + 4) * 136 + (mrow ^ s1)]);
            a[3] = __float_as_uint(Qh[(kb + tig + 4) * 136 + ((mrow + 8) ^ s1)]);
            if (SPLIT) {
                al[0] = __float_as_uint(Ql[(kb + tig) * 136 + (mrow ^ s0)]);
                al[1] = __float_as_uint(Ql[(kb + tig) * 136 + ((mrow + 8) ^ s0)]);
                al[2] = __float_as_uint(Ql[(kb + tig + 4) * 136 + (mrow ^ s1)]);
                al[3] = __float_as_uint(Ql[(kb + tig + 4) * 136 + ((mrow + 8) ^ s1)]);
            }
#pragma unroll
            for (int gq = 0; gq < 2; gq++) {
                uint32_t bb[4][2], bl[4][2];
#pragma unroll
                for (int j = 0; j < 4; j++) {
                    int n0 = (gq * 4 + j) * 8 + gid;
                    bb[j][0] = __float_as_uint(Kh[(kb + tig) * 72 + (n0 ^ s0)]);
                    bb[j][1] = __float_as_uint(Kh[(kb + tig + 4) * 72 + (n0 ^ s1)]);
                    if (SPLIT) {
                        bl[j][0] = __float_as_uint(Kl[(kb + tig) * 72 + (n0 ^ s0)]);
                        bl[j][1] = __float_as_uint(Kl[(kb + tig + 4) * 72 + (n0 ^ s1)]);
                    }
                }
#pragma unroll
                for (int j = 0; j < 4; j++) mma_tf32(s[gq * 4 + j], a, bb[j]);
                if (SPLIT) {
#pragma unroll
                    for (int j = 0; j < 4; j++) mma_tf32(s[gq * 4 + j], a, bl[j]);
#pragma unroll
                    for (int j = 0; j < 4; j++) mma_tf32(s[gq * 4 + j], al, bb[j]);
                }
            }
        }

        int rowg = qb * 128 + warp * 16 + gid;
        if (kt * 64 + 63 > rowg) {
#pragma unroll
            for (int nt = 0; nt < 8; nt++)
#pragma unroll
                for (int c = 0; c < 4; c++) {
                    int col = kt * 64 + nt * 8 + 2 * tig + (c & 1);
                    int row = rowg + ((c & 2) ? 8 : 0);
                    float sv = s[nt][c] * 0.125f;
                    s[nt][c] = (col > row) ? -1e30f : sv;
                }
        } else {
#pragma unroll
            for (int nt = 0; nt < 8; nt++)
#pragma unroll
                for (int c = 0; c < 4; c++) s[nt][c] *= 0.125f;
        }

        float rmA = -1e30f, rmB = -1e30f;
#pragma unroll
        for (int nt = 0; nt < 8; nt++) {
            rmA = fmaxf(rmA, fmaxf(s[nt][0], s[nt][1]));
            rmB = fmaxf(rmB, fmaxf(s[nt][2], s[nt][3]));
        }
#pragma unroll
        for (int off = 1; off < 4; off <<= 1) {
            rmA = fmaxf(rmA, __shfl_xor_sync(0xffffffffu, rmA, off));
            rmB = fmaxf(rmB, __shfl_xor_sync(0xffffffffu, rmB, off));
        }
        float mnA = fmaxf(mA, rmA), mnB = fmaxf(mB, rmB);
        float alA = __expf(mA - mnA), alB = __expf(mB - mnB);
        float rsA = 0.f, rsB = 0.f;
#pragma unroll
        for (int nt = 0; nt < 8; nt++) {
            s[nt][0] = __expf(s[nt][0] - mnA); rsA += s[nt][0];
            s[nt][1] = __expf(s[nt][1] - mnA); rsA += s[nt][1];
            s[nt][2] = __expf(s[nt][2] - mnB); rsB += s[nt][2];
            s[nt][3] = __expf(s[nt][3] - mnB); rsB += s[nt][3];
        }
#pragma unroll
        for (int off = 1; off < 4; off <<= 1) {
            rsA += __shfl_xor_sync(0xffffffffu, rsA, off);
            rsB += __shfl_xor_sync(0xffffffffu, rsB, off);
        }
        lA = lA * alA + rsA; mA = mnA;
        lB = lB * alB + rsB; mB = mnB;
#pragma unroll
        for (int nt = 0; nt < 8; nt++) {
            o[nt][0] *= alA; o[nt][1] *= alA;
            o[nt][2] *= alB; o[nt][3] *= alB;
        }

        __syncwarp();
#pragma unroll
        for (int nt = 0; nt < 8; nt++)
#pragma unroll
            for (int c = 0; c < 4; c++) {
                int cl = nt * 8 + 2 * tig + (c & 1);
                int mr = warp * 16 + gid + ((c & 2) ? 8 : 0);
                float p = s[nt][c], ph = tf32r(p);
                Ph[cl * 136 + mr] = ph;
                if (SPLIT) Pl[cl * 136 + mr] = tf32r(p - ph);
            }
        __syncwarp();

#pragma unroll
        for (int ks = 0; ks < 8; ks++) {
            int kb = ks * 8;
            uint32_t a[4], al[4];
            a[0] = __float_as_uint(Ph[(kb + tig) * 136 + mrow]);
            a[1] = __float_as_uint(Ph[(kb + tig) * 136 + mrow + 8]);
            a[2] = __float_as_uint(Ph[(kb + tig + 4) * 136 + mrow]);
            a[3] = __float_as_uint(Ph[(kb + tig + 4) * 136 + mrow + 8]);
            if (SPLIT) {
                al[0] = __float_as_uint(Pl[(kb + tig) * 136 + mrow]);
                al[1] = __float_as_uint(Pl[(kb + tig) * 136 + mrow + 8]);
                al[2] = __float_as_uint(Pl[(kb + tig + 4) * 136 + mrow]);
                al[3] = __float_as_uint(Pl[(kb + tig + 4) * 136 + mrow + 8]);
            }
#pragma unroll
            for (int gq = 0; gq < 2; gq++) {
                uint32_t bb[4][2], bl[4][2];
#pragma unroll
                for (int j = 0; j < 4; j++) {
                    int n0 = (gq * 4 + j) * 8 + gid;
                    bb[j][0] = __float_as_uint(Vh[(kb + tig) * 72 + n0]);
                    bb[j][1] = __float_as_uint(Vh[(kb + tig + 4) * 72 + n0]);
                    if (SPLIT) {
                        bl[j][0] = __float_as_uint(Vl[(kb + tig) * 72 + n0]);
                        bl[j][1] = __float_as_uint(Vl[(kb + tig + 4) * 72 + n0]);
                    }
                }
#pragma unroll
                for (int j = 0; j < 4; j++) mma_tf32(o[gq * 4 + j], a, bb[j]);
                if (SPLIT) {
#pragma unroll
                    for (int j = 0; j < 4; j++) mma_tf32(o[gq * 4 + j], a, bl[j]);
#pragma unroll
                    for (int j = 0; j < 4; j++) mma_tf32(o[gq * 4 + j], al, bb[j]);
                }
            }
        }
    }

    float invA = 1.0f / lA, invB = 1.0f / lB;
    size_t rbase0 = ((size_t)(b * Sq + qb * 128 + warp * 16 + gid)) * Dq + h * HD;
    size_t rbase1 = rbase0 + (size_t)8 * Dq;
#pragma unroll
    for (int nt = 0; nt < 8; nt++) {
        int d0 = nt * 8 + 2 * tig;
        *(float2*)&g_Y[rbase0 + d0] = make_float2(o[nt][0] * invA, o[nt][1] * invA);
        *(float2*)&g_Y[rbase1 + d0] = make_float2(o[nt][2] * invB, o[nt][3] * invB);
    }
}

// ---------------- gating -----------------------------------------------------
__global__ void gate_token_kernel(const float* __restrict__ gw,
                                  const float* __restrict__ gb, int layer) {
    int t = blockIdx.x * 4 + (threadIdx.x >> 5);
    int lane = threadIdx.x & 31;
    if (t >= TOK) return;
    const float* hrow = g_H + (size_t)t * Dq;
    const float* gwl = gw + (size_t)layer * Dq * Ee;
    float acc[Ee] = {};
    for (int d = lane; d < Dq; d += 32) {
        float hv = hrow[d];
        const float* g = gwl + (size_t)d * Ee;
#pragma unroll
        for (int e = 0; e < Ee; e++) acc[e] += hv * g[e];
    }
#pragma unroll
    for (int e = 0; e < Ee; e++)
        for (int off = 16; off; off >>= 1)
            acc[e] += __shfl_xor_sync(0xffffffffu, acc[e], off);
    if (lane == 0) {
        float lg[Ee];
#pragma unroll
        for (int e = 0; e < Ee; e++) lg[e] = acc[e] + gb[layer * Ee + e];
        int i1, i2; float w1, w2;
        top2_of8(lg, i1, i2, w1, w2);
        g_te[t * 2] = i1; g_te[t * 2 + 1] = i2;
        g_tw[t * 2] = w1; g_tw[t * 2 + 1] = w2;
    }
}

__global__ void xmean_kernel() {
    int b = blockIdx.y;
    int d = blockIdx.x * 256 + threadIdx.x;
    float s = 0.f;
    for (int ss = 0; ss < Sq; ss++)
        s += g_H[((size_t)(b * Sq + ss)) * Dq + d];
    g_xmean[b * Dq + d] = s * (1.0f / Sq);
}

__global__ void gate_seq_kernel(const float* __restrict__ gw,
                                const float* __restrict__ gb, int layer) {
    int b = blockIdx.x;
    int tid = threadIdx.x, e = tid >> 5, lane = tid & 31;
    const float* gwl = gw + (size_t)layer * Dq * Ee;
    float acc = 0.f;
    for (int d = lane; d < Dq; d += 32)
        acc += g_xmean[b * Dq + d] * gwl[(size_t)d * Ee + e];
    for (int off = 16; off; off >>= 1)
        acc += __shfl_xor_sync(0xffffffffu, acc, off);
    __shared__ float lg[Ee];
    if (lane == 0) lg[e] = acc + gb[layer * Ee + e];
    __syncthreads();
    if (tid == 0) {
        int i1, i2; float w1, w2;
        top2_of8(lg, i1, i2, w1, w2);
        g_bsel[b * 2] = i1; g_bsel[b * 2 + 1] = i2;
        g_bw[b * 2] = w1;  g_bw[b * 2 + 1] = w2;
    }
}

__global__ void zero_counts_kernel() {
    if (threadIdx.x < Ee) g_counts[threadIdx.x] = 0;
}

__global__ void assign_kernel(int seq_mode) {
    int t = blockIdx.x * 256 + threadIdx.x;
    if (t >= TOK) return;
    int e1, e2; float w1, w2;
    if (seq_mode) {
        int b = t / Sq;
        e1 = g_bsel[b * 2]; e2 = g_bsel[b * 2 + 1];
        w1 = g_bw[b * 2];   w2 = g_bw[b * 2 + 1];
    } else {
        e1 = g_te[t * 2]; e2 = g_te[t * 2 + 1];
        w1 = g_tw[t * 2]; w2 = g_tw[t * 2 + 1];
    }
    int s1 = atomicAdd(&g_counts[e1], 1);
    g_tok[e1 * TOK + s1] = t; g_wt[e1 * TOK + s1] = w1;
    int s2 = atomicAdd(&g_counts[e2], 1);
    g_tok[e2 * TOK + s2] = t; g_wt[e2 * TOK + s2] = w2;
}

// ---------------- host side --------------------------------------------------
extern "C" void kernel_launch(void* const* d_in, const int* in_sizes, int n_in,
                              void* d_out, int out_size) {
    const float* x      = (const float*)d_in[0];
    const float* ln1_w  = (const float*)d_in[1];
    const float* ln1_b  = (const float*)d_in[2];
    const float* ln2_w  = (const float*)d_in[3];
    const float* ln2_b  = (const float*)d_in[4];
    const float* wq     = (const float*)d_in[5];
    const float* wk     = (const float*)d_in[6];
    const float* wv     = (const float*)d_in[7];
    const float* wo     = (const float*)d_in[8];
    const float* bq     = (const float*)d_in[9];
    const float* bk     = (const float*)d_in[10];
    const float* bv     = (const float*)d_in[11];
    const float* bo     = (const float*)d_in[12];
    const float* gate_w = (const float*)d_in[13];
    const float* gate_b = (const float*)d_in[14];
    const float* e_w1   = (const float*)d_in[15];
    const float* e_b1   = (const float*)d_in[16];
    const float* e_w2   = (const float*)d_in[17];
    const float* e_b2   = (const float*)d_in[18];

    float *Xp, *Hp, *Qp, *Kp, *Vp, *Yp;
    cudaGetSymbolAddress((void**)&Xp, g_X);
    cudaGetSymbolAddress((void**)&Hp, g_H);
    cudaGetSymbolAddress((void**)&Qp, g_Q);
    cudaGetSymbolAddress((void**)&Kp, g_K);
    cudaGetSymbolAddress((void**)&Vp, g_V);
    cudaGetSymbolAddress((void**)&Yp, g_Y);

    static int attr_set = 0;
    if (!attr_set) {
        cudaFuncSetAttribute(gemm_h3<0>, cudaFuncAttributeMaxDynamicSharedMemorySize, SMEM_H3);
        cudaFuncSetAttribute(gemm_h3<1>, cudaFuncAttributeMaxDynamicSharedMemorySize, SMEM_H3);
        cudaFuncSetAttribute(gemm_hb<0>, cudaFuncAttributeMaxDynamicSharedMemorySize, SMEM_HB);
        cudaFuncSetAttribute(gemm_hb<1>, cudaFuncAttributeMaxDynamicSharedMemorySize, SMEM_HB);
        cudaFuncSetAttribute(gemm_hb<2>, cudaFuncAttributeMaxDynamicSharedMemorySize, SMEM_HB);
        cudaFuncSetAttribute(gemm_hb<3>, cudaFuncAttributeMaxDynamicSharedMemorySize, SMEM_HB);
        cudaFuncSetAttribute(flash_tc<0>, cudaFuncAttributeMaxDynamicSharedMemorySize, FL_SMEM0);
        cudaFuncSetAttribute(flash_tc<1>, cudaFuncAttributeMaxDynamicSharedMemorySize, FL_SMEM1);
        attr_set = 1;
    }

    const size_t DD = (size_t)Dq * Dq;
    const int nelem = TOK * Dq;

    copy_in_kernel<<<nelem / 256, 256>>>(x);

    dim3 gsplit(Dq / 128, TOK / 128);          // 8 x 32
    dim3 ghb(Dq / 256, TOK / 128);             // 4 x 32
    for (int l = 0; l < Ll; l++) {
        // --- attention block ---
        ln_kernel<<<TOK, 256>>>(ln1_w + (size_t)l * Dq, ln1_b + (size_t)l * Dq);
        if (l == 0) {
            gemm_h3<0><<<gsplit, 512, SMEM_H3>>>(Hp, wq + l * DD, bq + (size_t)l * Dq, Qp, Dq, Dq, l);
            gemm_h3<0><<<gsplit, 512, SMEM_H3>>>(Hp, wk + l * DD, bk + (size_t)l * Dq, Kp, Dq, Dq, l);
            gemm_h3<0><<<gsplit, 512, SMEM_H3>>>(Hp, wv + l * DD, bv + (size_t)l * Dq, Vp, Dq, Dq, l);
            flash_tc<1><<<dim3(Sq / 128, Hh, Bq), 256, FL_SMEM1>>>();
            gemm_h3<1><<<gsplit, 512, SMEM_H3>>>(Yp, wo + l * DD, bo + (size_t)l * Dq, Xp, Dq, Dq, l);
        } else {
            gemm_hb<0><<<ghb, 512, SMEM_HB>>>(Hp, wq + l * DD, bq + (size_t)l * Dq, Qp, Dq, Dq, l);
            gemm_hb<0><<<ghb, 512, SMEM_HB>>>(Hp, wk + l * DD, bk + (size_t)l * Dq, Kp, Dq, Dq, l);
            gemm_hb<0><<<ghb, 512, SMEM_HB>>>(Hp, wv + l * DD, bv + (size_t)l * Dq, Vp, Dq, Dq, l);
            flash_tc<0><<<dim3(Sq / 128, Hh, Bq), 256, FL_SMEM0>>>();
            gemm_hb<1><<<ghb, 512, SMEM_HB>>>(Yp, wo + l * DD, bo + (size_t)l * Dq, Xp, Dq, Dq, l);
        }

        // --- MoE block ---
        ln_kernel<<<TOK, 256>>>(ln2_w + (size_t)l * Dq, ln2_b + (size_t)l * Dq);
        if (l % 2 == 0) {
            gate_token_kernel<<<TOK / 4, 128>>>(gate_w, gate_b, l);
        } else {
            xmean_kernel<<<dim3(Dq / 256, Bq), 256>>>();
            gate_seq_kernel<<<Bq, 256>>>(gate_w, gate_b, l);
        }
        zero_counts_kernel<<<1, 32>>>();
        assign_kernel<<<TOK / 256, 256>>>(l % 2);
        gemm_hb<2><<<dim3(DFFq / 256, TOK / 128, Ee), 512, SMEM_HB>>>(nullptr, e_w1, e_b1, nullptr, Dq, DFFq, l);
        gemm_hb<3><<<dim3(Dq / 256, TOK / 128, Ee), 512, SMEM_HB>>>(nullptr, e_w2, e_b2, nullptr, DFFq, Dq, l);
    }

    copy_out_kernel<<<nelem / 256, 256>>>((float*)d_out);
    (void)in_sizes; (void)n_in; (void)out_size;
}

// round 9
// speedup vs baseline: 9.1363x; 1.0604x over previous
#include <cuda_runtime.h>
#include <cuda_fp16.h>
#include <math.h>
#include <stdint.h>

#define Bq   4
#define Sq   1024
#define Dq   1024
#define Hh   16
#define HD   64
#define Ll   2
#define Ee   8
#define DFFq 4096
#define TOK  (Bq*Sq)   // 4096

// ---------------- static scratch ---------------------------------------------
__device__ float g_X[TOK*Dq];
__device__ float g_H[TOK*Dq];
__device__ float g_Q[TOK*Dq];
__device__ float g_K[TOK*Dq];
__device__ float g_V[TOK*Dq];
__device__ float g_Y[TOK*Dq];
__device__ float g_hidden[(size_t)Ee*TOK*DFFq];
__device__ float g_moeout[(size_t)Ee*TOK*Dq];    // 128MB: weighted expert outputs
__device__ int   g_counts[Ee];
__device__ int   g_tok[Ee*TOK];
__device__ float g_wt[Ee*TOK];
__device__ int   g_islot[TOK*2];                 // token -> (e*TOK+slot) x2
__device__ int   g_te[TOK*2];
__device__ float g_tw[TOK*2];
__device__ int   g_bsel[Bq*2];
__device__ float g_bw[Bq*2];
__device__ float g_xmean[Bq*Dq];

// ---------------- helpers ----------------------------------------------------
__device__ __forceinline__ void top2_of8(const float* lg, int& i1, int& i2,
                                         float& w1, float& w2) {
    i1 = 0; float v1 = lg[0];
#pragma unroll
    for (int e = 1; e < Ee; e++) if (lg[e] > v1) { v1 = lg[e]; i1 = e; }
    i2 = -1; float v2 = -3.0e38f;
#pragma unroll
    for (int e = 0; e < Ee; e++) if (e != i1 && lg[e] > v2) { v2 = lg[e]; i2 = e; }
    float ex = expf(v2 - v1);
    w1 = 1.0f / (1.0f + ex);
    w2 = ex / (1.0f + ex);
}
__device__ __forceinline__ float gelu_exact(float x) {
    return 0.5f * x * (1.0f + erff(x * 0.7071067811865476f));
}
__device__ __forceinline__ void mma_f16(float c[4], const uint32_t a[4],
                                        const uint32_t b[2]) {
    asm volatile(
        "mma.sync.aligned.m16n8k16.row.col.f32.f16.f16.f32 "
        "{%0,%1,%2,%3},{%4,%5,%6,%7},{%8,%9},{%0,%1,%2,%3};"
        : "+f"(c[0]), "+f"(c[1]), "+f"(c[2]), "+f"(c[3])
        : "r"(a[0]), "r"(a[1]), "r"(a[2]), "r"(a[3]), "r"(b[0]), "r"(b[1]));
}
__device__ __forceinline__ uint32_t pack_h2(__half a, __half b) {
    __half2 h = __halves2half2(a, b);
    return *(uint32_t*)&h;
}
__device__ __forceinline__ uint32_t pack_f2h(float a, float b) {
    return pack_h2(__float2half_rn(a), __float2half_rn(b));
}

// ---------------- simple kernels ---------------------------------------------
__global__ void copy_in_kernel(const float* __restrict__ src) {
    int i = blockIdx.x * 256 + threadIdx.x;
    g_X[i] = src[i];
}
__global__ void copy_out_kernel(float* __restrict__ dst) {
    int i = blockIdx.x * 256 + threadIdx.x;
    dst[i] = g_X[i];
}

__global__ void ln_kernel(const float* __restrict__ w, const float* __restrict__ b) {
    int t = blockIdx.x, tid = threadIdx.x;
    const float* xr = g_X + (size_t)t * Dq;
    float s = 0.f, s2 = 0.f;
    for (int d = tid; d < Dq; d += 256) { float v = xr[d]; s += v; s2 += v * v; }
    __shared__ float r1[256], r2[256];
    r1[tid] = s; r2[tid] = s2; __syncthreads();
    for (int off = 128; off; off >>= 1) {
        if (tid < off) { r1[tid] += r1[tid + off]; r2[tid] += r2[tid + off]; }
        __syncthreads();
    }
    float mean = r1[0] * (1.0f / Dq);
    float var  = r2[0] * (1.0f / Dq) - mean * mean;
    float rstd = rsqrtf(var + 1e-5f);
    float* hr = g_H + (size_t)t * Dq;
    for (int d = tid; d < Dq; d += 256)
        hr[d] = (xr[d] - mean) * rstd * w[d] + b[d];
}

// ---------------- fp16 3-pass split GEMM (layer-0 path, 128x128, 512 thr) ----
#define T2W 136
#define T2SZ (8*T2W)
#define H3BUF (4*T2SZ)
#define SMEM_H3 ((256 + 2*H3BUF) * 4)   // 35840 B

template<int MODE>
__global__ void __launch_bounds__(512, 1)
gemm_h3(const float* __restrict__ A, const float* __restrict__ Wall,
        const float* __restrict__ ball, float* __restrict__ Cp,
        int Kd, int N, int layer) {
    extern __shared__ float smf[];
    uint32_t* tiles = (uint32_t*)(smf + 256);

    int tid = threadIdx.x;
    int rowBase = blockIdx.y * 128, colBase = blockIdx.x * 128;
    const float* bias = ball;

    int lrA = tid >> 2, kcA4 = (tid & 3) << 2, kpA = (tid & 3) << 1;
    const float* Ap = A + (size_t)(rowBase + lrA) * Kd + kcA4;
    int kpB = tid >> 6, nB = (tid & 63) << 1;
    const float* Wp = Wall + (size_t)(2 * kpB) * N + colBase + nB;

    int lane = tid & 31, warp = tid >> 5;
    int wm = (warp & 3) * 32, wn = (warp >> 2) * 32;
    int gid = lane >> 2, tig = lane & 3;

    float acc[2][4][4];
#pragma unroll
    for (int a = 0; a < 2; a++)
#pragma unroll
        for (int b2 = 0; b2 < 4; b2++)
#pragma unroll
            for (int c = 0; c < 4; c++) acc[a][b2][c] = 0.f;

    int nk = Kd / 16;
    float4 av;
    float2 br0, br1;
    av  = *(const float4*)(Ap);
    br0 = *(const float2*)(Wp);
    br1 = *(const float2*)(Wp + N);

    {
        uint32_t* Ahi = tiles;
        uint32_t* Alo = tiles + T2SZ;
        uint32_t* Bhi = tiles + 2 * T2SZ;
        uint32_t* Blo = tiles + 3 * T2SZ;
        __half h0 = __float2half_rn(av.x), h1 = __float2half_rn(av.y);
        __half h2 = __float2half_rn(av.z), h3 = __float2half_rn(av.w);
        Ahi[kpA * T2W + lrA]       = pack_h2(h0, h1);
        Ahi[(kpA + 1) * T2W + lrA] = pack_h2(h2, h3);
        Alo[kpA * T2W + lrA]       = pack_f2h(av.x - __half2float(h0), av.y - __half2float(h1));
        Alo[(kpA + 1) * T2W + lrA] = pack_f2h(av.z - __half2float(h2), av.w - __half2float(h3));
        __half w00 = __float2half_rn(br0.x), w10 = __float2half_rn(br1.x);
        __half w01 = __float2half_rn(br0.y), w11 = __float2half_rn(br1.y);
        Bhi[kpB * T2W + nB]     = pack_h2(w00, w10);
        Bhi[kpB * T2W + nB + 1] = pack_h2(w01, w11);
        Blo[kpB * T2W + nB]     = pack_f2h(br0.x - __half2float(w00), br1.x - __half2float(w10));
        Blo[kpB * T2W + nB + 1] = pack_f2h(br0.y - __half2float(w01), br1.y - __half2float(w11));
    }
    __syncthreads();

    for (int t = 0; t < nk; t++) {
        if (t + 1 < nk) {
            av  = *(const float4*)(Ap + (size_t)(t + 1) * 16);
            const float* w2 = Wp + (size_t)(t + 1) * 16 * N;
            br0 = *(const float2*)(w2);
            br1 = *(const float2*)(w2 + N);
        }
        int s = t & 1;
        const uint32_t* Ahi = tiles + s * H3BUF;
        const uint32_t* Alo = Ahi + T2SZ;
        const uint32_t* Bhi = Ahi + 2 * T2SZ;
        const uint32_t* Blo = Ahi + 3 * T2SZ;

        uint32_t ah[2][4], al[2][4], bh[4][2], bl[4][2];
#pragma unroll
        for (int mt = 0; mt < 2; mt++) {
            int m0 = wm + mt * 16 + gid;
            ah[mt][0] = Ahi[tig * T2W + m0];
            ah[mt][1] = Ahi[tig * T2W + m0 + 8];
            ah[mt][2] = Ahi[(tig + 4) * T2W + m0];
            ah[mt][3] = Ahi[(tig + 4) * T2W + m0 + 8];
            al[mt][0] = Alo[tig * T2W + m0];
            al[mt][1] = Alo[tig * T2W + m0 + 8];
            al[mt][2] = Alo[(tig + 4) * T2W + m0];
            al[mt][3] = Alo[(tig + 4) * T2W + m0 + 8];
        }
#pragma unroll
        for (int nt = 0; nt < 4; nt++) {
            int n0 = wn + nt * 8 + gid;
            bh[nt][0] = Bhi[tig * T2W + n0];
            bh[nt][1] = Bhi[(tig + 4) * T2W + n0];
            bl[nt][0] = Blo[tig * T2W + n0];
            bl[nt][1] = Blo[(tig + 4) * T2W + n0];
        }
#pragma unroll
        for (int mt = 0; mt < 2; mt++)
#pragma unroll
            for (int nt = 0; nt < 4; nt++)
                mma_f16(acc[mt][nt], ah[mt], bh[nt]);
#pragma unroll
        for (int mt = 0; mt < 2; mt++)
#pragma unroll
            for (int nt = 0; nt < 4; nt++)
                mma_f16(acc[mt][nt], ah[mt], bl[nt]);
#pragma unroll
        for (int mt = 0; mt < 2; mt++)
#pragma unroll
            for (int nt = 0; nt < 4; nt++)
                mma_f16(acc[mt][nt], al[mt], bh[nt]);

        if (t + 1 < nk) {
            int s2 = s ^ 1;
            uint32_t* Ahi2 = tiles + s2 * H3BUF;
            uint32_t* Alo2 = Ahi2 + T2SZ;
            uint32_t* Bhi2 = Ahi2 + 2 * T2SZ;
            uint32_t* Blo2 = Ahi2 + 3 * T2SZ;
            __half h0 = __float2half_rn(av.x), h1 = __float2half_rn(av.y);
            __half h2 = __float2half_rn(av.z), h3 = __float2half_rn(av.w);
            Ahi2[kpA * T2W + lrA]       = pack_h2(h0, h1);
            Ahi2[(kpA + 1) * T2W + lrA] = pack_h2(h2, h3);
            Alo2[kpA * T2W + lrA]       = pack_f2h(av.x - __half2float(h0), av.y - __half2float(h1));
            Alo2[(kpA + 1) * T2W + lrA] = pack_f2h(av.z - __half2float(h2), av.w - __half2float(h3));
            __half w00 = __float2half_rn(br0.x), w10 = __float2half_rn(br1.x);
            __half w01 = __float2half_rn(br0.y), w11 = __float2half_rn(br1.y);
            Bhi2[kpB * T2W + nB]     = pack_h2(w00, w10);
            Bhi2[kpB * T2W + nB + 1] = pack_h2(w01, w11);
            Blo2[kpB * T2W + nB]     = pack_f2h(br0.x - __half2float(w00), br1.x - __half2float(w10));
            Blo2[kpB * T2W + nB + 1] = pack_f2h(br0.y - __half2float(w01), br1.y - __half2float(w11));
        }
        __syncthreads();
    }

#pragma unroll
    for (int mt = 0; mt < 2; mt++) {
#pragma unroll
        for (int c = 0; c < 4; c++) {
            int r = rowBase + wm + mt * 16 + gid + ((c & 2) ? 8 : 0);
#pragma unroll
            for (int nt = 0; nt < 4; nt++) {
                int cg = colBase + wn + nt * 8 + tig * 2 + (c & 1);
                float v = acc[mt][nt][c] + bias[cg];
                if (MODE == 1) v += Cp[(size_t)r * N + cg];
                Cp[(size_t)r * N + cg] = v;
            }
        }
    }
}

// ---------------- fp16 1-pass big-tile GEMM (128x256, 512 thr) ---------------
// MODE 0: C = A@W + bias    MODE 1: C += Res   MODE 2: MoE GEMM1 (GELU)
// MODE 3: MoE GEMM2 -> g_moeout (weighted, plain stores)
#define HB_AW 136
#define HB_BW 264
#define HB_AT (8*HB_AW)
#define HB_BT (8*HB_BW)
#define HB_BUF (HB_AT+HB_BT)
#define SMEM_HB ((256 + 2*HB_BUF) * 4)   // 26624 B

template<int MODE>
__global__ void __launch_bounds__(512, 1)
gemm_hb(const float* __restrict__ A, const float* __restrict__ Wall,
        const float* __restrict__ ball, float* __restrict__ Cp,
        int Kd, int N, int layer) {
    extern __shared__ float smf[];
    int*   s_tok = (int*)smf;
    float* s_wt  = smf + 128;
    uint32_t* tiles = (uint32_t*)(smf + 256);

    int tid = threadIdx.x;
    int rowBase = blockIdx.y * 128, colBase = blockIdx.x * 256;

    int e = 0, cnt = 0;
    const float* W = Wall;
    const float* bias = ball;
    if (MODE >= 2) {
        e = blockIdx.z;
        cnt = g_counts[e];
        if (rowBase >= cnt) return;
        W    = Wall + (size_t)(layer * Ee + e) * Kd * N;
        bias = ball + (size_t)(layer * Ee + e) * N;
        if (tid < 128) {
            int r = rowBase + tid;
            int rc = r < cnt ? r : cnt - 1;
            s_tok[tid] = g_tok[e * TOK + rc];
            s_wt[tid]  = g_wt [e * TOK + rc];
        }
        __syncthreads();
    }

    int lrA = tid >> 2, kcA4 = (tid & 3) << 2, kpA = (tid & 3) << 1;
    const float* Ap;
    if (MODE == 2)      Ap = g_H + (size_t)s_tok[lrA] * Kd + kcA4;
    else if (MODE == 3) Ap = g_hidden + ((size_t)e * TOK + rowBase + lrA) * Kd + kcA4;
    else                Ap = A + (size_t)(rowBase + lrA) * Kd + kcA4;

    int kpB = tid >> 6, nB4 = (tid & 63) << 2;
    const float* Wp = W + (size_t)(2 * kpB) * N + colBase + nB4;

    int lane = tid & 31, warp = tid >> 5;
    int wm = (warp & 1) * 64, wn = (warp >> 1) * 32;
    int gid = lane >> 2, tig = lane & 3;

    float acc[4][4][4];
#pragma unroll
    for (int a = 0; a < 4; a++)
#pragma unroll
        for (int b2 = 0; b2 < 4; b2++)
#pragma unroll
            for (int c = 0; c < 4; c++) acc[a][b2][c] = 0.f;

    int nk = Kd / 16;
    float4 av, bv0, bv1;
    av  = *(const float4*)(Ap);
    bv0 = *(const float4*)(Wp);
    bv1 = *(const float4*)(Wp + N);
    {
        uint32_t* As = tiles;
        uint32_t* Bs = tiles + HB_AT;
        As[kpA * HB_AW + lrA]       = pack_f2h(av.x, av.y);
        As[(kpA + 1) * HB_AW + lrA] = pack_f2h(av.z, av.w);
        Bs[kpB * HB_BW + nB4 + 0] = pack_f2h(bv0.x, bv1.x);
        Bs[kpB * HB_BW + nB4 + 1] = pack_f2h(bv0.y, bv1.y);
        Bs[kpB * HB_BW + nB4 + 2] = pack_f2h(bv0.z, bv1.z);
        Bs[kpB * HB_BW + nB4 + 3] = pack_f2h(bv0.w, bv1.w);
    }
    __syncthreads();

    for (int t = 0; t < nk; t++) {
        if (t + 1 < nk) {
            av  = *(const float4*)(Ap + (size_t)(t + 1) * 16);
            const float* w2 = Wp + (size_t)(t + 1) * 16 * N;
            bv0 = *(const float4*)(w2);
            bv1 = *(const float4*)(w2 + N);
        }
        int s = t & 1;
        const uint32_t* As = tiles + s * HB_BUF;
        const uint32_t* Bs = As + HB_AT;

        uint32_t af[4][4], bf[4][2];
#pragma unroll
        for (int mt = 0; mt < 4; mt++) {
            int m0 = wm + mt * 16 + gid;
            af[mt][0] = As[tig * HB_AW + m0];
            af[mt][1] = As[tig * HB_AW + m0 + 8];
            af[mt][2] = As[(tig + 4) * HB_AW + m0];
            af[mt][3] = As[(tig + 4) * HB_AW + m0 + 8];
        }
#pragma unroll
        for (int nt = 0; nt < 4; nt++) {
            int n0 = wn + nt * 8 + gid;
            bf[nt][0] = Bs[tig * HB_BW + n0];
            bf[nt][1] = Bs[(tig + 4) * HB_BW + n0];
        }
#pragma unroll
        for (int mt = 0; mt < 4; mt++)
#pragma unroll
            for (int nt = 0; nt < 4; nt++)
                mma_f16(acc[mt][nt], af[mt], bf[nt]);

        if (t + 1 < nk) {
            int s2 = s ^ 1;
            uint32_t* As2 = tiles + s2 * HB_BUF;
            uint32_t* Bs2 = As2 + HB_AT;
            As2[kpA * HB_AW + lrA]       = pack_f2h(av.x, av.y);
            As2[(kpA + 1) * HB_AW + lrA] = pack_f2h(av.z, av.w);
            Bs2[kpB * HB_BW + nB4 + 0] = pack_f2h(bv0.x, bv1.x);
            Bs2[kpB * HB_BW + nB4 + 1] = pack_f2h(bv0.y, bv1.y);
            Bs2[kpB * HB_BW + nB4 + 2] = pack_f2h(bv0.z, bv1.z);
            Bs2[kpB * HB_BW + nB4 + 3] = pack_f2h(bv0.w, bv1.w);
        }
        __syncthreads();
    }

#pragma unroll
    for (int mt = 0; mt < 4; mt++) {
#pragma unroll
        for (int c = 0; c < 4; c++) {
            int rl = wm + mt * 16 + gid + ((c & 2) ? 8 : 0);
            int r  = rowBase + rl;
#pragma unroll
            for (int nt = 0; nt < 4; nt++) {
                int cg = colBase + wn + nt * 8 + tig * 2 + (c & 1);
                float v = acc[mt][nt][c] + bias[cg];
                if (MODE == 0) {
                    Cp[(size_t)r * N + cg] = v;
                } else if (MODE == 1) {
                    Cp[(size_t)r * N + cg] = v + Cp[(size_t)r * N + cg];
                } else if (MODE == 2) {
                    if (r < cnt)
                        g_hidden[((size_t)e * TOK + r) * N + cg] = gelu_exact(v);
                } else {
                    g_moeout[((size_t)(e * TOK + r)) * N + cg] = v * s_wt[rl];
                }
            }
        }
    }
}

// MoE combine: x[t] += moeout[slot1] + moeout[slot2]   (float4, no atomics)
__global__ void moe_combine() {
    int i = blockIdx.x * 256 + threadIdx.x;     // over TOK*Dq/4
    int t = i >> 8;
    int c4 = (i & 255) << 2;
    int s0 = g_islot[t * 2], s1 = g_islot[t * 2 + 1];
    float4 a = *(const float4*)&g_moeout[(size_t)s0 * Dq + c4];
    float4 b = *(const float4*)&g_moeout[(size_t)s1 * Dq + c4];
    float4 x = *(float4*)&g_X[(size_t)t * Dq + c4];
    x.x += a.x + b.x; x.y += a.y + b.y; x.z += a.z + b.z; x.w += a.w + b.w;
    *(float4*)&g_X[(size_t)t * Dq + c4] = x;
}

// ---------------- fp16 tensor-core flash attention ---------------------------
// 128-q block, 8 warps x m16, m16n8k16. SPLIT=1: fp16 3-pass Dekker split.
// half2-kpair layouts: Q2[dpair][m](136), K2[dpair][n](72), V2[kpair][d](72),
// P2[kpair][m](136)
#define FQ2 (32*136)
#define FK2 (32*72)
#define FV2 (32*72)
#define FP2 (32*136)
#define FL2_TOT (FQ2+FK2+FV2+FP2)        // 13312 u32
#define FL2_SMEM0 (FL2_TOT*4)             // 53248 B
#define FL2_SMEM1 (FL2_TOT*8)             // 106496 B

template<int SPLIT>
__global__ void __launch_bounds__(256)
flash_h() {
    extern __shared__ uint32_t fu[];
    uint32_t* Qh = fu;
    uint32_t* Ql = Qh + FQ2;
    uint32_t* Kh = Qh + FQ2 * (SPLIT + 1);
    uint32_t* Kl = Kh + FK2;
    uint32_t* Vh = Kh + FK2 * (SPLIT + 1);
    uint32_t* Vl = Vh + FV2;
    uint32_t* Ph = Vh + FV2 * (SPLIT + 1);
    uint32_t* Pl = Ph + FP2;

    int qb = blockIdx.x, h = blockIdx.y, b = blockIdx.z;
    int tid = threadIdx.x, warp = tid >> 5, lane = tid & 31;
    int gid = lane >> 2, tig = lane & 3;
    int mrow = warp * 16 + gid;

    // load Q (128 x 64) -> Q2[dpair][m]
    for (int i = tid; i < 2048; i += 256) {
        int r = i >> 4, d4 = (i & 15) << 2, dp = (i & 15) << 1;
        float4 v = *(const float4*)&g_Q[((size_t)(b * Sq + qb * 128 + r)) * Dq + h * HD + d4];
        __half h0 = __float2half_rn(v.x), h1 = __float2half_rn(v.y);
        __half h2 = __float2half_rn(v.z), h3 = __float2half_rn(v.w);
        Qh[dp * 136 + r]       = pack_h2(h0, h1);
        Qh[(dp + 1) * 136 + r] = pack_h2(h2, h3);
        if (SPLIT) {
            Ql[dp * 136 + r]       = pack_f2h(v.x - __half2float(h0), v.y - __half2float(h1));
            Ql[(dp + 1) * 136 + r] = pack_f2h(v.z - __half2float(h2), v.w - __half2float(h3));
        }
    }

    float mA = -1e30f, mB = -1e30f, lA = 0.f, lB = 0.f;
    float o[8][4];
#pragma unroll
    for (int nt = 0; nt < 8; nt++)
#pragma unroll
        for (int c = 0; c < 4; c++) o[nt][c] = 0.f;

    int nkt = 2 * qb + 2;
    for (int kt = 0; kt < nkt; kt++) {
        __syncthreads();
        // K: K2[dpair][n]
        for (int i = tid; i < 1024; i += 256) {
            int r = i >> 4, d4 = (i & 15) << 2, dp = (i & 15) << 1;
            size_t base = ((size_t)(b * Sq + kt * 64 + r)) * Dq + h * HD + d4;
            float4 kv = *(const float4*)&g_K[base];
            __half h0 = __float2half_rn(kv.x), h1 = __float2half_rn(kv.y);
            __half h2 = __float2half_rn(kv.z), h3 = __float2half_rn(kv.w);
            Kh[dp * 72 + r]       = pack_h2(h0, h1);
            Kh[(dp + 1) * 72 + r] = pack_h2(h2, h3);
            if (SPLIT) {
                Kl[dp * 72 + r]       = pack_f2h(kv.x - __half2float(h0), kv.y - __half2float(h1));
                Kl[(dp + 1) * 72 + r] = pack_f2h(kv.z - __half2float(h2), kv.w - __half2float(h3));
            }
        }
        // V: V2[kpair][d] packs rows (2kp, 2kp+1)
        for (int i = tid; i < 512; i += 256) {
            int kp = i >> 4, d4 = (i & 15) << 2;
            size_t base0 = ((size_t)(b * Sq + kt * 64 + 2 * kp)) * Dq + h * HD + d4;
            float4 v0 = *(const float4*)&g_V[base0];
            float4 v1 = *(const float4*)&g_V[base0 + Dq];
            float a0[4] = {v0.x, v0.y, v0.z, v0.w};
            float a1[4] = {v1.x, v1.y, v1.z, v1.w};
#pragma unroll
            for (int j = 0; j < 4; j++) {
                __half p0 = __float2half_rn(a0[j]), p1 = __float2half_rn(a1[j]);
                Vh[kp * 72 + d4 + j] = pack_h2(p0, p1);
                if (SPLIT)
                    Vl[kp * 72 + d4 + j] = pack_f2h(a0[j] - __half2float(p0),
                                                    a1[j] - __half2float(p1));
            }
        }
        __syncthreads();

        // S = Q @ K^T
        float s[8][4];
#pragma unroll
        for (int nt = 0; nt < 8; nt++)
#pragma unroll
            for (int c = 0; c < 4; c++) s[nt][c] = 0.f;

#pragma unroll
        for (int ks = 0; ks < 4; ks++) {
            int kp0 = 8 * ks + tig, kp1 = 8 * ks + tig + 4;
            uint32_t a[4], al[4];
            a[0] = Qh[kp0 * 136 + mrow];
            a[1] = Qh[kp0 * 136 + mrow + 8];
            a[2] = Qh[kp1 * 136 + mrow];
            a[3] = Qh[kp1 * 136 + mrow + 8];
            if (SPLIT) {
                al[0] = Ql[kp0 * 136 + mrow];
                al[1] = Ql[kp0 * 136 + mrow + 8];
                al[2] = Ql[kp1 * 136 + mrow];
                al[3] = Ql[kp1 * 136 + mrow + 8];
            }
#pragma unroll
            for (int gq = 0; gq < 2; gq++) {
                uint32_t bb[4][2], bl[4][2];
#pragma unroll
                for (int j = 0; j < 4; j++) {
                    int n0 = (gq * 4 + j) * 8 + gid;
                    bb[j][0] = Kh[kp0 * 72 + n0];
                    bb[j][1] = Kh[kp1 * 72 + n0];
                    if (SPLIT) {
                        bl[j][0] = Kl[kp0 * 72 + n0];
                        bl[j][1] = Kl[kp1 * 72 + n0];
                    }
                }
#pragma unroll
                for (int j = 0; j < 4; j++) mma_f16(s[gq * 4 + j], a, bb[j]);
                if (SPLIT) {
#pragma unroll
                    for (int j = 0; j < 4; j++) mma_f16(s[gq * 4 + j], a, bl[j]);
#pragma unroll
                    for (int j = 0; j < 4; j++) mma_f16(s[gq * 4 + j], al, bb[j]);
                }
            }
        }

        int rowg = qb * 128 + warp * 16 + gid;
        if (kt * 64 + 63 > rowg) {
#pragma unroll
            for (int nt = 0; nt < 8; nt++)
#pragma unroll
                for (int c = 0; c < 4; c++) {
                    int col = kt * 64 + nt * 8 + 2 * tig + (c & 1);
                    int row = rowg + ((c & 2) ? 8 : 0);
                    float sv = s[nt][c] * 0.125f;
                    s[nt][c] = (col > row) ? -1e30f : sv;
                }
        } else {
#pragma unroll
            for (int nt = 0; nt < 8; nt++)
#pragma unroll
                for (int c = 0; c < 4; c++) s[nt][c] *= 0.125f;
        }

        float rmA = -1e30f, rmB = -1e30f;
#pragma unroll
        for (int nt = 0; nt < 8; nt++) {
            rmA = fmaxf(rmA, fmaxf(s[nt][0], s[nt][1]));
            rmB = fmaxf(rmB, fmaxf(s[nt][2], s[nt][3]));
        }
#pragma unroll
        for (int off = 1; off < 4; off <<= 1) {
            rmA = fmaxf(rmA, __shfl_xor_sync(0xffffffffu, rmA, off));
            rmB = fmaxf(rmB, __shfl_xor_sync(0xffffffffu, rmB, off));
        }
        float mnA = fmaxf(mA, rmA), mnB = fmaxf(mB, rmB);
        float alA = __expf(mA - mnA), alB = __expf(mB - mnB);
        float rsA = 0.f, rsB = 0.f;
#pragma unroll
        for (int nt = 0; nt < 8; nt++) {
            s[nt][0] = __expf(s[nt][0] - mnA); rsA += s[nt][0];
            s[nt][1] = __expf(s[nt][1] - mnA); rsA += s[nt][1];
            s[nt][2] = __expf(s[nt][2] - mnB); rsB += s[nt][2];
            s[nt][3] = __expf(s[nt][3] - mnB); rsB += s[nt][3];
        }
#pragma unroll
        for (int off = 1; off < 4; off <<= 1) {
            rsA += __shfl_xor_sync(0xffffffffu, rsA, off);
            rsB += __shfl_xor_sync(0xffffffffu, rsB, off);
        }
        lA = lA * alA + rsA; mA = mnA;
        lB = lB * alB + rsB; mB = mnB;
#pragma unroll
        for (int nt = 0; nt < 8; nt++) {
            o[nt][0] *= alA; o[nt][1] *= alA;
            o[nt][2] *= alB; o[nt][3] *= alB;
        }

        // stage P -> P2[kpair][m] (warp-private rows)
        __syncwarp();
#pragma unroll
        for (int nt = 0; nt < 8; nt++) {
            int kpP = nt * 4 + tig;
            __half p0 = __float2half_rn(s[nt][0]), p1 = __float2half_rn(s[nt][1]);
            __half p2 = __float2half_rn(s[nt][2]), p3 = __float2half_rn(s[nt][3]);
            Ph[kpP * 136 + mrow]     = pack_h2(p0, p1);
            Ph[kpP * 136 + mrow + 8] = pack_h2(p2, p3);
            if (SPLIT) {
                Pl[kpP * 136 + mrow]     = pack_f2h(s[nt][0] - __half2float(p0),
                                                    s[nt][1] - __half2float(p1));
                Pl[kpP * 136 + mrow + 8] = pack_f2h(s[nt][2] - __half2float(p2),
                                                    s[nt][3] - __half2float(p3));
            }
        }
        __syncwarp();

        // O += P @ V
#pragma unroll
        for (int ks = 0; ks < 4; ks++) {
            int kp0 = 8 * ks + tig, kp1 = 8 * ks + tig + 4;
            uint32_t a[4], al[4];
            a[0] = Ph[kp0 * 136 + mrow];
            a[1] = Ph[kp0 * 136 + mrow + 8];
            a[2] = Ph[kp1 * 136 + mrow];
            a[3] = Ph[kp1 * 136 + mrow + 8];
            if (SPLIT) {
                al[0] = Pl[kp0 * 136 + mrow];
                al[1] = Pl[kp0 * 136 + mrow + 8];
                al[2] = Pl[kp1 * 136 + mrow];
                al[3] = Pl[kp1 * 136 + mrow + 8];
            }
#pragma unroll
            for (int gq = 0; gq < 2; gq++) {
                uint32_t bb[4][2], bl[4][2];
#pragma unroll
                for (int j = 0; j < 4; j++) {
                    int n0 = (gq * 4 + j) * 8 + gid;
                    bb[j][0] = Vh[kp0 * 72 + n0];
                    bb[j][1] = Vh[kp1 * 72 + n0];
                    if (SPLIT) {
                        bl[j][0] = Vl[kp0 * 72 + n0];
                        bl[j][1] = Vl[kp1 * 72 + n0];
                    }
                }
#pragma unroll
                for (int j = 0; j < 4; j++) mma_f16(o[gq * 4 + j], a, bb[j]);
                if (SPLIT) {
#pragma unroll
                    for (int j = 0; j < 4; j++) mma_f16(o[gq * 4 + j], a, bl[j]);
#pragma unroll
                    for (int j = 0; j < 4; j++) mma_f16(o[gq * 4 + j], al, bb[j]);
                }
            }
        }
    }

    float invA = 1.0f / lA, invB = 1.0f / lB;
    size_t rbase0 = ((size_t)(b * Sq + qb * 128 + warp * 16 + gid)) * Dq + h * HD;
    size_t rbase1 = rbase0 + (size_t)8 * Dq;
#pragma unroll
    for (int nt = 0; nt < 8; nt++) {
        int d0 = nt * 8 + 2 * tig;
        *(float2*)&g_Y[rbase0 + d0] = make_float2(o[nt][0] * invA, o[nt][1] * invA);
        *(float2*)&g_Y[rbase1 + d0] = make_float2(o[nt][2] * invB, o[nt][3] * invB);
    }
}

// ---------------- gating -----------------------------------------------------
__global__ void gate_token_kernel(const float* __restrict__ gw,
                                  const float* __restrict__ gb, int layer) {
    int t = blockIdx.x * 4 + (threadIdx.x >> 5);
    int lane = threadIdx.x & 31;
    if (t >= TOK) return;
    const float* hrow = g_H + (size_t)t * Dq;
    const float* gwl = gw + (size_t)layer * Dq * Ee;
    float acc[Ee] = {};
    for (int d = lane; d < Dq; d += 32) {
        float hv = hrow[d];
        const float* g = gwl + (size_t)d * Ee;
#pragma unroll
        for (int e = 0; e < Ee; e++) acc[e] += hv * g[e];
    }
#pragma unroll
    for (int e = 0; e < Ee; e++)
        for (int off = 16; off; off >>= 1)
            acc[e] += __shfl_xor_sync(0xffffffffu, acc[e], off);
    if (lane == 0) {
        float lg[Ee];
#pragma unroll
        for (int e = 0; e < Ee; e++) lg[e] = acc[e] + gb[layer * Ee + e];
        int i1, i2; float w1, w2;
        top2_of8(lg, i1, i2, w1, w2);
        g_te[t * 2] = i1; g_te[t * 2 + 1] = i2;
        g_tw[t * 2] = w1; g_tw[t * 2 + 1] = w2;
    }
}

__global__ void xmean_kernel() {
    int b = blockIdx.y;
    int d = blockIdx.x * 256 + threadIdx.x;
    float s = 0.f;
    for (int ss = 0; ss < Sq; ss++)
        s += g_H[((size_t)(b * Sq + ss)) * Dq + d];
    g_xmean[b * Dq + d] = s * (1.0f / Sq);
}

__global__ void gate_seq_kernel(const float* __restrict__ gw,
                                const float* __restrict__ gb, int layer) {
    int b = blockIdx.x;
    int tid = threadIdx.x, e = tid >> 5, lane = tid & 31;
    const float* gwl = gw + (size_t)layer * Dq * Ee;
    float acc = 0.f;
    for (int d = lane; d < Dq; d += 32)
        acc += g_xmean[b * Dq + d] * gwl[(size_t)d * Ee + e];
    for (int off = 16; off; off >>= 1)
        acc += __shfl_xor_sync(0xffffffffu, acc, off);
    __shared__ float lg[Ee];
    if (lane == 0) lg[e] = acc + gb[layer * Ee + e];
    __syncthreads();
    if (tid == 0) {
        int i1, i2; float w1, w2;
        top2_of8(lg, i1, i2, w1, w2);
        g_bsel[b * 2] = i1; g_bsel[b * 2 + 1] = i2;
        g_bw[b * 2] = w1;  g_bw[b * 2 + 1] = w2;
    }
}

__global__ void zero_counts_kernel() {
    if (threadIdx.x < Ee) g_counts[threadIdx.x] = 0;
}

__global__ void assign_kernel(int seq_mode) {
    int t = blockIdx.x * 256 + threadIdx.x;
    if (t >= TOK) return;
    int e1, e2; float w1, w2;
    if (seq_mode) {
        int b = t / Sq;
        e1 = g_bsel[b * 2]; e2 = g_bsel[b * 2 + 1];
        w1 = g_bw[b * 2];   w2 = g_bw[b * 2 + 1];
    } else {
        e1 = g_te[t * 2]; e2 = g_te[t * 2 + 1];
        w1 = g_tw[t * 2]; w2 = g_tw[t * 2 + 1];
    }
    int s1 = atomicAdd(&g_counts[e1], 1);
    g_tok[e1 * TOK + s1] = t; g_wt[e1 * TOK + s1] = w1;
    g_islot[t * 2] = e1 * TOK + s1;
    int s2 = atomicAdd(&g_counts[e2], 1);
    g_tok[e2 * TOK + s2] = t; g_wt[e2 * TOK + s2] = w2;
    g_islot[t * 2 + 1] = e2 * TOK + s2;
}

// ---------------- host side --------------------------------------------------
extern "C" void kernel_launch(void* const* d_in, const int* in_sizes, int n_in,
                              void* d_out, int out_size) {
    const float* x      = (const float*)d_in[0];
    const float* ln1_w  = (const float*)d_in[1];
    const float* ln1_b  = (const float*)d_in[2];
    const float* ln2_w  = (const float*)d_in[3];
    const float* ln2_b  = (const float*)d_in[4];
    const float* wq     = (const float*)d_in[5];
    const float* wk     = (const float*)d_in[6];
    const float* wv     = (const float*)d_in[7];
    const float* wo     = (const float*)d_in[8];
    const float* bq     = (const float*)d_in[9];
    const float* bk     = (const float*)d_in[10];
    const float* bv     = (const float*)d_in[11];
    const float* bo     = (const float*)d_in[12];
    const float* gate_w = (const float*)d_in[13];
    const float* gate_b = (const float*)d_in[14];
    const float* e_w1   = (const float*)d_in[15];
    const float* e_b1   = (const float*)d_in[16];
    const float* e_w2   = (const float*)d_in[17];
    const float* e_b2   = (const float*)d_in[18];

    float *Xp, *Hp, *Qp, *Kp, *Vp, *Yp;
    cudaGetSymbolAddress((void**)&Xp, g_X);
    cudaGetSymbolAddress((void**)&Hp, g_H);
    cudaGetSymbolAddress((void**)&Qp, g_Q);
    cudaGetSymbolAddress((void**)&Kp, g_K);
    cudaGetSymbolAddress((void**)&Vp, g_V);
    cudaGetSymbolAddress((void**)&Yp, g_Y);

    static int attr_set = 0;
    if (!attr_set) {
        cudaFuncSetAttribute(gemm_h3<0>, cudaFuncAttributeMaxDynamicSharedMemorySize, SMEM_H3);
        cudaFuncSetAttribute(gemm_h3<1>, cudaFuncAttributeMaxDynamicSharedMemorySize, SMEM_H3);
        cudaFuncSetAttribute(gemm_hb<0>, cudaFuncAttributeMaxDynamicSharedMemorySize, SMEM_HB);
        cudaFuncSetAttribute(gemm_hb<1>, cudaFuncAttributeMaxDynamicSharedMemorySize, SMEM_HB);
        cudaFuncSetAttribute(gemm_hb<2>, cudaFuncAttributeMaxDynamicSharedMemorySize, SMEM_HB);
        cudaFuncSetAttribute(gemm_hb<3>, cudaFuncAttributeMaxDynamicSharedMemorySize, SMEM_HB);
        cudaFuncSetAttribute(flash_h<0>, cudaFuncAttributeMaxDynamicSharedMemorySize, FL2_SMEM0);
        cudaFuncSetAttribute(flash_h<1>, cudaFuncAttributeMaxDynamicSharedMemorySize, FL2_SMEM1);
        attr_set = 1;
    }

    const size_t DD = (size_t)Dq * Dq;
    const int nelem = TOK * Dq;

    copy_in_kernel<<<nelem / 256, 256>>>(x);

    dim3 gsplit(Dq / 128, TOK / 128);          // 8 x 32
    dim3 ghb(Dq / 256, TOK / 128);             // 4 x 32
    for (int l = 0; l < Ll; l++) {
        // --- attention block ---
        ln_kernel<<<TOK, 256>>>(ln1_w + (size_t)l * Dq, ln1_b + (size_t)l * Dq);
        if (l == 0) {
            gemm_h3<0><<<gsplit, 512, SMEM_H3>>>(Hp, wq + l * DD, bq + (size_t)l * Dq, Qp, Dq, Dq, l);
            gemm_h3<0><<<gsplit, 512, SMEM_H3>>>(Hp, wk + l * DD, bk + (size_t)l * Dq, Kp, Dq, Dq, l);
            gemm_h3<0><<<gsplit, 512, SMEM_H3>>>(Hp, wv + l * DD, bv + (size_t)l * Dq, Vp, Dq, Dq, l);
            flash_h<1><<<dim3(Sq / 128, Hh, Bq), 256, FL2_SMEM1>>>();
            gemm_h3<1><<<gsplit, 512, SMEM_H3>>>(Yp, wo + l * DD, bo + (size_t)l * Dq, Xp, Dq, Dq, l);
        } else {
            gemm_hb<0><<<ghb, 512, SMEM_HB>>>(Hp, wq + l * DD, bq + (size_t)l * Dq, Qp, Dq, Dq, l);
            gemm_hb<0><<<ghb, 512, SMEM_HB>>>(Hp, wk + l * DD, bk + (size_t)l * Dq, Kp, Dq, Dq, l);
            gemm_hb<0><<<ghb, 512, SMEM_HB>>>(Hp, wv + l * DD, bv + (size_t)l * Dq, Vp, Dq, Dq, l);
            flash_h<0><<<dim3(Sq / 128, Hh, Bq), 256, FL2_SMEM0>>>();
            gemm_hb<1><<<ghb, 512, SMEM_HB>>>(Yp, wo + l * DD, bo + (size_t)l * Dq, Xp, Dq, Dq, l);
        }

        // --- MoE block ---
        ln_kernel<<<TOK, 256>>>(ln2_w + (size_t)l * Dq, ln2_b + (size_t)l * Dq);
        if (l % 2 == 0) {
            gate_token_kernel<<<TOK / 4, 128>>>(gate_w, gate_b, l);
        } else {
            xmean_kernel<<<dim3(Dq / 256, Bq), 256>>>();
            gate_seq_kernel<<<Bq, 256>>>(gate_w, gate_b, l);
        }
        zero_counts_kernel<<<1, 32>>>();
        assign_kernel<<<TOK / 256, 256>>>(l % 2);
        gemm_hb<2><<<dim3(DFFq / 256, TOK / 128, Ee), 512, SMEM_HB>>>(nullptr, e_w1, e_b1, nullptr, Dq, DFFq, l);
        gemm_hb<3><<<dim3(Dq / 256, TOK / 128, Ee), 512, SMEM_HB>>>(nullptr, e_w2, e_b2, nullptr, DFFq, Dq, l);
        moe_combine<<<nelem / 1024, 256>>>();
    }

    copy_out_kernel<<<nelem / 256, 256>>>((float*)d_out);
    (void)in_sizes; (void)n_in; (void)out_size;
}

// round 10
// speedup vs baseline: 10.4687x; 1.1458x over previous
#include <cuda_runtime.h>
#include <cuda_fp16.h>
#include <math.h>
#include <stdint.h>

#define Bq   4
#define Sq   1024
#define Dq   1024
#define Hh   16
#define HD   64
#define Ll   2
#define Ee   8
#define DFFq 4096
#define TOK  (Bq*Sq)   // 4096

// ---------------- static scratch ---------------------------------------------
__device__ float g_X[TOK*Dq];
__device__ float g_H[TOK*Dq];
__device__ float g_Q[TOK*Dq];
__device__ float g_K[TOK*Dq];
__device__ float g_V[TOK*Dq];
__device__ float g_Y[TOK*Dq];
__device__ float g_hidden[(size_t)Ee*TOK*DFFq];
__device__ float g_moeout[(size_t)Ee*TOK*Dq];
__device__ int   g_counts[Ee];
__device__ int   g_tok[Ee*TOK];
__device__ float g_wt[Ee*TOK];
__device__ int   g_islot[TOK*2];
__device__ int   g_te[TOK*2];
__device__ float g_tw[TOK*2];
__device__ int   g_bsel[Bq*2];
__device__ float g_bw[Bq*2];
__device__ float g_xmean[Bq*Dq];

// ---------------- helpers ----------------------------------------------------
__device__ __forceinline__ void top2_of8(const float* lg, int& i1, int& i2,
                                         float& w1, float& w2) {
    i1 = 0; float v1 = lg[0];
#pragma unroll
    for (int e = 1; e < Ee; e++) if (lg[e] > v1) { v1 = lg[e]; i1 = e; }
    i2 = -1; float v2 = -3.0e38f;
#pragma unroll
    for (int e = 0; e < Ee; e++) if (e != i1 && lg[e] > v2) { v2 = lg[e]; i2 = e; }
    float ex = expf(v2 - v1);
    w1 = 1.0f / (1.0f + ex);
    w2 = ex / (1.0f + ex);
}
__device__ __forceinline__ float gelu_exact(float x) {
    return 0.5f * x * (1.0f + erff(x * 0.7071067811865476f));
}
__device__ __forceinline__ void mma_f16(float c[4], const uint32_t a[4],
                                        const uint32_t b[2]) {
    asm volatile(
        "mma.sync.aligned.m16n8k16.row.col.f32.f16.f16.f32 "
        "{%0,%1,%2,%3},{%4,%5,%6,%7},{%8,%9},{%0,%1,%2,%3};"
        : "+f"(c[0]), "+f"(c[1]), "+f"(c[2]), "+f"(c[3])
        : "r"(a[0]), "r"(a[1]), "r"(a[2]), "r"(a[3]), "r"(b[0]), "r"(b[1]));
}
__device__ __forceinline__ uint32_t pack_h2(__half a, __half b) {
    __half2 h = __halves2half2(a, b);
    return *(uint32_t*)&h;
}
__device__ __forceinline__ uint32_t pack_f2h(float a, float b) {
    return pack_h2(__float2half_rn(a), __float2half_rn(b));
}

// ---------------- simple kernels ---------------------------------------------
__global__ void copy_in_kernel(const float* __restrict__ src) {
    int i = blockIdx.x * 256 + threadIdx.x;
    g_X[i] = src[i];
}
__global__ void copy_out_kernel(float* __restrict__ dst) {
    int i = blockIdx.x * 256 + threadIdx.x;
    dst[i] = g_X[i];
}

__global__ void ln_kernel(const float* __restrict__ w, const float* __restrict__ b) {
    int t = blockIdx.x, tid = threadIdx.x;
    const float* xr = g_X + (size_t)t * Dq;
    float s = 0.f, s2 = 0.f;
    for (int d = tid; d < Dq; d += 256) { float v = xr[d]; s += v; s2 += v * v; }
    __shared__ float r1[256], r2[256];
    r1[tid] = s; r2[tid] = s2; __syncthreads();
    for (int off = 128; off; off >>= 1) {
        if (tid < off) { r1[tid] += r1[tid + off]; r2[tid] += r2[tid + off]; }
        __syncthreads();
    }
    float mean = r1[0] * (1.0f / Dq);
    float var  = r2[0] * (1.0f / Dq) - mean * mean;
    float rstd = rsqrtf(var + 1e-5f);
    float* hr = g_H + (size_t)t * Dq;
    for (int d = tid; d < Dq; d += 256)
        hr[d] = (xr[d] - mean) * rstd * w[d] + b[d];
}

// ---------------- fp16 3-pass split GEMM (layer-0, 128x128, BK=32) -----------
// MODE 0: fused QKV (blockIdx.z selects W/bias/C)   MODE 1: C += Res
#define T2W 136
#define T2SZ (16*T2W)                 // 2176 u32 per tile (16 kpairs)
#define H3BUF (4*T2SZ)                // Ahi Alo Bhi Blo
#define SMEM_H3 (2*H3BUF*4)           // 69632 B

template<int MODE>
__global__ void __launch_bounds__(512, 1)
gemm_h3(const float* __restrict__ A,
        const float* __restrict__ W0, const float* __restrict__ W1,
        const float* __restrict__ W2,
        const float* __restrict__ b0, const float* __restrict__ b1,
        const float* __restrict__ b2,
        float* __restrict__ C0, float* __restrict__ C1, float* __restrict__ C2,
        int Kd, int N) {
    extern __shared__ uint32_t tiles[];
    int z = (MODE == 0) ? blockIdx.z : 0;
    const float* Wall = (z == 0) ? W0 : (z == 1 ? W1 : W2);
    const float* bias = (z == 0) ? b0 : (z == 1 ? b1 : b2);
    float* Cp         = (z == 0) ? C0 : (z == 1 ? C1 : C2);

    int tid = threadIdx.x;
    int rowBase = blockIdx.y * 128, colBase = blockIdx.x * 128;

    int lrA = tid >> 2, kcA4 = (tid & 3) << 2, kpA = (tid & 3) << 1;
    const float* Ap = A + (size_t)(rowBase + lrA) * Kd + kcA4;
    int kpB = tid >> 6, nB = (tid & 63) << 1;
    const float* Wp = Wall + (size_t)(2 * kpB) * N + colBase + nB;

    int lane = tid & 31, warp = tid >> 5;
    int wm = (warp & 3) * 32, wn = (warp >> 2) * 32;
    int gid = lane >> 2, tig = lane & 3;

    float acc[2][4][4];
#pragma unroll
    for (int a = 0; a < 2; a++)
#pragma unroll
        for (int b3 = 0; b3 < 4; b3++)
#pragma unroll
            for (int c = 0; c < 4; c++) acc[a][b3][c] = 0.f;

    int nk = Kd / 32;
    float4 av0, av1;
    float2 br0, br1, br2, br3;
    av0 = *(const float4*)(Ap);
    av1 = *(const float4*)(Ap + 16);
    br0 = *(const float2*)(Wp);
    br1 = *(const float2*)(Wp + N);
    br2 = *(const float2*)(Wp + (size_t)16 * N);
    br3 = *(const float2*)(Wp + (size_t)17 * N);

#define H3_STORE(BUF)                                                          \
    {                                                                          \
        uint32_t* Ahi = (BUF);                                                 \
        uint32_t* Alo = (BUF) + T2SZ;                                          \
        uint32_t* Bhi = (BUF) + 2 * T2SZ;                                      \
        uint32_t* Blo = (BUF) + 3 * T2SZ;                                      \
        __half h0 = __float2half_rn(av0.x), h1 = __float2half_rn(av0.y);       \
        __half h2 = __float2half_rn(av0.z), h3 = __float2half_rn(av0.w);       \
        Ahi[kpA * T2W + lrA]       = pack_h2(h0, h1);                          \
        Ahi[(kpA + 1) * T2W + lrA] = pack_h2(h2, h3);                          \
        Alo[kpA * T2W + lrA]       = pack_f2h(av0.x - __half2float(h0), av0.y - __half2float(h1)); \
        Alo[(kpA + 1) * T2W + lrA] = pack_f2h(av0.z - __half2float(h2), av0.w - __half2float(h3)); \
        __half g0 = __float2half_rn(av1.x), g1 = __float2half_rn(av1.y);       \
        __half g2 = __float2half_rn(av1.z), g3 = __float2half_rn(av1.w);       \
        Ahi[(kpA + 8) * T2W + lrA] = pack_h2(g0, g1);                          \
        Ahi[(kpA + 9) * T2W + lrA] = pack_h2(g2, g3);                          \
        Alo[(kpA + 8) * T2W + lrA] = pack_f2h(av1.x - __half2float(g0), av1.y - __half2float(g1)); \
        Alo[(kpA + 9) * T2W + lrA] = pack_f2h(av1.z - __half2float(g2), av1.w - __half2float(g3)); \
        __half w00 = __float2half_rn(br0.x), w10 = __float2half_rn(br1.x);     \
        __half w01 = __float2half_rn(br0.y), w11 = __float2half_rn(br1.y);     \
        Bhi[kpB * T2W + nB]     = pack_h2(w00, w10);                           \
        Bhi[kpB * T2W + nB + 1] = pack_h2(w01, w11);                           \
        Blo[kpB * T2W + nB]     = pack_f2h(br0.x - __half2float(w00), br1.x - __half2float(w10)); \
        Blo[kpB * T2W + nB + 1] = pack_f2h(br0.y - __half2float(w01), br1.y - __half2float(w11)); \
        __half u00 = __float2half_rn(br2.x), u10 = __float2half_rn(br3.x);     \
        __half u01 = __float2half_rn(br2.y), u11 = __float2half_rn(br3.y);     \
        Bhi[(kpB + 8) * T2W + nB]     = pack_h2(u00, u10);                     \
        Bhi[(kpB + 8) * T2W + nB + 1] = pack_h2(u01, u11);                     \
        Blo[(kpB + 8) * T2W + nB]     = pack_f2h(br2.x - __half2float(u00), br3.x - __half2float(u10)); \
        Blo[(kpB + 8) * T2W + nB + 1] = pack_f2h(br2.y - __half2float(u01), br3.y - __half2float(u11)); \
    }

    H3_STORE(tiles);
    __syncthreads();

    for (int t = 0; t < nk; t++) {
        if (t + 1 < nk) {
            const float* a2 = Ap + (size_t)(t + 1) * 32;
            av0 = *(const float4*)(a2);
            av1 = *(const float4*)(a2 + 16);
            const float* w2 = Wp + (size_t)(t + 1) * 32 * N;
            br0 = *(const float2*)(w2);
            br1 = *(const float2*)(w2 + N);
            br2 = *(const float2*)(w2 + (size_t)16 * N);
            br3 = *(const float2*)(w2 + (size_t)17 * N);
        }
        int s = t & 1;
        const uint32_t* Ahi = tiles + s * H3BUF;
        const uint32_t* Alo = Ahi + T2SZ;
        const uint32_t* Bhi = Ahi + 2 * T2SZ;
        const uint32_t* Blo = Ahi + 3 * T2SZ;

#pragma unroll
        for (int sub = 0; sub < 2; sub++) {
            int ko = sub * 8;
            uint32_t ah[2][4], al[2][4], bh[4][2], bl[4][2];
#pragma unroll
            for (int mt = 0; mt < 2; mt++) {
                int m0 = wm + mt * 16 + gid;
                ah[mt][0] = Ahi[(ko + tig) * T2W + m0];
                ah[mt][1] = Ahi[(ko + tig) * T2W + m0 + 8];
                ah[mt][2] = Ahi[(ko + tig + 4) * T2W + m0];
                ah[mt][3] = Ahi[(ko + tig + 4) * T2W + m0 + 8];
                al[mt][0] = Alo[(ko + tig) * T2W + m0];
                al[mt][1] = Alo[(ko + tig) * T2W + m0 + 8];
                al[mt][2] = Alo[(ko + tig + 4) * T2W + m0];
                al[mt][3] = Alo[(ko + tig + 4) * T2W + m0 + 8];
            }
#pragma unroll
            for (int nt = 0; nt < 4; nt++) {
                int n0 = wn + nt * 8 + gid;
                bh[nt][0] = Bhi[(ko + tig) * T2W + n0];
                bh[nt][1] = Bhi[(ko + tig + 4) * T2W + n0];
                bl[nt][0] = Blo[(ko + tig) * T2W + n0];
                bl[nt][1] = Blo[(ko + tig + 4) * T2W + n0];
            }
#pragma unroll
            for (int mt = 0; mt < 2; mt++)
#pragma unroll
                for (int nt = 0; nt < 4; nt++)
                    mma_f16(acc[mt][nt], ah[mt], bh[nt]);
#pragma unroll
            for (int mt = 0; mt < 2; mt++)
#pragma unroll
                for (int nt = 0; nt < 4; nt++)
                    mma_f16(acc[mt][nt], ah[mt], bl[nt]);
#pragma unroll
            for (int mt = 0; mt < 2; mt++)
#pragma unroll
                for (int nt = 0; nt < 4; nt++)
                    mma_f16(acc[mt][nt], al[mt], bh[nt]);
        }

        if (t + 1 < nk) {
            uint32_t* nb = tiles + (s ^ 1) * H3BUF;
            H3_STORE(nb);
        }
        __syncthreads();
    }
#undef H3_STORE

#pragma unroll
    for (int mt = 0; mt < 2; mt++) {
#pragma unroll
        for (int c = 0; c < 4; c++) {
            int r = rowBase + wm + mt * 16 + gid + ((c & 2) ? 8 : 0);
#pragma unroll
            for (int nt = 0; nt < 4; nt++) {
                int cg = colBase + wn + nt * 8 + tig * 2 + (c & 1);
                float v = acc[mt][nt][c] + bias[cg];
                if (MODE == 1) v += Cp[(size_t)r * N + cg];
                Cp[(size_t)r * N + cg] = v;
            }
        }
    }
}

// ---------------- fp16 1-pass big-tile GEMM (128x256, BK=32, 512 thr) --------
// MODE 0: fused QKV (z)   MODE 1: C += Res   MODE 2: MoE GEMM1 (GELU, z=expert)
// MODE 3: MoE GEMM2 -> g_moeout (weighted)
#define HB_AW 136
#define HB_BW 264
#define HB_AT (16*HB_AW)              // 2176
#define HB_BT (16*HB_BW)              // 4224
#define HB_BUF (HB_AT+HB_BT)          // 6400
#define SMEM_HB ((256 + 2*HB_BUF) * 4)   // 52224 B

template<int MODE>
__global__ void __launch_bounds__(512, 1)
gemm_hb(const float* __restrict__ A,
        const float* __restrict__ W0, const float* __restrict__ W1,
        const float* __restrict__ W2,
        const float* __restrict__ b0, const float* __restrict__ b1,
        const float* __restrict__ b2,
        float* __restrict__ C0, float* __restrict__ C1, float* __restrict__ C2,
        int Kd, int N, int layer) {
    extern __shared__ float smf[];
    int*   s_tok = (int*)smf;
    float* s_wt  = smf + 128;
    uint32_t* tiles = (uint32_t*)(smf + 256);

    int tid = threadIdx.x;
    int rowBase = blockIdx.y * 128, colBase = blockIdx.x * 256;

    int e = 0, cnt = 0;
    const float* W;
    const float* bias;
    float* Cp = C0;
    if (MODE >= 2) {
        e = blockIdx.z;
        cnt = g_counts[e];
        if (rowBase >= cnt) return;
        W    = W0 + (size_t)(layer * Ee + e) * Kd * N;
        bias = b0 + (size_t)(layer * Ee + e) * N;
        if (tid < 128) {
            int r = rowBase + tid;
            int rc = r < cnt ? r : cnt - 1;
            s_tok[tid] = g_tok[e * TOK + rc];
            s_wt[tid]  = g_wt [e * TOK + rc];
        }
        __syncthreads();
    } else {
        int z = (MODE == 0) ? blockIdx.z : 0;
        W    = (z == 0) ? W0 : (z == 1 ? W1 : W2);
        bias = (z == 0) ? b0 : (z == 1 ? b1 : b2);
        Cp   = (z == 0) ? C0 : (z == 1 ? C1 : C2);
    }

    int lrA = tid >> 2, kcA4 = (tid & 3) << 2, kpA = (tid & 3) << 1;
    const float* Ap;
    if (MODE == 2)      Ap = g_H + (size_t)s_tok[lrA] * Kd + kcA4;
    else if (MODE == 3) Ap = g_hidden + ((size_t)e * TOK + rowBase + lrA) * Kd + kcA4;
    else                Ap = A + (size_t)(rowBase + lrA) * Kd + kcA4;

    int kpB = tid >> 6, nB4 = (tid & 63) << 2;
    const float* Wp = W + (size_t)(2 * kpB) * N + colBase + nB4;

    int lane = tid & 31, warp = tid >> 5;
    int wm = (warp & 1) * 64, wn = (warp >> 1) * 32;
    int gid = lane >> 2, tig = lane & 3;

    float acc[4][4][4];
#pragma unroll
    for (int a = 0; a < 4; a++)
#pragma unroll
        for (int b3 = 0; b3 < 4; b3++)
#pragma unroll
            for (int c = 0; c < 4; c++) acc[a][b3][c] = 0.f;

    int nk = Kd / 32;
    float4 av0, av1, bv0, bv1, bv2, bv3;
    av0 = *(const float4*)(Ap);
    av1 = *(const float4*)(Ap + 16);
    bv0 = *(const float4*)(Wp);
    bv1 = *(const float4*)(Wp + N);
    bv2 = *(const float4*)(Wp + (size_t)16 * N);
    bv3 = *(const float4*)(Wp + (size_t)17 * N);

#define HB_STORE(BUF)                                                          \
    {                                                                          \
        uint32_t* As = (BUF);                                                  \
        uint32_t* Bs = (BUF) + HB_AT;                                          \
        As[kpA * HB_AW + lrA]       = pack_f2h(av0.x, av0.y);                  \
        As[(kpA + 1) * HB_AW + lrA] = pack_f2h(av0.z, av0.w);                  \
        As[(kpA + 8) * HB_AW + lrA] = pack_f2h(av1.x, av1.y);                  \
        As[(kpA + 9) * HB_AW + lrA] = pack_f2h(av1.z, av1.w);                  \
        Bs[kpB * HB_BW + nB4 + 0] = pack_f2h(bv0.x, bv1.x);                    \
        Bs[kpB * HB_BW + nB4 + 1] = pack_f2h(bv0.y, bv1.y);                    \
        Bs[kpB * HB_BW + nB4 + 2] = pack_f2h(bv0.z, bv1.z);                    \
        Bs[kpB * HB_BW + nB4 + 3] = pack_f2h(bv0.w, bv1.w);                    \
        Bs[(kpB + 8) * HB_BW + nB4 + 0] = pack_f2h(bv2.x, bv3.x);              \
        Bs[(kpB + 8) * HB_BW + nB4 + 1] = pack_f2h(bv2.y, bv3.y);              \
        Bs[(kpB + 8) * HB_BW + nB4 + 2] = pack_f2h(bv2.z, bv3.z);              \
        Bs[(kpB + 8) * HB_BW + nB4 + 3] = pack_f2h(bv2.w, bv3.w);              \
    }

    HB_STORE(tiles);
    __syncthreads();

    for (int t = 0; t < nk; t++) {
        if (t + 1 < nk) {
            const float* a2 = Ap + (size_t)(t + 1) * 32;
            av0 = *(const float4*)(a2);
            av1 = *(const float4*)(a2 + 16);
            const float* w2 = Wp + (size_t)(t + 1) * 32 * N;
            bv0 = *(const float4*)(w2);
            bv1 = *(const float4*)(w2 + N);
            bv2 = *(const float4*)(w2 + (size_t)16 * N);
            bv3 = *(const float4*)(w2 + (size_t)17 * N);
        }
        int s = t & 1;
        const uint32_t* As = tiles + s * HB_BUF;
        const uint32_t* Bs = As + HB_AT;

#pragma unroll
        for (int sub = 0; sub < 2; sub++) {
            int ko = sub * 8;
            uint32_t af[4][4], bf[4][2];
#pragma unroll
            for (int mt = 0; mt < 4; mt++) {
                int m0 = wm + mt * 16 + gid;
                af[mt][0] = As[(ko + tig) * HB_AW + m0];
                af[mt][1] = As[(ko + tig) * HB_AW + m0 + 8];
                af[mt][2] = As[(ko + tig + 4) * HB_AW + m0];
                af[mt][3] = As[(ko + tig + 4) * HB_AW + m0 + 8];
            }
#pragma unroll
            for (int nt = 0; nt < 4; nt++) {
                int n0 = wn + nt * 8 + gid;
                bf[nt][0] = Bs[(ko + tig) * HB_BW + n0];
                bf[nt][1] = Bs[(ko + tig + 4) * HB_BW + n0];
            }
#pragma unroll
            for (int mt = 0; mt < 4; mt++)
#pragma unroll
                for (int nt = 0; nt < 4; nt++)
                    mma_f16(acc[mt][nt], af[mt], bf[nt]);
        }

        if (t + 1 < nk) {
            uint32_t* nb = tiles + (s ^ 1) * HB_BUF;
            HB_STORE(nb);
        }
        __syncthreads();
    }
#undef HB_STORE

#pragma unroll
    for (int mt = 0; mt < 4; mt++) {
#pragma unroll
        for (int c = 0; c < 4; c++) {
            int rl = wm + mt * 16 + gid + ((c & 2) ? 8 : 0);
            int r  = rowBase + rl;
#pragma unroll
            for (int nt = 0; nt < 4; nt++) {
                int cg = colBase + wn + nt * 8 + tig * 2 + (c & 1);
                float v = acc[mt][nt][c] + bias[cg];
                if (MODE == 0) {
                    Cp[(size_t)r * N + cg] = v;
                } else if (MODE == 1) {
                    Cp[(size_t)r * N + cg] = v + Cp[(size_t)r * N + cg];
                } else if (MODE == 2) {
                    if (r < cnt)
                        g_hidden[((size_t)e * TOK + r) * N + cg] = gelu_exact(v);
                } else {
                    g_moeout[((size_t)(e * TOK + r)) * N + cg] = v * s_wt[rl];
                }
            }
        }
    }
}

// MoE combine: x[t] += moeout[slot1] + moeout[slot2]
__global__ void moe_combine() {
    int i = blockIdx.x * 256 + threadIdx.x;
    int t = i >> 8;
    int c4 = (i & 255) << 2;
    int s0 = g_islot[t * 2], s1 = g_islot[t * 2 + 1];
    float4 a = *(const float4*)&g_moeout[(size_t)s0 * Dq + c4];
    float4 b = *(const float4*)&g_moeout[(size_t)s1 * Dq + c4];
    float4 x = *(float4*)&g_X[(size_t)t * Dq + c4];
    x.x += a.x + b.x; x.y += a.y + b.y; x.z += a.z + b.z; x.w += a.w + b.w;
    *(float4*)&g_X[(size_t)t * Dq + c4] = x;
}

// ---------------- fp16 tensor-core flash attention ---------------------------
#define FQ2 (32*136)
#define FK2 (32*72)
#define FV2 (32*72)
#define FP2 (32*136)
#define FL2_TOT (FQ2+FK2+FV2+FP2)
#define FL2_SMEM0 (FL2_TOT*4)
#define FL2_SMEM1 (FL2_TOT*8)

template<int SPLIT>
__global__ void __launch_bounds__(256)
flash_h() {
    extern __shared__ uint32_t fu[];
    uint32_t* Qh = fu;
    uint32_t* Ql = Qh + FQ2;
    uint32_t* Kh = Qh + FQ2 * (SPLIT + 1);
    uint32_t* Kl = Kh + FK2;
    uint32_t* Vh = Kh + FK2 * (SPLIT + 1);
    uint32_t* Vl = Vh + FV2;
    uint32_t* Ph = Vh + FV2 * (SPLIT + 1);
    uint32_t* Pl = Ph + FP2;

    int qb = blockIdx.x, h = blockIdx.y, b = blockIdx.z;
    int tid = threadIdx.x, warp = tid >> 5, lane = tid & 31;
    int gid = lane >> 2, tig = lane & 3;
    int mrow = warp * 16 + gid;

    for (int i = tid; i < 2048; i += 256) {
        int r = i >> 4, d4 = (i & 15) << 2, dp = (i & 15) << 1;
        float4 v = *(const float4*)&g_Q[((size_t)(b * Sq + qb * 128 + r)) * Dq + h * HD + d4];
        __half h0 = __float2half_rn(v.x), h1 = __float2half_rn(v.y);
        __half h2 = __float2half_rn(v.z), h3 = __float2half_rn(v.w);
        Qh[dp * 136 + r]       = pack_h2(h0, h1);
        Qh[(dp + 1) * 136 + r] = pack_h2(h2, h3);
        if (SPLIT) {
            Ql[dp * 136 + r]       = pack_f2h(v.x - __half2float(h0), v.y - __half2float(h1));
            Ql[(dp + 1) * 136 + r] = pack_f2h(v.z - __half2float(h2), v.w - __half2float(h3));
        }
    }

    float mA = -1e30f, mB = -1e30f, lA = 0.f, lB = 0.f;
    float o[8][4];
#pragma unroll
    for (int nt = 0; nt < 8; nt++)
#pragma unroll
        for (int c = 0; c < 4; c++) o[nt][c] = 0.f;

    int nkt = 2 * qb + 2;
    for (int kt = 0; kt < nkt; kt++) {
        __syncthreads();
        for (int i = tid; i < 1024; i += 256) {
            int r = i >> 4, d4 = (i & 15) << 2, dp = (i & 15) << 1;
            size_t base = ((size_t)(b * Sq + kt * 64 + r)) * Dq + h * HD + d4;
            float4 kv = *(const float4*)&g_K[base];
            __half h0 = __float2half_rn(kv.x), h1 = __float2half_rn(kv.y);
            __half h2 = __float2half_rn(kv.z), h3 = __float2half_rn(kv.w);
            Kh[dp * 72 + r]       = pack_h2(h0, h1);
            Kh[(dp + 1) * 72 + r] = pack_h2(h2, h3);
            if (SPLIT) {
                Kl[dp * 72 + r]       = pack_f2h(kv.x - __half2float(h0), kv.y - __half2float(h1));
                Kl[(dp + 1) * 72 + r] = pack_f2h(kv.z - __half2float(h2), kv.w - __half2float(h3));
            }
        }
        for (int i = tid; i < 512; i += 256) {
            int kp = i >> 4, d4 = (i & 15) << 2;
            size_t base0 = ((size_t)(b * Sq + kt * 64 + 2 * kp)) * Dq + h * HD + d4;
            float4 v0 = *(const float4*)&g_V[base0];
            float4 v1 = *(const float4*)&g_V[base0 + Dq];
            float a0[4] = {v0.x, v0.y, v0.z, v0.w};
            float a1[4] = {v1.x, v1.y, v1.z, v1.w};
#pragma unroll
            for (int j = 0; j < 4; j++) {
                __half p0 = __float2half_rn(a0[j]), p1 = __float2half_rn(a1[j]);
                Vh[kp * 72 + d4 + j] = pack_h2(p0, p1);
                if (SPLIT)
                    Vl[kp * 72 + d4 + j] = pack_f2h(a0[j] - __half2float(p0),
                                                    a1[j] - __half2float(p1));
            }
        }
        __syncthreads();

        float s[8][4];
#pragma unroll
        for (int nt = 0; nt < 8; nt++)
#pragma unroll
            for (int c = 0; c < 4; c++) s[nt][c] = 0.f;

#pragma unroll
        for (int ks = 0; ks < 4; ks++) {
            int kp0 = 8 * ks + tig, kp1 = 8 * ks + tig + 4;
            uint32_t a[4], al[4];
            a[0] = Qh[kp0 * 136 + mrow];
            a[1] = Qh[kp0 * 136 + mrow + 8];
            a[2] = Qh[kp1 * 136 + mrow];
            a[3] = Qh[kp1 * 136 + mrow + 8];
            if (SPLIT) {
                al[0] = Ql[kp0 * 136 + mrow];
                al[1] = Ql[kp0 * 136 + mrow + 8];
                al[2] = Ql[kp1 * 136 + mrow];
                al[3] = Ql[kp1 * 136 + mrow + 8];
            }
#pragma unroll
            for (int gq = 0; gq < 2; gq++) {
                uint32_t bb[4][2], bl[4][2];
#pragma unroll
                for (int j = 0; j < 4; j++) {
                    int n0 = (gq * 4 + j) * 8 + gid;
                    bb[j][0] = Kh[kp0 * 72 + n0];
                    bb[j][1] = Kh[kp1 * 72 + n0];
                    if (SPLIT) {
                        bl[j][0] = Kl[kp0 * 72 + n0];
                        bl[j][1] = Kl[kp1 * 72 + n0];
                    }
                }
#pragma unroll
                for (int j = 0; j < 4; j++) mma_f16(s[gq * 4 + j], a, bb[j]);
                if (SPLIT) {
#pragma unroll
                    for (int j = 0; j < 4; j++) mma_f16(s[gq * 4 + j], a, bl[j]);
#pragma unroll
                    for (int j = 0; j < 4; j++) mma_f16(s[gq * 4 + j], al, bb[j]);
                }
            }
        }

        int rowg = qb * 128 + warp * 16 + gid;
        if (kt * 64 + 63 > rowg) {
#pragma unroll
            for (int nt = 0; nt < 8; nt++)
#pragma unroll
                for (int c = 0; c < 4; c++) {
                    int col = kt * 64 + nt * 8 + 2 * tig + (c & 1);
                    int row = rowg + ((c & 2) ? 8 : 0);
                    float sv = s[nt][c] * 0.125f;
                    s[nt][c] = (col > row) ? -1e30f : sv;
                }
        } else {
#pragma unroll
            for (int nt = 0; nt < 8; nt++)
#pragma unroll
                for (int c = 0; c < 4; c++) s[nt][c] *= 0.125f;
        }

        float rmA = -1e30f, rmB = -1e30f;
#pragma unroll
        for (int nt = 0; nt < 8; nt++) {
            rmA = fmaxf(rmA, fmaxf(s[nt][0], s[nt][1]));
            rmB = fmaxf(rmB, fmaxf(s[nt][2], s[nt][3]));
        }
#pragma unroll
        for (int off = 1; off < 4; off <<= 1) {
            rmA = fmaxf(rmA, __shfl_xor_sync(0xffffffffu, rmA, off));
            rmB = fmaxf(rmB, __shfl_xor_sync(0xffffffffu, rmB, off));
        }
        float mnA = fmaxf(mA, rmA), mnB = fmaxf(mB, rmB);
        float alA = __expf(mA - mnA), alB = __expf(mB - mnB);
        float rsA = 0.f, rsB = 0.f;
#pragma unroll
        for (int nt = 0; nt < 8; nt++) {
            s[nt][0] = __expf(s[nt][0] - mnA); rsA += s[nt][0];
            s[nt][1] = __expf(s[nt][1] - mnA); rsA += s[nt][1];
            s[nt][2] = __expf(s[nt][2] - mnB); rsB += s[nt][2];
            s[nt][3] = __expf(s[nt][3] - mnB); rsB += s[nt][3];
        }
#pragma unroll
        for (int off = 1; off < 4; off <<= 1) {
            rsA += __shfl_xor_sync(0xffffffffu, rsA, off);
            rsB += __shfl_xor_sync(0xffffffffu, rsB, off);
        }
        lA = lA * alA + rsA; mA = mnA;
        lB = lB * alB + rsB; mB = mnB;
#pragma unroll
        for (int nt = 0; nt < 8; nt++) {
            o[nt][0] *= alA; o[nt][1] *= alA;
            o[nt][2] *= alB; o[nt][3] *= alB;
        }

        __syncwarp();
#pragma unroll
        for (int nt = 0; nt < 8; nt++) {
            int kpP = nt * 4 + tig;
            __half p0 = __float2half_rn(s[nt][0]), p1 = __float2half_rn(s[nt][1]);
            __half p2 = __float2half_rn(s[nt][2]), p3 = __float2half_rn(s[nt][3]);
            Ph[kpP * 136 + mrow]     = pack_h2(p0, p1);
            Ph[kpP * 136 + mrow + 8] = pack_h2(p2, p3);
            if (SPLIT) {
                Pl[kpP * 136 + mrow]     = pack_f2h(s[nt][0] - __half2float(p0),
                                                    s[nt][1] - __half2float(p1));
                Pl[kpP * 136 + mrow + 8] = pack_f2h(s[nt][2] - __half2float(p2),
                                                    s[nt][3] - __half2float(p3));
            }
        }
        __syncwarp();

#pragma unroll
        for (int ks = 0; ks < 4; ks++) {
            int kp0 = 8 * ks + tig, kp1 = 8 * ks + tig + 4;
            uint32_t a[4], al[4];
            a[0] = Ph[kp0 * 136 + mrow];
            a[1] = Ph[kp0 * 136 + mrow + 8];
            a[2] = Ph[kp1 * 136 + mrow];
            a[3] = Ph[kp1 * 136 + mrow + 8];
            if (SPLIT) {
                al[0] = Pl[kp0 * 136 + mrow];
                al[1] = Pl[kp0 * 136 + mrow + 8];
                al[2] = Pl[kp1 * 136 + mrow];
                al[3] = Pl[kp1 * 136 + mrow + 8];
            }
#pragma unroll
            for (int gq = 0; gq < 2; gq++) {
                uint32_t bb[4][2], bl[4][2];
#pragma unroll
                for (int j = 0; j < 4; j++) {
                    int n0 = (gq * 4 + j) * 8 + gid;
                    bb[j][0] = Vh[kp0 * 72 + n0];
                    bb[j][1] = Vh[kp1 * 72 + n0];
                    if (SPLIT) {
                        bl[j][0] = Vl[kp0 * 72 + n0];
                        bl[j][1] = Vl[kp1 * 72 + n0];
                    }
                }
#pragma unroll
                for (int j = 0; j < 4; j++) mma_f16(o[gq * 4 + j], a, bb[j]);
                if (SPLIT) {
#pragma unroll
                    for (int j = 0; j < 4; j++) mma_f16(o[gq * 4 + j], a, bl[j]);
#pragma unroll
                    for (int j = 0; j < 4; j++) mma_f16(o[gq * 4 + j], al, bb[j]);
                }
            }
        }
    }

    float invA = 1.0f / lA, invB = 1.0f / lB;
    size_t rbase0 = ((size_t)(b * Sq + qb * 128 + warp * 16 + gid)) * Dq + h * HD;
    size_t rbase1 = rbase0 + (size_t)8 * Dq;
#pragma unroll
    for (int nt = 0; nt < 8; nt++) {
        int d0 = nt * 8 + 2 * tig;
        *(float2*)&g_Y[rbase0 + d0] = make_float2(o[nt][0] * invA, o[nt][1] * invA);
        *(float2*)&g_Y[rbase1 + d0] = make_float2(o[nt][2] * invB, o[nt][3] * invB);
    }
}

// ---------------- gating -----------------------------------------------------
__global__ void gate_token_kernel(const float* __restrict__ gw,
                                  const float* __restrict__ gb, int layer) {
    int t = blockIdx.x * 4 + (threadIdx.x >> 5);
    int lane = threadIdx.x & 31;
    if (t >= TOK) return;
    const float* hrow = g_H + (size_t)t * Dq;
    const float* gwl = gw + (size_t)layer * Dq * Ee;
    float acc[Ee] = {};
    for (int d = lane; d < Dq; d += 32) {
        float hv = hrow[d];
        const float* g = gwl + (size_t)d * Ee;
#pragma unroll
        for (int e = 0; e < Ee; e++) acc[e] += hv * g[e];
    }
#pragma unroll
    for (int e = 0; e < Ee; e++)
        for (int off = 16; off; off >>= 1)
            acc[e] += __shfl_xor_sync(0xffffffffu, acc[e], off);
    if (lane == 0) {
        float lg[Ee];
#pragma unroll
        for (int e = 0; e < Ee; e++) lg[e] = acc[e] + gb[layer * Ee + e];
        int i1, i2; float w1, w2;
        top2_of8(lg, i1, i2, w1, w2);
        g_te[t * 2] = i1; g_te[t * 2 + 1] = i2;
        g_tw[t * 2] = w1; g_tw[t * 2 + 1] = w2;
    }
}

__global__ void xmean_kernel() {
    int b = blockIdx.y;
    int d = blockIdx.x * 256 + threadIdx.x;
    float s = 0.f;
    for (int ss = 0; ss < Sq; ss++)
        s += g_H[((size_t)(b * Sq + ss)) * Dq + d];
    g_xmean[b * Dq + d] = s * (1.0f / Sq);
}

__global__ void gate_seq_kernel(const float* __restrict__ gw,
                                const float* __restrict__ gb, int layer) {
    int b = blockIdx.x;
    int tid = threadIdx.x, e = tid >> 5, lane = tid & 31;
    const float* gwl = gw + (size_t)layer * Dq * Ee;
    float acc = 0.f;
    for (int d = lane; d < Dq; d += 32)
        acc += g_xmean[b * Dq + d] * gwl[(size_t)d * Ee + e];
    for (int off = 16; off; off >>= 1)
        acc += __shfl_xor_sync(0xffffffffu, acc, off);
    __shared__ float lg[Ee];
    if (lane == 0) lg[e] = acc + gb[layer * Ee + e];
    __syncthreads();
    if (tid == 0) {
        int i1, i2; float w1, w2;
        top2_of8(lg, i1, i2, w1, w2);
        g_bsel[b * 2] = i1; g_bsel[b * 2 + 1] = i2;
        g_bw[b * 2] = w1;  g_bw[b * 2 + 1] = w2;
    }
}

__global__ void zero_counts_kernel() {
    if (threadIdx.x < Ee) g_counts[threadIdx.x] = 0;
}

__global__ void assign_kernel(int seq_mode) {
    int t = blockIdx.x * 256 + threadIdx.x;
    if (t >= TOK) return;
    int e1, e2; float w1, w2;
    if (seq_mode) {
        int b = t / Sq;
        e1 = g_bsel[b * 2]; e2 = g_bsel[b * 2 + 1];
        w1 = g_bw[b * 2];   w2 = g_bw[b * 2 + 1];
    } else {
        e1 = g_te[t * 2]; e2 = g_te[t * 2 + 1];
        w1 = g_tw[t * 2]; w2 = g_tw[t * 2 + 1];
    }
    int s1 = atomicAdd(&g_counts[e1], 1);
    g_tok[e1 * TOK + s1] = t; g_wt[e1 * TOK + s1] = w1;
    g_islot[t * 2] = e1 * TOK + s1;
    int s2 = atomicAdd(&g_counts[e2], 1);
    g_tok[e2 * TOK + s2] = t; g_wt[e2 * TOK + s2] = w2;
    g_islot[t * 2 + 1] = e2 * TOK + s2;
}

// ---------------- host side --------------------------------------------------
extern "C" void kernel_launch(void* const* d_in, const int* in_sizes, int n_in,
                              void* d_out, int out_size) {
    const float* x      = (const float*)d_in[0];
    const float* ln1_w  = (const float*)d_in[1];
    const float* ln1_b  = (const float*)d_in[2];
    const float* ln2_w  = (const float*)d_in[3];
    const float* ln2_b  = (const float*)d_in[4];
    const float* wq     = (const float*)d_in[5];
    const float* wk     = (const float*)d_in[6];
    const float* wv     = (const float*)d_in[7];
    const float* wo     = (const float*)d_in[8];
    const float* bq     = (const float*)d_in[9];
    const float* bk     = (const float*)d_in[10];
    const float* bv     = (const float*)d_in[11];
    const float* bo     = (const float*)d_in[12];
    const float* gate_w = (const float*)d_in[13];
    const float* gate_b = (const float*)d_in[14];
    const float* e_w1   = (const float*)d_in[15];
    const float* e_b1   = (const float*)d_in[16];
    const float* e_w2   = (const float*)d_in[17];
    const float* e_b2   = (const float*)d_in[18];

    float *Xp, *Hp, *Qp, *Kp, *Vp, *Yp;
    cudaGetSymbolAddress((void**)&Xp, g_X);
    cudaGetSymbolAddress((void**)&Hp, g_H);
    cudaGetSymbolAddress((void**)&Qp, g_Q);
    cudaGetSymbolAddress((void**)&Kp, g_K);
    cudaGetSymbolAddress((void**)&Vp, g_V);
    cudaGetSymbolAddress((void**)&Yp, g_Y);

    static int attr_set = 0;
    if (!attr_set) {
        cudaFuncSetAttribute(gemm_h3<0>, cudaFuncAttributeMaxDynamicSharedMemorySize, SMEM_H3);
        cudaFuncSetAttribute(gemm_h3<1>, cudaFuncAttributeMaxDynamicSharedMemorySize, SMEM_H3);
        cudaFuncSetAttribute(gemm_hb<0>, cudaFuncAttributeMaxDynamicSharedMemorySize, SMEM_HB);
        cudaFuncSetAttribute(gemm_hb<1>, cudaFuncAttributeMaxDynamicSharedMemorySize, SMEM_HB);
        cudaFuncSetAttribute(gemm_hb<2>, cudaFuncAttributeMaxDynamicSharedMemorySize, SMEM_HB);
        cudaFuncSetAttribute(gemm_hb<3>, cudaFuncAttributeMaxDynamicSharedMemorySize, SMEM_HB);
        cudaFuncSetAttribute(flash_h<0>, cudaFuncAttributeMaxDynamicSharedMemorySize, FL2_SMEM0);
        cudaFuncSetAttribute(flash_h<1>, cudaFuncAttributeMaxDynamicSharedMemorySize, FL2_SMEM1);
        attr_set = 1;
    }

    const size_t DD = (size_t)Dq * Dq;
    const int nelem = TOK * Dq;

    copy_in_kernel<<<nelem / 256, 256>>>(x);

    for (int l = 0; l < Ll; l++) {
        const float* WQ = wq + l * DD;
        const float* WK = wk + l * DD;
        const float* WV = wv + l * DD;
        const float* WO = wo + l * DD;
        const float* BQ = bq + (size_t)l * Dq;
        const float* BK = bk + (size_t)l * Dq;
        const float* BV = bv + (size_t)l * Dq;
        const float* BO = bo + (size_t)l * Dq;

        ln_kernel<<<TOK, 256>>>(ln1_w + (size_t)l * Dq, ln1_b + (size_t)l * Dq);
        if (l == 0) {
            gemm_h3<0><<<dim3(8, 32, 3), 512, SMEM_H3>>>(
                Hp, WQ, WK, WV, BQ, BK, BV, Qp, Kp, Vp, Dq, Dq);
            flash_h<1><<<dim3(Sq / 128, Hh, Bq), 256, FL2_SMEM1>>>();
            gemm_h3<1><<<dim3(8, 32), 512, SMEM_H3>>>(
                Yp, WO, nullptr, nullptr, BO, nullptr, nullptr, Xp, nullptr, nullptr, Dq, Dq);
        } else {
            gemm_hb<0><<<dim3(4, 32, 3), 512, SMEM_HB>>>(
                Hp, WQ, WK, WV, BQ, BK, BV, Qp, Kp, Vp, Dq, Dq, l);
            flash_h<0><<<dim3(Sq / 128, Hh, Bq), 256, FL2_SMEM0>>>();
            gemm_hb<1><<<dim3(4, 32), 512, SMEM_HB>>>(
                Yp, WO, nullptr, nullptr, BO, nullptr, nullptr, Xp, nullptr, nullptr, Dq, Dq, l);
        }

        ln_kernel<<<TOK, 256>>>(ln2_w + (size_t)l * Dq, ln2_b + (size_t)l * Dq);
        if (l % 2 == 0) {
            gate_token_kernel<<<TOK / 4, 128>>>(gate_w, gate_b, l);
        } else {
            xmean_kernel<<<dim3(Dq / 256, Bq), 256>>>();
            gate_seq_kernel<<<Bq, 256>>>(gate_w, gate_b, l);
        }
        zero_counts_kernel<<<1, 32>>>();
        assign_kernel<<<TOK / 256, 256>>>(l % 2);
        gemm_hb<2><<<dim3(DFFq / 256, TOK / 128, Ee), 512, SMEM_HB>>>(
            nullptr, e_w1, nullptr, nullptr, e_b1, nullptr, nullptr,
            nullptr, nullptr, nullptr, Dq, DFFq, l);
        gemm_hb<3><<<dim3(Dq / 256, TOK / 128, Ee), 512, SMEM_HB>>>(
            nullptr, e_w2, nullptr, nullptr, e_b2, nullptr, nullptr,
            nullptr, nullptr, nullptr, DFFq, Dq, l);
        moe_combine<<<nelem / 1024, 256>>>();
    }

    copy_out_kernel<<<nelem / 256, 256>>>((float*)d_out);
    (void)in_sizes; (void)n_in; (void)out_size;
}

// round 11
// speedup vs baseline: 10.6155x; 1.0140x over previous
#include <cuda_runtime.h>
#include <cuda_fp16.h>
#include <math.h>
#include <stdint.h>

#define Bq   4
#define Sq   1024
#define Dq   1024
#define Hh   16
#define HD   64
#define Ll   2
#define Ee   8
#define DFFq 4096
#define TOK  (Bq*Sq)   // 4096

// ---------------- static scratch ---------------------------------------------
__device__ float g_X[TOK*Dq];
__device__ float g_H[TOK*Dq];
__device__ float g_Q[TOK*Dq];
__device__ float g_K[TOK*Dq];
__device__ float g_V[TOK*Dq];
__device__ float g_Y[TOK*Dq];
__device__ float g_hidden[(size_t)Ee*TOK*DFFq];
__device__ float g_moeout[(size_t)Ee*TOK*Dq];
__device__ int   g_counts[Ee];
__device__ int   g_tok[Ee*TOK];
__device__ float g_wt[Ee*TOK];
__device__ int   g_islot[TOK*2];
__device__ int   g_te[TOK*2];
__device__ float g_tw[TOK*2];
__device__ int   g_bsel[Bq*2];
__device__ float g_bw[Bq*2];
__device__ float g_xmean[Bq*Dq];

// ---------------- helpers ----------------------------------------------------
__device__ __forceinline__ void top2_of8(const float* lg, int& i1, int& i2,
                                         float& w1, float& w2) {
    i1 = 0; float v1 = lg[0];
#pragma unroll
    for (int e = 1; e < Ee; e++) if (lg[e] > v1) { v1 = lg[e]; i1 = e; }
    i2 = -1; float v2 = -3.0e38f;
#pragma unroll
    for (int e = 0; e < Ee; e++) if (e != i1 && lg[e] > v2) { v2 = lg[e]; i2 = e; }
    float ex = expf(v2 - v1);
    w1 = 1.0f / (1.0f + ex);
    w2 = ex / (1.0f + ex);
}
__device__ __forceinline__ float gelu_exact(float x) {
    return 0.5f * x * (1.0f + erff(x * 0.7071067811865476f));
}
__device__ __forceinline__ void mma_f16(float c[4], const uint32_t a[4],
                                        const uint32_t b[2]) {
    asm volatile(
        "mma.sync.aligned.m16n8k16.row.col.f32.f16.f16.f32 "
        "{%0,%1,%2,%3},{%4,%5,%6,%7},{%8,%9},{%0,%1,%2,%3};"
        : "+f"(c[0]), "+f"(c[1]), "+f"(c[2]), "+f"(c[3])
        : "r"(a[0]), "r"(a[1]), "r"(a[2]), "r"(a[3]), "r"(b[0]), "r"(b[1]));
}
__device__ __forceinline__ uint32_t pack_h2(__half a, __half b) {
    __half2 h = __halves2half2(a, b);
    return *(uint32_t*)&h;
}
__device__ __forceinline__ uint32_t pack_f2h(float a, float b) {
    return pack_h2(__float2half_rn(a), __float2half_rn(b));
}

// ---------------- simple kernels ---------------------------------------------
__global__ void copy_in_kernel(const float* __restrict__ src) {
    int i = blockIdx.x * 256 + threadIdx.x;
    g_X[i] = src[i];
}
__global__ void copy_out_kernel(float* __restrict__ dst) {
    int i = blockIdx.x * 256 + threadIdx.x;
    dst[i] = g_X[i];
}

__global__ void ln_kernel(const float* __restrict__ w, const float* __restrict__ b) {
    int t = blockIdx.x, tid = threadIdx.x;
    const float* xr = g_X + (size_t)t * Dq;
    float s = 0.f, s2 = 0.f;
    for (int d = tid; d < Dq; d += 256) { float v = xr[d]; s += v; s2 += v * v; }
    __shared__ float r1[256], r2[256];
    r1[tid] = s; r2[tid] = s2; __syncthreads();
    for (int off = 128; off; off >>= 1) {
        if (tid < off) { r1[tid] += r1[tid + off]; r2[tid] += r2[tid + off]; }
        __syncthreads();
    }
    float mean = r1[0] * (1.0f / Dq);
    float var  = r2[0] * (1.0f / Dq) - mean * mean;
    float rstd = rsqrtf(var + 1e-5f);
    float* hr = g_H + (size_t)t * Dq;
    for (int d = tid; d < Dq; d += 256)
        hr[d] = (xr[d] - mean) * rstd * w[d] + b[d];
}

// ---------------- fp16 3-pass split GEMM (layer-0, 128x128, BK=32) -----------
#define T2W 136
#define T2SZ (16*T2W)
#define H3BUF (4*T2SZ)
#define SMEM_H3 (2*H3BUF*4)           // 69632 B

template<int MODE>
__global__ void __launch_bounds__(512, 1)
gemm_h3(const float* __restrict__ A,
        const float* __restrict__ W0, const float* __restrict__ W1,
        const float* __restrict__ W2,
        const float* __restrict__ b0, const float* __restrict__ b1,
        const float* __restrict__ b2,
        float* __restrict__ C0, float* __restrict__ C1, float* __restrict__ C2,
        int Kd, int N) {
    extern __shared__ uint32_t tiles[];
    int z = (MODE == 0) ? blockIdx.z : 0;
    const float* Wall = (z == 0) ? W0 : (z == 1 ? W1 : W2);
    const float* bias = (z == 0) ? b0 : (z == 1 ? b1 : b2);
    float* Cp         = (z == 0) ? C0 : (z == 1 ? C1 : C2);

    int tid = threadIdx.x;
    int rowBase = blockIdx.y * 128, colBase = blockIdx.x * 128;

    int lrA = tid >> 2, kcA4 = (tid & 3) << 2, kpA = (tid & 3) << 1;
    const float* Ap = A + (size_t)(rowBase + lrA) * Kd + kcA4;
    int kpB = tid >> 6, nB = (tid & 63) << 1;
    const float* Wp = Wall + (size_t)(2 * kpB) * N + colBase + nB;

    int lane = tid & 31, warp = tid >> 5;
    int wm = (warp & 3) * 32, wn = (warp >> 2) * 32;
    int gid = lane >> 2, tig = lane & 3;

    float acc[2][4][4];
#pragma unroll
    for (int a = 0; a < 2; a++)
#pragma unroll
        for (int b3 = 0; b3 < 4; b3++)
#pragma unroll
            for (int c = 0; c < 4; c++) acc[a][b3][c] = 0.f;

    int nk = Kd / 32;
    float4 av0, av1;
    float2 br0, br1, br2, br3;
    av0 = *(const float4*)(Ap);
    av1 = *(const float4*)(Ap + 16);
    br0 = *(const float2*)(Wp);
    br1 = *(const float2*)(Wp + N);
    br2 = *(const float2*)(Wp + (size_t)16 * N);
    br3 = *(const float2*)(Wp + (size_t)17 * N);

#define H3_STORE(BUF)                                                          \
    {                                                                          \
        uint32_t* Ahi = (BUF);                                                 \
        uint32_t* Alo = (BUF) + T2SZ;                                          \
        uint32_t* Bhi = (BUF) + 2 * T2SZ;                                      \
        uint32_t* Blo = (BUF) + 3 * T2SZ;                                      \
        __half h0 = __float2half_rn(av0.x), h1 = __float2half_rn(av0.y);       \
        __half h2 = __float2half_rn(av0.z), h3 = __float2half_rn(av0.w);       \
        Ahi[kpA * T2W + lrA]       = pack_h2(h0, h1);                          \
        Ahi[(kpA + 1) * T2W + lrA] = pack_h2(h2, h3);                          \
        Alo[kpA * T2W + lrA]       = pack_f2h(av0.x - __half2float(h0), av0.y - __half2float(h1)); \
        Alo[(kpA + 1) * T2W + lrA] = pack_f2h(av0.z - __half2float(h2), av0.w - __half2float(h3)); \
        __half g0 = __float2half_rn(av1.x), g1 = __float2half_rn(av1.y);       \
        __half g2 = __float2half_rn(av1.z), g3 = __float2half_rn(av1.w);       \
        Ahi[(kpA + 8) * T2W + lrA] = pack_h2(g0, g1);                          \
        Ahi[(kpA + 9) * T2W + lrA] = pack_h2(g2, g3);                          \
        Alo[(kpA + 8) * T2W + lrA] = pack_f2h(av1.x - __half2float(g0), av1.y - __half2float(g1)); \
        Alo[(kpA + 9) * T2W + lrA] = pack_f2h(av1.z - __half2float(g2), av1.w - __half2float(g3)); \
        __half w00 = __float2half_rn(br0.x), w10 = __float2half_rn(br1.x);     \
        __half w01 = __float2half_rn(br0.y), w11 = __float2half_rn(br1.y);     \
        Bhi[kpB * T2W + nB]     = pack_h2(w00, w10);                           \
        Bhi[kpB * T2W + nB + 1] = pack_h2(w01, w11);                           \
        Blo[kpB * T2W + nB]     = pack_f2h(br0.x - __half2float(w00), br1.x - __half2float(w10)); \
        Blo[kpB * T2W + nB + 1] = pack_f2h(br0.y - __half2float(w01), br1.y - __half2float(w11)); \
        __half u00 = __float2half_rn(br2.x), u10 = __float2half_rn(br3.x);     \
        __half u01 = __float2half_rn(br2.y), u11 = __float2half_rn(br3.y);     \
        Bhi[(kpB + 8) * T2W + nB]     = pack_h2(u00, u10);                     \
        Bhi[(kpB + 8) * T2W + nB + 1] = pack_h2(u01, u11);                     \
        Blo[(kpB + 8) * T2W + nB]     = pack_f2h(br2.x - __half2float(u00), br3.x - __half2float(u10)); \
        Blo[(kpB + 8) * T2W + nB + 1] = pack_f2h(br2.y - __half2float(u01), br3.y - __half2float(u11)); \
    }

    H3_STORE(tiles);
    __syncthreads();

    for (int t = 0; t < nk; t++) {
        if (t + 1 < nk) {
            const float* a2 = Ap + (size_t)(t + 1) * 32;
            av0 = *(const float4*)(a2);
            av1 = *(const float4*)(a2 + 16);
            const float* w2 = Wp + (size_t)(t + 1) * 32 * N;
            br0 = *(const float2*)(w2);
            br1 = *(const float2*)(w2 + N);
            br2 = *(const float2*)(w2 + (size_t)16 * N);
            br3 = *(const float2*)(w2 + (size_t)17 * N);
        }
        int s = t & 1;
        const uint32_t* Ahi = tiles + s * H3BUF;
        const uint32_t* Alo = Ahi + T2SZ;
        const uint32_t* Bhi = Ahi + 2 * T2SZ;
        const uint32_t* Blo = Ahi + 3 * T2SZ;

#pragma unroll
        for (int sub = 0; sub < 2; sub++) {
            int ko = sub * 8;
            uint32_t ah[2][4], al[2][4], bh[4][2], bl[4][2];
#pragma unroll
            for (int mt = 0; mt < 2; mt++) {
                int m0 = wm + mt * 16 + gid;
                ah[mt][0] = Ahi[(ko + tig) * T2W + m0];
                ah[mt][1] = Ahi[(ko + tig) * T2W + m0 + 8];
                ah[mt][2] = Ahi[(ko + tig + 4) * T2W + m0];
                ah[mt][3] = Ahi[(ko + tig + 4) * T2W + m0 + 8];
                al[mt][0] = Alo[(ko + tig) * T2W + m0];
                al[mt][1] = Alo[(ko + tig) * T2W + m0 + 8];
                al[mt][2] = Alo[(ko + tig + 4) * T2W + m0];
                al[mt][3] = Alo[(ko + tig + 4) * T2W + m0 + 8];
            }
#pragma unroll
            for (int nt = 0; nt < 4; nt++) {
                int n0 = wn + nt * 8 + gid;
                bh[nt][0] = Bhi[(ko + tig) * T2W + n0];
                bh[nt][1] = Bhi[(ko + tig + 4) * T2W + n0];
                bl[nt][0] = Blo[(ko + tig) * T2W + n0];
                bl[nt][1] = Blo[(ko + tig + 4) * T2W + n0];
            }
#pragma unroll
            for (int mt = 0; mt < 2; mt++)
#pragma unroll
                for (int nt = 0; nt < 4; nt++)
                    mma_f16(acc[mt][nt], ah[mt], bh[nt]);
#pragma unroll
            for (int mt = 0; mt < 2; mt++)
#pragma unroll
                for (int nt = 0; nt < 4; nt++)
                    mma_f16(acc[mt][nt], ah[mt], bl[nt]);
#pragma unroll
            for (int mt = 0; mt < 2; mt++)
#pragma unroll
                for (int nt = 0; nt < 4; nt++)
                    mma_f16(acc[mt][nt], al[mt], bh[nt]);
        }

        if (t + 1 < nk) {
            uint32_t* nb = tiles + (s ^ 1) * H3BUF;
            H3_STORE(nb);
        }
        __syncthreads();
    }
#undef H3_STORE

#pragma unroll
    for (int mt = 0; mt < 2; mt++) {
#pragma unroll
        for (int c = 0; c < 4; c++) {
            int r = rowBase + wm + mt * 16 + gid + ((c & 2) ? 8 : 0);
#pragma unroll
            for (int nt = 0; nt < 4; nt++) {
                int cg = colBase + wn + nt * 8 + tig * 2 + (c & 1);
                float v = acc[mt][nt][c] + bias[cg];
                if (MODE == 1) v += Cp[(size_t)r * N + cg];
                Cp[(size_t)r * N + cg] = v;
            }
        }
    }
}

// ---------------- fp16 1-pass big-tile GEMM (128x256, BK=32, 512 thr) --------
#define HB_AW 136
#define HB_BW 264
#define HB_AT (16*HB_AW)
#define HB_BT (16*HB_BW)
#define HB_BUF (HB_AT+HB_BT)
#define SMEM_HB ((256 + 2*HB_BUF) * 4)   // 52224 B

template<int MODE>
__global__ void __launch_bounds__(512, 1)
gemm_hb(const float* __restrict__ A,
        const float* __restrict__ W0, const float* __restrict__ W1,
        const float* __restrict__ W2,
        const float* __restrict__ b0, const float* __restrict__ b1,
        const float* __restrict__ b2,
        float* __restrict__ C0, float* __restrict__ C1, float* __restrict__ C2,
        int Kd, int N, int layer) {
    extern __shared__ float smf[];
    int*   s_tok = (int*)smf;
    float* s_wt  = smf + 128;
    uint32_t* tiles = (uint32_t*)(smf + 256);

    int tid = threadIdx.x;
    int rowBase = blockIdx.y * 128, colBase = blockIdx.x * 256;

    int e = 0, cnt = 0;
    const float* W;
    const float* bias;
    float* Cp = C0;
    if (MODE >= 2) {
        e = blockIdx.z;
        cnt = g_counts[e];
        if (rowBase >= cnt) return;
        W    = W0 + (size_t)(layer * Ee + e) * Kd * N;
        bias = b0 + (size_t)(layer * Ee + e) * N;
        if (tid < 128) {
            int r = rowBase + tid;
            int rc = r < cnt ? r : cnt - 1;
            s_tok[tid] = g_tok[e * TOK + rc];
            s_wt[tid]  = g_wt [e * TOK + rc];
        }
        __syncthreads();
    } else {
        int z = (MODE == 0) ? blockIdx.z : 0;
        W    = (z == 0) ? W0 : (z == 1 ? W1 : W2);
        bias = (z == 0) ? b0 : (z == 1 ? b1 : b2);
        Cp   = (z == 0) ? C0 : (z == 1 ? C1 : C2);
    }

    int lrA = tid >> 2, kcA4 = (tid & 3) << 2, kpA = (tid & 3) << 1;
    const float* Ap;
    if (MODE == 2)      Ap = g_H + (size_t)s_tok[lrA] * Kd + kcA4;
    else if (MODE == 3) Ap = g_hidden + ((size_t)e * TOK + rowBase + lrA) * Kd + kcA4;
    else                Ap = A + (size_t)(rowBase + lrA) * Kd + kcA4;

    int kpB = tid >> 6, nB4 = (tid & 63) << 2;
    const float* Wp = W + (size_t)(2 * kpB) * N + colBase + nB4;

    int lane = tid & 31, warp = tid >> 5;
    int wm = (warp & 1) * 64, wn = (warp >> 1) * 32;
    int gid = lane >> 2, tig = lane & 3;

    float acc[4][4][4];
#pragma unroll
    for (int a = 0; a < 4; a++)
#pragma unroll
        for (int b3 = 0; b3 < 4; b3++)
#pragma unroll
            for (int c = 0; c < 4; c++) acc[a][b3][c] = 0.f;

    int nk = Kd / 32;
    float4 av0, av1, bv0, bv1, bv2, bv3;
    av0 = *(const float4*)(Ap);
    av1 = *(const float4*)(Ap + 16);
    bv0 = *(const float4*)(Wp);
    bv1 = *(const float4*)(Wp + N);
    bv2 = *(const float4*)(Wp + (size_t)16 * N);
    bv3 = *(const float4*)(Wp + (size_t)17 * N);

#define HB_STORE(BUF)                                                          \
    {                                                                          \
        uint32_t* As = (BUF);                                                  \
        uint32_t* Bs = (BUF) + HB_AT;                                          \
        As[kpA * HB_AW + lrA]       = pack_f2h(av0.x, av0.y);                  \
        As[(kpA + 1) * HB_AW + lrA] = pack_f2h(av0.z, av0.w);                  \
        As[(kpA + 8) * HB_AW + lrA] = pack_f2h(av1.x, av1.y);                  \
        As[(kpA + 9) * HB_AW + lrA] = pack_f2h(av1.z, av1.w);                  \
        Bs[kpB * HB_BW + nB4 + 0] = pack_f2h(bv0.x, bv1.x);                    \
        Bs[kpB * HB_BW + nB4 + 1] = pack_f2h(bv0.y, bv1.y);                    \
        Bs[kpB * HB_BW + nB4 + 2] = pack_f2h(bv0.z, bv1.z);                    \
        Bs[kpB * HB_BW + nB4 + 3] = pack_f2h(bv0.w, bv1.w);                    \
        Bs[(kpB + 8) * HB_BW + nB4 + 0] = pack_f2h(bv2.x, bv3.x);              \
        Bs[(kpB + 8) * HB_BW + nB4 + 1] = pack_f2h(bv2.y, bv3.y);              \
        Bs[(kpB + 8) * HB_BW + nB4 + 2] = pack_f2h(bv2.z, bv3.z);              \
        Bs[(kpB + 8) * HB_BW + nB4 + 3] = pack_f2h(bv2.w, bv3.w);              \
    }

    HB_STORE(tiles);
    __syncthreads();

    for (int t = 0; t < nk; t++) {
        if (t + 1 < nk) {
            const float* a2 = Ap + (size_t)(t + 1) * 32;
            av0 = *(const float4*)(a2);
            av1 = *(const float4*)(a2 + 16);
            const float* w2 = Wp + (size_t)(t + 1) * 32 * N;
            bv0 = *(const float4*)(w2);
            bv1 = *(const float4*)(w2 + N);
            bv2 = *(const float4*)(w2 + (size_t)16 * N);
            bv3 = *(const float4*)(w2 + (size_t)17 * N);
        }
        int s = t & 1;
        const uint32_t* As = tiles + s * HB_BUF;
        const uint32_t* Bs = As + HB_AT;

#pragma unroll
        for (int sub = 0; sub < 2; sub++) {
            int ko = sub * 8;
            uint32_t af[4][4], bf[4][2];
#pragma unroll
            for (int mt = 0; mt < 4; mt++) {
                int m0 = wm + mt * 16 + gid;
                af[mt][0] = As[(ko + tig) * HB_AW + m0];
                af[mt][1] = As[(ko + tig) * HB_AW + m0 + 8];
                af[mt][2] = As[(ko + tig + 4) * HB_AW + m0];
                af[mt][3] = As[(ko + tig + 4) * HB_AW + m0 + 8];
            }
#pragma unroll
            for (int nt = 0; nt < 4; nt++) {
                int n0 = wn + nt * 8 + gid;
                bf[nt][0] = Bs[(ko + tig) * HB_BW + n0];
                bf[nt][1] = Bs[(ko + tig + 4) * HB_BW + n0];
            }
#pragma unroll
            for (int mt = 0; mt < 4; mt++)
#pragma unroll
                for (int nt = 0; nt < 4; nt++)
                    mma_f16(acc[mt][nt], af[mt], bf[nt]);
        }

        if (t + 1 < nk) {
            uint32_t* nb = tiles + (s ^ 1) * HB_BUF;
            HB_STORE(nb);
        }
        __syncthreads();
    }
#undef HB_STORE

#pragma unroll
    for (int mt = 0; mt < 4; mt++) {
#pragma unroll
        for (int c = 0; c < 4; c++) {
            int rl = wm + mt * 16 + gid + ((c & 2) ? 8 : 0);
            int r  = rowBase + rl;
#pragma unroll
            for (int nt = 0; nt < 4; nt++) {
                int cg = colBase + wn + nt * 8 + tig * 2 + (c & 1);
                float v = acc[mt][nt][c] + bias[cg];
                if (MODE == 0) {
                    Cp[(size_t)r * N + cg] = v;
                } else if (MODE == 1) {
                    Cp[(size_t)r * N + cg] = v + Cp[(size_t)r * N + cg];
                } else if (MODE == 2) {
                    if (r < cnt)
                        g_hidden[((size_t)e * TOK + r) * N + cg] = gelu_exact(v);
                } else {
                    g_moeout[((size_t)(e * TOK + r)) * N + cg] = v * s_wt[rl];
                }
            }
        }
    }
}

// MoE combine
__global__ void moe_combine() {
    int i = blockIdx.x * 256 + threadIdx.x;
    int t = i >> 8;
    int c4 = (i & 255) << 2;
    int s0 = g_islot[t * 2], s1 = g_islot[t * 2 + 1];
    float4 a = *(const float4*)&g_moeout[(size_t)s0 * Dq + c4];
    float4 b = *(const float4*)&g_moeout[(size_t)s1 * Dq + c4];
    float4 x = *(float4*)&g_X[(size_t)t * Dq + c4];
    x.x += a.x + b.x; x.y += a.y + b.y; x.z += a.z + b.z; x.w += a.w + b.w;
    *(float4*)&g_X[(size_t)t * Dq + c4] = x;
}

// ---------------- fp16 tensor-core flash attention ---------------------------
// LPT (heavy qb first), 2 CTAs/SM, V deferred to regs during QK phase.
#define FQ2 (32*136)
#define FK2 (32*72)
#define FV2 (32*72)
#define FP2 (32*136)
#define FL2_TOT (FQ2+FK2+FV2+FP2)
#define FL2_SMEM0 (FL2_TOT*4)
#define FL2_SMEM1 (FL2_TOT*8)

template<int SPLIT>
__global__ void __launch_bounds__(256, 2)
flash_h() {
    extern __shared__ uint32_t fu[];
    uint32_t* Qh = fu;
    uint32_t* Ql = Qh + FQ2;
    uint32_t* Kh = Qh + FQ2 * (SPLIT + 1);
    uint32_t* Kl = Kh + FK2;
    uint32_t* Vh = Kh + FK2 * (SPLIT + 1);
    uint32_t* Vl = Vh + FV2;
    uint32_t* Ph = Vh + FV2 * (SPLIT + 1);
    uint32_t* Pl = Ph + FP2;

    int qb = (int)(gridDim.x - 1 - blockIdx.x);   // LPT: heavy blocks first
    int h = blockIdx.y, b = blockIdx.z;
    int tid = threadIdx.x, warp = tid >> 5, lane = tid & 31;
    int gid = lane >> 2, tig = lane & 3;
    int mrow = warp * 16 + gid;

    for (int i = tid; i < 2048; i += 256) {
        int r = i >> 4, d4 = (i & 15) << 2, dp = (i & 15) << 1;
        float4 v = *(const float4*)&g_Q[((size_t)(b * Sq + qb * 128 + r)) * Dq + h * HD + d4];
        __half h0 = __float2half_rn(v.x), h1 = __float2half_rn(v.y);
        __half h2 = __float2half_rn(v.z), h3 = __float2half_rn(v.w);
        Qh[dp * 136 + r]       = pack_h2(h0, h1);
        Qh[(dp + 1) * 136 + r] = pack_h2(h2, h3);
        if (SPLIT) {
            Ql[dp * 136 + r]       = pack_f2h(v.x - __half2float(h0), v.y - __half2float(h1));
            Ql[(dp + 1) * 136 + r] = pack_f2h(v.z - __half2float(h2), v.w - __half2float(h3));
        }
    }

    float mA = -1e30f, mB = -1e30f, lA = 0.f, lB = 0.f;
    float o[8][4];
#pragma unroll
    for (int nt = 0; nt < 8; nt++)
#pragma unroll
        for (int c = 0; c < 4; c++) o[nt][c] = 0.f;

    int nkt = 2 * qb + 2;
    for (int kt = 0; kt < nkt; kt++) {
        __syncthreads();    // prior PV done reading Vh/Ph; Qh ready (first iter)
        // K -> smem
        for (int i = tid; i < 1024; i += 256) {
            int r = i >> 4, d4 = (i & 15) << 2, dp = (i & 15) << 1;
            size_t base = ((size_t)(b * Sq + kt * 64 + r)) * Dq + h * HD + d4;
            float4 kv = *(const float4*)&g_K[base];
            __half h0 = __float2half_rn(kv.x), h1 = __float2half_rn(kv.y);
            __half h2 = __float2half_rn(kv.z), h3 = __float2half_rn(kv.w);
            Kh[dp * 72 + r]       = pack_h2(h0, h1);
            Kh[(dp + 1) * 72 + r] = pack_h2(h2, h3);
            if (SPLIT) {
                Kl[dp * 72 + r]       = pack_f2h(kv.x - __half2float(h0), kv.y - __half2float(h1));
                Kl[(dp + 1) * 72 + r] = pack_f2h(kv.z - __half2float(h2), kv.w - __half2float(h3));
            }
        }
        // V -> registers (in flight during QK + softmax)
        float4 vr0[2], vr1[2];
#pragma unroll
        for (int ii = 0; ii < 2; ii++) {
            int i = tid + ii * 256;
            int kp = i >> 4, d4 = (i & 15) << 2;
            size_t base0 = ((size_t)(b * Sq + kt * 64 + 2 * kp)) * Dq + h * HD + d4;
            vr0[ii] = *(const float4*)&g_V[base0];
            vr1[ii] = *(const float4*)&g_V[base0 + Dq];
        }
        __syncthreads();    // Kh visible

        // S = Q @ K^T
        float s[8][4];
#pragma unroll
        for (int nt = 0; nt < 8; nt++)
#pragma unroll
            for (int c = 0; c < 4; c++) s[nt][c] = 0.f;

#pragma unroll
        for (int ks = 0; ks < 4; ks++) {
            int kp0 = 8 * ks + tig, kp1 = 8 * ks + tig + 4;
            uint32_t a[4], al[4];
            a[0] = Qh[kp0 * 136 + mrow];
            a[1] = Qh[kp0 * 136 + mrow + 8];
            a[2] = Qh[kp1 * 136 + mrow];
            a[3] = Qh[kp1 * 136 + mrow + 8];
            if (SPLIT) {
                al[0] = Ql[kp0 * 136 + mrow];
                al[1] = Ql[kp0 * 136 + mrow + 8];
                al[2] = Ql[kp1 * 136 + mrow];
                al[3] = Ql[kp1 * 136 + mrow + 8];
            }
#pragma unroll
            for (int gq = 0; gq < 2; gq++) {
                uint32_t bb[4][2], bl[4][2];
#pragma unroll
                for (int j = 0; j < 4; j++) {
                    int n0 = (gq * 4 + j) * 8 + gid;
                    bb[j][0] = Kh[kp0 * 72 + n0];
                    bb[j][1] = Kh[kp1 * 72 + n0];
                    if (SPLIT) {
                        bl[j][0] = Kl[kp0 * 72 + n0];
                        bl[j][1] = Kl[kp1 * 72 + n0];
                    }
                }
#pragma unroll
                for (int j = 0; j < 4; j++) mma_f16(s[gq * 4 + j], a, bb[j]);
                if (SPLIT) {
#pragma unroll
                    for (int j = 0; j < 4; j++) mma_f16(s[gq * 4 + j], a, bl[j]);
#pragma unroll
                    for (int j = 0; j < 4; j++) mma_f16(s[gq * 4 + j], al, bb[j]);
                }
            }
        }

        int rowg = qb * 128 + warp * 16 + gid;
        if (kt * 64 + 63 > rowg) {
#pragma unroll
            for (int nt = 0; nt < 8; nt++)
#pragma unroll
                for (int c = 0; c < 4; c++) {
                    int col = kt * 64 + nt * 8 + 2 * tig + (c & 1);
                    int row = rowg + ((c & 2) ? 8 : 0);
                    float sv = s[nt][c] * 0.125f;
                    s[nt][c] = (col > row) ? -1e30f : sv;
                }
        } else {
#pragma unroll
            for (int nt = 0; nt < 8; nt++)
#pragma unroll
                for (int c = 0; c < 4; c++) s[nt][c] *= 0.125f;
        }

        float rmA = -1e30f, rmB = -1e30f;
#pragma unroll
        for (int nt = 0; nt < 8; nt++) {
            rmA = fmaxf(rmA, fmaxf(s[nt][0], s[nt][1]));
            rmB = fmaxf(rmB, fmaxf(s[nt][2], s[nt][3]));
        }
#pragma unroll
        for (int off = 1; off < 4; off <<= 1) {
            rmA = fmaxf(rmA, __shfl_xor_sync(0xffffffffu, rmA, off));
            rmB = fmaxf(rmB, __shfl_xor_sync(0xffffffffu, rmB, off));
        }
        float mnA = fmaxf(mA, rmA), mnB = fmaxf(mB, rmB);
        float alA = __expf(mA - mnA), alB = __expf(mB - mnB);
        float rsA = 0.f, rsB = 0.f;
#pragma unroll
        for (int nt = 0; nt < 8; nt++) {
            s[nt][0] = __expf(s[nt][0] - mnA); rsA += s[nt][0];
            s[nt][1] = __expf(s[nt][1] - mnA); rsA += s[nt][1];
            s[nt][2] = __expf(s[nt][2] - mnB); rsB += s[nt][2];
            s[nt][3] = __expf(s[nt][3] - mnB); rsB += s[nt][3];
        }
#pragma unroll
        for (int off = 1; off < 4; off <<= 1) {
            rsA += __shfl_xor_sync(0xffffffffu, rsA, off);
            rsB += __shfl_xor_sync(0xffffffffu, rsB, off);
        }
        lA = lA * alA + rsA; mA = mnA;
        lB = lB * alB + rsB; mB = mnB;
#pragma unroll
        for (int nt = 0; nt < 8; nt++) {
            o[nt][0] *= alA; o[nt][1] *= alA;
            o[nt][2] *= alB; o[nt][3] *= alB;
        }

        // stage P (warp-private rows) and V (from regs) into smem
#pragma unroll
        for (int nt = 0; nt < 8; nt++) {
            int kpP = nt * 4 + tig;
            __half p0 = __float2half_rn(s[nt][0]), p1 = __float2half_rn(s[nt][1]);
            __half p2 = __float2half_rn(s[nt][2]), p3 = __float2half_rn(s[nt][3]);
            Ph[kpP * 136 + mrow]     = pack_h2(p0, p1);
            Ph[kpP * 136 + mrow + 8] = pack_h2(p2, p3);
            if (SPLIT) {
                Pl[kpP * 136 + mrow]     = pack_f2h(s[nt][0] - __half2float(p0),
                                                    s[nt][1] - __half2float(p1));
                Pl[kpP * 136 + mrow + 8] = pack_f2h(s[nt][2] - __half2float(p2),
                                                    s[nt][3] - __half2float(p3));
            }
        }
#pragma unroll
        for (int ii = 0; ii < 2; ii++) {
            int i = tid + ii * 256;
            int kp = i >> 4, d4 = (i & 15) << 2;
            float a0[4] = {vr0[ii].x, vr0[ii].y, vr0[ii].z, vr0[ii].w};
            float a1[4] = {vr1[ii].x, vr1[ii].y, vr1[ii].z, vr1[ii].w};
#pragma unroll
            for (int j = 0; j < 4; j++) {
                __half p0 = __float2half_rn(a0[j]), p1 = __float2half_rn(a1[j]);
                Vh[kp * 72 + d4 + j] = pack_h2(p0, p1);
                if (SPLIT)
                    Vl[kp * 72 + d4 + j] = pack_f2h(a0[j] - __half2float(p0),
                                                    a1[j] - __half2float(p1));
            }
        }
        __syncthreads();    // Vh visible to all warps

        // O += P @ V
#pragma unroll
        for (int ks = 0; ks < 4; ks++) {
            int kp0 = 8 * ks + tig, kp1 = 8 * ks + tig + 4;
            uint32_t a[4], al[4];
            a[0] = Ph[kp0 * 136 + mrow];
            a[1] = Ph[kp0 * 136 + mrow + 8];
            a[2] = Ph[kp1 * 136 + mrow];
            a[3] = Ph[kp1 * 136 + mrow + 8];
            if (SPLIT) {
                al[0] = Pl[kp0 * 136 + mrow];
                al[1] = Pl[kp0 * 136 + mrow + 8];
                al[2] = Pl[kp1 * 136 + mrow];
                al[3] = Pl[kp1 * 136 + mrow + 8];
            }
#pragma unroll
            for (int gq = 0; gq < 2; gq++) {
                uint32_t bb[4][2], bl[4][2];
#pragma unroll
                for (int j = 0; j < 4; j++) {
                    int n0 = (gq * 4 + j) * 8 + gid;
                    bb[j][0] = Vh[kp0 * 72 + n0];
                    bb[j][1] = Vh[kp1 * 72 + n0];
                    if (SPLIT) {
                        bl[j][0] = Vl[kp0 * 72 + n0];
                        bl[j][1] = Vl[kp1 * 72 + n0];
                    }
                }
#pragma unroll
                for (int j = 0; j < 4; j++) mma_f16(o[gq * 4 + j], a, bb[j]);
                if (SPLIT) {
#pragma unroll
                    for (int j = 0; j < 4; j++) mma_f16(o[gq * 4 + j], a, bl[j]);
#pragma unroll
                    for (int j = 0; j < 4; j++) mma_f16(o[gq * 4 + j], al, bb[j]);
                }
            }
        }
    }

    float invA = 1.0f / lA, invB = 1.0f / lB;
    size_t rbase0 = ((size_t)(b * Sq + qb * 128 + warp * 16 + gid)) * Dq + h * HD;
    size_t rbase1 = rbase0 + (size_t)8 * Dq;
#pragma unroll
    for (int nt = 0; nt < 8; nt++) {
        int d0 = nt * 8 + 2 * tig;
        *(float2*)&g_Y[rbase0 + d0] = make_float2(o[nt][0] * invA, o[nt][1] * invA);
        *(float2*)&g_Y[rbase1 + d0] = make_float2(o[nt][2] * invB, o[nt][3] * invB);
    }
}

// ---------------- gating -----------------------------------------------------
__global__ void gate_token_kernel(const float* __restrict__ gw,
                                  const float* __restrict__ gb, int layer) {
    int t = blockIdx.x * 4 + (threadIdx.x >> 5);
    int lane = threadIdx.x & 31;
    if (t >= TOK) return;
    const float* hrow = g_H + (size_t)t * Dq;
    const float* gwl = gw + (size_t)layer * Dq * Ee;
    float acc[Ee] = {};
    for (int d = lane; d < Dq; d += 32) {
        float hv = hrow[d];
        const float* g = gwl + (size_t)d * Ee;
#pragma unroll
        for (int e = 0; e < Ee; e++) acc[e] += hv * g[e];
    }
#pragma unroll
    for (int e = 0; e < Ee; e++)
        for (int off = 16; off; off >>= 1)
            acc[e] += __shfl_xor_sync(0xffffffffu, acc[e], off);
    if (lane == 0) {
        float lg[Ee];
#pragma unroll
        for (int e = 0; e < Ee; e++) lg[e] = acc[e] + gb[layer * Ee + e];
        int i1, i2; float w1, w2;
        top2_of8(lg, i1, i2, w1, w2);
        g_te[t * 2] = i1; g_te[t * 2 + 1] = i2;
        g_tw[t * 2] = w1; g_tw[t * 2 + 1] = w2;
    }
}

__global__ void xmean_kernel() {
    int b = blockIdx.y;
    int d = blockIdx.x * 256 + threadIdx.x;
    float s = 0.f;
    for (int ss = 0; ss < Sq; ss++)
        s += g_H[((size_t)(b * Sq + ss)) * Dq + d];
    g_xmean[b * Dq + d] = s * (1.0f / Sq);
}

__global__ void gate_seq_kernel(const float* __restrict__ gw,
                                const float* __restrict__ gb, int layer) {
    int b = blockIdx.x;
    int tid = threadIdx.x, e = tid >> 5, lane = tid & 31;
    const float* gwl = gw + (size_t)layer * Dq * Ee;
    float acc = 0.f;
    for (int d = lane; d < Dq; d += 32)
        acc += g_xmean[b * Dq + d] * gwl[(size_t)d * Ee + e];
    for (int off = 16; off; off >>= 1)
        acc += __shfl_xor_sync(0xffffffffu, acc, off);
    __shared__ float lg[Ee];
    if (lane == 0) lg[e] = acc + gb[layer * Ee + e];
    __syncthreads();
    if (tid == 0) {
        int i1, i2; float w1, w2;
        top2_of8(lg, i1, i2, w1, w2);
        g_bsel[b * 2] = i1; g_bsel[b * 2 + 1] = i2;
        g_bw[b * 2] = w1;  g_bw[b * 2 + 1] = w2;
    }
}

__global__ void zero_counts_kernel() {
    if (threadIdx.x < Ee) g_counts[threadIdx.x] = 0;
}

__global__ void assign_kernel(int seq_mode) {
    int t = blockIdx.x * 256 + threadIdx.x;
    if (t >= TOK) return;
    int e1, e2; float w1, w2;
    if (seq_mode) {
        int b = t / Sq;
        e1 = g_bsel[b * 2]; e2 = g_bsel[b * 2 + 1];
        w1 = g_bw[b * 2];   w2 = g_bw[b * 2 + 1];
    } else {
        e1 = g_te[t * 2]; e2 = g_te[t * 2 + 1];
        w1 = g_tw[t * 2]; w2 = g_tw[t * 2 + 1];
    }
    int s1 = atomicAdd(&g_counts[e1], 1);
    g_tok[e1 * TOK + s1] = t; g_wt[e1 * TOK + s1] = w1;
    g_islot[t * 2] = e1 * TOK + s1;
    int s2 = atomicAdd(&g_counts[e2], 1);
    g_tok[e2 * TOK + s2] = t; g_wt[e2 * TOK + s2] = w2;
    g_islot[t * 2 + 1] = e2 * TOK + s2;
}

// ---------------- host side --------------------------------------------------
extern "C" void kernel_launch(void* const* d_in, const int* in_sizes, int n_in,
                              void* d_out, int out_size) {
    const float* x      = (const float*)d_in[0];
    const float* ln1_w  = (const float*)d_in[1];
    const float* ln1_b  = (const float*)d_in[2];
    const float* ln2_w  = (const float*)d_in[3];
    const float* ln2_b  = (const float*)d_in[4];
    const float* wq     = (const float*)d_in[5];
    const float* wk     = (const float*)d_in[6];
    const float* wv     = (const float*)d_in[7];
    const float* wo     = (const float*)d_in[8];
    const float* bq     = (const float*)d_in[9];
    const float* bk     = (const float*)d_in[10];
    const float* bv     = (const float*)d_in[11];
    const float* bo     = (const float*)d_in[12];
    const float* gate_w = (const float*)d_in[13];
    const float* gate_b = (const float*)d_in[14];
    const float* e_w1   = (const float*)d_in[15];
    const float* e_b1   = (const float*)d_in[16];
    const float* e_w2   = (const float*)d_in[17];
    const float* e_b2   = (const float*)d_in[18];

    float *Xp, *Hp, *Qp, *Kp, *Vp, *Yp;
    cudaGetSymbolAddress((void**)&Xp, g_X);
    cudaGetSymbolAddress((void**)&Hp, g_H);
    cudaGetSymbolAddress((void**)&Qp, g_Q);
    cudaGetSymbolAddress((void**)&Kp, g_K);
    cudaGetSymbolAddress((void**)&Vp, g_V);
    cudaGetSymbolAddress((void**)&Yp, g_Y);

    static int attr_set = 0;
    if (!attr_set) {
        cudaFuncSetAttribute(gemm_h3<0>, cudaFuncAttributeMaxDynamicSharedMemorySize, SMEM_H3);
        cudaFuncSetAttribute(gemm_h3<1>, cudaFuncAttributeMaxDynamicSharedMemorySize, SMEM_H3);
        cudaFuncSetAttribute(gemm_hb<0>, cudaFuncAttributeMaxDynamicSharedMemorySize, SMEM_HB);
        cudaFuncSetAttribute(gemm_hb<1>, cudaFuncAttributeMaxDynamicSharedMemorySize, SMEM_HB);
        cudaFuncSetAttribute(gemm_hb<2>, cudaFuncAttributeMaxDynamicSharedMemorySize, SMEM_HB);
        cudaFuncSetAttribute(gemm_hb<3>, cudaFuncAttributeMaxDynamicSharedMemorySize, SMEM_HB);
        cudaFuncSetAttribute(flash_h<0>, cudaFuncAttributeMaxDynamicSharedMemorySize, FL2_SMEM0);
        cudaFuncSetAttribute(flash_h<1>, cudaFuncAttributeMaxDynamicSharedMemorySize, FL2_SMEM1);
        attr_set = 1;
    }

    const size_t DD = (size_t)Dq * Dq;
    const int nelem = TOK * Dq;

    copy_in_kernel<<<nelem / 256, 256>>>(x);

    for (int l = 0; l < Ll; l++) {
        const float* WQ = wq + l * DD;
        const float* WK = wk + l * DD;
        const float* WV = wv + l * DD;
        const float* WO = wo + l * DD;
        const float* BQ = bq + (size_t)l * Dq;
        const float* BK = bk + (size_t)l * Dq;
        const float* BV = bv + (size_t)l * Dq;
        const float* BO = bo + (size_t)l * Dq;

        ln_kernel<<<TOK, 256>>>(ln1_w + (size_t)l * Dq, ln1_b + (size_t)l * Dq);
        if (l == 0) {
            gemm_h3<0><<<dim3(8, 32, 3), 512, SMEM_H3>>>(
                Hp, WQ, WK, WV, BQ, BK, BV, Qp, Kp, Vp, Dq, Dq);
            flash_h<1><<<dim3(Sq / 128, Hh, Bq), 256, FL2_SMEM1>>>();
            gemm_h3<1><<<dim3(8, 32), 512, SMEM_H3>>>(
                Yp, WO, nullptr, nullptr, BO, nullptr, nullptr, Xp, nullptr, nullptr, Dq, Dq);
        } else {
            gemm_hb<0><<<dim3(4, 32, 3), 512, SMEM_HB>>>(
                Hp, WQ, WK, WV, BQ, BK, BV, Qp, Kp, Vp, Dq, Dq, l);
            flash_h<0><<<dim3(Sq / 128, Hh, Bq), 256, FL2_SMEM0>>>();
            gemm_hb<1><<<dim3(4, 32), 512, SMEM_HB>>>(
                Yp, WO, nullptr, nullptr, BO, nullptr, nullptr, Xp, nullptr, nullptr, Dq, Dq, l);
        }

        ln_kernel<<<TOK, 256>>>(ln2_w + (size_t)l * Dq, ln2_b + (size_t)l * Dq);
        if (l % 2 == 0) {
            gate_token_kernel<<<TOK / 4, 128>>>(gate_w, gate_b, l);
        } else {
            xmean_kernel<<<dim3(Dq / 256, Bq), 256>>>();
            gate_seq_kernel<<<Bq, 256>>>(gate_w, gate_b, l);
        }
        zero_counts_kernel<<<1, 32>>>();
        assign_kernel<<<TOK / 256, 256>>>(l % 2);
        gemm_hb<2><<<dim3(DFFq / 256, TOK / 128, Ee), 512, SMEM_HB>>>(
            nullptr, e_w1, nullptr, nullptr, e_b1, nullptr, nullptr,
            nullptr, nullptr, nullptr, Dq, DFFq, l);
        gemm_hb<3><<<dim3(Dq / 256, TOK / 128, Ee), 512, SMEM_HB>>>(
            nullptr, e_w2, nullptr, nullptr, e_b2, nullptr, nullptr,
            nullptr, nullptr, nullptr, DFFq, Dq, l);
        moe_combine<<<nelem / 1024, 256>>>();
    }

    copy_out_kernel<<<nelem / 256, 256>>>((float*)d_out);
    (void)in_sizes; (void)n_in; (void)out_size;
}

// round 12
// speedup vs baseline: 10.7532x; 1.0130x over previous
#include <cuda_runtime.h>
#include <cuda_fp16.h>
#include <math.h>
#include <stdint.h>

#define Bq   4
#define Sq   1024
#define Dq   1024
#define Hh   16
#define HD   64
#define Ll   2
#define Ee   8
#define DFFq 4096
#define TOK  (Bq*Sq)   // 4096

// ---------------- static scratch ---------------------------------------------
__device__ float g_X[TOK*Dq];
__device__ float g_H[TOK*Dq];
__device__ float g_Q[TOK*Dq];
__device__ float g_K[TOK*Dq];
__device__ float g_V[TOK*Dq];
__device__ float g_Y[TOK*Dq];
__device__ float g_hidden[(size_t)Ee*TOK*DFFq];
__device__ float g_moeout[(size_t)Ee*TOK*Dq];
__device__ int   g_counts[Ee];
__device__ int   g_tok[Ee*TOK];
__device__ float g_wt[Ee*TOK];
__device__ int   g_islot[TOK*2];
__device__ int   g_te[TOK*2];
__device__ float g_tw[TOK*2];
__device__ int   g_bsel[Bq*2];
__device__ float g_bw[Bq*2];
__device__ float g_xmean[Bq*Dq];

// ---------------- helpers ----------------------------------------------------
__device__ __forceinline__ void top2_of8(const float* lg, int& i1, int& i2,
                                         float& w1, float& w2) {
    i1 = 0; float v1 = lg[0];
#pragma unroll
    for (int e = 1; e < Ee; e++) if (lg[e] > v1) { v1 = lg[e]; i1 = e; }
    i2 = -1; float v2 = -3.0e38f;
#pragma unroll
    for (int e = 0; e < Ee; e++) if (e != i1 && lg[e] > v2) { v2 = lg[e]; i2 = e; }
    float ex = expf(v2 - v1);
    w1 = 1.0f / (1.0f + ex);
    w2 = ex / (1.0f + ex);
}
__device__ __forceinline__ float gelu_exact(float x) {
    return 0.5f * x * (1.0f + erff(x * 0.7071067811865476f));
}
__device__ __forceinline__ void mma_f16(float c[4], const uint32_t a[4],
                                        const uint32_t b[2]) {
    asm volatile(
        "mma.sync.aligned.m16n8k16.row.col.f32.f16.f16.f32 "
        "{%0,%1,%2,%3},{%4,%5,%6,%7},{%8,%9},{%0,%1,%2,%3};"
        : "+f"(c[0]), "+f"(c[1]), "+f"(c[2]), "+f"(c[3])
        : "r"(a[0]), "r"(a[1]), "r"(a[2]), "r"(a[3]), "r"(b[0]), "r"(b[1]));
}
__device__ __forceinline__ uint32_t pack_h2(__half a, __half b) {
    __half2 h = __halves2half2(a, b);
    return *(uint32_t*)&h;
}
__device__ __forceinline__ uint32_t pack_f2h(float a, float b) {
    return pack_h2(__float2half_rn(a), __float2half_rn(b));
}

// ---------------- simple kernels ---------------------------------------------
__global__ void copy_in_kernel(const float* __restrict__ src) {
    int i = blockIdx.x * 256 + threadIdx.x;
    g_X[i] = src[i];
}

__global__ void ln_kernel(const float* __restrict__ w, const float* __restrict__ b) {
    int t = blockIdx.x, tid = threadIdx.x;
    const float* xr = g_X + (size_t)t * Dq;
    float s = 0.f, s2 = 0.f;
    for (int d = tid; d < Dq; d += 256) { float v = xr[d]; s += v; s2 += v * v; }
    __shared__ float r1[256], r2[256];
    r1[tid] = s; r2[tid] = s2; __syncthreads();
    for (int off = 128; off; off >>= 1) {
        if (tid < off) { r1[tid] += r1[tid + off]; r2[tid] += r2[tid + off]; }
        __syncthreads();
    }
    float mean = r1[0] * (1.0f / Dq);
    float var  = r2[0] * (1.0f / Dq) - mean * mean;
    float rstd = rsqrtf(var + 1e-5f);
    float* hr = g_H + (size_t)t * Dq;
    for (int d = tid; d < Dq; d += 256)
        hr[d] = (xr[d] - mean) * rstd * w[d] + b[d];
}

// combine prev-layer MoE into x, then LayerNorm (fused moe_combine + ln1)
__global__ void ln_combine_kernel(const float* __restrict__ w, const float* __restrict__ b) {
    int t = blockIdx.x, tid = threadIdx.x;
    int s0 = g_islot[t * 2], s1 = g_islot[t * 2 + 1];
    float* xr = g_X + (size_t)t * Dq;
    const float* m0 = g_moeout + (size_t)s0 * Dq;
    const float* m1 = g_moeout + (size_t)s1 * Dq;
    float s = 0.f, s2 = 0.f;
    for (int d = tid; d < Dq; d += 256) {
        float v = xr[d] + m0[d] + m1[d];
        xr[d] = v;
        s += v; s2 += v * v;
    }
    __shared__ float r1[256], r2[256];
    r1[tid] = s; r2[tid] = s2; __syncthreads();
    for (int off = 128; off; off >>= 1) {
        if (tid < off) { r1[tid] += r1[tid + off]; r2[tid] += r2[tid + off]; }
        __syncthreads();
    }
    float mean = r1[0] * (1.0f / Dq);
    float var  = r2[0] * (1.0f / Dq) - mean * mean;
    float rstd = rsqrtf(var + 1e-5f);
    float* hr = g_H + (size_t)t * Dq;
    for (int d = tid; d < Dq; d += 256)
        hr[d] = (xr[d] - mean) * rstd * w[d] + b[d];
}

// final combine + output write (fused moe_combine + copy_out)
__global__ void combine_out_kernel(float* __restrict__ dst) {
    int i = blockIdx.x * 256 + threadIdx.x;     // over TOK*Dq/4
    int t = i >> 8;
    int c4 = (i & 255) << 2;
    int s0 = g_islot[t * 2], s1 = g_islot[t * 2 + 1];
    float4 a = *(const float4*)&g_moeout[(size_t)s0 * Dq + c4];
    float4 b = *(const float4*)&g_moeout[(size_t)s1 * Dq + c4];
    float4 x = *(const float4*)&g_X[(size_t)t * Dq + c4];
    x.x += a.x + b.x; x.y += a.y + b.y; x.z += a.z + b.z; x.w += a.w + b.w;
    *(float4*)&dst[(size_t)t * Dq + c4] = x;
}

// ---------------- fp16 3-pass split GEMM (layer-0, 128x128, BK=32) -----------
#define T2W 136
#define T2SZ (16*T2W)
#define H3BUF (4*T2SZ)
#define SMEM_H3 (2*H3BUF*4)           // 69632 B

template<int MODE>
__global__ void __launch_bounds__(512, 1)
gemm_h3(const float* __restrict__ A,
        const float* __restrict__ W0, const float* __restrict__ W1,
        const float* __restrict__ W2,
        const float* __restrict__ b0, const float* __restrict__ b1,
        const float* __restrict__ b2,
        float* __restrict__ C0, float* __restrict__ C1, float* __restrict__ C2,
        int Kd, int N) {
    extern __shared__ uint32_t tiles[];
    int z = (MODE == 0) ? blockIdx.z : 0;
    const float* Wall = (z == 0) ? W0 : (z == 1 ? W1 : W2);
    const float* bias = (z == 0) ? b0 : (z == 1 ? b1 : b2);
    float* Cp         = (z == 0) ? C0 : (z == 1 ? C1 : C2);

    int tid = threadIdx.x;
    int rowBase = blockIdx.y * 128, colBase = blockIdx.x * 128;

    int lrA = tid >> 2, kcA4 = (tid & 3) << 2, kpA = (tid & 3) << 1;
    const float* Ap = A + (size_t)(rowBase + lrA) * Kd + kcA4;
    int kpB = tid >> 6, nB = (tid & 63) << 1;
    const float* Wp = Wall + (size_t)(2 * kpB) * N + colBase + nB;

    int lane = tid & 31, warp = tid >> 5;
    int wm = (warp & 3) * 32, wn = (warp >> 2) * 32;
    int gid = lane >> 2, tig = lane & 3;

    float acc[2][4][4];
#pragma unroll
    for (int a = 0; a < 2; a++)
#pragma unroll
        for (int b3 = 0; b3 < 4; b3++)
#pragma unroll
            for (int c = 0; c < 4; c++) acc[a][b3][c] = 0.f;

    int nk = Kd / 32;
    float4 av0, av1;
    float2 br0, br1, br2, br3;
    av0 = *(const float4*)(Ap);
    av1 = *(const float4*)(Ap + 16);
    br0 = *(const float2*)(Wp);
    br1 = *(const float2*)(Wp + N);
    br2 = *(const float2*)(Wp + (size_t)16 * N);
    br3 = *(const float2*)(Wp + (size_t)17 * N);

#define H3_STORE(BUF)                                                          \
    {                                                                          \
        uint32_t* Ahi = (BUF);                                                 \
        uint32_t* Alo = (BUF) + T2SZ;                                          \
        uint32_t* Bhi = (BUF) + 2 * T2SZ;                                      \
        uint32_t* Blo = (BUF) + 3 * T2SZ;                                      \
        __half h0 = __float2half_rn(av0.x), h1 = __float2half_rn(av0.y);       \
        __half h2 = __float2half_rn(av0.z), h3 = __float2half_rn(av0.w);       \
        Ahi[kpA * T2W + lrA]       = pack_h2(h0, h1);                          \
        Ahi[(kpA + 1) * T2W + lrA] = pack_h2(h2, h3);                          \
        Alo[kpA * T2W + lrA]       = pack_f2h(av0.x - __half2float(h0), av0.y - __half2float(h1)); \
        Alo[(kpA + 1) * T2W + lrA] = pack_f2h(av0.z - __half2float(h2), av0.w - __half2float(h3)); \
        __half g0 = __float2half_rn(av1.x), g1 = __float2half_rn(av1.y);       \
        __half g2 = __float2half_rn(av1.z), g3 = __float2half_rn(av1.w);       \
        Ahi[(kpA + 8) * T2W + lrA] = pack_h2(g0, g1);                          \
        Ahi[(kpA + 9) * T2W + lrA] = pack_h2(g2, g3);                          \
        Alo[(kpA + 8) * T2W + lrA] = pack_f2h(av1.x - __half2float(g0), av1.y - __half2float(g1)); \
        Alo[(kpA + 9) * T2W + lrA] = pack_f2h(av1.z - __half2float(g2), av1.w - __half2float(g3)); \
        __half w00 = __float2half_rn(br0.x), w10 = __float2half_rn(br1.x);     \
        __half w01 = __float2half_rn(br0.y), w11 = __float2half_rn(br1.y);     \
        Bhi[kpB * T2W + nB]     = pack_h2(w00, w10);                           \
        Bhi[kpB * T2W + nB + 1] = pack_h2(w01, w11);                           \
        Blo[kpB * T2W + nB]     = pack_f2h(br0.x - __half2float(w00), br1.x - __half2float(w10)); \
        Blo[kpB * T2W + nB + 1] = pack_f2h(br0.y - __half2float(w01), br1.y - __half2float(w11)); \
        __half u00 = __float2half_rn(br2.x), u10 = __float2half_rn(br3.x);     \
        __half u01 = __float2half_rn(br2.y), u11 = __float2half_rn(br3.y);     \
        Bhi[(kpB + 8) * T2W + nB]     = pack_h2(u00, u10);                     \
        Bhi[(kpB + 8) * T2W + nB + 1] = pack_h2(u01, u11);                     \
        Blo[(kpB + 8) * T2W + nB]     = pack_f2h(br2.x - __half2float(u00), br3.x - __half2float(u10)); \
        Blo[(kpB + 8) * T2W + nB + 1] = pack_f2h(br2.y - __half2float(u01), br3.y - __half2float(u11)); \
    }

    H3_STORE(tiles);
    __syncthreads();

    for (int t = 0; t < nk; t++) {
        if (t + 1 < nk) {
            const float* a2 = Ap + (size_t)(t + 1) * 32;
            av0 = *(const float4*)(a2);
            av1 = *(const float4*)(a2 + 16);
            const float* w2 = Wp + (size_t)(t + 1) * 32 * N;
            br0 = *(const float2*)(w2);
            br1 = *(const float2*)(w2 + N);
            br2 = *(const float2*)(w2 + (size_t)16 * N);
            br3 = *(const float2*)(w2 + (size_t)17 * N);
        }
        int s = t & 1;
        const uint32_t* Ahi = tiles + s * H3BUF;
        const uint32_t* Alo = Ahi + T2SZ;
        const uint32_t* Bhi = Ahi + 2 * T2SZ;
        const uint32_t* Blo = Ahi + 3 * T2SZ;

#pragma unroll
        for (int sub = 0; sub < 2; sub++) {
            int ko = sub * 8;
            uint32_t ah[2][4], al[2][4], bh[4][2], bl[4][2];
#pragma unroll
            for (int mt = 0; mt < 2; mt++) {
                int m0 = wm + mt * 16 + gid;
                ah[mt][0] = Ahi[(ko + tig) * T2W + m0];
                ah[mt][1] = Ahi[(ko + tig) * T2W + m0 + 8];
                ah[mt][2] = Ahi[(ko + tig + 4) * T2W + m0];
                ah[mt][3] = Ahi[(ko + tig + 4) * T2W + m0 + 8];
                al[mt][0] = Alo[(ko + tig) * T2W + m0];
                al[mt][1] = Alo[(ko + tig) * T2W + m0 + 8];
                al[mt][2] = Alo[(ko + tig + 4) * T2W + m0];
                al[mt][3] = Alo[(ko + tig + 4) * T2W + m0 + 8];
            }
#pragma unroll
            for (int nt = 0; nt < 4; nt++) {
                int n0 = wn + nt * 8 + gid;
                bh[nt][0] = Bhi[(ko + tig) * T2W + n0];
                bh[nt][1] = Bhi[(ko + tig + 4) * T2W + n0];
                bl[nt][0] = Blo[(ko + tig) * T2W + n0];
                bl[nt][1] = Blo[(ko + tig + 4) * T2W + n0];
            }
#pragma unroll
            for (int mt = 0; mt < 2; mt++)
#pragma unroll
                for (int nt = 0; nt < 4; nt++)
                    mma_f16(acc[mt][nt], ah[mt], bh[nt]);
#pragma unroll
            for (int mt = 0; mt < 2; mt++)
#pragma unroll
                for (int nt = 0; nt < 4; nt++)
                    mma_f16(acc[mt][nt], ah[mt], bl[nt]);
#pragma unroll
            for (int mt = 0; mt < 2; mt++)
#pragma unroll
                for (int nt = 0; nt < 4; nt++)
                    mma_f16(acc[mt][nt], al[mt], bh[nt]);
        }

        if (t + 1 < nk) {
            uint32_t* nb = tiles + (s ^ 1) * H3BUF;
            H3_STORE(nb);
        }
        __syncthreads();
    }
#undef H3_STORE

#pragma unroll
    for (int mt = 0; mt < 2; mt++) {
#pragma unroll
        for (int c = 0; c < 4; c++) {
            int r = rowBase + wm + mt * 16 + gid + ((c & 2) ? 8 : 0);
#pragma unroll
            for (int nt = 0; nt < 4; nt++) {
                int cg = colBase + wn + nt * 8 + tig * 2 + (c & 1);
                float v = acc[mt][nt][c] + bias[cg];
                if (MODE == 1) v += Cp[(size_t)r * N + cg];
                Cp[(size_t)r * N + cg] = v;
            }
        }
    }
}

// ---------------- fp16 1-pass big-tile GEMM (128x256, BK=32, 512 thr) --------
#define HB_AW 136
#define HB_BW 264
#define HB_AT (16*HB_AW)
#define HB_BT (16*HB_BW)
#define HB_BUF (HB_AT+HB_BT)
#define SMEM_HB ((256 + 2*HB_BUF) * 4)   // 52224 B

template<int MODE>
__global__ void __launch_bounds__(512, 1)
gemm_hb(const float* __restrict__ A,
        const float* __restrict__ W0, const float* __restrict__ W1,
        const float* __restrict__ W2,
        const float* __restrict__ b0, const float* __restrict__ b1,
        const float* __restrict__ b2,
        float* __restrict__ C0, float* __restrict__ C1, float* __restrict__ C2,
        int Kd, int N, int layer) {
    extern __shared__ float smf[];
    int*   s_tok = (int*)smf;
    float* s_wt  = smf + 128;
    uint32_t* tiles = (uint32_t*)(smf + 256);

    int tid = threadIdx.x;
    int rowBase = blockIdx.y * 128, colBase = blockIdx.x * 256;

    int e = 0, cnt = 0;
    const float* W;
    const float* bias;
    float* Cp = C0;
    if (MODE >= 2) {
        e = blockIdx.z;
        cnt = g_counts[e];
        if (rowBase >= cnt) return;
        W    = W0 + (size_t)(layer * Ee + e) * Kd * N;
        bias = b0 + (size_t)(layer * Ee + e) * N;
        if (tid < 128) {
            int r = rowBase + tid;
            int rc = r < cnt ? r : cnt - 1;
            s_tok[tid] = g_tok[e * TOK + rc];
            s_wt[tid]  = g_wt [e * TOK + rc];
        }
        __syncthreads();
    } else {
        int z = (MODE == 0) ? blockIdx.z : 0;
        W    = (z == 0) ? W0 : (z == 1 ? W1 : W2);
        bias = (z == 0) ? b0 : (z == 1 ? b1 : b2);
        Cp   = (z == 0) ? C0 : (z == 1 ? C1 : C2);
    }

    int lrA = tid >> 2, kcA4 = (tid & 3) << 2, kpA = (tid & 3) << 1;
    const float* Ap;
    if (MODE == 2)      Ap = g_H + (size_t)s_tok[lrA] * Kd + kcA4;
    else if (MODE == 3) Ap = g_hidden + ((size_t)e * TOK + rowBase + lrA) * Kd + kcA4;
    else                Ap = A + (size_t)(rowBase + lrA) * Kd + kcA4;

    int kpB = tid >> 6, nB4 = (tid & 63) << 2;
    const float* Wp = W + (size_t)(2 * kpB) * N + colBase + nB4;

    int lane = tid & 31, warp = tid >> 5;
    int wm = (warp & 1) * 64, wn = (warp >> 1) * 32;
    int gid = lane >> 2, tig = lane & 3;

    float acc[4][4][4];
#pragma unroll
    for (int a = 0; a < 4; a++)
#pragma unroll
        for (int b3 = 0; b3 < 4; b3++)
#pragma unroll
            for (int c = 0; c < 4; c++) acc[a][b3][c] = 0.f;

    int nk = Kd / 32;
    float4 av0, av1, bv0, bv1, bv2, bv3;
    av0 = *(const float4*)(Ap);
    av1 = *(const float4*)(Ap + 16);
    bv0 = *(const float4*)(Wp);
    bv1 = *(const float4*)(Wp + N);
    bv2 = *(const float4*)(Wp + (size_t)16 * N);
    bv3 = *(const float4*)(Wp + (size_t)17 * N);

#define HB_STORE(BUF)                                                          \
    {                                                                          \
        uint32_t* As = (BUF);                                                  \
        uint32_t* Bs = (BUF) + HB_AT;                                          \
        As[kpA * HB_AW + lrA]       = pack_f2h(av0.x, av0.y);                  \
        As[(kpA + 1) * HB_AW + lrA] = pack_f2h(av0.z, av0.w);                  \
        As[(kpA + 8) * HB_AW + lrA] = pack_f2h(av1.x, av1.y);                  \
        As[(kpA + 9) * HB_AW + lrA] = pack_f2h(av1.z, av1.w);                  \
        Bs[kpB * HB_BW + nB4 + 0] = pack_f2h(bv0.x, bv1.x);                    \
        Bs[kpB * HB_BW + nB4 + 1] = pack_f2h(bv0.y, bv1.y);                    \
        Bs[kpB * HB_BW + nB4 + 2] = pack_f2h(bv0.z, bv1.z);                    \
        Bs[kpB * HB_BW + nB4 + 3] = pack_f2h(bv0.w, bv1.w);                    \
        Bs[(kpB + 8) * HB_BW + nB4 + 0] = pack_f2h(bv2.x, bv3.x);              \
        Bs[(kpB + 8) * HB_BW + nB4 + 1] = pack_f2h(bv2.y, bv3.y);              \
        Bs[(kpB + 8) * HB_BW + nB4 + 2] = pack_f2h(bv2.z, bv3.z);              \
        Bs[(kpB + 8) * HB_BW + nB4 + 3] = pack_f2h(bv2.w, bv3.w);              \
    }

    HB_STORE(tiles);
    __syncthreads();

    for (int t = 0; t < nk; t++) {
        if (t + 1 < nk) {
            const float* a2 = Ap + (size_t)(t + 1) * 32;
            av0 = *(const float4*)(a2);
            av1 = *(const float4*)(a2 + 16);
            const float* w2 = Wp + (size_t)(t + 1) * 32 * N;
            bv0 = *(const float4*)(w2);
            bv1 = *(const float4*)(w2 + N);
            bv2 = *(const float4*)(w2 + (size_t)16 * N);
            bv3 = *(const float4*)(w2 + (size_t)17 * N);
        }
        int s = t & 1;
        const uint32_t* As = tiles + s * HB_BUF;
        const uint32_t* Bs = As + HB_AT;

#pragma unroll
        for (int sub = 0; sub < 2; sub++) {
            int ko = sub * 8;
            uint32_t af[4][4], bf[4][2];
#pragma unroll
            for (int mt = 0; mt < 4; mt++) {
                int m0 = wm + mt * 16 + gid;
                af[mt][0] = As[(ko + tig) * HB_AW + m0];
                af[mt][1] = As[(ko + tig) * HB_AW + m0 + 8];
                af[mt][2] = As[(ko + tig + 4) * HB_AW + m0];
                af[mt][3] = As[(ko + tig + 4) * HB_AW + m0 + 8];
            }
#pragma unroll
            for (int nt = 0; nt < 4; nt++) {
                int n0 = wn + nt * 8 + gid;
                bf[nt][0] = Bs[(ko + tig) * HB_BW + n0];
                bf[nt][1] = Bs[(ko + tig + 4) * HB_BW + n0];
            }
#pragma unroll
            for (int mt = 0; mt < 4; mt++)
#pragma unroll
                for (int nt = 0; nt < 4; nt++)
                    mma_f16(acc[mt][nt], af[mt], bf[nt]);
        }

        if (t + 1 < nk) {
            uint32_t* nb = tiles + (s ^ 1) * HB_BUF;
            HB_STORE(nb);
        }
        __syncthreads();
    }
#undef HB_STORE

#pragma unroll
    for (int mt = 0; mt < 4; mt++) {
#pragma unroll
        for (int c = 0; c < 4; c++) {
            int rl = wm + mt * 16 + gid + ((c & 2) ? 8 : 0);
            int r  = rowBase + rl;
#pragma unroll
            for (int nt = 0; nt < 4; nt++) {
                int cg = colBase + wn + nt * 8 + tig * 2 + (c & 1);
                float v = acc[mt][nt][c] + bias[cg];
                if (MODE == 0) {
                    Cp[(size_t)r * N + cg] = v;
                } else if (MODE == 1) {
                    Cp[(size_t)r * N + cg] = v + Cp[(size_t)r * N + cg];
                } else if (MODE == 2) {
                    if (r < cnt)
                        g_hidden[((size_t)e * TOK + r) * N + cg] = gelu_exact(v);
                } else {
                    g_moeout[((size_t)(e * TOK + r)) * N + cg] = v * s_wt[rl];
                }
            }
        }
    }
}

// ---------------- fp16 split flash attention (layer 0, unchanged) ------------
#define FQ2 (32*136)
#define FK2 (32*72)
#define FV2 (32*72)
#define FP2 (32*136)
#define FL2_TOT (FQ2+FK2+FV2+FP2)
#define FL2_SMEM1 (FL2_TOT*8)

template<int SPLIT>
__global__ void __launch_bounds__(256, 2)
flash_h() {
    extern __shared__ uint32_t fu[];
    uint32_t* Qh = fu;
    uint32_t* Ql = Qh + FQ2;
    uint32_t* Kh = Qh + FQ2 * (SPLIT + 1);
    uint32_t* Kl = Kh + FK2;
    uint32_t* Vh = Kh + FK2 * (SPLIT + 1);
    uint32_t* Vl = Vh + FV2;
    uint32_t* Ph = Vh + FV2 * (SPLIT + 1);
    uint32_t* Pl = Ph + FP2;

    int qb = (int)(gridDim.x - 1 - blockIdx.x);
    int h = blockIdx.y, b = blockIdx.z;
    int tid = threadIdx.x, warp = tid >> 5, lane = tid & 31;
    int gid = lane >> 2, tig = lane & 3;
    int mrow = warp * 16 + gid;

    for (int i = tid; i < 2048; i += 256) {
        int r = i >> 4, d4 = (i & 15) << 2, dp = (i & 15) << 1;
        float4 v = *(const float4*)&g_Q[((size_t)(b * Sq + qb * 128 + r)) * Dq + h * HD + d4];
        __half h0 = __float2half_rn(v.x), h1 = __float2half_rn(v.y);
        __half h2 = __float2half_rn(v.z), h3 = __float2half_rn(v.w);
        Qh[dp * 136 + r]       = pack_h2(h0, h1);
        Qh[(dp + 1) * 136 + r] = pack_h2(h2, h3);
        if (SPLIT) {
            Ql[dp * 136 + r]       = pack_f2h(v.x - __half2float(h0), v.y - __half2float(h1));
            Ql[(dp + 1) * 136 + r] = pack_f2h(v.z - __half2float(h2), v.w - __half2float(h3));
        }
    }

    float mA = -1e30f, mB = -1e30f, lA = 0.f, lB = 0.f;
    float o[8][4];
#pragma unroll
    for (int nt = 0; nt < 8; nt++)
#pragma unroll
        for (int c = 0; c < 4; c++) o[nt][c] = 0.f;

    int nkt = 2 * qb + 2;
    for (int kt = 0; kt < nkt; kt++) {
        __syncthreads();
        for (int i = tid; i < 1024; i += 256) {
            int r = i >> 4, d4 = (i & 15) << 2, dp = (i & 15) << 1;
            size_t base = ((size_t)(b * Sq + kt * 64 + r)) * Dq + h * HD + d4;
            float4 kv = *(const float4*)&g_K[base];
            __half h0 = __float2half_rn(kv.x), h1 = __float2half_rn(kv.y);
            __half h2 = __float2half_rn(kv.z), h3 = __float2half_rn(kv.w);
            Kh[dp * 72 + r]       = pack_h2(h0, h1);
            Kh[(dp + 1) * 72 + r] = pack_h2(h2, h3);
            if (SPLIT) {
                Kl[dp * 72 + r]       = pack_f2h(kv.x - __half2float(h0), kv.y - __half2float(h1));
                Kl[(dp + 1) * 72 + r] = pack_f2h(kv.z - __half2float(h2), kv.w - __half2float(h3));
            }
        }
        float4 vr0[2], vr1[2];
#pragma unroll
        for (int ii = 0; ii < 2; ii++) {
            int i = tid + ii * 256;
            int kp = i >> 4, d4 = (i & 15) << 2;
            size_t base0 = ((size_t)(b * Sq + kt * 64 + 2 * kp)) * Dq + h * HD + d4;
            vr0[ii] = *(const float4*)&g_V[base0];
            vr1[ii] = *(const float4*)&g_V[base0 + Dq];
        }
        __syncthreads();

        float s[8][4];
#pragma unroll
        for (int nt = 0; nt < 8; nt++)
#pragma unroll
            for (int c = 0; c < 4; c++) s[nt][c] = 0.f;

#pragma unroll
        for (int ks = 0; ks < 4; ks++) {
            int kp0 = 8 * ks + tig, kp1 = 8 * ks + tig + 4;
            uint32_t a[4], al[4];
            a[0] = Qh[kp0 * 136 + mrow];
            a[1] = Qh[kp0 * 136 + mrow + 8];
            a[2] = Qh[kp1 * 136 + mrow];
            a[3] = Qh[kp1 * 136 + mrow + 8];
            if (SPLIT) {
                al[0] = Ql[kp0 * 136 + mrow];
                al[1] = Ql[kp0 * 136 + mrow + 8];
                al[2] = Ql[kp1 * 136 + mrow];
                al[3] = Ql[kp1 * 136 + mrow + 8];
            }
#pragma unroll
            for (int gq = 0; gq < 2; gq++) {
                uint32_t bb[4][2], bl[4][2];
#pragma unroll
                for (int j = 0; j < 4; j++) {
                    int n0 = (gq * 4 + j) * 8 + gid;
                    bb[j][0] = Kh[kp0 * 72 + n0];
                    bb[j][1] = Kh[kp1 * 72 + n0];
                    if (SPLIT) {
                        bl[j][0] = Kl[kp0 * 72 + n0];
                        bl[j][1] = Kl[kp1 * 72 + n0];
                    }
                }
#pragma unroll
                for (int j = 0; j < 4; j++) mma_f16(s[gq * 4 + j], a, bb[j]);
                if (SPLIT) {
#pragma unroll
                    for (int j = 0; j < 4; j++) mma_f16(s[gq * 4 + j], a, bl[j]);
#pragma unroll
                    for (int j = 0; j < 4; j++) mma_f16(s[gq * 4 + j], al, bb[j]);
                }
            }
        }

        int rowg = qb * 128 + warp * 16 + gid;
        if (kt * 64 + 63 > rowg) {
#pragma unroll
            for (int nt = 0; nt < 8; nt++)
#pragma unroll
                for (int c = 0; c < 4; c++) {
                    int col = kt * 64 + nt * 8 + 2 * tig + (c & 1);
                    int row = rowg + ((c & 2) ? 8 : 0);
                    float sv = s[nt][c] * 0.125f;
                    s[nt][c] = (col > row) ? -1e30f : sv;
                }
        } else {
#pragma unroll
            for (int nt = 0; nt < 8; nt++)
#pragma unroll
                for (int c = 0; c < 4; c++) s[nt][c] *= 0.125f;
        }

        float rmA = -1e30f, rmB = -1e30f;
#pragma unroll
        for (int nt = 0; nt < 8; nt++) {
            rmA = fmaxf(rmA, fmaxf(s[nt][0], s[nt][1]));
            rmB = fmaxf(rmB, fmaxf(s[nt][2], s[nt][3]));
        }
#pragma unroll
        for (int off = 1; off < 4; off <<= 1) {
            rmA = fmaxf(rmA, __shfl_xor_sync(0xffffffffu, rmA, off));
            rmB = fmaxf(rmB, __shfl_xor_sync(0xffffffffu, rmB, off));
        }
        float mnA = fmaxf(mA, rmA), mnB = fmaxf(mB, rmB);
        float alA = __expf(mA - mnA), alB = __expf(mB - mnB);
        float rsA = 0.f, rsB = 0.f;
#pragma unroll
        for (int nt = 0; nt < 8; nt++) {
            s[nt][0] = __expf(s[nt][0] - mnA); rsA += s[nt][0];
            s[nt][1] = __expf(s[nt][1] - mnA); rsA += s[nt][1];
            s[nt][2] = __expf(s[nt][2] - mnB); rsB += s[nt][2];
            s[nt][3] = __expf(s[nt][3] - mnB); rsB += s[nt][3];
        }
#pragma unroll
        for (int off = 1; off < 4; off <<= 1) {
            rsA += __shfl_xor_sync(0xffffffffu, rsA, off);
            rsB += __shfl_xor_sync(0xffffffffu, rsB, off);
        }
        lA = lA * alA + rsA; mA = mnA;
        lB = lB * alB + rsB; mB = mnB;
#pragma unroll
        for (int nt = 0; nt < 8; nt++) {
            o[nt][0] *= alA; o[nt][1] *= alA;
            o[nt][2] *= alB; o[nt][3] *= alB;
        }

#pragma unroll
        for (int nt = 0; nt < 8; nt++) {
            int kpP = nt * 4 + tig;
            __half p0 = __float2half_rn(s[nt][0]), p1 = __float2half_rn(s[nt][1]);
            __half p2 = __float2half_rn(s[nt][2]), p3 = __float2half_rn(s[nt][3]);
            Ph[kpP * 136 + mrow]     = pack_h2(p0, p1);
            Ph[kpP * 136 + mrow + 8] = pack_h2(p2, p3);
            if (SPLIT) {
                Pl[kpP * 136 + mrow]     = pack_f2h(s[nt][0] - __half2float(p0),
                                                    s[nt][1] - __half2float(p1));
                Pl[kpP * 136 + mrow + 8] = pack_f2h(s[nt][2] - __half2float(p2),
                                                    s[nt][3] - __half2float(p3));
            }
        }
#pragma unroll
        for (int ii = 0; ii < 2; ii++) {
            int i = tid + ii * 256;
            int kp = i >> 4, d4 = (i & 15) << 2;
            float a0[4] = {vr0[ii].x, vr0[ii].y, vr0[ii].z, vr0[ii].w};
            float a1[4] = {vr1[ii].x, vr1[ii].y, vr1[ii].z, vr1[ii].w};
#pragma unroll
            for (int j = 0; j < 4; j++) {
                __half p0 = __float2half_rn(a0[j]), p1 = __float2half_rn(a1[j]);
                Vh[kp * 72 + d4 + j] = pack_h2(p0, p1);
                if (SPLIT)
                    Vl[kp * 72 + d4 + j] = pack_f2h(a0[j] - __half2float(p0),
                                                    a1[j] - __half2float(p1));
            }
        }
        __syncthreads();

#pragma unroll
        for (int ks = 0; ks < 4; ks++) {
            int kp0 = 8 * ks + tig, kp1 = 8 * ks + tig + 4;
            uint32_t a[4], al[4];
            a[0] = Ph[kp0 * 136 + mrow];
            a[1] = Ph[kp0 * 136 + mrow + 8];
            a[2] = Ph[kp1 * 136 + mrow];
            a[3] = Ph[kp1 * 136 + mrow + 8];
            if (SPLIT) {
                al[0] = Pl[kp0 * 136 + mrow];
                al[1] = Pl[kp0 * 136 + mrow + 8];
                al[2] = Pl[kp1 * 136 + mrow];
                al[3] = Pl[kp1 * 136 + mrow + 8];
            }
#pragma unroll
            for (int gq = 0; gq < 2; gq++) {
                uint32_t bb[4][2], bl[4][2];
#pragma unroll
                for (int j = 0; j < 4; j++) {
                    int n0 = (gq * 4 + j) * 8 + gid;
                    bb[j][0] = Vh[kp0 * 72 + n0];
                    bb[j][1] = Vh[kp1 * 72 + n0];
                    if (SPLIT) {
                        bl[j][0] = Vl[kp0 * 72 + n0];
                        bl[j][1] = Vl[kp1 * 72 + n0];
                    }
                }
#pragma unroll
                for (int j = 0; j < 4; j++) mma_f16(o[gq * 4 + j], a, bb[j]);
                if (SPLIT) {
#pragma unroll
                    for (int j = 0; j < 4; j++) mma_f16(o[gq * 4 + j], a, bl[j]);
#pragma unroll
                    for (int j = 0; j < 4; j++) mma_f16(o[gq * 4 + j], al, bb[j]);
                }
            }
        }
    }

    float invA = 1.0f / lA, invB = 1.0f / lB;
    size_t rbase0 = ((size_t)(b * Sq + qb * 128 + warp * 16 + gid)) * Dq + h * HD;
    size_t rbase1 = rbase0 + (size_t)8 * Dq;
#pragma unroll
    for (int nt = 0; nt < 8; nt++) {
        int d0 = nt * 8 + 2 * tig;
        *(float2*)&g_Y[rbase0 + d0] = make_float2(o[nt][0] * invA, o[nt][1] * invA);
        *(float2*)&g_Y[rbase1 + d0] = make_float2(o[nt][2] * invB, o[nt][3] * invB);
    }
}

// ---------------- fp16 1-pass flash (layer 1, pipelined K/V) -----------------
// K single-buffered, V double-buffered; next-tile K/V issued to regs at iter
// start and stored at the mid barrier -> global latency hidden under QK+softmax.
#define F0_Q  (32*136)
#define F0_K  (32*72)
#define F0_V  (32*72)
#define F0_P  (32*136)
#define FL0_SMEM ((F0_Q + F0_K + 2*F0_V + F0_P) * 4)   // 62464 B

__global__ void __launch_bounds__(256, 2)
flash_h0() {
    extern __shared__ uint32_t fu[];
    uint32_t* Qh = fu;
    uint32_t* Kh = Qh + F0_Q;
    uint32_t* Vh0 = Kh + F0_K;
    uint32_t* Vh1 = Vh0 + F0_V;
    uint32_t* Ph = Vh1 + F0_V;

    int qb = (int)(gridDim.x - 1 - blockIdx.x);
    int h = blockIdx.y, b = blockIdx.z;
    int tid = threadIdx.x, warp = tid >> 5, lane = tid & 31;
    int gid = lane >> 2, tig = lane & 3;
    int mrow = warp * 16 + gid;

    // Q load
    for (int i = tid; i < 2048; i += 256) {
        int r = i >> 4, d4 = (i & 15) << 2, dp = (i & 15) << 1;
        float4 v = *(const float4*)&g_Q[((size_t)(b * Sq + qb * 128 + r)) * Dq + h * HD + d4];
        Qh[dp * 136 + r]       = pack_f2h(v.x, v.y);
        Qh[(dp + 1) * 136 + r] = pack_f2h(v.z, v.w);
    }
    // preload tile 0: K -> Kh, V -> Vh0
    for (int i = tid; i < 1024; i += 256) {
        int r = i >> 4, d4 = (i & 15) << 2, dp = (i & 15) << 1;
        size_t base = ((size_t)(b * Sq + r)) * Dq + h * HD + d4;
        float4 kv = *(const float4*)&g_K[base];
        Kh[dp * 72 + r]       = pack_f2h(kv.x, kv.y);
        Kh[(dp + 1) * 72 + r] = pack_f2h(kv.z, kv.w);
    }
    for (int i = tid; i < 512; i += 256) {
        int kp = i >> 4, d4 = (i & 15) << 2;
        size_t base0 = ((size_t)(b * Sq + 2 * kp)) * Dq + h * HD + d4;
        float4 v0 = *(const float4*)&g_V[base0];
        float4 v1 = *(const float4*)&g_V[base0 + Dq];
        Vh0[kp * 72 + d4 + 0] = pack_f2h(v0.x, v1.x);
        Vh0[kp * 72 + d4 + 1] = pack_f2h(v0.y, v1.y);
        Vh0[kp * 72 + d4 + 2] = pack_f2h(v0.z, v1.z);
        Vh0[kp * 72 + d4 + 3] = pack_f2h(v0.w, v1.w);
    }
    __syncthreads();

    float mA = -1e30f, mB = -1e30f, lA = 0.f, lB = 0.f;
    float o[8][4];
#pragma unroll
    for (int nt = 0; nt < 8; nt++)
#pragma unroll
        for (int c = 0; c < 4; c++) o[nt][c] = 0.f;

    int nkt = 2 * qb + 2;
    for (int kt = 0; kt < nkt; kt++) {
        uint32_t* Vcur = (kt & 1) ? Vh1 : Vh0;
        uint32_t* Vnxt = (kt & 1) ? Vh0 : Vh1;

        // issue next-tile K/V loads (land during QK + softmax)
        float4 kreg[4], vr0[2], vr1[2];
        bool more = (kt + 1 < nkt);
        if (more) {
#pragma unroll
            for (int ii = 0; ii < 4; ii++) {
                int i = tid + ii * 256;
                int r = i >> 4, d4 = (i & 15) << 2;
                kreg[ii] = *(const float4*)&g_K[((size_t)(b * Sq + (kt + 1) * 64 + r)) * Dq + h * HD + d4];
            }
#pragma unroll
            for (int ii = 0; ii < 2; ii++) {
                int i = tid + ii * 256;
                int kp = i >> 4, d4 = (i & 15) << 2;
                size_t base0 = ((size_t)(b * Sq + (kt + 1) * 64 + 2 * kp)) * Dq + h * HD + d4;
                vr0[ii] = *(const float4*)&g_V[base0];
                vr1[ii] = *(const float4*)&g_V[base0 + Dq];
            }
        }

        // S = Q @ K^T
        float s[8][4];
#pragma unroll
        for (int nt = 0; nt < 8; nt++)
#pragma unroll
            for (int c = 0; c < 4; c++) s[nt][c] = 0.f;
#pragma unroll
        for (int ks = 0; ks < 4; ks++) {
            int kp0 = 8 * ks + tig, kp1 = 8 * ks + tig + 4;
            uint32_t a[4];
            a[0] = Qh[kp0 * 136 + mrow];
            a[1] = Qh[kp0 * 136 + mrow + 8];
            a[2] = Qh[kp1 * 136 + mrow];
            a[3] = Qh[kp1 * 136 + mrow + 8];
#pragma unroll
            for (int gq = 0; gq < 2; gq++) {
                uint32_t bb[4][2];
#pragma unroll
                for (int j = 0; j < 4; j++) {
                    int n0 = (gq * 4 + j) * 8 + gid;
                    bb[j][0] = Kh[kp0 * 72 + n0];
                    bb[j][1] = Kh[kp1 * 72 + n0];
                }
#pragma unroll
                for (int j = 0; j < 4; j++) mma_f16(s[gq * 4 + j], a, bb[j]);
            }
        }

        int rowg = qb * 128 + warp * 16 + gid;
        if (kt * 64 + 63 > rowg) {
#pragma unroll
            for (int nt = 0; nt < 8; nt++)
#pragma unroll
                for (int c = 0; c < 4; c++) {
                    int col = kt * 64 + nt * 8 + 2 * tig + (c & 1);
                    int row = rowg + ((c & 2) ? 8 : 0);
                    float sv = s[nt][c] * 0.125f;
                    s[nt][c] = (col > row) ? -1e30f : sv;
                }
        } else {
#pragma unroll
            for (int nt = 0; nt < 8; nt++)
#pragma unroll
                for (int c = 0; c < 4; c++) s[nt][c] *= 0.125f;
        }

        float rmA = -1e30f, rmB = -1e30f;
#pragma unroll
        for (int nt = 0; nt < 8; nt++) {
            rmA = fmaxf(rmA, fmaxf(s[nt][0], s[nt][1]));
            rmB = fmaxf(rmB, fmaxf(s[nt][2], s[nt][3]));
        }
#pragma unroll
        for (int off = 1; off < 4; off <<= 1) {
            rmA = fmaxf(rmA, __shfl_xor_sync(0xffffffffu, rmA, off));
            rmB = fmaxf(rmB, __shfl_xor_sync(0xffffffffu, rmB, off));
        }
        float mnA = fmaxf(mA, rmA), mnB = fmaxf(mB, rmB);
        float alA = __expf(mA - mnA), alB = __expf(mB - mnB);
        float rsA = 0.f, rsB = 0.f;
#pragma unroll
        for (int nt = 0; nt < 8; nt++) {
            s[nt][0] = __expf(s[nt][0] - mnA); rsA += s[nt][0];
            s[nt][1] = __expf(s[nt][1] - mnA); rsA += s[nt][1];
            s[nt][2] = __expf(s[nt][2] - mnB); rsB += s[nt][2];
            s[nt][3] = __expf(s[nt][3] - mnB); rsB += s[nt][3];
        }
#pragma unroll
        for (int off = 1; off < 4; off <<= 1) {
            rsA += __shfl_xor_sync(0xffffffffu, rsA, off);
            rsB += __shfl_xor_sync(0xffffffffu, rsB, off);
        }
        lA = lA * alA + rsA; mA = mnA;
        lB = lB * alB + rsB; mB = mnB;
#pragma unroll
        for (int nt = 0; nt < 8; nt++) {
            o[nt][0] *= alA; o[nt][1] *= alA;
            o[nt][2] *= alB; o[nt][3] *= alB;
        }

        // barrier: QK reads of Kh done; PV(kt-1) reads of Ph/Vnxt done
        __syncthreads();

        // store P, next K, next V
#pragma unroll
        for (int nt = 0; nt < 8; nt++) {
            int kpP = nt * 4 + tig;
            Ph[kpP * 136 + mrow]     = pack_f2h(s[nt][0], s[nt][1]);
            Ph[kpP * 136 + mrow + 8] = pack_f2h(s[nt][2], s[nt][3]);
        }
        if (more) {
#pragma unroll
            for (int ii = 0; ii < 4; ii++) {
                int i = tid + ii * 256;
                int r = i >> 4, dp = (i & 15) << 1;
                Kh[dp * 72 + r]       = pack_f2h(kreg[ii].x, kreg[ii].y);
                Kh[(dp + 1) * 72 + r] = pack_f2h(kreg[ii].z, kreg[ii].w);
            }
#pragma unroll
            for (int ii = 0; ii < 2; ii++) {
                int i = tid + ii * 256;
                int kp = i >> 4, d4 = (i & 15) << 2;
                Vnxt[kp * 72 + d4 + 0] = pack_f2h(vr0[ii].x, vr1[ii].x);
                Vnxt[kp * 72 + d4 + 1] = pack_f2h(vr0[ii].y, vr1[ii].y);
                Vnxt[kp * 72 + d4 + 2] = pack_f2h(vr0[ii].z, vr1[ii].z);
                Vnxt[kp * 72 + d4 + 3] = pack_f2h(vr0[ii].w, vr1[ii].w);
            }
        }
        __syncthreads();

        // O += P @ V (current tile)
#pragma unroll
        for (int ks = 0; ks < 4; ks++) {
            int kp0 = 8 * ks + tig, kp1 = 8 * ks + tig + 4;
            uint32_t a[4];
            a[0] = Ph[kp0 * 136 + mrow];
            a[1] = Ph[kp0 * 136 + mrow + 8];
            a[2] = Ph[kp1 * 136 + mrow];
            a[3] = Ph[kp1 * 136 + mrow + 8];
#pragma unroll
            for (int gq = 0; gq < 2; gq++) {
                uint32_t bb[4][2];
#pragma unroll
                for (int j = 0; j < 4; j++) {
                    int n0 = (gq * 4 + j) * 8 + gid;
                    bb[j][0] = Vcur[kp0 * 72 + n0];
                    bb[j][1] = Vcur[kp1 * 72 + n0];
                }
#pragma unroll
                for (int j = 0; j < 4; j++) mma_f16(o[gq * 4 + j], a, bb[j]);
            }
        }
    }

    float invA = 1.0f / lA, invB = 1.0f / lB;
    size_t rbase0 = ((size_t)(b * Sq + qb * 128 + warp * 16 + gid)) * Dq + h * HD;
    size_t rbase1 = rbase0 + (size_t)8 * Dq;
#pragma unroll
    for (int nt = 0; nt < 8; nt++) {
        int d0 = nt * 8 + 2 * tig;
        *(float2*)&g_Y[rbase0 + d0] = make_float2(o[nt][0] * invA, o[nt][1] * invA);
        *(float2*)&g_Y[rbase1 + d0] = make_float2(o[nt][2] * invB, o[nt][3] * invB);
    }
}

// ---------------- gating -----------------------------------------------------
__global__ void gate_token_kernel(const float* __restrict__ gw,
                                  const float* __restrict__ gb, int layer) {
    if (blockIdx.x == 0 && threadIdx.x < Ee) g_counts[threadIdx.x] = 0;
    int t = blockIdx.x * 4 + (threadIdx.x >> 5);
    int lane = threadIdx.x & 31;
    if (t >= TOK) return;
    const float* hrow = g_H + (size_t)t * Dq;
    const float* gwl = gw + (size_t)layer * Dq * Ee;
    float acc[Ee] = {};
    for (int d = lane; d < Dq; d += 32) {
        float hv = hrow[d];
        const float* g = gwl + (size_t)d * Ee;
#pragma unroll
        for (int e = 0; e < Ee; e++) acc[e] += hv * g[e];
    }
#pragma unroll
    for (int e = 0; e < Ee; e++)
        for (int off = 16; off; off >>= 1)
            acc[e] += __shfl_xor_sync(0xffffffffu, acc[e], off);
    if (lane == 0) {
        float lg[Ee];
#pragma unroll
        for (int e = 0; e < Ee; e++) lg[e] = acc[e] + gb[layer * Ee + e];
        int i1, i2; float w1, w2;
        top2_of8(lg, i1, i2, w1, w2);
        g_te[t * 2] = i1; g_te[t * 2 + 1] = i2;
        g_tw[t * 2] = w1; g_tw[t * 2 + 1] = w2;
    }
}

__global__ void xmean_kernel() {
    int b = blockIdx.y;
    int d = blockIdx.x * 256 + threadIdx.x;
    float s = 0.f;
    for (int ss = 0; ss < Sq; ss++)
        s += g_H[((size_t)(b * Sq + ss)) * Dq + d];
    g_xmean[b * Dq + d] = s * (1.0f / Sq);
}

__global__ void gate_seq_kernel(const float* __restrict__ gw,
                                const float* __restrict__ gb, int layer) {
    if (blockIdx.x == 0 && threadIdx.x < Ee) g_counts[threadIdx.x] = 0;
    int b = blockIdx.x;
    int tid = threadIdx.x, e = tid >> 5, lane = tid & 31;
    const float* gwl = gw + (size_t)layer * Dq * Ee;
    float acc = 0.f;
    for (int d = lane; d < Dq; d += 32)
        acc += g_xmean[b * Dq + d] * gwl[(size_t)d * Ee + e];
    for (int off = 16; off; off >>= 1)
        acc += __shfl_xor_sync(0xffffffffu, acc, off);
    __shared__ float lg[Ee];
    if (lane == 0) lg[e] = acc + gb[layer * Ee + e];
    __syncthreads();
    if (tid == 0) {
        int i1, i2; float w1, w2;
        top2_of8(lg, i1, i2, w1, w2);
        g_bsel[b * 2] = i1; g_bsel[b * 2 + 1] = i2;
        g_bw[b * 2] = w1;  g_bw[b * 2 + 1] = w2;
    }
}

__global__ void assign_kernel(int seq_mode) {
    int t = blockIdx.x * 256 + threadIdx.x;
    if (t >= TOK) return;
    int e1, e2; float w1, w2;
    if (seq_mode) {
        int b = t / Sq;
        e1 = g_bsel[b * 2]; e2 = g_bsel[b * 2 + 1];
        w1 = g_bw[b * 2];   w2 = g_bw[b * 2 + 1];
    } else {
        e1 = g_te[t * 2]; e2 = g_te[t * 2 + 1];
        w1 = g_tw[t * 2]; w2 = g_tw[t * 2 + 1];
    }
    int s1 = atomicAdd(&g_counts[e1], 1);
    g_tok[e1 * TOK + s1] = t; g_wt[e1 * TOK + s1] = w1;
    g_islot[t * 2] = e1 * TOK + s1;
    int s2 = atomicAdd(&g_counts[e2], 1);
    g_tok[e2 * TOK + s2] = t; g_wt[e2 * TOK + s2] = w2;
    g_islot[t * 2 + 1] = e2 * TOK + s2;
}

// ---------------- host side --------------------------------------------------
extern "C" void kernel_launch(void* const* d_in, const int* in_sizes, int n_in,
                              void* d_out, int out_size) {
    const float* x      = (const float*)d_in[0];
    const float* ln1_w  = (const float*)d_in[1];
    const float* ln1_b  = (const float*)d_in[2];
    const float* ln2_w  = (const float*)d_in[3];
    const float* ln2_b  = (const float*)d_in[4];
    const float* wq     = (const float*)d_in[5];
    const float* wk     = (const float*)d_in[6];
    const float* wv     = (const float*)d_in[7];
    const float* wo     = (const float*)d_in[8];
    const float* bq     = (const float*)d_in[9];
    const float* bk     = (const float*)d_in[10];
    const float* bv     = (const float*)d_in[11];
    const float* bo     = (const float*)d_in[12];
    const float* gate_w = (const float*)d_in[13];
    const float* gate_b = (const float*)d_in[14];
    const float* e_w1   = (const float*)d_in[15];
    const float* e_b1   = (const float*)d_in[16];
    const float* e_w2   = (const float*)d_in[17];
    const float* e_b2   = (const float*)d_in[18];

    float *Xp, *Hp, *Qp, *Kp, *Vp, *Yp;
    cudaGetSymbolAddress((void**)&Xp, g_X);
    cudaGetSymbolAddress((void**)&Hp, g_H);
    cudaGetSymbolAddress((void**)&Qp, g_Q);
    cudaGetSymbolAddress((void**)&Kp, g_K);
    cudaGetSymbolAddress((void**)&Vp, g_V);
    cudaGetSymbolAddress((void**)&Yp, g_Y);

    static int attr_set = 0;
    if (!attr_set) {
        cudaFuncSetAttribute(gemm_h3<0>, cudaFuncAttributeMaxDynamicSharedMemorySize, SMEM_H3);
        cudaFuncSetAttribute(gemm_h3<1>, cudaFuncAttributeMaxDynamicSharedMemorySize, SMEM_H3);
        cudaFuncSetAttribute(gemm_hb<0>, cudaFuncAttributeMaxDynamicSharedMemorySize, SMEM_HB);
        cudaFuncSetAttribute(gemm_hb<1>, cudaFuncAttributeMaxDynamicSharedMemorySize, SMEM_HB);
        cudaFuncSetAttribute(gemm_hb<2>, cudaFuncAttributeMaxDynamicSharedMemorySize, SMEM_HB);
        cudaFuncSetAttribute(gemm_hb<3>, cudaFuncAttributeMaxDynamicSharedMemorySize, SMEM_HB);
        cudaFuncSetAttribute(flash_h<1>, cudaFuncAttributeMaxDynamicSharedMemorySize, FL2_SMEM1);
        cudaFuncSetAttribute(flash_h0,   cudaFuncAttributeMaxDynamicSharedMemorySize, FL0_SMEM);
        attr_set = 1;
    }

    const size_t DD = (size_t)Dq * Dq;
    const int nelem = TOK * Dq;

    copy_in_kernel<<<nelem / 256, 256>>>(x);

    for (int l = 0; l < Ll; l++) {
        const float* WQ = wq + l * DD;
        const float* WK = wk + l * DD;
        const float* WV = wv + l * DD;
        const float* WO = wo + l * DD;
        const float* BQ = bq + (size_t)l * Dq;
        const float* BK = bk + (size_t)l * Dq;
        const float* BV = bv + (size_t)l * Dq;
        const float* BO = bo + (size_t)l * Dq;

        // ln1 (fused with previous layer's MoE combine when l > 0)
        if (l == 0)
            ln_kernel<<<TOK, 256>>>(ln1_w + (size_t)l * Dq, ln1_b + (size_t)l * Dq);
        else
            ln_combine_kernel<<<TOK, 256>>>(ln1_w + (size_t)l * Dq, ln1_b + (size_t)l * Dq);

        if (l == 0) {
            gemm_h3<0><<<dim3(8, 32, 3), 512, SMEM_H3>>>(
                Hp, WQ, WK, WV, BQ, BK, BV, Qp, Kp, Vp, Dq, Dq);
            flash_h<1><<<dim3(Sq / 128, Hh, Bq), 256, FL2_SMEM1>>>();
            gemm_h3<1><<<dim3(8, 32), 512, SMEM_H3>>>(
                Yp, WO, nullptr, nullptr, BO, nullptr, nullptr, Xp, nullptr, nullptr, Dq, Dq);
        } else {
            gemm_hb<0><<<dim3(4, 32, 3), 512, SMEM_HB>>>(
                Hp, WQ, WK, WV, BQ, BK, BV, Qp, Kp, Vp, Dq, Dq, l);
            flash_h0<<<dim3(Sq / 128, Hh, Bq), 256, FL0_SMEM>>>();
            gemm_hb<1><<<dim3(4, 32), 512, SMEM_HB>>>(
                Yp, WO, nullptr, nullptr, BO, nullptr, nullptr, Xp, nullptr, nullptr, Dq, Dq, l);
        }

        ln_kernel<<<TOK, 256>>>(ln2_w + (size_t)l * Dq, ln2_b + (size_t)l * Dq);
        if (l % 2 == 0) {
            gate_token_kernel<<<TOK / 4, 128>>>(gate_w, gate_b, l);
        } else {
            xmean_kernel<<<dim3(Dq / 256, Bq), 256>>>();
            gate_seq_kernel<<<Bq, 256>>>(gate_w, gate_b, l);
        }
        assign_kernel<<<TOK / 256, 256>>>(l % 2);
        gemm_hb<2><<<dim3(DFFq / 256, TOK / 128, Ee), 512, SMEM_HB>>>(
            nullptr, e_w1, nullptr, nullptr, e_b1, nullptr, nullptr,
            nullptr, nullptr, nullptr, Dq, DFFq, l);
        gemm_hb<3><<<dim3(Dq / 256, TOK / 128, Ee), 512, SMEM_HB>>>(
            nullptr, e_w2, nullptr, nullptr, e_b2, nullptr, nullptr,
            nullptr, nullptr, nullptr, DFFq, Dq, l);
    }

    combine_out_kernel<<<nelem / 1024, 256>>>((float*)d_out);
    (void)in_sizes; (void)n_in; (void)out_size;
}

// round 13
// speedup vs baseline: 10.8245x; 1.0066x over previous
#include <cuda_runtime.h>
#include <cuda_fp16.h>
#include <math.h>
#include <stdint.h>

#define Bq   4
#define Sq   1024
#define Dq   1024
#define Hh   16
#define HD   64
#define Ll   2
#define Ee   8
#define DFFq 4096
#define TOK  (Bq*Sq)   // 4096

// ---------------- static scratch ---------------------------------------------
__device__ float g_X[TOK*Dq];
__device__ float g_H[TOK*Dq];
__device__ float g_Q[TOK*Dq];          // layer-0 (fp32, split path)
__device__ float g_K[TOK*Dq];
__device__ float g_V[TOK*Dq];
__device__ float g_Y[TOK*Dq];
__device__ __half g_Qh[TOK*Dq];        // layer-1 (fp16 path)
__device__ __half g_Kh[TOK*Dq];
__device__ __half g_Vh[TOK*Dq];
__device__ __half g_Yh[TOK*Dq];
__device__ __half g_hidden_h[(size_t)Ee*TOK*DFFq];   // 256MB fp16
__device__ float g_moeout[(size_t)Ee*TOK*Dq];
__device__ int   g_counts[Ee];
__device__ int   g_tok[Ee*TOK];
__device__ float g_wt[Ee*TOK];
__device__ int   g_islot[TOK*2];
__device__ int   g_te[TOK*2];
__device__ float g_tw[TOK*2];
__device__ int   g_bsel[Bq*2];
__device__ float g_bw[Bq*2];
__device__ float g_xmean[Bq*Dq];

// ---------------- helpers ----------------------------------------------------
__device__ __forceinline__ void top2_of8(const float* lg, int& i1, int& i2,
                                         float& w1, float& w2) {
    i1 = 0; float v1 = lg[0];
#pragma unroll
    for (int e = 1; e < Ee; e++) if (lg[e] > v1) { v1 = lg[e]; i1 = e; }
    i2 = -1; float v2 = -3.0e38f;
#pragma unroll
    for (int e = 0; e < Ee; e++) if (e != i1 && lg[e] > v2) { v2 = lg[e]; i2 = e; }
    float ex = expf(v2 - v1);
    w1 = 1.0f / (1.0f + ex);
    w2 = ex / (1.0f + ex);
}
__device__ __forceinline__ float gelu_exact(float x) {
    return 0.5f * x * (1.0f + erff(x * 0.7071067811865476f));
}
__device__ __forceinline__ void mma_f16(float c[4], const uint32_t a[4],
                                        const uint32_t b[2]) {
    asm volatile(
        "mma.sync.aligned.m16n8k16.row.col.f32.f16.f16.f32 "
        "{%0,%1,%2,%3},{%4,%5,%6,%7},{%8,%9},{%0,%1,%2,%3};"
        : "+f"(c[0]), "+f"(c[1]), "+f"(c[2]), "+f"(c[3])
        : "r"(a[0]), "r"(a[1]), "r"(a[2]), "r"(a[3]), "r"(b[0]), "r"(b[1]));
}
__device__ __forceinline__ uint32_t pack_h2(__half a, __half b) {
    __half2 h = __halves2half2(a, b);
    return *(uint32_t*)&h;
}
__device__ __forceinline__ uint32_t pack_f2h(float a, float b) {
    return pack_h2(__float2half_rn(a), __float2half_rn(b));
}

// ---------------- simple kernels ---------------------------------------------
__global__ void copy_in_kernel(const float* __restrict__ src) {
    int i = blockIdx.x * 256 + threadIdx.x;
    g_X[i] = src[i];
}

__global__ void ln_kernel(const float* __restrict__ w, const float* __restrict__ b) {
    int t = blockIdx.x, tid = threadIdx.x;
    const float* xr = g_X + (size_t)t * Dq;
    float s = 0.f, s2 = 0.f;
    for (int d = tid; d < Dq; d += 256) { float v = xr[d]; s += v; s2 += v * v; }
    __shared__ float r1[256], r2[256];
    r1[tid] = s; r2[tid] = s2; __syncthreads();
    for (int off = 128; off; off >>= 1) {
        if (tid < off) { r1[tid] += r1[tid + off]; r2[tid] += r2[tid + off]; }
        __syncthreads();
    }
    float mean = r1[0] * (1.0f / Dq);
    float var  = r2[0] * (1.0f / Dq) - mean * mean;
    float rstd = rsqrtf(var + 1e-5f);
    float* hr = g_H + (size_t)t * Dq;
    for (int d = tid; d < Dq; d += 256)
        hr[d] = (xr[d] - mean) * rstd * w[d] + b[d];
}

__global__ void ln_combine_kernel(const float* __restrict__ w, const float* __restrict__ b) {
    int t = blockIdx.x, tid = threadIdx.x;
    int s0 = g_islot[t * 2], s1 = g_islot[t * 2 + 1];
    float* xr = g_X + (size_t)t * Dq;
    const float* m0 = g_moeout + (size_t)s0 * Dq;
    const float* m1 = g_moeout + (size_t)s1 * Dq;
    float s = 0.f, s2 = 0.f;
    for (int d = tid; d < Dq; d += 256) {
        float v = xr[d] + m0[d] + m1[d];
        xr[d] = v;
        s += v; s2 += v * v;
    }
    __shared__ float r1[256], r2[256];
    r1[tid] = s; r2[tid] = s2; __syncthreads();
    for (int off = 128; off; off >>= 1) {
        if (tid < off) { r1[tid] += r1[tid + off]; r2[tid] += r2[tid + off]; }
        __syncthreads();
    }
    float mean = r1[0] * (1.0f / Dq);
    float var  = r2[0] * (1.0f / Dq) - mean * mean;
    float rstd = rsqrtf(var + 1e-5f);
    float* hr = g_H + (size_t)t * Dq;
    for (int d = tid; d < Dq; d += 256)
        hr[d] = (xr[d] - mean) * rstd * w[d] + b[d];
}

__global__ void combine_out_kernel(float* __restrict__ dst) {
    int i = blockIdx.x * 256 + threadIdx.x;
    int t = i >> 8;
    int c4 = (i & 255) << 2;
    int s0 = g_islot[t * 2], s1 = g_islot[t * 2 + 1];
    float4 a = *(const float4*)&g_moeout[(size_t)s0 * Dq + c4];
    float4 b = *(const float4*)&g_moeout[(size_t)s1 * Dq + c4];
    float4 x = *(const float4*)&g_X[(size_t)t * Dq + c4];
    x.x += a.x + b.x; x.y += a.y + b.y; x.z += a.z + b.z; x.w += a.w + b.w;
    *(float4*)&dst[(size_t)t * Dq + c4] = x;
}

// ---------------- fp16 3-pass split GEMM (layer-0, 128x128, BK=32) -----------
#define T2W 136
#define T2SZ (16*T2W)
#define H3BUF (4*T2SZ)
#define SMEM_H3 (2*H3BUF*4)           // 69632 B

template<int MODE>
__global__ void __launch_bounds__(512, 1)
gemm_h3(const float* __restrict__ A,
        const float* __restrict__ W0, const float* __restrict__ W1,
        const float* __restrict__ W2,
        const float* __restrict__ b0, const float* __restrict__ b1,
        const float* __restrict__ b2,
        float* __restrict__ C0, float* __restrict__ C1, float* __restrict__ C2,
        int Kd, int N) {
    extern __shared__ uint32_t tiles[];
    int z = (MODE == 0) ? blockIdx.z : 0;
    const float* Wall = (z == 0) ? W0 : (z == 1 ? W1 : W2);
    const float* bias = (z == 0) ? b0 : (z == 1 ? b1 : b2);
    float* Cp         = (z == 0) ? C0 : (z == 1 ? C1 : C2);

    int tid = threadIdx.x;
    int rowBase = blockIdx.y * 128, colBase = blockIdx.x * 128;

    int lrA = tid >> 2, kcA4 = (tid & 3) << 2, kpA = (tid & 3) << 1;
    const float* Ap = A + (size_t)(rowBase + lrA) * Kd + kcA4;
    int kpB = tid >> 6, nB = (tid & 63) << 1;
    const float* Wp = Wall + (size_t)(2 * kpB) * N + colBase + nB;

    int lane = tid & 31, warp = tid >> 5;
    int wm = (warp & 3) * 32, wn = (warp >> 2) * 32;
    int gid = lane >> 2, tig = lane & 3;

    float acc[2][4][4];
#pragma unroll
    for (int a = 0; a < 2; a++)
#pragma unroll
        for (int b3 = 0; b3 < 4; b3++)
#pragma unroll
            for (int c = 0; c < 4; c++) acc[a][b3][c] = 0.f;

    int nk = Kd / 32;
    float4 av0, av1;
    float2 br0, br1, br2, br3;
    av0 = *(const float4*)(Ap);
    av1 = *(const float4*)(Ap + 16);
    br0 = *(const float2*)(Wp);
    br1 = *(const float2*)(Wp + N);
    br2 = *(const float2*)(Wp + (size_t)16 * N);
    br3 = *(const float2*)(Wp + (size_t)17 * N);

#define H3_STORE(BUF)                                                          \
    {                                                                          \
        uint32_t* Ahi = (BUF);                                                 \
        uint32_t* Alo = (BUF) + T2SZ;                                          \
        uint32_t* Bhi = (BUF) + 2 * T2SZ;                                      \
        uint32_t* Blo = (BUF) + 3 * T2SZ;                                      \
        __half h0 = __float2half_rn(av0.x), h1 = __float2half_rn(av0.y);       \
        __half h2 = __float2half_rn(av0.z), h3 = __float2half_rn(av0.w);       \
        Ahi[kpA * T2W + lrA]       = pack_h2(h0, h1);                          \
        Ahi[(kpA + 1) * T2W + lrA] = pack_h2(h2, h3);                          \
        Alo[kpA * T2W + lrA]       = pack_f2h(av0.x - __half2float(h0), av0.y - __half2float(h1)); \
        Alo[(kpA + 1) * T2W + lrA] = pack_f2h(av0.z - __half2float(h2), av0.w - __half2float(h3)); \
        __half g0 = __float2half_rn(av1.x), g1 = __float2half_rn(av1.y);       \
        __half g2 = __float2half_rn(av1.z), g3 = __float2half_rn(av1.w);       \
        Ahi[(kpA + 8) * T2W + lrA] = pack_h2(g0, g1);                          \
        Ahi[(kpA + 9) * T2W + lrA] = pack_h2(g2, g3);                          \
        Alo[(kpA + 8) * T2W + lrA] = pack_f2h(av1.x - __half2float(g0), av1.y - __half2float(g1)); \
        Alo[(kpA + 9) * T2W + lrA] = pack_f2h(av1.z - __half2float(g2), av1.w - __half2float(g3)); \
        __half w00 = __float2half_rn(br0.x), w10 = __float2half_rn(br1.x);     \
        __half w01 = __float2half_rn(br0.y), w11 = __float2half_rn(br1.y);     \
        Bhi[kpB * T2W + nB]     = pack_h2(w00, w10);                           \
        Bhi[kpB * T2W + nB + 1] = pack_h2(w01, w11);                           \
        Blo[kpB * T2W + nB]     = pack_f2h(br0.x - __half2float(w00), br1.x - __half2float(w10)); \
        Blo[kpB * T2W + nB + 1] = pack_f2h(br0.y - __half2float(w01), br1.y - __half2float(w11)); \
        __half u00 = __float2half_rn(br2.x), u10 = __float2half_rn(br3.x);     \
        __half u01 = __float2half_rn(br2.y), u11 = __float2half_rn(br3.y);     \
        Bhi[(kpB + 8) * T2W + nB]     = pack_h2(u00, u10);                     \
        Bhi[(kpB + 8) * T2W + nB + 1] = pack_h2(u01, u11);                     \
        Blo[(kpB + 8) * T2W + nB]     = pack_f2h(br2.x - __half2float(u00), br3.x - __half2float(u10)); \
        Blo[(kpB + 8) * T2W + nB + 1] = pack_f2h(br2.y - __half2float(u01), br3.y - __half2float(u11)); \
    }

    H3_STORE(tiles);
    __syncthreads();

    for (int t = 0; t < nk; t++) {
        if (t + 1 < nk) {
            const float* a2 = Ap + (size_t)(t + 1) * 32;
            av0 = *(const float4*)(a2);
            av1 = *(const float4*)(a2 + 16);
            const float* w2 = Wp + (size_t)(t + 1) * 32 * N;
            br0 = *(const float2*)(w2);
            br1 = *(const float2*)(w2 + N);
            br2 = *(const float2*)(w2 + (size_t)16 * N);
            br3 = *(const float2*)(w2 + (size_t)17 * N);
        }
        int s = t & 1;
        const uint32_t* Ahi = tiles + s * H3BUF;
        const uint32_t* Alo = Ahi + T2SZ;
        const uint32_t* Bhi = Ahi + 2 * T2SZ;
        const uint32_t* Blo = Ahi + 3 * T2SZ;

#pragma unroll
        for (int sub = 0; sub < 2; sub++) {
            int ko = sub * 8;
            uint32_t ah[2][4], al[2][4], bh[4][2], bl[4][2];
#pragma unroll
            for (int mt = 0; mt < 2; mt++) {
                int m0 = wm + mt * 16 + gid;
                ah[mt][0] = Ahi[(ko + tig) * T2W + m0];
                ah[mt][1] = Ahi[(ko + tig) * T2W + m0 + 8];
                ah[mt][2] = Ahi[(ko + tig + 4) * T2W + m0];
                ah[mt][3] = Ahi[(ko + tig + 4) * T2W + m0 + 8];
                al[mt][0] = Alo[(ko + tig) * T2W + m0];
                al[mt][1] = Alo[(ko + tig) * T2W + m0 + 8];
                al[mt][2] = Alo[(ko + tig + 4) * T2W + m0];
                al[mt][3] = Alo[(ko + tig + 4) * T2W + m0 + 8];
            }
#pragma unroll
            for (int nt = 0; nt < 4; nt++) {
                int n0 = wn + nt * 8 + gid;
                bh[nt][0] = Bhi[(ko + tig) * T2W + n0];
                bh[nt][1] = Bhi[(ko + tig + 4) * T2W + n0];
                bl[nt][0] = Blo[(ko + tig) * T2W + n0];
                bl[nt][1] = Blo[(ko + tig + 4) * T2W + n0];
            }
#pragma unroll
            for (int mt = 0; mt < 2; mt++)
#pragma unroll
                for (int nt = 0; nt < 4; nt++)
                    mma_f16(acc[mt][nt], ah[mt], bh[nt]);
#pragma unroll
            for (int mt = 0; mt < 2; mt++)
#pragma unroll
                for (int nt = 0; nt < 4; nt++)
                    mma_f16(acc[mt][nt], ah[mt], bl[nt]);
#pragma unroll
            for (int mt = 0; mt < 2; mt++)
#pragma unroll
                for (int nt = 0; nt < 4; nt++)
                    mma_f16(acc[mt][nt], al[mt], bh[nt]);
        }

        if (t + 1 < nk) {
            uint32_t* nb = tiles + (s ^ 1) * H3BUF;
            H3_STORE(nb);
        }
        __syncthreads();
    }
#undef H3_STORE

#pragma unroll
    for (int mt = 0; mt < 2; mt++) {
#pragma unroll
        for (int c = 0; c < 4; c++) {
            int r = rowBase + wm + mt * 16 + gid + ((c & 2) ? 8 : 0);
#pragma unroll
            for (int nt = 0; nt < 4; nt++) {
                int cg = colBase + wn + nt * 8 + tig * 2 + (c & 1);
                float v = acc[mt][nt][c] + bias[cg];
                if (MODE == 1) v += Cp[(size_t)r * N + cg];
                Cp[(size_t)r * N + cg] = v;
            }
        }
    }
}

// ---------------- fp16 1-pass big-tile GEMM (128x256, BK=32, 512 thr) --------
// MODE 0: fused QKV -> HALF outputs   MODE 1: half A (g_Yh), C += Res (fp32)
// MODE 2: MoE GEMM1 -> half g_hidden_h (GELU)
// MODE 3: half A (g_hidden_h) -> fp32 g_moeout (weighted)
#define HB_AW 136
#define HB_BW 264
#define HB_AT (16*HB_AW)
#define HB_BT (16*HB_BW)
#define HB_BUF (HB_AT+HB_BT)
#define SMEM_HB ((256 + 2*HB_BUF) * 4)   // 52224 B

template<int MODE>
__global__ void __launch_bounds__(512, 1)
gemm_hb(const void* __restrict__ A,
        const float* __restrict__ W0, const float* __restrict__ W1,
        const float* __restrict__ W2,
        const float* __restrict__ b0, const float* __restrict__ b1,
        const float* __restrict__ b2,
        void* __restrict__ C0, void* __restrict__ C1, void* __restrict__ C2,
        int Kd, int N, int layer) {
    constexpr bool A_HALF   = (MODE == 1 || MODE == 3);
    constexpr bool OUT_HALF = (MODE == 0 || MODE == 2);
    extern __shared__ float smf[];
    int*   s_tok = (int*)smf;
    float* s_wt  = smf + 128;
    uint32_t* tiles = (uint32_t*)(smf + 256);

    int tid = threadIdx.x;
    int rowBase = blockIdx.y * 128, colBase = blockIdx.x * 256;

    int e = 0, cnt = 0;
    const float* W;
    const float* bias;
    int z = 0;
    if (MODE >= 2) {
        e = blockIdx.z;
        cnt = g_counts[e];
        if (rowBase >= cnt) return;
        W    = W0 + (size_t)(layer * Ee + e) * Kd * N;
        bias = b0 + (size_t)(layer * Ee + e) * N;
        if (tid < 128) {
            int r = rowBase + tid;
            int rc = r < cnt ? r : cnt - 1;
            s_tok[tid] = g_tok[e * TOK + rc];
            s_wt[tid]  = g_wt [e * TOK + rc];
        }
        __syncthreads();
    } else {
        z = (MODE == 0) ? blockIdx.z : 0;
        W    = (z == 0) ? W0 : (z == 1 ? W1 : W2);
        bias = (z == 0) ? b0 : (z == 1 ? b1 : b2);
    }

    int lrA = tid >> 2, kcA4 = (tid & 3) << 2, kpA = (tid & 3) << 1;
    const float*  Apf = nullptr;
    const __half* Aph = nullptr;
    if (MODE == 2)      Apf = g_H + (size_t)s_tok[lrA] * Kd + kcA4;
    else if (MODE == 3) Aph = g_hidden_h + ((size_t)e * TOK + rowBase + lrA) * Kd + kcA4;
    else if (MODE == 1) Aph = (const __half*)A + (size_t)(rowBase + lrA) * Kd + kcA4;
    else                Apf = (const float*)A + (size_t)(rowBase + lrA) * Kd + kcA4;

    int kpB = tid >> 6, nB4 = (tid & 63) << 2;
    const float* Wp = W + (size_t)(2 * kpB) * N + colBase + nB4;

    int lane = tid & 31, warp = tid >> 5;
    int wm = (warp & 1) * 64, wn = (warp >> 1) * 32;
    int gid = lane >> 2, tig = lane & 3;

    float acc[4][4][4];
#pragma unroll
    for (int a = 0; a < 4; a++)
#pragma unroll
        for (int b3 = 0; b3 < 4; b3++)
#pragma unroll
            for (int c = 0; c < 4; c++) acc[a][b3][c] = 0.f;

    int nk = Kd / 32;
    float4 av0, av1, bv0, bv1, bv2, bv3;
    uint2 au0, au1;
    if (A_HALF) {
        au0 = *(const uint2*)(Aph);
        au1 = *(const uint2*)(Aph + 16);
    } else {
        av0 = *(const float4*)(Apf);
        av1 = *(const float4*)(Apf + 16);
    }
    bv0 = *(const float4*)(Wp);
    bv1 = *(const float4*)(Wp + N);
    bv2 = *(const float4*)(Wp + (size_t)16 * N);
    bv3 = *(const float4*)(Wp + (size_t)17 * N);

#define HB_STORE(BUF)                                                          \
    {                                                                          \
        uint32_t* As = (BUF);                                                  \
        uint32_t* Bs = (BUF) + HB_AT;                                          \
        if (A_HALF) {                                                          \
            As[kpA * HB_AW + lrA]       = au0.x;                               \
            As[(kpA + 1) * HB_AW + lrA] = au0.y;                               \
            As[(kpA + 8) * HB_AW + lrA] = au1.x;                               \
            As[(kpA + 9) * HB_AW + lrA] = au1.y;                               \
        } else {                                                               \
            As[kpA * HB_AW + lrA]       = pack_f2h(av0.x, av0.y);              \
            As[(kpA + 1) * HB_AW + lrA] = pack_f2h(av0.z, av0.w);              \
            As[(kpA + 8) * HB_AW + lrA] = pack_f2h(av1.x, av1.y);              \
            As[(kpA + 9) * HB_AW + lrA] = pack_f2h(av1.z, av1.w);              \
        }                                                                      \
        Bs[kpB * HB_BW + nB4 + 0] = pack_f2h(bv0.x, bv1.x);                    \
        Bs[kpB * HB_BW + nB4 + 1] = pack_f2h(bv0.y, bv1.y);                    \
        Bs[kpB * HB_BW + nB4 + 2] = pack_f2h(bv0.z, bv1.z);                    \
        Bs[kpB * HB_BW + nB4 + 3] = pack_f2h(bv0.w, bv1.w);                    \
        Bs[(kpB + 8) * HB_BW + nB4 + 0] = pack_f2h(bv2.x, bv3.x);              \
        Bs[(kpB + 8) * HB_BW + nB4 + 1] = pack_f2h(bv2.y, bv3.y);              \
        Bs[(kpB + 8) * HB_BW + nB4 + 2] = pack_f2h(bv2.z, bv3.z);              \
        Bs[(kpB + 8) * HB_BW + nB4 + 3] = pack_f2h(bv2.w, bv3.w);              \
    }

    HB_STORE(tiles);
    __syncthreads();

    for (int t = 0; t < nk; t++) {
        if (t + 1 < nk) {
            if (A_HALF) {
                au0 = *(const uint2*)(Aph + (size_t)(t + 1) * 32);
                au1 = *(const uint2*)(Aph + (size_t)(t + 1) * 32 + 16);
            } else {
                const float* a2 = Apf + (size_t)(t + 1) * 32;
                av0 = *(const float4*)(a2);
                av1 = *(const float4*)(a2 + 16);
            }
            const float* w2 = Wp + (size_t)(t + 1) * 32 * N;
            bv0 = *(const float4*)(w2);
            bv1 = *(const float4*)(w2 + N);
            bv2 = *(const float4*)(w2 + (size_t)16 * N);
            bv3 = *(const float4*)(w2 + (size_t)17 * N);
        }
        int s = t & 1;
        const uint32_t* As = tiles + s * HB_BUF;
        const uint32_t* Bs = As + HB_AT;

#pragma unroll
        for (int sub = 0; sub < 2; sub++) {
            int ko = sub * 8;
            uint32_t af[4][4], bf[4][2];
#pragma unroll
            for (int mt = 0; mt < 4; mt++) {
                int m0 = wm + mt * 16 + gid;
                af[mt][0] = As[(ko + tig) * HB_AW + m0];
                af[mt][1] = As[(ko + tig) * HB_AW + m0 + 8];
                af[mt][2] = As[(ko + tig + 4) * HB_AW + m0];
                af[mt][3] = As[(ko + tig + 4) * HB_AW + m0 + 8];
            }
#pragma unroll
            for (int nt = 0; nt < 4; nt++) {
                int n0 = wn + nt * 8 + gid;
                bf[nt][0] = Bs[(ko + tig) * HB_BW + n0];
                bf[nt][1] = Bs[(ko + tig + 4) * HB_BW + n0];
            }
#pragma unroll
            for (int mt = 0; mt < 4; mt++)
#pragma unroll
                for (int nt = 0; nt < 4; nt++)
                    mma_f16(acc[mt][nt], af[mt], bf[nt]);
        }

        if (t + 1 < nk) {
            uint32_t* nb = tiles + (s ^ 1) * HB_BUF;
            HB_STORE(nb);
        }
        __syncthreads();
    }
#undef HB_STORE

    if (OUT_HALF) {
        __half* outh = nullptr;
        if (MODE == 0) outh = (__half*)((z == 0) ? C0 : (z == 1 ? C1 : C2));
#pragma unroll
        for (int mt = 0; mt < 4; mt++) {
#pragma unroll
            for (int rp = 0; rp < 2; rp++) {
                int r = rowBase + wm + mt * 16 + gid + rp * 8;
                if (MODE == 2 && r >= cnt) continue;
#pragma unroll
                for (int nt = 0; nt < 4; nt++) {
                    int cg0 = colBase + wn + nt * 8 + tig * 2;
                    float v0 = acc[mt][nt][rp * 2]     + bias[cg0];
                    float v1 = acc[mt][nt][rp * 2 + 1] + bias[cg0 + 1];
                    if (MODE == 2) { v0 = gelu_exact(v0); v1 = gelu_exact(v1); }
                    uint32_t pk = pack_f2h(v0, v1);
                    if (MODE == 0)
                        *(uint32_t*)&outh[(size_t)r * N + cg0] = pk;
                    else
                        *(uint32_t*)&g_hidden_h[((size_t)e * TOK + r) * N + cg0] = pk;
                }
            }
        }
    } else {
        float* Cpf = (float*)C0;
#pragma unroll
        for (int mt = 0; mt < 4; mt++) {
#pragma unroll
            for (int c = 0; c < 4; c++) {
                int rl = wm + mt * 16 + gid + ((c & 2) ? 8 : 0);
                int r  = rowBase + rl;
#pragma unroll
                for (int nt = 0; nt < 4; nt++) {
                    int cg = colBase + wn + nt * 8 + tig * 2 + (c & 1);
                    float v = acc[mt][nt][c] + bias[cg];
                    if (MODE == 1) {
                        Cpf[(size_t)r * N + cg] = v + Cpf[(size_t)r * N + cg];
                    } else {
                        g_moeout[((size_t)(e * TOK + r)) * N + cg] = v * s_wt[rl];
                    }
                }
            }
        }
    }
}

// ---------------- fp16 split flash attention (layer 0) -----------------------
#define FQ2 (32*136)
#define FK2 (32*72)
#define FV2 (32*72)
#define FP2 (32*136)
#define FL2_TOT (FQ2+FK2+FV2+FP2)
#define FL2_SMEM1 (FL2_TOT*8)

template<int SPLIT>
__global__ void __launch_bounds__(256, 2)
flash_h() {
    extern __shared__ uint32_t fu[];
    uint32_t* Qh = fu;
    uint32_t* Ql = Qh + FQ2;
    uint32_t* Kh = Qh + FQ2 * (SPLIT + 1);
    uint32_t* Kl = Kh + FK2;
    uint32_t* Vh = Kh + FK2 * (SPLIT + 1);
    uint32_t* Vl = Vh + FV2;
    uint32_t* Ph = Vh + FV2 * (SPLIT + 1);
    uint32_t* Pl = Ph + FP2;

    int qb = (int)(gridDim.x - 1 - blockIdx.x);
    int h = blockIdx.y, b = blockIdx.z;
    int tid = threadIdx.x, warp = tid >> 5, lane = tid & 31;
    int gid = lane >> 2, tig = lane & 3;
    int mrow = warp * 16 + gid;

    for (int i = tid; i < 2048; i += 256) {
        int r = i >> 4, d4 = (i & 15) << 2, dp = (i & 15) << 1;
        float4 v = *(const float4*)&g_Q[((size_t)(b * Sq + qb * 128 + r)) * Dq + h * HD + d4];
        __half h0 = __float2half_rn(v.x), h1 = __float2half_rn(v.y);
        __half h2 = __float2half_rn(v.z), h3 = __float2half_rn(v.w);
        Qh[dp * 136 + r]       = pack_h2(h0, h1);
        Qh[(dp + 1) * 136 + r] = pack_h2(h2, h3);
        if (SPLIT) {
            Ql[dp * 136 + r]       = pack_f2h(v.x - __half2float(h0), v.y - __half2float(h1));
            Ql[(dp + 1) * 136 + r] = pack_f2h(v.z - __half2float(h2), v.w - __half2float(h3));
        }
    }

    float mA = -1e30f, mB = -1e30f, lA = 0.f, lB = 0.f;
    float o[8][4];
#pragma unroll
    for (int nt = 0; nt < 8; nt++)
#pragma unroll
        for (int c = 0; c < 4; c++) o[nt][c] = 0.f;

    int nkt = 2 * qb + 2;
    for (int kt = 0; kt < nkt; kt++) {
        __syncthreads();
        for (int i = tid; i < 1024; i += 256) {
            int r = i >> 4, d4 = (i & 15) << 2, dp = (i & 15) << 1;
            size_t base = ((size_t)(b * Sq + kt * 64 + r)) * Dq + h * HD + d4;
            float4 kv = *(const float4*)&g_K[base];
            __half h0 = __float2half_rn(kv.x), h1 = __float2half_rn(kv.y);
            __half h2 = __float2half_rn(kv.z), h3 = __float2half_rn(kv.w);
            Kh[dp * 72 + r]       = pack_h2(h0, h1);
            Kh[(dp + 1) * 72 + r] = pack_h2(h2, h3);
            if (SPLIT) {
                Kl[dp * 72 + r]       = pack_f2h(kv.x - __half2float(h0), kv.y - __half2float(h1));
                Kl[(dp + 1) * 72 + r] = pack_f2h(kv.z - __half2float(h2), kv.w - __half2float(h3));
            }
        }
        float4 vr0[2], vr1[2];
#pragma unroll
        for (int ii = 0; ii < 2; ii++) {
            int i = tid + ii * 256;
            int kp = i >> 4, d4 = (i & 15) << 2;
            size_t base0 = ((size_t)(b * Sq + kt * 64 + 2 * kp)) * Dq + h * HD + d4;
            vr0[ii] = *(const float4*)&g_V[base0];
            vr1[ii] = *(const float4*)&g_V[base0 + Dq];
        }
        __syncthreads();

        float s[8][4];
#pragma unroll
        for (int nt = 0; nt < 8; nt++)
#pragma unroll
            for (int c = 0; c < 4; c++) s[nt][c] = 0.f;

#pragma unroll
        for (int ks = 0; ks < 4; ks++) {
            int kp0 = 8 * ks + tig, kp1 = 8 * ks + tig + 4;
            uint32_t a[4], al[4];
            a[0] = Qh[kp0 * 136 + mrow];
            a[1] = Qh[kp0 * 136 + mrow + 8];
            a[2] = Qh[kp1 * 136 + mrow];
            a[3] = Qh[kp1 * 136 + mrow + 8];
            if (SPLIT) {
                al[0] = Ql[kp0 * 136 + mrow];
                al[1] = Ql[kp0 * 136 + mrow + 8];
                al[2] = Ql[kp1 * 136 + mrow];
                al[3] = Ql[kp1 * 136 + mrow + 8];
            }
#pragma unroll
            for (int gq = 0; gq < 2; gq++) {
                uint32_t bb[4][2], bl[4][2];
#pragma unroll
                for (int j = 0; j < 4; j++) {
                    int n0 = (gq * 4 + j) * 8 + gid;
                    bb[j][0] = Kh[kp0 * 72 + n0];
                    bb[j][1] = Kh[kp1 * 72 + n0];
                    if (SPLIT) {
                        bl[j][0] = Kl[kp0 * 72 + n0];
                        bl[j][1] = Kl[kp1 * 72 + n0];
                    }
                }
#pragma unroll
                for (int j = 0; j < 4; j++) mma_f16(s[gq * 4 + j], a, bb[j]);
                if (SPLIT) {
#pragma unroll
                    for (int j = 0; j < 4; j++) mma_f16(s[gq * 4 + j], a, bl[j]);
#pragma unroll
                    for (int j = 0; j < 4; j++) mma_f16(s[gq * 4 + j], al, bb[j]);
                }
            }
        }

        int rowg = qb * 128 + warp * 16 + gid;
        if (kt * 64 + 63 > rowg) {
#pragma unroll
            for (int nt = 0; nt < 8; nt++)
#pragma unroll
                for (int c = 0; c < 4; c++) {
                    int col = kt * 64 + nt * 8 + 2 * tig + (c & 1);
                    int row = rowg + ((c & 2) ? 8 : 0);
                    float sv = s[nt][c] * 0.125f;
                    s[nt][c] = (col > row) ? -1e30f : sv;
                }
        } else {
#pragma unroll
            for (int nt = 0; nt < 8; nt++)
#pragma unroll
                for (int c = 0; c < 4; c++) s[nt][c] *= 0.125f;
        }

        float rmA = -1e30f, rmB = -1e30f;
#pragma unroll
        for (int nt = 0; nt < 8; nt++) {
            rmA = fmaxf(rmA, fmaxf(s[nt][0], s[nt][1]));
            rmB = fmaxf(rmB, fmaxf(s[nt][2], s[nt][3]));
        }
#pragma unroll
        for (int off = 1; off < 4; off <<= 1) {
            rmA = fmaxf(rmA, __shfl_xor_sync(0xffffffffu, rmA, off));
            rmB = fmaxf(rmB, __shfl_xor_sync(0xffffffffu, rmB, off));
        }
        float mnA = fmaxf(mA, rmA), mnB = fmaxf(mB, rmB);
        float alA = __expf(mA - mnA), alB = __expf(mB - mnB);
        float rsA = 0.f, rsB = 0.f;
#pragma unroll
        for (int nt = 0; nt < 8; nt++) {
            s[nt][0] = __expf(s[nt][0] - mnA); rsA += s[nt][0];
            s[nt][1] = __expf(s[nt][1] - mnA); rsA += s[nt][1];
            s[nt][2] = __expf(s[nt][2] - mnB); rsB += s[nt][2];
            s[nt][3] = __expf(s[nt][3] - mnB); rsB += s[nt][3];
        }
#pragma unroll
        for (int off = 1; off < 4; off <<= 1) {
            rsA += __shfl_xor_sync(0xffffffffu, rsA, off);
            rsB += __shfl_xor_sync(0xffffffffu, rsB, off);
        }
        lA = lA * alA + rsA; mA = mnA;
        lB = lB * alB + rsB; mB = mnB;
#pragma unroll
        for (int nt = 0; nt < 8; nt++) {
            o[nt][0] *= alA; o[nt][1] *= alA;
            o[nt][2] *= alB; o[nt][3] *= alB;
        }

#pragma unroll
        for (int nt = 0; nt < 8; nt++) {
            int kpP = nt * 4 + tig;
            __half p0 = __float2half_rn(s[nt][0]), p1 = __float2half_rn(s[nt][1]);
            __half p2 = __float2half_rn(s[nt][2]), p3 = __float2half_rn(s[nt][3]);
            Ph[kpP * 136 + mrow]     = pack_h2(p0, p1);
            Ph[kpP * 136 + mrow + 8] = pack_h2(p2, p3);
            if (SPLIT) {
                Pl[kpP * 136 + mrow]     = pack_f2h(s[nt][0] - __half2float(p0),
                                                    s[nt][1] - __half2float(p1));
                Pl[kpP * 136 + mrow + 8] = pack_f2h(s[nt][2] - __half2float(p2),
                                                    s[nt][3] - __half2float(p3));
            }
        }
#pragma unroll
        for (int ii = 0; ii < 2; ii++) {
            int i = tid + ii * 256;
            int kp = i >> 4, d4 = (i & 15) << 2;
            float a0[4] = {vr0[ii].x, vr0[ii].y, vr0[ii].z, vr0[ii].w};
            float a1[4] = {vr1[ii].x, vr1[ii].y, vr1[ii].z, vr1[ii].w};
#pragma unroll
            for (int j = 0; j < 4; j++) {
                __half p0 = __float2half_rn(a0[j]), p1 = __float2half_rn(a1[j]);
                Vh[kp * 72 + d4 + j] = pack_h2(p0, p1);
                if (SPLIT)
                    Vl[kp * 72 + d4 + j] = pack_f2h(a0[j] - __half2float(p0),
                                                    a1[j] - __half2float(p1));
            }
        }
        __syncthreads();

#pragma unroll
        for (int ks = 0; ks < 4; ks++) {
            int kp0 = 8 * ks + tig, kp1 = 8 * ks + tig + 4;
            uint32_t a[4], al[4];
            a[0] = Ph[kp0 * 136 + mrow];
            a[1] = Ph[kp0 * 136 + mrow + 8];
            a[2] = Ph[kp1 * 136 + mrow];
            a[3] = Ph[kp1 * 136 + mrow + 8];
            if (SPLIT) {
                al[0] = Pl[kp0 * 136 + mrow];
                al[1] = Pl[kp0 * 136 + mrow + 8];
                al[2] = Pl[kp1 * 136 + mrow];
                al[3] = Pl[kp1 * 136 + mrow + 8];
            }
#pragma unroll
            for (int gq = 0; gq < 2; gq++) {
                uint32_t bb[4][2], bl[4][2];
#pragma unroll
                for (int j = 0; j < 4; j++) {
                    int n0 = (gq * 4 + j) * 8 + gid;
                    bb[j][0] = Vh[kp0 * 72 + n0];
                    bb[j][1] = Vh[kp1 * 72 + n0];
                    if (SPLIT) {
                        bl[j][0] = Vl[kp0 * 72 + n0];
                        bl[j][1] = Vl[kp1 * 72 + n0];
                    }
                }
#pragma unroll
                for (int j = 0; j < 4; j++) mma_f16(o[gq * 4 + j], a, bb[j]);
                if (SPLIT) {
#pragma unroll
                    for (int j = 0; j < 4; j++) mma_f16(o[gq * 4 + j], a, bl[j]);
#pragma unroll
                    for (int j = 0; j < 4; j++) mma_f16(o[gq * 4 + j], al, bb[j]);
                }
            }
        }
    }

    float invA = 1.0f / lA, invB = 1.0f / lB;
    size_t rbase0 = ((size_t)(b * Sq + qb * 128 + warp * 16 + gid)) * Dq + h * HD;
    size_t rbase1 = rbase0 + (size_t)8 * Dq;
#pragma unroll
    for (int nt = 0; nt < 8; nt++) {
        int d0 = nt * 8 + 2 * tig;
        *(float2*)&g_Y[rbase0 + d0] = make_float2(o[nt][0] * invA, o[nt][1] * invA);
        *(float2*)&g_Y[rbase1 + d0] = make_float2(o[nt][2] * invB, o[nt][3] * invB);
    }
}

// ---------------- fp16 1-pass flash (layer 1, pipelined, half I/O) -----------
#define F0_Q  (32*136)
#define F0_K  (32*72)
#define F0_V  (32*72)
#define F0_P  (32*136)
#define FL0_SMEM ((F0_Q + F0_K + 2*F0_V + F0_P) * 4)   // 62464 B

__global__ void __launch_bounds__(256, 2)
flash_h0() {
    extern __shared__ uint32_t fu[];
    uint32_t* Qh = fu;
    uint32_t* Kh = Qh + F0_Q;
    uint32_t* Vh0 = Kh + F0_K;
    uint32_t* Vh1 = Vh0 + F0_V;
    uint32_t* Ph = Vh1 + F0_V;

    int qb = (int)(gridDim.x - 1 - blockIdx.x);
    int h = blockIdx.y, b = blockIdx.z;
    int tid = threadIdx.x, warp = tid >> 5, lane = tid & 31;
    int gid = lane >> 2, tig = lane & 3;
    int mrow = warp * 16 + gid;

    // Q load (half source: uint4 = 8 halves = 4 smem words)
    for (int i = tid; i < 1024; i += 256) {
        int r = i >> 3, d8 = (i & 7) << 3, dp = d8 >> 1;
        uint4 u = *(const uint4*)&g_Qh[((size_t)(b * Sq + qb * 128 + r)) * Dq + h * HD + d8];
        Qh[(dp + 0) * 136 + r] = u.x;
        Qh[(dp + 1) * 136 + r] = u.y;
        Qh[(dp + 2) * 136 + r] = u.z;
        Qh[(dp + 3) * 136 + r] = u.w;
    }
    // preload tile 0: K, V
    for (int i = tid; i < 512; i += 256) {
        int r = i >> 3, d8 = (i & 7) << 3, dp = d8 >> 1;
        uint4 u = *(const uint4*)&g_Kh[((size_t)(b * Sq + r)) * Dq + h * HD + d8];
        Kh[(dp + 0) * 72 + r] = u.x;
        Kh[(dp + 1) * 72 + r] = u.y;
        Kh[(dp + 2) * 72 + r] = u.z;
        Kh[(dp + 3) * 72 + r] = u.w;
    }
    for (int i = tid; i < 512; i += 256) {
        int kp = i >> 4, d4 = (i & 15) << 2;
        size_t base0 = ((size_t)(b * Sq + 2 * kp)) * Dq + h * HD + d4;
        uint2 a = *(const uint2*)&g_Vh[base0];
        uint2 c = *(const uint2*)&g_Vh[base0 + Dq];
        Vh0[kp * 72 + d4 + 0] = __byte_perm(a.x, c.x, 0x5410);
        Vh0[kp * 72 + d4 + 1] = __byte_perm(a.x, c.x, 0x7632);
        Vh0[kp * 72 + d4 + 2] = __byte_perm(a.y, c.y, 0x5410);
        Vh0[kp * 72 + d4 + 3] = __byte_perm(a.y, c.y, 0x7632);
    }
    __syncthreads();

    float mA = -1e30f, mB = -1e30f, lA = 0.f, lB = 0.f;
    float o[8][4];
#pragma unroll
    for (int nt = 0; nt < 8; nt++)
#pragma unroll
        for (int c = 0; c < 4; c++) o[nt][c] = 0.f;

    int nkt = 2 * qb + 2;
    for (int kt = 0; kt < nkt; kt++) {
        uint32_t* Vcur = (kt & 1) ? Vh1 : Vh0;
        uint32_t* Vnxt = (kt & 1) ? Vh0 : Vh1;

        uint4 kreg[2];
        uint2 va[2], vb[2];
        bool more = (kt + 1 < nkt);
        if (more) {
#pragma unroll
            for (int ii = 0; ii < 2; ii++) {
                int i = tid + ii * 256;
                int r = i >> 3, d8 = (i & 7) << 3;
                kreg[ii] = *(const uint4*)&g_Kh[((size_t)(b * Sq + (kt + 1) * 64 + r)) * Dq + h * HD + d8];
            }
#pragma unroll
            for (int ii = 0; ii < 2; ii++) {
                int i = tid + ii * 256;
                int kp = i >> 4, d4 = (i & 15) << 2;
                size_t base0 = ((size_t)(b * Sq + (kt + 1) * 64 + 2 * kp)) * Dq + h * HD + d4;
                va[ii] = *(const uint2*)&g_Vh[base0];
                vb[ii] = *(const uint2*)&g_Vh[base0 + Dq];
            }
        }

        // S = Q @ K^T
        float s[8][4];
#pragma unroll
        for (int nt = 0; nt < 8; nt++)
#pragma unroll
            for (int c = 0; c < 4; c++) s[nt][c] = 0.f;
#pragma unroll
        for (int ks = 0; ks < 4; ks++) {
            int kp0 = 8 * ks + tig, kp1 = 8 * ks + tig + 4;
            uint32_t a[4];
            a[0] = Qh[kp0 * 136 + mrow];
            a[1] = Qh[kp0 * 136 + mrow + 8];
            a[2] = Qh[kp1 * 136 + mrow];
            a[3] = Qh[kp1 * 136 + mrow + 8];
#pragma unroll
            for (int gq = 0; gq < 2; gq++) {
                uint32_t bb[4][2];
#pragma unroll
                for (int j = 0; j < 4; j++) {
                    int n0 = (gq * 4 + j) * 8 + gid;
                    bb[j][0] = Kh[kp0 * 72 + n0];
                    bb[j][1] = Kh[kp1 * 72 + n0];
                }
#pragma unroll
                for (int j = 0; j < 4; j++) mma_f16(s[gq * 4 + j], a, bb[j]);
            }
        }

        int rowg = qb * 128 + warp * 16 + gid;
        if (kt * 64 + 63 > rowg) {
#pragma unroll
            for (int nt = 0; nt < 8; nt++)
#pragma unroll
                for (int c = 0; c < 4; c++) {
                    int col = kt * 64 + nt * 8 + 2 * tig + (c & 1);
                    int row = rowg + ((c & 2) ? 8 : 0);
                    float sv = s[nt][c] * 0.125f;
                    s[nt][c] = (col > row) ? -1e30f : sv;
                }
        } else {
#pragma unroll
            for (int nt = 0; nt < 8; nt++)
#pragma unroll
                for (int c = 0; c < 4; c++) s[nt][c] *= 0.125f;
        }

        float rmA = -1e30f, rmB = -1e30f;
#pragma unroll
        for (int nt = 0; nt < 8; nt++) {
            rmA = fmaxf(rmA, fmaxf(s[nt][0], s[nt][1]));
            rmB = fmaxf(rmB, fmaxf(s[nt][2], s[nt][3]));
        }
#pragma unroll
        for (int off = 1; off < 4; off <<= 1) {
            rmA = fmaxf(rmA, __shfl_xor_sync(0xffffffffu, rmA, off));
            rmB = fmaxf(rmB, __shfl_xor_sync(0xffffffffu, rmB, off));
        }
        float mnA = fmaxf(mA, rmA), mnB = fmaxf(mB, rmB);
        float alA = __expf(mA - mnA), alB = __expf(mB - mnB);
        float rsA = 0.f, rsB = 0.f;
#pragma unroll
        for (int nt = 0; nt < 8; nt++) {
            s[nt][0] = __expf(s[nt][0] - mnA); rsA += s[nt][0];
            s[nt][1] = __expf(s[nt][1] - mnA); rsA += s[nt][1];
            s[nt][2] = __expf(s[nt][2] - mnB); rsB += s[nt][2];
            s[nt][3] = __expf(s[nt][3] - mnB); rsB += s[nt][3];
        }
#pragma unroll
        for (int off = 1; off < 4; off <<= 1) {
            rsA += __shfl_xor_sync(0xffffffffu, rsA, off);
            rsB += __shfl_xor_sync(0xffffffffu, rsB, off);
        }
        lA = lA * alA + rsA; mA = mnA;
        lB = lB * alB + rsB; mB = mnB;
#pragma unroll
        for (int nt = 0; nt < 8; nt++) {
            o[nt][0] *= alA; o[nt][1] *= alA;
            o[nt][2] *= alB; o[nt][3] *= alB;
        }

        __syncthreads();

#pragma unroll
        for (int nt = 0; nt < 8; nt++) {
            int kpP = nt * 4 + tig;
            Ph[kpP * 136 + mrow]     = pack_f2h(s[nt][0], s[nt][1]);
            Ph[kpP * 136 + mrow + 8] = pack_f2h(s[nt][2], s[nt][3]);
        }
        if (more) {
#pragma unroll
            for (int ii = 0; ii < 2; ii++) {
                int i = tid + ii * 256;
                int r = i >> 3, dp = ((i & 7) << 3) >> 1;
                Kh[(dp + 0) * 72 + r] = kreg[ii].x;
                Kh[(dp + 1) * 72 + r] = kreg[ii].y;
                Kh[(dp + 2) * 72 + r] = kreg[ii].z;
                Kh[(dp + 3) * 72 + r] = kreg[ii].w;
            }
#pragma unroll
            for (int ii = 0; ii < 2; ii++) {
                int i = tid + ii * 256;
                int kp = i >> 4, d4 = (i & 15) << 2;
                Vnxt[kp * 72 + d4 + 0] = __byte_perm(va[ii].x, vb[ii].x, 0x5410);
                Vnxt[kp * 72 + d4 + 1] = __byte_perm(va[ii].x, vb[ii].x, 0x7632);
                Vnxt[kp * 72 + d4 + 2] = __byte_perm(va[ii].y, vb[ii].y, 0x5410);
                Vnxt[kp * 72 + d4 + 3] = __byte_perm(va[ii].y, vb[ii].y, 0x7632);
            }
        }
        __syncthreads();

#pragma unroll
        for (int ks = 0; ks < 4; ks++) {
            int kp0 = 8 * ks + tig, kp1 = 8 * ks + tig + 4;
            uint32_t a[4];
            a[0] = Ph[kp0 * 136 + mrow];
            a[1] = Ph[kp0 * 136 + mrow + 8];
            a[2] = Ph[kp1 * 136 + mrow];
            a[3] = Ph[kp1 * 136 + mrow + 8];
#pragma unroll
            for (int gq = 0; gq < 2; gq++) {
                uint32_t bb[4][2];
#pragma unroll
                for (int j = 0; j < 4; j++) {
                    int n0 = (gq * 4 + j) * 8 + gid;
                    bb[j][0] = Vcur[kp0 * 72 + n0];
                    bb[j][1] = Vcur[kp1 * 72 + n0];
                }
#pragma unroll
                for (int j = 0; j < 4; j++) mma_f16(o[gq * 4 + j], a, bb[j]);
            }
        }
    }

    // write Y as fp16 (rn at producer; consumed directly by O-proj)
    float invA = 1.0f / lA, invB = 1.0f / lB;
    size_t rbase0 = ((size_t)(b * Sq + qb * 128 + warp * 16 + gid)) * Dq + h * HD;
    size_t rbase1 = rbase0 + (size_t)8 * Dq;
#pragma unroll
    for (int nt = 0; nt < 8; nt++) {
        int d0 = nt * 8 + 2 * tig;
        *(uint32_t*)&g_Yh[rbase0 + d0] = pack_f2h(o[nt][0] * invA, o[nt][1] * invA);
        *(uint32_t*)&g_Yh[rbase1 + d0] = pack_f2h(o[nt][2] * invB, o[nt][3] * invB);
    }
}

// ---------------- gating -----------------------------------------------------
__global__ void gate_token_kernel(const float* __restrict__ gw,
                                  const float* __restrict__ gb, int layer) {
    if (blockIdx.x == 0 && threadIdx.x < Ee) g_counts[threadIdx.x] = 0;
    int t = blockIdx.x * 4 + (threadIdx.x >> 5);
    int lane = threadIdx.x & 31;
    if (t >= TOK) return;
    const float* hrow = g_H + (size_t)t * Dq;
    const float* gwl = gw + (size_t)layer * Dq * Ee;
    float acc[Ee] = {};
    for (int d = lane; d < Dq; d += 32) {
        float hv = hrow[d];
        const float* g = gwl + (size_t)d * Ee;
#pragma unroll
        for (int e = 0; e < Ee; e++) acc[e] += hv * g[e];
    }
#pragma unroll
    for (int e = 0; e < Ee; e++)
        for (int off = 16; off; off >>= 1)
            acc[e] += __shfl_xor_sync(0xffffffffu, acc[e], off);
    if (lane == 0) {
        float lg[Ee];
#pragma unroll
        for (int e = 0; e < Ee; e++) lg[e] = acc[e] + gb[layer * Ee + e];
        int i1, i2; float w1, w2;
        top2_of8(lg, i1, i2, w1, w2);
        g_te[t * 2] = i1; g_te[t * 2 + 1] = i2;
        g_tw[t * 2] = w1; g_tw[t * 2 + 1] = w2;
    }
}

__global__ void xmean_kernel() {
    int b = blockIdx.y;
    int d = blockIdx.x * 256 + threadIdx.x;
    float s = 0.f;
    for (int ss = 0; ss < Sq; ss++)
        s += g_H[((size_t)(b * Sq + ss)) * Dq + d];
    g_xmean[b * Dq + d] = s * (1.0f / Sq);
}

__global__ void gate_seq_kernel(const float* __restrict__ gw,
                                const float* __restrict__ gb, int layer) {
    if (blockIdx.x == 0 && threadIdx.x < Ee) g_counts[threadIdx.x] = 0;
    int b = blockIdx.x;
    int tid = threadIdx.x, e = tid >> 5, lane = tid & 31;
    const float* gwl = gw + (size_t)layer * Dq * Ee;
    float acc = 0.f;
    for (int d = lane; d < Dq; d += 32)
        acc += g_xmean[b * Dq + d] * gwl[(size_t)d * Ee + e];
    for (int off = 16; off; off >>= 1)
        acc += __shfl_xor_sync(0xffffffffu, acc, off);
    __shared__ float lg[Ee];
    if (lane == 0) lg[e] = acc + gb[layer * Ee + e];
    __syncthreads();
    if (tid == 0) {
        int i1, i2; float w1, w2;
        top2_of8(lg, i1, i2, w1, w2);
        g_bsel[b * 2] = i1; g_bsel[b * 2 + 1] = i2;
        g_bw[b * 2] = w1;  g_bw[b * 2 + 1] = w2;
    }
}

__global__ void assign_kernel(int seq_mode) {
    int t = blockIdx.x * 256 + threadIdx.x;
    if (t >= TOK) return;
    int e1, e2; float w1, w2;
    if (seq_mode) {
        int b = t / Sq;
        e1 = g_bsel[b * 2]; e2 = g_bsel[b * 2 + 1];
        w1 = g_bw[b * 2];   w2 = g_bw[b * 2 + 1];
    } else {
        e1 = g_te[t * 2]; e2 = g_te[t * 2 + 1];
        w1 = g_tw[t * 2]; w2 = g_tw[t * 2 + 1];
    }
    int s1 = atomicAdd(&g_counts[e1], 1);
    g_tok[e1 * TOK + s1] = t; g_wt[e1 * TOK + s1] = w1;
    g_islot[t * 2] = e1 * TOK + s1;
    int s2 = atomicAdd(&g_counts[e2], 1);
    g_tok[e2 * TOK + s2] = t; g_wt[e2 * TOK + s2] = w2;
    g_islot[t * 2 + 1] = e2 * TOK + s2;
}

// ---------------- host side --------------------------------------------------
extern "C" void kernel_launch(void* const* d_in, const int* in_sizes, int n_in,
                              void* d_out, int out_size) {
    const float* x      = (const float*)d_in[0];
    const float* ln1_w  = (const float*)d_in[1];
    const float* ln1_b  = (const float*)d_in[2];
    const float* ln2_w  = (const float*)d_in[3];
    const float* ln2_b  = (const float*)d_in[4];
    const float* wq     = (const float*)d_in[5];
    const float* wk     = (const float*)d_in[6];
    const float* wv     = (const float*)d_in[7];
    const float* wo     = (const float*)d_in[8];
    const float* bq     = (const float*)d_in[9];
    const float* bk     = (const float*)d_in[10];
    const float* bv     = (const float*)d_in[11];
    const float* bo     = (const float*)d_in[12];
    const float* gate_w = (const float*)d_in[13];
    const float* gate_b = (const float*)d_in[14];
    const float* e_w1   = (const float*)d_in[15];
    const float* e_b1   = (const float*)d_in[16];
    const float* e_w2   = (const float*)d_in[17];
    const float* e_b2   = (const float*)d_in[18];

    float *Xp, *Hp, *Qp, *Kp, *Vp, *Yp;
    void *Qhp, *Khp, *Vhp, *Yhp;
    cudaGetSymbolAddress((void**)&Xp, g_X);
    cudaGetSymbolAddress((void**)&Hp, g_H);
    cudaGetSymbolAddress((void**)&Qp, g_Q);
    cudaGetSymbolAddress((void**)&Kp, g_K);
    cudaGetSymbolAddress((void**)&Vp, g_V);
    cudaGetSymbolAddress((void**)&Yp, g_Y);
    cudaGetSymbolAddress(&Qhp, g_Qh);
    cudaGetSymbolAddress(&Khp, g_Kh);
    cudaGetSymbolAddress(&Vhp, g_Vh);
    cudaGetSymbolAddress(&Yhp, g_Yh);

    static int attr_set = 0;
    if (!attr_set) {
        cudaFuncSetAttribute(gemm_h3<0>, cudaFuncAttributeMaxDynamicSharedMemorySize, SMEM_H3);
        cudaFuncSetAttribute(gemm_h3<1>, cudaFuncAttributeMaxDynamicSharedMemorySize, SMEM_H3);
        cudaFuncSetAttribute(gemm_hb<0>, cudaFuncAttributeMaxDynamicSharedMemorySize, SMEM_HB);
        cudaFuncSetAttribute(gemm_hb<1>, cudaFuncAttributeMaxDynamicSharedMemorySize, SMEM_HB);
        cudaFuncSetAttribute(gemm_hb<2>, cudaFuncAttributeMaxDynamicSharedMemorySize, SMEM_HB);
        cudaFuncSetAttribute(gemm_hb<3>, cudaFuncAttributeMaxDynamicSharedMemorySize, SMEM_HB);
        cudaFuncSetAttribute(flash_h<1>, cudaFuncAttributeMaxDynamicSharedMemorySize, FL2_SMEM1);
        cudaFuncSetAttribute(flash_h0,   cudaFuncAttributeMaxDynamicSharedMemorySize, FL0_SMEM);
        attr_set = 1;
    }

    const size_t DD = (size_t)Dq * Dq;
    const int nelem = TOK * Dq;

    copy_in_kernel<<<nelem / 256, 256>>>(x);

    for (int l = 0; l < Ll; l++) {
        const float* WQ = wq + l * DD;
        const float* WK = wk + l * DD;
        const float* WV = wv + l * DD;
        const float* WO = wo + l * DD;
        const float* BQ = bq + (size_t)l * Dq;
        const float* BK = bk + (size_t)l * Dq;
        const float* BV = bv + (size_t)l * Dq;
        const float* BO = bo + (size_t)l * Dq;

        if (l == 0)
            ln_kernel<<<TOK, 256>>>(ln1_w + (size_t)l * Dq, ln1_b + (size_t)l * Dq);
        else
            ln_combine_kernel<<<TOK, 256>>>(ln1_w + (size_t)l * Dq, ln1_b + (size_t)l * Dq);

        if (l == 0) {
            gemm_h3<0><<<dim3(8, 32, 3), 512, SMEM_H3>>>(
                Hp, WQ, WK, WV, BQ, BK, BV, Qp, Kp, Vp, Dq, Dq);
            flash_h<1><<<dim3(Sq / 128, Hh, Bq), 256, FL2_SMEM1>>>();
            gemm_h3<1><<<dim3(8, 32), 512, SMEM_H3>>>(
                Yp, WO, nullptr, nullptr, BO, nullptr, nullptr, Xp, nullptr, nullptr, Dq, Dq);
        } else {
            gemm_hb<0><<<dim3(4, 32, 3), 512, SMEM_HB>>>(
                Hp, WQ, WK, WV, BQ, BK, BV, Qhp, Khp, Vhp, Dq, Dq, l);
            flash_h0<<<dim3(Sq / 128, Hh, Bq), 256, FL0_SMEM>>>();
            gemm_hb<1><<<dim3(4, 32), 512, SMEM_HB>>>(
                Yhp, WO, nullptr, nullptr, BO, nullptr, nullptr, Xp, nullptr, nullptr, Dq, Dq, l);
        }

        ln_kernel<<<TOK, 256>>>(ln2_w + (size_t)l * Dq, ln2_b + (size_t)l * Dq);
        if (l % 2 == 0) {
            gate_token_kernel<<<TOK / 4, 128>>>(gate_w, gate_b, l);
        } else {
            xmean_kernel<<<dim3(Dq / 256, Bq), 256>>>();
            gate_seq_kernel<<<Bq, 256>>>(gate_w, gate_b, l);
        }
        assign_kernel<<<TOK / 256, 256>>>(l % 2);
        gemm_hb<2><<<dim3(DFFq / 256, TOK / 128, Ee), 512, SMEM_HB>>>(
            nullptr, e_w1, nullptr, nullptr, e_b1, nullptr, nullptr,
            nullptr, nullptr, nullptr, Dq, DFFq, l);
        gemm_hb<3><<<dim3(Dq / 256, TOK / 128, Ee), 512, SMEM_HB>>>(
            nullptr, e_w2, nullptr, nullptr, e_b2, nullptr, nullptr,
            nullptr, nullptr, nullptr, DFFq, Dq, l);
    }

    combine_out_kernel<<<nelem / 1024, 256>>>((float*)d_out);
    (void)in_sizes; (void)n_in; (void)out_size;
}